// round 1
// baseline (speedup 1.0000x reference)
#include <cuda_runtime.h>
#include <cuda_bf16.h>
#include <math.h>

// Problem constants
#define BB 4
#define TT 2048
#define DD 1024
#define HH 8
#define DH 64
#define EE 5
#define NTOK (BB*TT)          // 8192
#define QKW (HH*DH)           // 512
#define GW  (HH*EE)           // 40
#define XVW (EE*DH)           // 320

// ---------------- scratch (device globals; no allocation allowed) ------------
__device__ float g_q   [NTOK*QKW];
__device__ float g_k   [NTOK*QKW];
__device__ float g_v   [NTOK*QKW];
__device__ float g_attn[NTOK*QKW];
__device__ float g_glv [NTOK*GW];
__device__ float g_glo [NTOK*GW];
__device__ float g_mask[NTOK*GW];
__device__ float g_xv  [NTOK*XVW];
__device__ float g_y   [NTOK*XVW];
__device__ float g_wvp [DD*XVW];

// ---------------- generic tiled SGEMM: C(MxN) = A(MxK) @ B(KxN), row-major ---
#define TS 64
#define KT 16
__global__ void sgemm_kernel(const float* __restrict__ A,
                             const float* __restrict__ B,
                             float* __restrict__ C,
                             int M, int N, int K) {
    __shared__ float As[KT][TS + 1];
    __shared__ float Bs[KT][TS + 1];
    const int tid = threadIdx.x;
    const int tx = tid % 16, ty = tid / 16;
    const int row0 = blockIdx.y * TS;
    const int col0 = blockIdx.x * TS;

    float acc[4][4];
#pragma unroll
    for (int i = 0; i < 4; i++)
#pragma unroll
        for (int j = 0; j < 4; j++) acc[i][j] = 0.f;

    for (int k0 = 0; k0 < K; k0 += KT) {
        // A tile: 64 rows x 16 k  (consecutive threads read consecutive k)
#pragma unroll
        for (int i = tid; i < TS * KT; i += 256) {
            int m = i / KT, kk = i % KT;
            int gr = row0 + m;
            As[kk][m] = (gr < M) ? A[(size_t)gr * K + k0 + kk] : 0.f;
        }
        // B tile: 16 k x 64 cols (consecutive threads read consecutive n)
#pragma unroll
        for (int i = tid; i < TS * KT; i += 256) {
            int n = i % TS, kk = i / TS;
            int gc = col0 + n;
            Bs[kk][n] = (gc < N) ? B[(size_t)(k0 + kk) * N + gc] : 0.f;
        }
        __syncthreads();
#pragma unroll
        for (int kk = 0; kk < KT; kk++) {
            float a[4], b[4];
#pragma unroll
            for (int i = 0; i < 4; i++) a[i] = As[kk][ty * 4 + i];
#pragma unroll
            for (int j = 0; j < 4; j++) b[j] = Bs[kk][tx * 4 + j];
#pragma unroll
            for (int i = 0; i < 4; i++)
#pragma unroll
                for (int j = 0; j < 4; j++) acc[i][j] += a[i] * b[j];
        }
        __syncthreads();
    }
#pragma unroll
    for (int i = 0; i < 4; i++) {
        int gr = row0 + ty * 4 + i;
        if (gr >= M) continue;
#pragma unroll
        for (int j = 0; j < 4; j++) {
            int gc = col0 + tx * 4 + j;
            if (gc < N) C[(size_t)gr * N + gc] = acc[i][j];
        }
    }
}

// ---------------- pack Wv (E,D,DH) -> (D, E*DH) row-major --------------------
__global__ void pack_wv_kernel(const float* __restrict__ Wv, float* __restrict__ Wp) {
    int idx = blockIdx.x * blockDim.x + threadIdx.x;
    if (idx >= DD * XVW) return;
    int d = idx / XVW;
    int n = idx % XVW;
    int e = n / DH, j = n % DH;
    Wp[idx] = Wv[((size_t)e * DD + d) * DH + j];
}

// -------- top-2 gating: sigmoid-weighted V combine + output mask -------------
// grid = NTOK, block = 256 (warp w handles head w)
__global__ void gate_combine_kernel(const float* __restrict__ glv,
                                    const float* __restrict__ glo,
                                    const float* __restrict__ xv,
                                    float* __restrict__ v,
                                    float* __restrict__ masko) {
    int token = blockIdx.x;
    int w = threadIdx.x / 32;   // head
    int lane = threadIdx.x % 32;

    // ---- V gate: top-2 of 5 with sigmoid weights ----
    const float* gv = glv + ((size_t)token * HH + w) * EE;
    float g[EE];
#pragma unroll
    for (int e = 0; e < EE; e++) g[e] = gv[e];
    int i1 = 0;
#pragma unroll
    for (int e = 1; e < EE; e++) if (g[e] > g[i1]) i1 = e;
    int i2 = (i1 == 0) ? 1 : 0;
#pragma unroll
    for (int e = 0; e < EE; e++) if (e != i1 && g[e] > g[i2]) i2 = e;
    float w1 = 1.f / (1.f + __expf(-g[i1]));
    float w2 = 1.f / (1.f + __expf(-g[i2]));

    const float* xvt = xv + (size_t)token * XVW;
    float* vt = v + (size_t)token * QKW + w * DH;
#pragma unroll
    for (int d = lane; d < DH; d += 32)
        vt[d] = w1 * xvt[i1 * DH + d] + w2 * xvt[i2 * DH + d];

    // ---- output gate: top-2 mask (unweighted) ----
    const float* go = glo + ((size_t)token * HH + w) * EE;
#pragma unroll
    for (int e = 0; e < EE; e++) g[e] = go[e];
    int o1 = 0;
#pragma unroll
    for (int e = 1; e < EE; e++) if (g[e] > g[o1]) o1 = e;
    int o2 = (o1 == 0) ? 1 : 0;
#pragma unroll
    for (int e = 0; e < EE; e++) if (e != o1 && g[e] > g[o2]) o2 = e;
    if (lane < EE)
        masko[((size_t)token * HH + w) * EE + lane] = (lane == o1 || lane == o2) ? 1.f : 0.f;
}

// ---------------- flash attention, fp32, non-causal --------------------------
// grid (T/64, B*H), 256 threads. q/k/v token-major: [(b*T+t)*512 + h*64 + d]
#define APAD 65
__global__ void attn_kernel(const float* __restrict__ q,
                            const float* __restrict__ k,
                            const float* __restrict__ v,
                            float* __restrict__ o) {
    extern __shared__ float sh[];
    float* Qs = sh;                  // [64][65]
    float* Ks = Qs + 64 * APAD;      // [64][65]
    float* Vs = Ks + 64 * APAD;      // [64][65]
    float* Ss = Vs + 64 * APAD;      // [64][65]

    const int bh = blockIdx.y;
    const int b = bh / HH, h = bh % HH;
    const int q0 = blockIdx.x * 64;
    const int tid = threadIdx.x;
    const int qr = tid / 4;                // 0..63
    const int seg = (tid % 4) * 16;        // 16 cols each
    const float scale = 0.125f;            // DH^-0.5

    // load Q tile
    for (int i = tid; i < 64 * 64; i += 256) {
        int r = i / 64, d = i % 64;
        Qs[r * APAD + d] = q[((size_t)(b * TT + q0 + r) * HH + h) * DH + d];
    }

    float om[16];
#pragma unroll
    for (int c = 0; c < 16; c++) om[c] = 0.f;
    float rm = -INFINITY, rl = 0.f;

    for (int t0 = 0; t0 < TT; t0 += 64) {
        __syncthreads();
        for (int i = tid; i < 64 * 64; i += 256) {
            int r = i / 64, d = i % 64;
            size_t gi = ((size_t)(b * TT + t0 + r) * HH + h) * DH + d;
            Ks[r * APAD + d] = k[gi];
            Vs[r * APAD + d] = v[gi];
        }
        __syncthreads();

        // S = scale * Q K^T for my 16 key cols
        float s[16];
#pragma unroll
        for (int kc = 0; kc < 16; kc++) {
            float acc = 0.f;
            const float* qp = &Qs[qr * APAD];
            const float* kp = &Ks[(seg + kc) * APAD];
#pragma unroll
            for (int d = 0; d < 64; d++) acc += qp[d] * kp[d];
            s[kc] = acc * scale;
        }
        // tile row-max across my 16 + 4 lanes of this row
        float tmax = s[0];
#pragma unroll
        for (int kc = 1; kc < 16; kc++) tmax = fmaxf(tmax, s[kc]);
        tmax = fmaxf(tmax, __shfl_xor_sync(0xffffffff, tmax, 1));
        tmax = fmaxf(tmax, __shfl_xor_sync(0xffffffff, tmax, 2));

        float mnew = fmaxf(rm, tmax);
        float corr = __expf(rm - mnew);
        float tsum = 0.f;
#pragma unroll
        for (int kc = 0; kc < 16; kc++) {
            float p = __expf(s[kc] - mnew);
            Ss[qr * APAD + seg + kc] = p;
            tsum += p;
        }
        tsum += __shfl_xor_sync(0xffffffff, tsum, 1);
        tsum += __shfl_xor_sync(0xffffffff, tsum, 2);
        rl = rl * corr + tsum;
        rm = mnew;
        __syncwarp();

        // O += P @ V  (my 16 dh cols)
#pragma unroll
        for (int c = 0; c < 16; c++) om[c] *= corr;
        const float* pp = &Ss[qr * APAD];
#pragma unroll 8
        for (int j = 0; j < 64; j++) {
            float pj = pp[j];
            const float* vp = &Vs[j * APAD + seg];
#pragma unroll
            for (int c = 0; c < 16; c++) om[c] += pj * vp[c];
        }
    }

    float inv = 1.f / rl;
    float* op = o + ((size_t)(b * TT + q0 + qr) * HH + h) * DH + seg;
#pragma unroll
    for (int c = 0; c < 16; c++) op[c] = om[c] * inv;
}

// -------- Y[t, e*64+k] = sum_h mask[t,h,e] * attn[t,h,k] ---------------------
__global__ void combine_out_kernel(const float* __restrict__ attn,
                                   const float* __restrict__ masko,
                                   float* __restrict__ Y) {
    int token = blockIdx.x;
    int t = threadIdx.x;            // 0..319
    int e = t / DH, j = t % DH;
    const float* ap = attn + (size_t)token * QKW;
    const float* mp = masko + (size_t)token * GW;
    float s = 0.f;
#pragma unroll
    for (int h = 0; h < HH; h++)
        s += mp[h * EE + e] * ap[h * DH + j];
    Y[(size_t)token * XVW + t] = s;
}

// ------------------------------- launch --------------------------------------
extern "C" void kernel_launch(void* const* d_in, const int* in_sizes, int n_in,
                              void* d_out, int out_size) {
    const float* x  = (const float*)d_in[0];
    const float* Wq = (const float*)d_in[1];
    const float* Wk = (const float*)d_in[2];
    const float* Ws = (const float*)d_in[3];
    const float* Wd = (const float*)d_in[4];
    const float* Wv = (const float*)d_in[5];
    const float* Wo = (const float*)d_in[6];
    float* out = (float*)d_out;

    float *q, *k, *v, *attn, *glv, *glo, *mask, *xv, *y, *wvp;
    cudaGetSymbolAddress((void**)&q,    g_q);
    cudaGetSymbolAddress((void**)&k,    g_k);
    cudaGetSymbolAddress((void**)&v,    g_v);
    cudaGetSymbolAddress((void**)&attn, g_attn);
    cudaGetSymbolAddress((void**)&glv,  g_glv);
    cudaGetSymbolAddress((void**)&glo,  g_glo);
    cudaGetSymbolAddress((void**)&mask, g_mask);
    cudaGetSymbolAddress((void**)&xv,   g_xv);
    cudaGetSymbolAddress((void**)&y,    g_y);
    cudaGetSymbolAddress((void**)&wvp,  g_wvp);

    // pack Wv -> (D, E*DH)
    pack_wv_kernel<<<(DD * XVW + 255) / 256, 256>>>(Wv, wvp);

    // projections
    dim3 blk(256);
    dim3 g_qk((QKW + TS - 1) / TS, (NTOK + TS - 1) / TS);
    dim3 g_g ((GW  + TS - 1) / TS, (NTOK + TS - 1) / TS);
    dim3 g_xv2((XVW + TS - 1) / TS, (NTOK + TS - 1) / TS);
    sgemm_kernel<<<g_qk, blk>>>(x, Wq, q,   NTOK, QKW, DD);
    sgemm_kernel<<<g_qk, blk>>>(x, Wk, k,   NTOK, QKW, DD);
    sgemm_kernel<<<g_g,  blk>>>(x, Ws, glv, NTOK, GW,  DD);
    sgemm_kernel<<<g_g,  blk>>>(x, Wd, glo, NTOK, GW,  DD);
    sgemm_kernel<<<g_xv2, blk>>>(x, wvp, xv, NTOK, XVW, DD);

    // gating + V combine + out-mask
    gate_combine_kernel<<<NTOK, 256>>>(glv, glo, xv, v, mask);

    // attention
    size_t smem = 4 * 64 * APAD * sizeof(float);
    cudaFuncSetAttribute(attn_kernel, cudaFuncAttributeMaxDynamicSharedMemorySize, (int)smem);
    dim3 ag(TT / 64, BB * HH);
    attn_kernel<<<ag, 256, smem>>>(q, k, v, attn);

    // masked head/expert combine, then output GEMM
    combine_out_kernel<<<NTOK, XVW>>>(attn, mask, y);
    dim3 g_o((DD + TS - 1) / TS, (NTOK + TS - 1) / TS);
    sgemm_kernel<<<g_o, blk>>>(y, Wo, out, NTOK, DD, XVW);
}

// round 2
// speedup vs baseline: 3.8992x; 3.8992x over previous
#include <cuda_runtime.h>
#include <cuda_bf16.h>
#include <math.h>

// Problem constants
#define BB 4
#define TT 2048
#define DD 1024
#define HH 8
#define DH 64
#define EE 5
#define NTOK (BB*TT)          // 8192
#define QKW (HH*DH)           // 512
#define GW  (HH*EE)           // 40
#define XVW (EE*DH)           // 320

// fused projection layout (row stride PW):
// [0:512) q | [512:1024) k | [1024:1344) xv | [1344:1384) glv | [1384:1424) glo | pad->1536
#define PW 1536
#define OFF_Q   0
#define OFF_K   512
#define OFF_XV  1024
#define OFF_GLV 1344
#define OFF_GLO 1384

// ---------------- scratch (device globals; no allocation allowed) ------------
__device__ float g_proj[(size_t)NTOK*PW];   // fused projections
__device__ float g_wall[(size_t)DD*PW];     // packed weights
__device__ float g_v   [(size_t)NTOK*QKW];
__device__ float g_attn[(size_t)NTOK*QKW];
__device__ float g_mask[(size_t)NTOK*GW];
__device__ float g_y   [(size_t)NTOK*XVW];

// =============== SGEMM: C(MxN)=A(MxK)@B(KxN), M%128==0, N%128==0, K%8==0 =====
#define BM 128
#define BN 128
#define BK 8

__global__ __launch_bounds__(256, 2)
void sgemm128(const float* __restrict__ A, const float* __restrict__ B,
              float* __restrict__ C, int M, int N, int K) {
    __shared__ float As[2][BK][BM];
    __shared__ float Bs[2][BK][BN];
    const int tid = threadIdx.x;
    const int row0 = blockIdx.y * BM;
    const int col0 = blockIdx.x * BN;

    const int arow = tid >> 1;          // 0..127
    const int acol = (tid & 1) * 4;     // 0 or 4
    const int brow = tid >> 5;          // 0..7
    const int bcol = (tid & 31) * 4;    // 0..124

    const float* Aptr = A + (size_t)(row0 + arow) * K + acol;
    const float* Bptr = B + (size_t)brow * N + col0 + bcol;

    const int tx = tid & 15, ty = tid >> 4;

    float acc[8][8];
#pragma unroll
    for (int i = 0; i < 8; i++)
#pragma unroll
        for (int j = 0; j < 8; j++) acc[i][j] = 0.f;

    const int nk = K / BK;

    // prefetch tile 0
    float4 aR = *(const float4*)Aptr;
    float4 bR = *(const float4*)Bptr;
    As[0][acol + 0][arow] = aR.x;
    As[0][acol + 1][arow] = aR.y;
    As[0][acol + 2][arow] = aR.z;
    As[0][acol + 3][arow] = aR.w;
    *(float4*)&Bs[0][brow][bcol] = bR;
    __syncthreads();

    int buf = 0;
    for (int kt = 0; kt < nk; kt++) {
        if (kt + 1 < nk) {
            aR = *(const float4*)(Aptr + (kt + 1) * BK);
            bR = *(const float4*)(Bptr + (size_t)(kt + 1) * BK * N);
        }
#pragma unroll
        for (int kk = 0; kk < BK; kk++) {
            float4 a0 = *(const float4*)&As[buf][kk][ty * 4];
            float4 a1 = *(const float4*)&As[buf][kk][ty * 4 + 64];
            float4 b0 = *(const float4*)&Bs[buf][kk][tx * 4];
            float4 b1 = *(const float4*)&Bs[buf][kk][tx * 4 + 64];
            float av[8] = {a0.x, a0.y, a0.z, a0.w, a1.x, a1.y, a1.z, a1.w};
            float bv[8] = {b0.x, b0.y, b0.z, b0.w, b1.x, b1.y, b1.z, b1.w};
#pragma unroll
            for (int i = 0; i < 8; i++)
#pragma unroll
                for (int j = 0; j < 8; j++) acc[i][j] += av[i] * bv[j];
        }
        if (kt + 1 < nk) {
            int nb = buf ^ 1;
            As[nb][acol + 0][arow] = aR.x;
            As[nb][acol + 1][arow] = aR.y;
            As[nb][acol + 2][arow] = aR.z;
            As[nb][acol + 3][arow] = aR.w;
            *(float4*)&Bs[nb][brow][bcol] = bR;
            buf = nb;
            __syncthreads();
        }
    }

#pragma unroll
    for (int i = 0; i < 8; i++) {
        int r = row0 + ty * 4 + (i < 4 ? i : 60 + i);   // ty*4+i  or  ty*4+64+(i-4)
        float4 c0 = make_float4(acc[i][0], acc[i][1], acc[i][2], acc[i][3]);
        float4 c1 = make_float4(acc[i][4], acc[i][5], acc[i][6], acc[i][7]);
        *(float4*)&C[(size_t)r * N + col0 + tx * 4]      = c0;
        *(float4*)&C[(size_t)r * N + col0 + tx * 4 + 64] = c1;
    }
}

// ----------- pack Wq|Wk|Wv|Ws|Wd -> (D, 1536) with zero pad ------------------
__global__ void pack_wall_kernel(const float* __restrict__ Wq,
                                 const float* __restrict__ Wk,
                                 const float* __restrict__ Ws,
                                 const float* __restrict__ Wd,
                                 const float* __restrict__ Wv,
                                 float* __restrict__ Wall) {
    int idx = blockIdx.x * blockDim.x + threadIdx.x;
    if (idx >= DD * PW) return;
    int d = idx / PW;
    int n = idx % PW;
    float val;
    if (n < 512) {
        val = Wq[(size_t)d * 512 + n];
    } else if (n < 1024) {
        val = Wk[(size_t)d * 512 + (n - 512)];
    } else if (n < 1344) {
        int e = (n - 1024) / DH, j = (n - 1024) % DH;
        val = Wv[((size_t)e * DD + d) * DH + j];
    } else if (n < 1384) {
        val = Ws[(size_t)d * GW + (n - 1344)];
    } else if (n < 1424) {
        val = Wd[(size_t)d * GW + (n - 1384)];
    } else {
        val = 0.f;
    }
    Wall[idx] = val;
}

// -------- top-2 gating: sigmoid-weighted V combine + output mask -------------
__global__ void gate_combine_kernel(const float* __restrict__ proj,
                                    float* __restrict__ v,
                                    float* __restrict__ masko) {
    int token = blockIdx.x;
    int w = threadIdx.x / 32;   // head
    int lane = threadIdx.x % 32;
    const float* base = proj + (size_t)token * PW;

    // ---- V gate: top-2 of 5 with sigmoid weights ----
    const float* gv = base + OFF_GLV + w * EE;
    float g[EE];
#pragma unroll
    for (int e = 0; e < EE; e++) g[e] = gv[e];
    int i1 = 0;
#pragma unroll
    for (int e = 1; e < EE; e++) if (g[e] > g[i1]) i1 = e;
    int i2 = (i1 == 0) ? 1 : 0;
#pragma unroll
    for (int e = 0; e < EE; e++) if (e != i1 && g[e] > g[i2]) i2 = e;
    float w1 = 1.f / (1.f + __expf(-g[i1]));
    float w2 = 1.f / (1.f + __expf(-g[i2]));

    const float* xvt = base + OFF_XV;
    float* vt = v + (size_t)token * QKW + w * DH;
#pragma unroll
    for (int d = lane; d < DH; d += 32)
        vt[d] = w1 * xvt[i1 * DH + d] + w2 * xvt[i2 * DH + d];

    // ---- output gate: top-2 mask ----
    const float* go = base + OFF_GLO + w * EE;
#pragma unroll
    for (int e = 0; e < EE; e++) g[e] = go[e];
    int o1 = 0;
#pragma unroll
    for (int e = 1; e < EE; e++) if (g[e] > g[o1]) o1 = e;
    int o2 = (o1 == 0) ? 1 : 0;
#pragma unroll
    for (int e = 0; e < EE; e++) if (e != o1 && g[e] > g[o2]) o2 = e;
    if (lane < EE)
        masko[((size_t)token * HH + w) * EE + lane] = (lane == o1 || lane == o2) ? 1.f : 0.f;
}

// ================= flash attention, fp32, 64x64 tiles, 4x4 micro =============
// q,k live in proj (stride PW), v in g_v (stride 512).
#define AT 68
__global__ __launch_bounds__(256)
void attn_kernel(const float* __restrict__ q,
                 const float* __restrict__ k,
                 const float* __restrict__ v,
                 float* __restrict__ o) {
    extern __shared__ float sh[];
    float* Qs = sh;                 // [64][AT] row-major [r][d]
    float* Kt = Qs + 64 * AT;       // [64][AT] transposed [d][c]
    float* Vs = Kt + 64 * AT;       // [64][AT] row-major [j][d]
    float* Ps = Vs + 64 * AT;       // [64][AT] row-major [r][j]

    const int bh = blockIdx.y;
    const int b = bh / HH, h = bh % HH;
    const int q0 = blockIdx.x * 64;
    const int tid = threadIdx.x;
    const int tx = tid & 15, ty = tid >> 4;
    const int r0 = ty * 4, c0 = tx * 4;
    const float scale = 0.125f;

    const float* qb = q + ((size_t)(b * TT + q0)) * PW + h * DH;

    // load Q tile (row-major, conflict-free float4)
#pragma unroll
    for (int it = 0; it < 4; it++) {
        int lin = it * 1024 + tid * 4;
        int r = lin >> 6, d = lin & 63;
        float4 t = *(const float4*)(qb + (size_t)r * PW + d);
        *(float4*)&Qs[r * AT + d] = t;
    }

    float om[4][4];
    float rm[4], rl[4];
#pragma unroll
    for (int i = 0; i < 4; i++) {
        rm[i] = -INFINITY; rl[i] = 0.f;
#pragma unroll
        for (int j = 0; j < 4; j++) om[i][j] = 0.f;
    }

    for (int t0 = 0; t0 < TT; t0 += 64) {
        __syncthreads();
        // load K (transposed) and V (row-major)
        const float* kb = k + ((size_t)(b * TT + t0)) * PW + h * DH;
        const float* vb = v + ((size_t)(b * TT + t0)) * QKW + h * DH;
#pragma unroll
        for (int it = 0; it < 4; it++) {
            int lin = it * 1024 + tid * 4;
            int r = lin >> 6, d = lin & 63;
            float4 kt = *(const float4*)(kb + (size_t)r * PW + d);
            Kt[(d + 0) * AT + r] = kt.x;
            Kt[(d + 1) * AT + r] = kt.y;
            Kt[(d + 2) * AT + r] = kt.z;
            Kt[(d + 3) * AT + r] = kt.w;
            float4 vt = *(const float4*)(vb + (size_t)r * QKW + d);
            *(float4*)&Vs[r * AT + d] = vt;
        }
        __syncthreads();

        // S = scale * Q K^T  (4 rows x 4 cols per thread)
        float s[4][4];
#pragma unroll
        for (int i = 0; i < 4; i++)
#pragma unroll
            for (int j = 0; j < 4; j++) s[i][j] = 0.f;
#pragma unroll 16
        for (int d = 0; d < 64; d++) {
            float4 kb4 = *(const float4*)&Kt[d * AT + c0];
            float qa0 = Qs[(r0 + 0) * AT + d];
            float qa1 = Qs[(r0 + 1) * AT + d];
            float qa2 = Qs[(r0 + 2) * AT + d];
            float qa3 = Qs[(r0 + 3) * AT + d];
            s[0][0] += qa0 * kb4.x; s[0][1] += qa0 * kb4.y; s[0][2] += qa0 * kb4.z; s[0][3] += qa0 * kb4.w;
            s[1][0] += qa1 * kb4.x; s[1][1] += qa1 * kb4.y; s[1][2] += qa1 * kb4.z; s[1][3] += qa1 * kb4.w;
            s[2][0] += qa2 * kb4.x; s[2][1] += qa2 * kb4.y; s[2][2] += qa2 * kb4.z; s[2][3] += qa2 * kb4.w;
            s[3][0] += qa3 * kb4.x; s[3][1] += qa3 * kb4.y; s[3][2] += qa3 * kb4.z; s[3][3] += qa3 * kb4.w;
        }

        // row stats across the 16 tx lanes of each ty
        float tmax[4];
#pragma unroll
        for (int i = 0; i < 4; i++) {
            float m = s[i][0] * scale;
#pragma unroll
            for (int j = 1; j < 4; j++) m = fmaxf(m, s[i][j] * scale);
            m = fmaxf(m, __shfl_xor_sync(0xffffffff, m, 1));
            m = fmaxf(m, __shfl_xor_sync(0xffffffff, m, 2));
            m = fmaxf(m, __shfl_xor_sync(0xffffffff, m, 4));
            m = fmaxf(m, __shfl_xor_sync(0xffffffff, m, 8));
            tmax[i] = m;
        }

        float corr[4];
#pragma unroll
        for (int i = 0; i < 4; i++) {
            float mnew = fmaxf(rm[i], tmax[i]);
            corr[i] = __expf(rm[i] - mnew);
            float ts = 0.f;
            float4 pr;
            float p0 = __expf(s[i][0] * scale - mnew);
            float p1 = __expf(s[i][1] * scale - mnew);
            float p2 = __expf(s[i][2] * scale - mnew);
            float p3 = __expf(s[i][3] * scale - mnew);
            pr = make_float4(p0, p1, p2, p3);
            ts = p0 + p1 + p2 + p3;
            *(float4*)&Ps[(r0 + i) * AT + c0] = pr;
            ts += __shfl_xor_sync(0xffffffff, ts, 1);
            ts += __shfl_xor_sync(0xffffffff, ts, 2);
            ts += __shfl_xor_sync(0xffffffff, ts, 4);
            ts += __shfl_xor_sync(0xffffffff, ts, 8);
            rl[i] = rl[i] * corr[i] + ts;
            rm[i] = mnew;
        }
        __syncthreads();

        // O = O*corr + P @ V   (cols c0..c0+3 of dh)
#pragma unroll
        for (int i = 0; i < 4; i++)
#pragma unroll
            for (int j = 0; j < 4; j++) om[i][j] *= corr[i];
#pragma unroll 16
        for (int j = 0; j < 64; j++) {
            float4 vb4 = *(const float4*)&Vs[j * AT + c0];
            float pa0 = Ps[(r0 + 0) * AT + j];
            float pa1 = Ps[(r0 + 1) * AT + j];
            float pa2 = Ps[(r0 + 2) * AT + j];
            float pa3 = Ps[(r0 + 3) * AT + j];
            om[0][0] += pa0 * vb4.x; om[0][1] += pa0 * vb4.y; om[0][2] += pa0 * vb4.z; om[0][3] += pa0 * vb4.w;
            om[1][0] += pa1 * vb4.x; om[1][1] += pa1 * vb4.y; om[1][2] += pa1 * vb4.z; om[1][3] += pa1 * vb4.w;
            om[2][0] += pa2 * vb4.x; om[2][1] += pa2 * vb4.y; om[2][2] += pa2 * vb4.z; om[2][3] += pa2 * vb4.w;
            om[3][0] += pa3 * vb4.x; om[3][1] += pa3 * vb4.y; om[3][2] += pa3 * vb4.z; om[3][3] += pa3 * vb4.w;
        }
    }

#pragma unroll
    for (int i = 0; i < 4; i++) {
        float inv = 1.f / rl[i];
        float4 r = make_float4(om[i][0] * inv, om[i][1] * inv, om[i][2] * inv, om[i][3] * inv);
        *(float4*)&o[((size_t)(b * TT + q0 + r0 + i)) * QKW + h * DH + c0] = r;
    }
}

// -------- Y[t, e*64+j] = sum_h mask[t,h,e] * attn[t,h,j] ---------------------
__global__ void combine_out_kernel(const float* __restrict__ attn,
                                   const float* __restrict__ masko,
                                   float* __restrict__ Y) {
    int token = blockIdx.x;
    int t = threadIdx.x;            // 0..319
    int e = t / DH, j = t % DH;
    const float* ap = attn + (size_t)token * QKW;
    const float* mp = masko + (size_t)token * GW;
    float s = 0.f;
#pragma unroll
    for (int h = 0; h < HH; h++)
        s += mp[h * EE + e] * ap[h * DH + j];
    Y[(size_t)token * XVW + t] = s;
}

// ------------------------------- launch --------------------------------------
extern "C" void kernel_launch(void* const* d_in, const int* in_sizes, int n_in,
                              void* d_out, int out_size) {
    const float* x  = (const float*)d_in[0];
    const float* Wq = (const float*)d_in[1];
    const float* Wk = (const float*)d_in[2];
    const float* Ws = (const float*)d_in[3];
    const float* Wd = (const float*)d_in[4];
    const float* Wv = (const float*)d_in[5];
    const float* Wo = (const float*)d_in[6];
    float* out = (float*)d_out;

    float *proj, *wall, *v, *attn, *mask, *y;
    cudaGetSymbolAddress((void**)&proj, g_proj);
    cudaGetSymbolAddress((void**)&wall, g_wall);
    cudaGetSymbolAddress((void**)&v,    g_v);
    cudaGetSymbolAddress((void**)&attn, g_attn);
    cudaGetSymbolAddress((void**)&mask, g_mask);
    cudaGetSymbolAddress((void**)&y,    g_y);

    // pack all weights into one (1024 x 1536) matrix
    pack_wall_kernel<<<(DD * PW + 255) / 256, 256>>>(Wq, Wk, Ws, Wd, Wv, wall);

    // one fused projection GEMM: (8192x1024) @ (1024x1536)
    dim3 gp(PW / BN, NTOK / BM);
    sgemm128<<<gp, 256>>>(x, wall, proj, NTOK, PW, DD);

    // gating + V combine + out-mask
    gate_combine_kernel<<<NTOK, 256>>>(proj, v, mask);

    // attention
    size_t smem = 4 * 64 * AT * sizeof(float);
    cudaFuncSetAttribute(attn_kernel, cudaFuncAttributeMaxDynamicSharedMemorySize, (int)smem);
    dim3 ag(TT / 64, BB * HH);
    attn_kernel<<<ag, 256, smem>>>(proj + OFF_Q, proj + OFF_K, v, attn);

    // masked head/expert combine, then output GEMM
    combine_out_kernel<<<NTOK, XVW>>>(attn, mask, y);
    dim3 go(DD / BN, NTOK / BM);
    sgemm128<<<go, 256>>>(y, Wo, out, NTOK, DD, XVW);
}

// round 4
// speedup vs baseline: 5.2429x; 1.3446x over previous
#include <cuda_runtime.h>
#include <cuda_bf16.h>
#include <math.h>
#include <stdint.h>

// Problem constants
#define BB 4
#define TT 2048
#define DD 1024
#define HH 8
#define DH 64
#define EE 5
#define NTOK (BB*TT)          // 8192
#define QKW (HH*DH)           // 512
#define GW  (HH*EE)           // 40
#define XVW (EE*DH)           // 320

// fused projection layout (row stride PW):
// [0:512) q | [512:1024) k | [1024:1344) xv | [1344:1384) glv | [1384:1424) glo | pad->1536
#define PW 1536
#define OFF_Q   0
#define OFF_K   512
#define OFF_XV  1024
#define OFF_GLV 1344
#define OFF_GLO 1384

// ---------------- scratch (device globals) ------------------------------------
__device__ float g_proj[(size_t)NTOK*PW];
__device__ float g_wall[(size_t)DD*PW];
__device__ float g_v   [(size_t)NTOK*QKW];
__device__ float g_attn[(size_t)NTOK*QKW];
__device__ float g_mask[(size_t)NTOK*GW];
__device__ float g_y   [(size_t)NTOK*XVW];

// ---------------- tf32 helpers ------------------------------------------------
__device__ __forceinline__ uint32_t f2tf32(float x) {
    uint32_t r;
    asm("cvt.rna.tf32.f32 %0, %1;" : "=r"(r) : "f"(x));
    return r;
}

// split x = hi + lo (both tf32); dropped part ~ eps^2
__device__ __forceinline__ void split_tf32(float x, uint32_t& h, uint32_t& l) {
    h = f2tf32(x);
    l = f2tf32(x - __uint_as_float(h));
}

__device__ __forceinline__ void mma_tf32(float c[4], const uint32_t a[4], const uint32_t b[2]) {
    asm volatile(
        "mma.sync.aligned.m16n8k8.row.col.f32.tf32.tf32.f32 "
        "{%0,%1,%2,%3},{%4,%5,%6,%7},{%8,%9},{%0,%1,%2,%3};"
        : "+f"(c[0]), "+f"(c[1]), "+f"(c[2]), "+f"(c[3])
        : "r"(a[0]), "r"(a[1]), "r"(a[2]), "r"(a[3]),
          "r"(b[0]), "r"(b[1]));
}

// =============== 3xTF32 GEMM: C=A@B, M%128==0, N%128==0, K%32==0 ==============
#define GP_A 36     // pad: 36%32=4 -> A-frag banks distinct
#define GP_B 136    // pad: 136%32=8 -> B-frag banks distinct

__global__ __launch_bounds__(256)
void tgemm3x(const float* __restrict__ A, const float* __restrict__ B,
             float* __restrict__ C, int M, int N, int K) {
    extern __shared__ uint32_t sm[];
    uint32_t* Ah = sm;                      // [128][GP_A]
    uint32_t* Al = Ah + 128 * GP_A;
    uint32_t* Bh = Al + 128 * GP_A;         // [32][GP_B]
    uint32_t* Bl = Bh + 32 * GP_B;

    const int tid = threadIdx.x;
    const int row0 = blockIdx.y * 128;
    const int col0 = blockIdx.x * 128;
    const int lane = tid & 31, w = tid >> 5;
    const int g = lane >> 2, t = lane & 3;
    const int wm = w >> 1, wn = w & 1;      // 4x2 warp grid: warp tile 32x64

    float c[2][8][4];
#pragma unroll
    for (int mt = 0; mt < 2; mt++)
#pragma unroll
        for (int nt = 0; nt < 8; nt++)
#pragma unroll
            for (int i = 0; i < 4; i++) c[mt][nt][i] = 0.f;

    const int nk = K / 32;

    float4 a4[4], b4[4];
#pragma unroll
    for (int it = 0; it < 4; it++) {
        int idA = it * 1024 + tid * 4;
        int ar = idA >> 5, ac = idA & 31;
        a4[it] = *(const float4*)(A + (size_t)(row0 + ar) * K + ac);
        int br = idA >> 7, bc = idA & 127;
        b4[it] = *(const float4*)(B + (size_t)br * N + col0 + bc);
    }

    for (int kt = 0; kt < nk; kt++) {
        __syncthreads();
#pragma unroll
        for (int it = 0; it < 4; it++) {
            int idA = it * 1024 + tid * 4;
            int ar = idA >> 5, ac = idA & 31;
            uint4 ah, al;
            split_tf32(a4[it].x, ah.x, al.x);
            split_tf32(a4[it].y, ah.y, al.y);
            split_tf32(a4[it].z, ah.z, al.z);
            split_tf32(a4[it].w, ah.w, al.w);
            *(uint4*)&Ah[ar * GP_A + ac] = ah;
            *(uint4*)&Al[ar * GP_A + ac] = al;
            int br = idA >> 7, bc = idA & 127;
            uint4 bh, bl;
            split_tf32(b4[it].x, bh.x, bl.x);
            split_tf32(b4[it].y, bh.y, bl.y);
            split_tf32(b4[it].z, bh.z, bl.z);
            split_tf32(b4[it].w, bh.w, bl.w);
            *(uint4*)&Bh[br * GP_B + bc] = bh;
            *(uint4*)&Bl[br * GP_B + bc] = bl;
        }
        __syncthreads();

        if (kt + 1 < nk) {
#pragma unroll
            for (int it = 0; it < 4; it++) {
                int idA = it * 1024 + tid * 4;
                int ar = idA >> 5, ac = idA & 31;
                a4[it] = *(const float4*)(A + (size_t)(row0 + ar) * K + (kt + 1) * 32 + ac);
                int br = idA >> 7, bc = idA & 127;
                b4[it] = *(const float4*)(B + (size_t)((kt + 1) * 32 + br) * N + col0 + bc);
            }
        }

#pragma unroll
        for (int kc = 0; kc < 4; kc++) {
            uint32_t afh[2][4], afl[2][4], bfh[8][2], bfl[8][2];
#pragma unroll
            for (int mt = 0; mt < 2; mt++) {
                int rb = wm * 32 + mt * 16;
                afh[mt][0] = Ah[(rb + g    ) * GP_A + kc * 8 + t];
                afh[mt][1] = Ah[(rb + g + 8) * GP_A + kc * 8 + t];
                afh[mt][2] = Ah[(rb + g    ) * GP_A + kc * 8 + t + 4];
                afh[mt][3] = Ah[(rb + g + 8) * GP_A + kc * 8 + t + 4];
                afl[mt][0] = Al[(rb + g    ) * GP_A + kc * 8 + t];
                afl[mt][1] = Al[(rb + g + 8) * GP_A + kc * 8 + t];
                afl[mt][2] = Al[(rb + g    ) * GP_A + kc * 8 + t + 4];
                afl[mt][3] = Al[(rb + g + 8) * GP_A + kc * 8 + t + 4];
            }
#pragma unroll
            for (int nt = 0; nt < 8; nt++) {
                int cb = wn * 64 + nt * 8;
                bfh[nt][0] = Bh[(kc * 8 + t    ) * GP_B + cb + g];
                bfh[nt][1] = Bh[(kc * 8 + t + 4) * GP_B + cb + g];
                bfl[nt][0] = Bl[(kc * 8 + t    ) * GP_B + cb + g];
                bfl[nt][1] = Bl[(kc * 8 + t + 4) * GP_B + cb + g];
            }
#pragma unroll
            for (int mt = 0; mt < 2; mt++)
#pragma unroll
                for (int nt = 0; nt < 8; nt++) {
                    mma_tf32(c[mt][nt], afh[mt], bfl[nt]);
                    mma_tf32(c[mt][nt], afl[mt], bfh[nt]);
                    mma_tf32(c[mt][nt], afh[mt], bfh[nt]);
                }
        }
    }

#pragma unroll
    for (int mt = 0; mt < 2; mt++) {
        int r0 = row0 + wm * 32 + mt * 16;
#pragma unroll
        for (int nt = 0; nt < 8; nt++) {
            int cc = col0 + wn * 64 + nt * 8 + 2 * t;
            *(float2*)&C[(size_t)(r0 + g    ) * N + cc] = make_float2(c[mt][nt][0], c[mt][nt][1]);
            *(float2*)&C[(size_t)(r0 + g + 8) * N + cc] = make_float2(c[mt][nt][2], c[mt][nt][3]);
        }
    }
}

// ----------- pack Wq|Wk|Wv|Ws|Wd -> (D, 1536) with zero pad ------------------
__global__ void pack_wall_kernel(const float* __restrict__ Wq,
                                 const float* __restrict__ Wk,
                                 const float* __restrict__ Ws,
                                 const float* __restrict__ Wd,
                                 const float* __restrict__ Wv,
                                 float* __restrict__ Wall) {
    int idx = blockIdx.x * blockDim.x + threadIdx.x;
    if (idx >= DD * PW) return;
    int d = idx / PW;
    int n = idx % PW;
    float val;
    if (n < 512) {
        val = Wq[(size_t)d * 512 + n];
    } else if (n < 1024) {
        val = Wk[(size_t)d * 512 + (n - 512)];
    } else if (n < 1344) {
        int e = (n - 1024) / DH, j = (n - 1024) % DH;
        val = Wv[((size_t)e * DD + d) * DH + j];
    } else if (n < 1384) {
        val = Ws[(size_t)d * GW + (n - 1344)];
    } else if (n < 1424) {
        val = Wd[(size_t)d * GW + (n - 1384)];
    } else {
        val = 0.f;
    }
    Wall[idx] = val;
}

// -------- top-2 gating: sigmoid-weighted V combine + output mask -------------
__global__ void gate_combine_kernel(const float* __restrict__ proj,
                                    float* __restrict__ v,
                                    float* __restrict__ masko) {
    int token = blockIdx.x;
    int w = threadIdx.x / 32;
    int lane = threadIdx.x % 32;
    const float* base = proj + (size_t)token * PW;

    const float* gv = base + OFF_GLV + w * EE;
    float g[EE];
#pragma unroll
    for (int e = 0; e < EE; e++) g[e] = gv[e];
    int i1 = 0;
#pragma unroll
    for (int e = 1; e < EE; e++) if (g[e] > g[i1]) i1 = e;
    int i2 = (i1 == 0) ? 1 : 0;
#pragma unroll
    for (int e = 0; e < EE; e++) if (e != i1 && g[e] > g[i2]) i2 = e;
    float w1 = 1.f / (1.f + __expf(-g[i1]));
    float w2 = 1.f / (1.f + __expf(-g[i2]));

    const float* xvt = base + OFF_XV;
    float* vt = v + (size_t)token * QKW + w * DH;
#pragma unroll
    for (int d = lane; d < DH; d += 32)
        vt[d] = w1 * xvt[i1 * DH + d] + w2 * xvt[i2 * DH + d];

    const float* go = base + OFF_GLO + w * EE;
#pragma unroll
    for (int e = 0; e < EE; e++) g[e] = go[e];
    int o1 = 0;
#pragma unroll
    for (int e = 1; e < EE; e++) if (g[e] > g[o1]) o1 = e;
    int o2 = (o1 == 0) ? 1 : 0;
#pragma unroll
    for (int e = 0; e < EE; e++) if (e != o1 && g[e] > g[o2]) o2 = e;
    if (lane < EE)
        masko[((size_t)token * HH + w) * EE + lane] = (lane == o1 || lane == o2) ? 1.f : 0.f;
}

// ================= flash attention, 3xTF32 MMA ================================
// 128 q rows per block, 8 warps x 16 rows, 64-key tiles.
// P redistributed C-frag -> A-frag via warp shuffles (no P smem).
#define AP 68
#define LOG2E 1.4426950408889634f

__global__ __launch_bounds__(256)
void attn_kernel(const float* __restrict__ q,
                 const float* __restrict__ k,
                 const float* __restrict__ v,
                 float* __restrict__ o) {
    extern __shared__ uint32_t sh[];
    uint32_t* Kh = sh;                 // [64][AP] tf32 hi, [key][d]
    uint32_t* Kl = Kh + 64 * AP;       // lo
    uint32_t* Vh = Kl + 64 * AP;       // [64][AP] [key][d]
    uint32_t* Vl = Vh + 64 * AP;

    const int bh = blockIdx.y;
    const int b = bh / HH, h = bh % HH;
    const int q0 = blockIdx.x * 128;
    const int tid = threadIdx.x;
    const int lane = tid & 31, w = tid >> 5;
    const int g = lane >> 2, t = lane & 3;
    const float scale = 0.125f;

    // --- Q fragments (hi/lo), register-resident, scale folded (exact pow2) ---
    const float* qb = q + (size_t)(b * TT + q0 + w * 16) * PW + h * DH;
    uint32_t qh[8][4], ql[8][4];
#pragma unroll
    for (int k0 = 0; k0 < 8; k0++) {
        split_tf32(scale * qb[(size_t)(g    ) * PW + k0 * 8 + t],     qh[k0][0], ql[k0][0]);
        split_tf32(scale * qb[(size_t)(g + 8) * PW + k0 * 8 + t],     qh[k0][1], ql[k0][1]);
        split_tf32(scale * qb[(size_t)(g    ) * PW + k0 * 8 + t + 4], qh[k0][2], ql[k0][2]);
        split_tf32(scale * qb[(size_t)(g + 8) * PW + k0 * 8 + t + 4], qh[k0][3], ql[k0][3]);
    }

    float om[8][4];
#pragma unroll
    for (int n = 0; n < 8; n++)
#pragma unroll
        for (int i = 0; i < 4; i++) om[n][i] = 0.f;
    float rm0 = -INFINITY, rm1 = -INFINITY, rl0 = 0.f, rl1 = 0.f;

    // prefetch tile 0
    float4 kf[4], vf[4];
    {
        const float* kb = k + (size_t)(b * TT) * PW + h * DH;
        const float* vb = v + (size_t)(b * TT) * QKW + h * DH;
#pragma unroll
        for (int it = 0; it < 4; it++) {
            int id = it * 1024 + tid * 4;
            int r = id >> 6, d = id & 63;
            kf[it] = *(const float4*)(kb + (size_t)r * PW + d);
            vf[it] = *(const float4*)(vb + (size_t)r * QKW + d);
        }
    }

    for (int t0 = 0; t0 < TT; t0 += 64) {
        __syncthreads();   // previous tile fully consumed
#pragma unroll
        for (int it = 0; it < 4; it++) {
            int id = it * 1024 + tid * 4;
            int r = id >> 6, d = id & 63;
            uint4 hh, ll;
            split_tf32(kf[it].x, hh.x, ll.x);
            split_tf32(kf[it].y, hh.y, ll.y);
            split_tf32(kf[it].z, hh.z, ll.z);
            split_tf32(kf[it].w, hh.w, ll.w);
            *(uint4*)&Kh[r * AP + d] = hh;
            *(uint4*)&Kl[r * AP + d] = ll;
            split_tf32(vf[it].x, hh.x, ll.x);
            split_tf32(vf[it].y, hh.y, ll.y);
            split_tf32(vf[it].z, hh.z, ll.z);
            split_tf32(vf[it].w, hh.w, ll.w);
            *(uint4*)&Vh[r * AP + d] = hh;
            *(uint4*)&Vl[r * AP + d] = ll;
        }
        __syncthreads();

        if (t0 + 64 < TT) {
            const float* kb = k + (size_t)(b * TT + t0 + 64) * PW + h * DH;
            const float* vb = v + (size_t)(b * TT + t0 + 64) * QKW + h * DH;
#pragma unroll
            for (int it = 0; it < 4; it++) {
                int id = it * 1024 + tid * 4;
                int r = id >> 6, d = id & 63;
                kf[it] = *(const float4*)(kb + (size_t)r * PW + d);
                vf[it] = *(const float4*)(vb + (size_t)r * QKW + d);
            }
        }

        // ---- S = Qs @ K^T (3xTF32): per-warp 16x64 ---------------------------
        float s[8][4];
#pragma unroll
        for (int n = 0; n < 8; n++)
#pragma unroll
            for (int i = 0; i < 4; i++) s[n][i] = 0.f;
#pragma unroll
        for (int k0 = 0; k0 < 8; k0++) {
#pragma unroll
            for (int n0 = 0; n0 < 8; n0++) {
                uint32_t bh2[2], bl2[2];
                bh2[0] = Kh[(n0 * 8 + g) * AP + k0 * 8 + t];
                bh2[1] = Kh[(n0 * 8 + g) * AP + k0 * 8 + t + 4];
                bl2[0] = Kl[(n0 * 8 + g) * AP + k0 * 8 + t];
                bl2[1] = Kl[(n0 * 8 + g) * AP + k0 * 8 + t + 4];
                mma_tf32(s[n0], qh[k0], bl2);
                mma_tf32(s[n0], ql[k0], bh2);
                mma_tf32(s[n0], qh[k0], bh2);
            }
        }

        // ---- online softmax --------------------------------------------------
        float m0 = s[0][0], m1 = s[0][2];
#pragma unroll
        for (int n = 0; n < 8; n++) {
            m0 = fmaxf(m0, fmaxf(s[n][0], s[n][1]));
            m1 = fmaxf(m1, fmaxf(s[n][2], s[n][3]));
        }
        m0 = fmaxf(m0, __shfl_xor_sync(0xffffffff, m0, 1));
        m0 = fmaxf(m0, __shfl_xor_sync(0xffffffff, m0, 2));
        m1 = fmaxf(m1, __shfl_xor_sync(0xffffffff, m1, 1));
        m1 = fmaxf(m1, __shfl_xor_sync(0xffffffff, m1, 2));

        float mn0 = fmaxf(rm0, m0);
        float mn1 = fmaxf(rm1, m1);
        float corr0 = exp2f((rm0 - mn0) * LOG2E);
        float corr1 = exp2f((rm1 - mn1) * LOG2E);

        float sum0 = 0.f, sum1 = 0.f;
#pragma unroll
        for (int n = 0; n < 8; n++) {
            s[n][0] = exp2f((s[n][0] - mn0) * LOG2E);
            s[n][1] = exp2f((s[n][1] - mn0) * LOG2E);
            s[n][2] = exp2f((s[n][2] - mn1) * LOG2E);
            s[n][3] = exp2f((s[n][3] - mn1) * LOG2E);
            sum0 += s[n][0] + s[n][1];
            sum1 += s[n][2] + s[n][3];
        }
        sum0 += __shfl_xor_sync(0xffffffff, sum0, 1);
        sum0 += __shfl_xor_sync(0xffffffff, sum0, 2);
        sum1 += __shfl_xor_sync(0xffffffff, sum1, 1);
        sum1 += __shfl_xor_sync(0xffffffff, sum1, 2);
        rl0 = rl0 * corr0 + sum0;
        rl1 = rl1 * corr1 + sum1;
        rm0 = mn0; rm1 = mn1;

#pragma unroll
        for (int n = 0; n < 8; n++) {
            om[n][0] *= corr0; om[n][1] *= corr0;
            om[n][2] *= corr1; om[n][3] *= corr1;
        }

        // ---- O += P @ V (3xTF32); P redistributed via shuffles ---------------
#pragma unroll
        for (int k0 = 0; k0 < 8; k0++) {
            int srcA = g * 4 + (t >> 1);
            int srcB = srcA + 2;
            float v00 = __shfl_sync(0xffffffff, s[k0][0], srcA);
            float v01 = __shfl_sync(0xffffffff, s[k0][1], srcA);
            float v02 = __shfl_sync(0xffffffff, s[k0][2], srcA);
            float v03 = __shfl_sync(0xffffffff, s[k0][3], srcA);
            float v10 = __shfl_sync(0xffffffff, s[k0][0], srcB);
            float v11 = __shfl_sync(0xffffffff, s[k0][1], srcB);
            float v12 = __shfl_sync(0xffffffff, s[k0][2], srcB);
            float v13 = __shfl_sync(0xffffffff, s[k0][3], srcB);
            bool odd = (t & 1);
            float a0 = odd ? v01 : v00;   // P[g   ][k0*8+t]
            float a1 = odd ? v03 : v02;   // P[g+8 ][k0*8+t]
            float a2 = odd ? v11 : v10;   // P[g   ][k0*8+t+4]
            float a3 = odd ? v13 : v12;   // P[g+8 ][k0*8+t+4]
            uint32_t ph[4], pl[4];
            split_tf32(a0, ph[0], pl[0]);
            split_tf32(a1, ph[1], pl[1]);
            split_tf32(a2, ph[2], pl[2]);
            split_tf32(a3, ph[3], pl[3]);
#pragma unroll
            for (int n0 = 0; n0 < 8; n0++) {
                uint32_t bh2[2], bl2[2];
                bh2[0] = Vh[(k0 * 8 + t    ) * AP + n0 * 8 + g];
                bh2[1] = Vh[(k0 * 8 + t + 4) * AP + n0 * 8 + g];
                bl2[0] = Vl[(k0 * 8 + t    ) * AP + n0 * 8 + g];
                bl2[1] = Vl[(k0 * 8 + t + 4) * AP + n0 * 8 + g];
                mma_tf32(om[n0], ph, bl2);
                mma_tf32(om[n0], pl, bh2);
                mma_tf32(om[n0], ph, bh2);
            }
        }
    }

    float inv0 = 1.f / rl0;
    float inv1 = 1.f / rl1;
    float* ob0 = o + (size_t)(b * TT + q0 + w * 16 + g    ) * QKW + h * DH + 2 * t;
    float* ob1 = o + (size_t)(b * TT + q0 + w * 16 + g + 8) * QKW + h * DH + 2 * t;
#pragma unroll
    for (int n0 = 0; n0 < 8; n0++) {
        *(float2*)(ob0 + n0 * 8) = make_float2(om[n0][0] * inv0, om[n0][1] * inv0);
        *(float2*)(ob1 + n0 * 8) = make_float2(om[n0][2] * inv1, om[n0][3] * inv1);
    }
}

// -------- Y[t, e*64+j] = sum_h mask[t,h,e] * attn[t,h,j] ---------------------
__global__ void combine_out_kernel(const float* __restrict__ attn,
                                   const float* __restrict__ masko,
                                   float* __restrict__ Y) {
    int token = blockIdx.x;
    int t = threadIdx.x;            // 0..319
    int e = t / DH, j = t % DH;
    const float* ap = attn + (size_t)token * QKW;
    const float* mp = masko + (size_t)token * GW;
    float s = 0.f;
#pragma unroll
    for (int h = 0; h < HH; h++)
        s += mp[h * EE + e] * ap[h * DH + j];
    Y[(size_t)token * XVW + t] = s;
}

// ------------------------------- launch --------------------------------------
extern "C" void kernel_launch(void* const* d_in, const int* in_sizes, int n_in,
                              void* d_out, int out_size) {
    const float* x  = (const float*)d_in[0];
    const float* Wq = (const float*)d_in[1];
    const float* Wk = (const float*)d_in[2];
    const float* Ws = (const float*)d_in[3];
    const float* Wd = (const float*)d_in[4];
    const float* Wv = (const float*)d_in[5];
    const float* Wo = (const float*)d_in[6];
    float* out = (float*)d_out;

    float *proj, *wall, *v, *attn, *mask, *y;
    cudaGetSymbolAddress((void**)&proj, g_proj);
    cudaGetSymbolAddress((void**)&wall, g_wall);
    cudaGetSymbolAddress((void**)&v,    g_v);
    cudaGetSymbolAddress((void**)&attn, g_attn);
    cudaGetSymbolAddress((void**)&mask, g_mask);
    cudaGetSymbolAddress((void**)&y,    g_y);

    // pack all weights into one (1024 x 1536) matrix
    pack_wall_kernel<<<(DD * PW + 255) / 256, 256>>>(Wq, Wk, Ws, Wd, Wv, wall);

    size_t gsm = (size_t)(128 * GP_A * 2 + 32 * GP_B * 2) * sizeof(uint32_t); // 71680
    cudaFuncSetAttribute(tgemm3x, cudaFuncAttributeMaxDynamicSharedMemorySize, (int)gsm);

    // fused projection GEMM (3xTF32): (8192x1024) @ (1024x1536)
    dim3 gp(PW / 128, NTOK / 128);
    tgemm3x<<<gp, 256, gsm>>>(x, wall, proj, NTOK, PW, DD);

    // gating + V combine + out-mask
    gate_combine_kernel<<<NTOK, 256>>>(proj, v, mask);

    // attention (3xTF32 MMA)
    size_t asm_ = (size_t)(4 * 64 * AP) * sizeof(uint32_t);  // 69632
    cudaFuncSetAttribute(attn_kernel, cudaFuncAttributeMaxDynamicSharedMemorySize, (int)asm_);
    dim3 ag(TT / 128, BB * HH);
    attn_kernel<<<ag, 256, asm_>>>(proj + OFF_Q, proj + OFF_K, v, attn);

    // masked head/expert combine, then output GEMM (3xTF32)
    combine_out_kernel<<<NTOK, XVW>>>(attn, mask, y);
    dim3 go(DD / 128, NTOK / 128);
    tgemm3x<<<go, 256, gsm>>>(y, Wo, out, NTOK, DD, XVW);
}

// round 5
// speedup vs baseline: 5.2453x; 1.0005x over previous
#include <cuda_runtime.h>
#include <cuda_bf16.h>
#include <math.h>
#include <stdint.h>

// Problem constants
#define BB 4
#define TT 2048
#define DD 1024
#define HH 8
#define DH 64
#define EE 5
#define NTOK (BB*TT)          // 8192
#define QKW (HH*DH)           // 512
#define GW  (HH*EE)           // 40
#define XVW (EE*DH)           // 320

// fused projection layout (row stride PW):
// [0:512) q | [512:1024) k | [1024:1344) xv | [1344:1384) glv | [1384:1424) glo | pad->1536
#define PW 1536
#define OFF_Q   0
#define OFF_K   512
#define OFF_XV  1024
#define OFF_GLV 1344
#define OFF_GLO 1384

// ---------------- scratch (device globals) ------------------------------------
__device__ float g_proj[(size_t)NTOK*PW];
__device__ float g_wall[(size_t)DD*PW];
__device__ float g_v   [(size_t)NTOK*QKW];
__device__ float g_attn[(size_t)NTOK*QKW];
__device__ float g_mask[(size_t)NTOK*GW];
__device__ float g_y   [(size_t)NTOK*XVW];

// ---------------- tf32 helpers ------------------------------------------------
__device__ __forceinline__ uint32_t f2tf32(float x) {
    uint32_t r;
    asm("cvt.rna.tf32.f32 %0, %1;" : "=r"(r) : "f"(x));
    return r;
}

// split x = hi + lo (both tf32); dropped part ~ eps^2
__device__ __forceinline__ void split_tf32(float x, uint32_t& h, uint32_t& l) {
    h = f2tf32(x);
    l = f2tf32(x - __uint_as_float(h));
}

__device__ __forceinline__ void mma_tf32(float c[4], const uint32_t a[4], const uint32_t b[2]) {
    asm volatile(
        "mma.sync.aligned.m16n8k8.row.col.f32.tf32.tf32.f32 "
        "{%0,%1,%2,%3},{%4,%5,%6,%7},{%8,%9},{%0,%1,%2,%3};"
        : "+f"(c[0]), "+f"(c[1]), "+f"(c[2]), "+f"(c[3])
        : "r"(a[0]), "r"(a[1]), "r"(a[2]), "r"(a[3]),
          "r"(b[0]), "r"(b[1]));
}

// =============== 3xTF32 GEMM: C=A@B, M%128==0, N%128==0, K%32==0 ==============
#define GP_A 36     // pad: 36%32=4 -> A-frag banks distinct
#define GP_B 136    // pad: 136%32=8 -> B-frag banks distinct

__global__ __launch_bounds__(256)
void tgemm3x(const float* __restrict__ A, const float* __restrict__ B,
             float* __restrict__ C, int M, int N, int K) {
    extern __shared__ uint32_t sm[];
    uint32_t* Ah = sm;                      // [128][GP_A]
    uint32_t* Al = Ah + 128 * GP_A;
    uint32_t* Bh = Al + 128 * GP_A;         // [32][GP_B]
    uint32_t* Bl = Bh + 32 * GP_B;

    const int tid = threadIdx.x;
    const int row0 = blockIdx.y * 128;
    const int col0 = blockIdx.x * 128;
    const int lane = tid & 31, w = tid >> 5;
    const int g = lane >> 2, t = lane & 3;
    const int wm = w >> 1, wn = w & 1;      // 4x2 warp grid: warp tile 32x64

    float c[2][8][4];
#pragma unroll
    for (int mt = 0; mt < 2; mt++)
#pragma unroll
        for (int nt = 0; nt < 8; nt++)
#pragma unroll
            for (int i = 0; i < 4; i++) c[mt][nt][i] = 0.f;

    const int nk = K / 32;

    float4 a4[4], b4[4];
#pragma unroll
    for (int it = 0; it < 4; it++) {
        int idA = it * 1024 + tid * 4;
        int ar = idA >> 5, ac = idA & 31;
        a4[it] = *(const float4*)(A + (size_t)(row0 + ar) * K + ac);
        int br = idA >> 7, bc = idA & 127;
        b4[it] = *(const float4*)(B + (size_t)br * N + col0 + bc);
    }

    for (int kt = 0; kt < nk; kt++) {
        __syncthreads();
#pragma unroll
        for (int it = 0; it < 4; it++) {
            int idA = it * 1024 + tid * 4;
            int ar = idA >> 5, ac = idA & 31;
            uint4 ah, al;
            split_tf32(a4[it].x, ah.x, al.x);
            split_tf32(a4[it].y, ah.y, al.y);
            split_tf32(a4[it].z, ah.z, al.z);
            split_tf32(a4[it].w, ah.w, al.w);
            *(uint4*)&Ah[ar * GP_A + ac] = ah;
            *(uint4*)&Al[ar * GP_A + ac] = al;
            int br = idA >> 7, bc = idA & 127;
            uint4 bh, bl;
            split_tf32(b4[it].x, bh.x, bl.x);
            split_tf32(b4[it].y, bh.y, bl.y);
            split_tf32(b4[it].z, bh.z, bl.z);
            split_tf32(b4[it].w, bh.w, bl.w);
            *(uint4*)&Bh[br * GP_B + bc] = bh;
            *(uint4*)&Bl[br * GP_B + bc] = bl;
        }
        __syncthreads();

        if (kt + 1 < nk) {
#pragma unroll
            for (int it = 0; it < 4; it++) {
                int idA = it * 1024 + tid * 4;
                int ar = idA >> 5, ac = idA & 31;
                a4[it] = *(const float4*)(A + (size_t)(row0 + ar) * K + (kt + 1) * 32 + ac);
                int br = idA >> 7, bc = idA & 127;
                b4[it] = *(const float4*)(B + (size_t)((kt + 1) * 32 + br) * N + col0 + bc);
            }
        }

#pragma unroll
        for (int kc = 0; kc < 4; kc++) {
            uint32_t afh[2][4], afl[2][4], bfh[8][2], bfl[8][2];
#pragma unroll
            for (int mt = 0; mt < 2; mt++) {
                int rb = wm * 32 + mt * 16;
                afh[mt][0] = Ah[(rb + g    ) * GP_A + kc * 8 + t];
                afh[mt][1] = Ah[(rb + g + 8) * GP_A + kc * 8 + t];
                afh[mt][2] = Ah[(rb + g    ) * GP_A + kc * 8 + t + 4];
                afh[mt][3] = Ah[(rb + g + 8) * GP_A + kc * 8 + t + 4];
                afl[mt][0] = Al[(rb + g    ) * GP_A + kc * 8 + t];
                afl[mt][1] = Al[(rb + g + 8) * GP_A + kc * 8 + t];
                afl[mt][2] = Al[(rb + g    ) * GP_A + kc * 8 + t + 4];
                afl[mt][3] = Al[(rb + g + 8) * GP_A + kc * 8 + t + 4];
            }
#pragma unroll
            for (int nt = 0; nt < 8; nt++) {
                int cb = wn * 64 + nt * 8;
                bfh[nt][0] = Bh[(kc * 8 + t    ) * GP_B + cb + g];
                bfh[nt][1] = Bh[(kc * 8 + t + 4) * GP_B + cb + g];
                bfl[nt][0] = Bl[(kc * 8 + t    ) * GP_B + cb + g];
                bfl[nt][1] = Bl[(kc * 8 + t + 4) * GP_B + cb + g];
            }
#pragma unroll
            for (int mt = 0; mt < 2; mt++)
#pragma unroll
                for (int nt = 0; nt < 8; nt++) {
                    mma_tf32(c[mt][nt], afh[mt], bfl[nt]);
                    mma_tf32(c[mt][nt], afl[mt], bfh[nt]);
                    mma_tf32(c[mt][nt], afh[mt], bfh[nt]);
                }
        }
    }

#pragma unroll
    for (int mt = 0; mt < 2; mt++) {
        int r0 = row0 + wm * 32 + mt * 16;
#pragma unroll
        for (int nt = 0; nt < 8; nt++) {
            int cc = col0 + wn * 64 + nt * 8 + 2 * t;
            *(float2*)&C[(size_t)(r0 + g    ) * N + cc] = make_float2(c[mt][nt][0], c[mt][nt][1]);
            *(float2*)&C[(size_t)(r0 + g + 8) * N + cc] = make_float2(c[mt][nt][2], c[mt][nt][3]);
        }
    }
}

// ----------- pack Wq|Wk|Wv|Ws|Wd -> (D, 1536) with zero pad ------------------
__global__ void pack_wall_kernel(const float* __restrict__ Wq,
                                 const float* __restrict__ Wk,
                                 const float* __restrict__ Ws,
                                 const float* __restrict__ Wd,
                                 const float* __restrict__ Wv,
                                 float* __restrict__ Wall) {
    int idx = blockIdx.x * blockDim.x + threadIdx.x;
    if (idx >= DD * PW) return;
    int d = idx / PW;
    int n = idx % PW;
    float val;
    if (n < 512) {
        val = Wq[(size_t)d * 512 + n];
    } else if (n < 1024) {
        val = Wk[(size_t)d * 512 + (n - 512)];
    } else if (n < 1344) {
        int e = (n - 1024) / DH, j = (n - 1024) % DH;
        val = Wv[((size_t)e * DD + d) * DH + j];
    } else if (n < 1384) {
        val = Ws[(size_t)d * GW + (n - 1344)];
    } else if (n < 1424) {
        val = Wd[(size_t)d * GW + (n - 1384)];
    } else {
        val = 0.f;
    }
    Wall[idx] = val;
}

// -------- top-2 gating: sigmoid-weighted V combine + output mask -------------
__global__ void gate_combine_kernel(const float* __restrict__ proj,
                                    float* __restrict__ v,
                                    float* __restrict__ masko) {
    int token = blockIdx.x;
    int w = threadIdx.x / 32;
    int lane = threadIdx.x % 32;
    const float* base = proj + (size_t)token * PW;

    const float* gv = base + OFF_GLV + w * EE;
    float g[EE];
#pragma unroll
    for (int e = 0; e < EE; e++) g[e] = gv[e];
    int i1 = 0;
#pragma unroll
    for (int e = 1; e < EE; e++) if (g[e] > g[i1]) i1 = e;
    int i2 = (i1 == 0) ? 1 : 0;
#pragma unroll
    for (int e = 0; e < EE; e++) if (e != i1 && g[e] > g[i2]) i2 = e;
    float w1 = 1.f / (1.f + __expf(-g[i1]));
    float w2 = 1.f / (1.f + __expf(-g[i2]));

    const float* xvt = base + OFF_XV;
    float* vt = v + (size_t)token * QKW + w * DH;
#pragma unroll
    for (int d = lane; d < DH; d += 32)
        vt[d] = w1 * xvt[i1 * DH + d] + w2 * xvt[i2 * DH + d];

    const float* go = base + OFF_GLO + w * EE;
#pragma unroll
    for (int e = 0; e < EE; e++) g[e] = go[e];
    int o1 = 0;
#pragma unroll
    for (int e = 1; e < EE; e++) if (g[e] > g[o1]) o1 = e;
    int o2 = (o1 == 0) ? 1 : 0;
#pragma unroll
    for (int e = 0; e < EE; e++) if (e != o1 && g[e] > g[o2]) o2 = e;
    if (lane < EE)
        masko[((size_t)token * HH + w) * EE + lane] = (lane == o1 || lane == o2) ? 1.f : 0.f;
}

// ================= flash attention, 3xTF32 MMA ================================
// 128 q rows per block, 8 warps x 16 rows, 64-key tiles.
// P redistributed C-frag -> A-frag via warp shuffles (no P smem).
#define AP 68
#define LOG2E 1.4426950408889634f

__global__ __launch_bounds__(256)
void attn_kernel(const float* __restrict__ q,
                 const float* __restrict__ k,
                 const float* __restrict__ v,
                 float* __restrict__ o) {
    extern __shared__ uint32_t sh[];
    uint32_t* Kh = sh;                 // [64][AP] tf32 hi, [key][d]
    uint32_t* Kl = Kh + 64 * AP;       // lo
    uint32_t* Vh = Kl + 64 * AP;       // [64][AP] [key][d]
    uint32_t* Vl = Vh + 64 * AP;

    const int bh = blockIdx.y;
    const int b = bh / HH, h = bh % HH;
    const int q0 = blockIdx.x * 128;
    const int tid = threadIdx.x;
    const int lane = tid & 31, w = tid >> 5;
    const int g = lane >> 2, t = lane & 3;
    const float scale = 0.125f;

    // --- Q fragments (hi/lo), register-resident, scale folded (exact pow2) ---
    const float* qb = q + (size_t)(b * TT + q0 + w * 16) * PW + h * DH;
    uint32_t qh[8][4], ql[8][4];
#pragma unroll
    for (int k0 = 0; k0 < 8; k0++) {
        split_tf32(scale * qb[(size_t)(g    ) * PW + k0 * 8 + t],     qh[k0][0], ql[k0][0]);
        split_tf32(scale * qb[(size_t)(g + 8) * PW + k0 * 8 + t],     qh[k0][1], ql[k0][1]);
        split_tf32(scale * qb[(size_t)(g    ) * PW + k0 * 8 + t + 4], qh[k0][2], ql[k0][2]);
        split_tf32(scale * qb[(size_t)(g + 8) * PW + k0 * 8 + t + 4], qh[k0][3], ql[k0][3]);
    }

    float om[8][4];
#pragma unroll
    for (int n = 0; n < 8; n++)
#pragma unroll
        for (int i = 0; i < 4; i++) om[n][i] = 0.f;
    float rm0 = -INFINITY, rm1 = -INFINITY, rl0 = 0.f, rl1 = 0.f;

    // prefetch tile 0
    float4 kf[4], vf[4];
    {
        const float* kb = k + (size_t)(b * TT) * PW + h * DH;
        const float* vb = v + (size_t)(b * TT) * QKW + h * DH;
#pragma unroll
        for (int it = 0; it < 4; it++) {
            int id = it * 1024 + tid * 4;
            int r = id >> 6, d = id & 63;
            kf[it] = *(const float4*)(kb + (size_t)r * PW + d);
            vf[it] = *(const float4*)(vb + (size_t)r * QKW + d);
        }
    }

    for (int t0 = 0; t0 < TT; t0 += 64) {
        __syncthreads();   // previous tile fully consumed
#pragma unroll
        for (int it = 0; it < 4; it++) {
            int id = it * 1024 + tid * 4;
            int r = id >> 6, d = id & 63;
            uint4 hh, ll;
            split_tf32(kf[it].x, hh.x, ll.x);
            split_tf32(kf[it].y, hh.y, ll.y);
            split_tf32(kf[it].z, hh.z, ll.z);
            split_tf32(kf[it].w, hh.w, ll.w);
            *(uint4*)&Kh[r * AP + d] = hh;
            *(uint4*)&Kl[r * AP + d] = ll;
            split_tf32(vf[it].x, hh.x, ll.x);
            split_tf32(vf[it].y, hh.y, ll.y);
            split_tf32(vf[it].z, hh.z, ll.z);
            split_tf32(vf[it].w, hh.w, ll.w);
            *(uint4*)&Vh[r * AP + d] = hh;
            *(uint4*)&Vl[r * AP + d] = ll;
        }
        __syncthreads();

        if (t0 + 64 < TT) {
            const float* kb = k + (size_t)(b * TT + t0 + 64) * PW + h * DH;
            const float* vb = v + (size_t)(b * TT + t0 + 64) * QKW + h * DH;
#pragma unroll
            for (int it = 0; it < 4; it++) {
                int id = it * 1024 + tid * 4;
                int r = id >> 6, d = id & 63;
                kf[it] = *(const float4*)(kb + (size_t)r * PW + d);
                vf[it] = *(const float4*)(vb + (size_t)r * QKW + d);
            }
        }

        // ---- S = Qs @ K^T (3xTF32): per-warp 16x64 ---------------------------
        float s[8][4];
#pragma unroll
        for (int n = 0; n < 8; n++)
#pragma unroll
            for (int i = 0; i < 4; i++) s[n][i] = 0.f;
#pragma unroll
        for (int k0 = 0; k0 < 8; k0++) {
#pragma unroll
            for (int n0 = 0; n0 < 8; n0++) {
                uint32_t bh2[2], bl2[2];
                bh2[0] = Kh[(n0 * 8 + g) * AP + k0 * 8 + t];
                bh2[1] = Kh[(n0 * 8 + g) * AP + k0 * 8 + t + 4];
                bl2[0] = Kl[(n0 * 8 + g) * AP + k0 * 8 + t];
                bl2[1] = Kl[(n0 * 8 + g) * AP + k0 * 8 + t + 4];
                mma_tf32(s[n0], qh[k0], bl2);
                mma_tf32(s[n0], ql[k0], bh2);
                mma_tf32(s[n0], qh[k0], bh2);
            }
        }

        // ---- online softmax --------------------------------------------------
        float m0 = s[0][0], m1 = s[0][2];
#pragma unroll
        for (int n = 0; n < 8; n++) {
            m0 = fmaxf(m0, fmaxf(s[n][0], s[n][1]));
            m1 = fmaxf(m1, fmaxf(s[n][2], s[n][3]));
        }
        m0 = fmaxf(m0, __shfl_xor_sync(0xffffffff, m0, 1));
        m0 = fmaxf(m0, __shfl_xor_sync(0xffffffff, m0, 2));
        m1 = fmaxf(m1, __shfl_xor_sync(0xffffffff, m1, 1));
        m1 = fmaxf(m1, __shfl_xor_sync(0xffffffff, m1, 2));

        float mn0 = fmaxf(rm0, m0);
        float mn1 = fmaxf(rm1, m1);
        float corr0 = exp2f((rm0 - mn0) * LOG2E);
        float corr1 = exp2f((rm1 - mn1) * LOG2E);

        float sum0 = 0.f, sum1 = 0.f;
#pragma unroll
        for (int n = 0; n < 8; n++) {
            s[n][0] = exp2f((s[n][0] - mn0) * LOG2E);
            s[n][1] = exp2f((s[n][1] - mn0) * LOG2E);
            s[n][2] = exp2f((s[n][2] - mn1) * LOG2E);
            s[n][3] = exp2f((s[n][3] - mn1) * LOG2E);
            sum0 += s[n][0] + s[n][1];
            sum1 += s[n][2] + s[n][3];
        }
        sum0 += __shfl_xor_sync(0xffffffff, sum0, 1);
        sum0 += __shfl_xor_sync(0xffffffff, sum0, 2);
        sum1 += __shfl_xor_sync(0xffffffff, sum1, 1);
        sum1 += __shfl_xor_sync(0xffffffff, sum1, 2);
        rl0 = rl0 * corr0 + sum0;
        rl1 = rl1 * corr1 + sum1;
        rm0 = mn0; rm1 = mn1;

#pragma unroll
        for (int n = 0; n < 8; n++) {
            om[n][0] *= corr0; om[n][1] *= corr0;
            om[n][2] *= corr1; om[n][3] *= corr1;
        }

        // ---- O += P @ V (3xTF32); P redistributed via shuffles ---------------
#pragma unroll
        for (int k0 = 0; k0 < 8; k0++) {
            int srcA = g * 4 + (t >> 1);
            int srcB = srcA + 2;
            float v00 = __shfl_sync(0xffffffff, s[k0][0], srcA);
            float v01 = __shfl_sync(0xffffffff, s[k0][1], srcA);
            float v02 = __shfl_sync(0xffffffff, s[k0][2], srcA);
            float v03 = __shfl_sync(0xffffffff, s[k0][3], srcA);
            float v10 = __shfl_sync(0xffffffff, s[k0][0], srcB);
            float v11 = __shfl_sync(0xffffffff, s[k0][1], srcB);
            float v12 = __shfl_sync(0xffffffff, s[k0][2], srcB);
            float v13 = __shfl_sync(0xffffffff, s[k0][3], srcB);
            bool odd = (t & 1);
            float a0 = odd ? v01 : v00;   // P[g   ][k0*8+t]
            float a1 = odd ? v03 : v02;   // P[g+8 ][k0*8+t]
            float a2 = odd ? v11 : v10;   // P[g   ][k0*8+t+4]
            float a3 = odd ? v13 : v12;   // P[g+8 ][k0*8+t+4]
            uint32_t ph[4], pl[4];
            split_tf32(a0, ph[0], pl[0]);
            split_tf32(a1, ph[1], pl[1]);
            split_tf32(a2, ph[2], pl[2]);
            split_tf32(a3, ph[3], pl[3]);
#pragma unroll
            for (int n0 = 0; n0 < 8; n0++) {
                uint32_t bh2[2], bl2[2];
                bh2[0] = Vh[(k0 * 8 + t    ) * AP + n0 * 8 + g];
                bh2[1] = Vh[(k0 * 8 + t + 4) * AP + n0 * 8 + g];
                bl2[0] = Vl[(k0 * 8 + t    ) * AP + n0 * 8 + g];
                bl2[1] = Vl[(k0 * 8 + t + 4) * AP + n0 * 8 + g];
                mma_tf32(om[n0], ph, bl2);
                mma_tf32(om[n0], pl, bh2);
                mma_tf32(om[n0], ph, bh2);
            }
        }
    }

    float inv0 = 1.f / rl0;
    float inv1 = 1.f / rl1;
    float* ob0 = o + (size_t)(b * TT + q0 + w * 16 + g    ) * QKW + h * DH + 2 * t;
    float* ob1 = o + (size_t)(b * TT + q0 + w * 16 + g + 8) * QKW + h * DH + 2 * t;
#pragma unroll
    for (int n0 = 0; n0 < 8; n0++) {
        *(float2*)(ob0 + n0 * 8) = make_float2(om[n0][0] * inv0, om[n0][1] * inv0);
        *(float2*)(ob1 + n0 * 8) = make_float2(om[n0][2] * inv1, om[n0][3] * inv1);
    }
}

// -------- Y[t, e*64+j] = sum_h mask[t,h,e] * attn[t,h,j] ---------------------
__global__ void combine_out_kernel(const float* __restrict__ attn,
                                   const float* __restrict__ masko,
                                   float* __restrict__ Y) {
    int token = blockIdx.x;
    int t = threadIdx.x;            // 0..319
    int e = t / DH, j = t % DH;
    const float* ap = attn + (size_t)token * QKW;
    const float* mp = masko + (size_t)token * GW;
    float s = 0.f;
#pragma unroll
    for (int h = 0; h < HH; h++)
        s += mp[h * EE + e] * ap[h * DH + j];
    Y[(size_t)token * XVW + t] = s;
}

// ------------------------------- launch --------------------------------------
extern "C" void kernel_launch(void* const* d_in, const int* in_sizes, int n_in,
                              void* d_out, int out_size) {
    const float* x  = (const float*)d_in[0];
    const float* Wq = (const float*)d_in[1];
    const float* Wk = (const float*)d_in[2];
    const float* Ws = (const float*)d_in[3];
    const float* Wd = (const float*)d_in[4];
    const float* Wv = (const float*)d_in[5];
    const float* Wo = (const float*)d_in[6];
    float* out = (float*)d_out;

    float *proj, *wall, *v, *attn, *mask, *y;
    cudaGetSymbolAddress((void**)&proj, g_proj);
    cudaGetSymbolAddress((void**)&wall, g_wall);
    cudaGetSymbolAddress((void**)&v,    g_v);
    cudaGetSymbolAddress((void**)&attn, g_attn);
    cudaGetSymbolAddress((void**)&mask, g_mask);
    cudaGetSymbolAddress((void**)&y,    g_y);

    // pack all weights into one (1024 x 1536) matrix
    pack_wall_kernel<<<(DD * PW + 255) / 256, 256>>>(Wq, Wk, Ws, Wd, Wv, wall);

    size_t gsm = (size_t)(128 * GP_A * 2 + 32 * GP_B * 2) * sizeof(uint32_t); // 71680
    cudaFuncSetAttribute(tgemm3x, cudaFuncAttributeMaxDynamicSharedMemorySize, (int)gsm);

    // fused projection GEMM (3xTF32): (8192x1024) @ (1024x1536)
    dim3 gp(PW / 128, NTOK / 128);
    tgemm3x<<<gp, 256, gsm>>>(x, wall, proj, NTOK, PW, DD);

    // gating + V combine + out-mask
    gate_combine_kernel<<<NTOK, 256>>>(proj, v, mask);

    // attention (3xTF32 MMA)
    size_t asm_ = (size_t)(4 * 64 * AP) * sizeof(uint32_t);  // 69632
    cudaFuncSetAttribute(attn_kernel, cudaFuncAttributeMaxDynamicSharedMemorySize, (int)asm_);
    dim3 ag(TT / 128, BB * HH);
    attn_kernel<<<ag, 256, asm_>>>(proj + OFF_Q, proj + OFF_K, v, attn);

    // masked head/expert combine, then output GEMM (3xTF32)
    combine_out_kernel<<<NTOK, XVW>>>(attn, mask, y);
    dim3 go(DD / 128, NTOK / 128);
    tgemm3x<<<go, 256, gsm>>>(y, Wo, out, NTOK, DD, XVW);
}

// round 7
// speedup vs baseline: 5.3657x; 1.0229x over previous
#include <cuda_runtime.h>
#include <cuda_bf16.h>
#include <math.h>
#include <stdint.h>

// Problem constants
#define BB 4
#define TT 2048
#define DD 1024
#define HH 8
#define DH 64
#define EE 5
#define NTOK (BB*TT)          // 8192
#define QKW (HH*DH)           // 512
#define GW  (HH*EE)           // 40
#define XVW (EE*DH)           // 320

// fused projection layout (row stride PW)
#define PW 1536
#define OFF_Q   0
#define OFF_K   512
#define OFF_XV  1024
#define OFF_GLV 1344
#define OFF_GLO 1384

// KV fragment blob: per (bh, tile64): [Kh|Kl|Vh|Vl], each 8 k0 x 32 lanes x 20 u32
#define ROWPAD 20
#define ARR_U32 (8*32*ROWPAD)     // 5120
#define TILE_U32 (4*ARR_U32)      // 20480 u32 = 81920 B
#define NTILE 32

// ---------------- scratch (device globals) ------------------------------------
__device__ float    g_proj [(size_t)NTOK*PW];
__device__ __align__(16) uint32_t g_wallh[(size_t)DD*PW];
__device__ __align__(16) uint32_t g_walll[(size_t)DD*PW];
__device__ __align__(16) uint32_t g_xh   [(size_t)NTOK*DD];
__device__ __align__(16) uint32_t g_xl   [(size_t)NTOK*DD];
__device__ float    g_v    [(size_t)NTOK*QKW];
__device__ float    g_attn [(size_t)NTOK*QKW];
__device__ float    g_mask [(size_t)NTOK*GW];
__device__ __align__(16) uint32_t g_yh   [(size_t)NTOK*XVW];
__device__ __align__(16) uint32_t g_yl   [(size_t)NTOK*XVW];
__device__ __align__(16) uint32_t g_woh  [(size_t)XVW*DD];
__device__ __align__(16) uint32_t g_wol  [(size_t)XVW*DD];
__device__ __align__(16) uint32_t g_blob [(size_t)BB*HH*NTILE*TILE_U32];   // 80 MB

// ---------------- helpers ------------------------------------------------------
__device__ __forceinline__ uint32_t f2tf32(float x) {
    uint32_t r;
    asm("cvt.rna.tf32.f32 %0, %1;" : "=r"(r) : "f"(x));
    return r;
}
__device__ __forceinline__ void split_tf32(float x, uint32_t& h, uint32_t& l) {
    h = f2tf32(x);
    l = f2tf32(x - __uint_as_float(h));
}
__device__ __forceinline__ void mma_tf32(float c[4], const uint32_t a[4], const uint32_t b[2]) {
    asm volatile(
        "mma.sync.aligned.m16n8k8.row.col.f32.tf32.tf32.f32 "
        "{%0,%1,%2,%3},{%4,%5,%6,%7},{%8,%9},{%0,%1,%2,%3};"
        : "+f"(c[0]), "+f"(c[1]), "+f"(c[2]), "+f"(c[3])
        : "r"(a[0]), "r"(a[1]), "r"(a[2]), "r"(a[3]),
          "r"(b[0]), "r"(b[1]));
}
__device__ __forceinline__ void cp16(uint32_t saddr, const void* g) {
    asm volatile("cp.async.cg.shared.global [%0], [%1], 16;\n" :: "r"(saddr), "l"(g));
}
#define CP_COMMIT() asm volatile("cp.async.commit_group;\n")
#define CP_WAIT(n)  asm volatile("cp.async.wait_group %0;\n" :: "n"(n))

// =============== pre-split kernels =============================================
__global__ void split_x_kernel(const float* __restrict__ x,
                               uint32_t* __restrict__ xh, uint32_t* __restrict__ xl) {
    size_t i = (size_t)blockIdx.x * blockDim.x + threadIdx.x;
    if (i >= (size_t)NTOK * DD) return;
    split_tf32(x[i], xh[i], xl[i]);
}

__global__ void split_wo_kernel(const float* __restrict__ Wo,
                                uint32_t* __restrict__ wh, uint32_t* __restrict__ wl) {
    size_t i = (size_t)blockIdx.x * blockDim.x + threadIdx.x;
    if (i >= (size_t)XVW * DD) return;
    split_tf32(Wo[i], wh[i], wl[i]);
}

__global__ void pack_wall_kernel(const float* __restrict__ Wq,
                                 const float* __restrict__ Wk,
                                 const float* __restrict__ Ws,
                                 const float* __restrict__ Wd,
                                 const float* __restrict__ Wv,
                                 uint32_t* __restrict__ Wh,
                                 uint32_t* __restrict__ Wl) {
    int idx = blockIdx.x * blockDim.x + threadIdx.x;
    if (idx >= DD * PW) return;
    int d = idx / PW, n = idx % PW;
    float val;
    if (n < 512)        val = Wq[(size_t)d * 512 + n];
    else if (n < 1024)  val = Wk[(size_t)d * 512 + (n - 512)];
    else if (n < 1344) {
        int e = (n - 1024) / DH, j = (n - 1024) % DH;
        val = Wv[((size_t)e * DD + d) * DH + j];
    }
    else if (n < 1384)  val = Ws[(size_t)d * GW + (n - 1344)];
    else if (n < 1424)  val = Wd[(size_t)d * GW + (n - 1384)];
    else                val = 0.f;
    split_tf32(val, Wh[idx], Wl[idx]);
}

// =============== 3xTF32 GEMM on pre-split operands, cp.async 2-stage ===========
#define SA 36
#define SB 136
#define OFF_AL 4608     // 128*SA
#define OFF_BH 9216
#define OFF_BL 13568    // 9216 + 32*SB
#define STG 17920       // u32 per stage

// full 128x32 A tile + 32x128 B tile per stage: 4 chunks per array per thread
__device__ __forceinline__ void gemm_stage_load(
    uint32_t dst, const uint32_t* __restrict__ Agh, const uint32_t* __restrict__ Agl,
    const uint32_t* __restrict__ Bgh, const uint32_t* __restrict__ Bgl,
    int row0, int col0, int k0, int K, int N, int tid) {
#pragma unroll
    for (int it = 0; it < 4; it++) {
        int idx = it * 1024 + tid * 4;
        int ar = idx >> 5, ac = idx & 31;
        cp16(dst + (uint32_t)(ar * SA + ac) * 4,
             Agh + (size_t)(row0 + ar) * K + k0 + ac);
        cp16(dst + (uint32_t)(OFF_AL + ar * SA + ac) * 4,
             Agl + (size_t)(row0 + ar) * K + k0 + ac);
        int br = idx >> 7, bc = idx & 127;
        cp16(dst + (uint32_t)(OFF_BH + br * SB + bc) * 4,
             Bgh + (size_t)(k0 + br) * N + col0 + bc);
        cp16(dst + (uint32_t)(OFF_BL + br * SB + bc) * 4,
             Bgl + (size_t)(k0 + br) * N + col0 + bc);
    }
}

__global__ __launch_bounds__(256)
void tgemm3s(const uint32_t* __restrict__ Agh, const uint32_t* __restrict__ Agl,
             const uint32_t* __restrict__ Bgh, const uint32_t* __restrict__ Bgl,
             float* __restrict__ C, int M, int N, int K) {
    extern __shared__ uint32_t sm[];    // 2 stages x STG
    const int tid = threadIdx.x;
    const int row0 = blockIdx.y * 128;
    const int col0 = blockIdx.x * 128;
    const int lane = tid & 31, w = tid >> 5;
    const int g = lane >> 2, t = lane & 3;
    const int wm = w >> 1, wn = w & 1;

    const uint32_t sb = (uint32_t)__cvta_generic_to_shared(sm);

    float c[2][8][4];
#pragma unroll
    for (int mt = 0; mt < 2; mt++)
#pragma unroll
        for (int nt = 0; nt < 8; nt++)
#pragma unroll
            for (int i = 0; i < 4; i++) c[mt][nt][i] = 0.f;

    const int nk = K / 32;

    // prologue: stage 0 <- ktile 0
    gemm_stage_load(sb, Agh, Agl, Bgh, Bgl, row0, col0, 0, K, N, tid);
    CP_COMMIT();

    for (int kt = 0; kt < nk; kt++) {
        const int st = kt & 1;
        if (kt + 1 < nk) {
            uint32_t d2 = sb + (uint32_t)((st ^ 1) * STG) * 4;
            gemm_stage_load(d2, Agh, Agl, Bgh, Bgl, row0, col0, (kt + 1) * 32, K, N, tid);
            CP_COMMIT();
            CP_WAIT(1);
        } else {
            CP_WAIT(0);
        }
        __syncthreads();

        const uint32_t* Ah = sm + st * STG;
        const uint32_t* Al = Ah + OFF_AL;
        const uint32_t* Bh = Ah + OFF_BH;
        const uint32_t* Bl = Ah + OFF_BL;

#pragma unroll
        for (int kc = 0; kc < 4; kc++) {
            uint32_t afh[2][4], afl[2][4], bfh[8][2], bfl[8][2];
#pragma unroll
            for (int mt = 0; mt < 2; mt++) {
                int rb = wm * 32 + mt * 16;
                afh[mt][0] = Ah[(rb + g    ) * SA + kc * 8 + t];
                afh[mt][1] = Ah[(rb + g + 8) * SA + kc * 8 + t];
                afh[mt][2] = Ah[(rb + g    ) * SA + kc * 8 + t + 4];
                afh[mt][3] = Ah[(rb + g + 8) * SA + kc * 8 + t + 4];
                afl[mt][0] = Al[(rb + g    ) * SA + kc * 8 + t];
                afl[mt][1] = Al[(rb + g + 8) * SA + kc * 8 + t];
                afl[mt][2] = Al[(rb + g    ) * SA + kc * 8 + t + 4];
                afl[mt][3] = Al[(rb + g + 8) * SA + kc * 8 + t + 4];
            }
#pragma unroll
            for (int nt = 0; nt < 8; nt++) {
                int cb = wn * 64 + nt * 8;
                bfh[nt][0] = Bh[(kc * 8 + t    ) * SB + cb + g];
                bfh[nt][1] = Bh[(kc * 8 + t + 4) * SB + cb + g];
                bfl[nt][0] = Bl[(kc * 8 + t    ) * SB + cb + g];
                bfl[nt][1] = Bl[(kc * 8 + t + 4) * SB + cb + g];
            }
#pragma unroll
            for (int mt = 0; mt < 2; mt++)
#pragma unroll
                for (int nt = 0; nt < 8; nt++) {
                    mma_tf32(c[mt][nt], afh[mt], bfl[nt]);
                    mma_tf32(c[mt][nt], afl[mt], bfh[nt]);
                    mma_tf32(c[mt][nt], afh[mt], bfh[nt]);
                }
        }
        __syncthreads();
    }

#pragma unroll
    for (int mt = 0; mt < 2; mt++) {
        int r0 = row0 + wm * 32 + mt * 16;
#pragma unroll
        for (int nt = 0; nt < 8; nt++) {
            int cc = col0 + wn * 64 + nt * 8 + 2 * t;
            *(float2*)&C[(size_t)(r0 + g    ) * N + cc] = make_float2(c[mt][nt][0], c[mt][nt][1]);
            *(float2*)&C[(size_t)(r0 + g + 8) * N + cc] = make_float2(c[mt][nt][2], c[mt][nt][3]);
        }
    }
}

// -------- top-2 gating: sigmoid-weighted V combine + output mask ---------------
__global__ void gate_combine_kernel(const float* __restrict__ proj,
                                    float* __restrict__ v,
                                    float* __restrict__ masko) {
    int token = blockIdx.x;
    int w = threadIdx.x / 32;
    int lane = threadIdx.x % 32;
    const float* base = proj + (size_t)token * PW;

    const float* gv = base + OFF_GLV + w * EE;
    float g[EE];
#pragma unroll
    for (int e = 0; e < EE; e++) g[e] = gv[e];
    int i1 = 0;
#pragma unroll
    for (int e = 1; e < EE; e++) if (g[e] > g[i1]) i1 = e;
    int i2 = (i1 == 0) ? 1 : 0;
#pragma unroll
    for (int e = 0; e < EE; e++) if (e != i1 && g[e] > g[i2]) i2 = e;
    float w1 = 1.f / (1.f + __expf(-g[i1]));
    float w2 = 1.f / (1.f + __expf(-g[i2]));

    const float* xvt = base + OFF_XV;
    float* vt = v + (size_t)token * QKW + w * DH;
#pragma unroll
    for (int d = lane; d < DH; d += 32)
        vt[d] = w1 * xvt[i1 * DH + d] + w2 * xvt[i2 * DH + d];

    const float* go = base + OFF_GLO + w * EE;
#pragma unroll
    for (int e = 0; e < EE; e++) g[e] = go[e];
    int o1 = 0;
#pragma unroll
    for (int e = 1; e < EE; e++) if (g[e] > g[o1]) o1 = e;
    int o2 = (o1 == 0) ? 1 : 0;
#pragma unroll
    for (int e = 0; e < EE; e++) if (e != o1 && g[e] > g[o2]) o2 = e;
    if (lane < EE)
        masko[((size_t)token * HH + w) * EE + lane] = (lane == o1 || lane == o2) ? 1.f : 0.f;
}

// =============== build K/V fragment blob =======================================
// Blob row layout: [k0][lane][ROWPAD] with slots 0..15 = n0*2+half.
// K slot: (k0*32 + g*4 + t)*20 + n0*2 + half = hi/lo(K[key=n0*8+g][d=k0*8+t+4*half])
// V slot: (k0*32 + g*4 + t)*20 + n0*2 + half = hi/lo(V[key=k0*8+t+4*half][d=n0*8+g])
__global__ void build_kv_kernel(const float* __restrict__ proj,
                                const float* __restrict__ v,
                                uint32_t* __restrict__ blob) {
    extern __shared__ uint32_t sbuf[];
    const int tile = blockIdx.x, bh = blockIdx.y;
    const int b = bh / HH, h = bh % HH;
    const int tid = threadIdx.x;
    const int r = tid >> 2;            // key row 0..63
    const int d0 = (tid & 3) * 16;

    const float* kb = proj + (size_t)(b * TT + tile * 64 + r) * PW + OFF_K + h * DH;
    const float* vb = v    + (size_t)(b * TT + tile * 64 + r) * QKW + h * DH;

#pragma unroll
    for (int i = 0; i < 4; i++) {
        int d = d0 + i * 4;
        float4 k4 = *(const float4*)(kb + d);
        float4 v4 = *(const float4*)(vb + d);
        float kvv[4] = {k4.x, k4.y, k4.z, k4.w};
        float vvv[4] = {v4.x, v4.y, v4.z, v4.w};
#pragma unroll
        for (int j = 0; j < 4; j++) {
            int dd = d + j;
            int addrK = ((dd >> 3) * 32 + (r & 7) * 4 + (dd & 3)) * ROWPAD
                      + (r >> 3) * 2 + ((dd >> 2) & 1);
            uint32_t hi, lo;
            split_tf32(kvv[j], hi, lo);
            sbuf[addrK] = hi;
            sbuf[ARR_U32 + addrK] = lo;
            int addrV = ((r >> 3) * 32 + (dd & 7) * 4 + (r & 3)) * ROWPAD
                      + (dd >> 3) * 2 + ((r >> 2) & 1);
            split_tf32(vvv[j], hi, lo);
            sbuf[2 * ARR_U32 + addrV] = hi;
            sbuf[3 * ARR_U32 + addrV] = lo;
        }
    }
    __syncthreads();

    uint32_t* dst = blob + ((size_t)bh * NTILE + tile) * TILE_U32;
#pragma unroll
    for (int i = 0; i < 20; i++) {
        int cc = tid + i * 256;
        *(uint4*)(dst + cc * 4) = *(const uint4*)(sbuf + cc * 4);
    }
}

// =============== flash attention, 3xTF32, fragment blob + cp.async =============
#define LOG2E 1.4426950408889634f

__global__ __launch_bounds__(256)
void attn2_kernel(const float* __restrict__ qg,
                  const uint32_t* __restrict__ blob,
                  float* __restrict__ o) {
    extern __shared__ uint32_t sh[];     // 2 stages x TILE_U32
    const int bh = blockIdx.y;
    const int b = bh / HH, h = bh % HH;
    const int q0 = blockIdx.x * 128;
    const int tid = threadIdx.x;
    const int lane = tid & 31, w = tid >> 5;
    const int g = lane >> 2, t = lane & 3;
    const float scale = 0.125f;

    const uint32_t* gblob = blob + (size_t)bh * NTILE * TILE_U32;
    const uint32_t sbase = (uint32_t)__cvta_generic_to_shared(sh);

    // start DMA of tile 0 before anything else
#pragma unroll
    for (int i = 0; i < 20; i++) {
        int cc = tid + i * 256;
        cp16(sbase + cc * 16, gblob + cc * 4);
    }
    CP_COMMIT();

    // Q fragments (hi/lo), scale folded (exact pow2)
    const float* qb = qg + (size_t)(b * TT + q0 + w * 16) * PW + h * DH;
    uint32_t qh[8][4], ql[8][4];
#pragma unroll
    for (int k0 = 0; k0 < 8; k0++) {
        split_tf32(scale * qb[(size_t)(g    ) * PW + k0 * 8 + t],     qh[k0][0], ql[k0][0]);
        split_tf32(scale * qb[(size_t)(g + 8) * PW + k0 * 8 + t],     qh[k0][1], ql[k0][1]);
        split_tf32(scale * qb[(size_t)(g    ) * PW + k0 * 8 + t + 4], qh[k0][2], ql[k0][2]);
        split_tf32(scale * qb[(size_t)(g + 8) * PW + k0 * 8 + t + 4], qh[k0][3], ql[k0][3]);
    }

    float om[8][4];
#pragma unroll
    for (int n = 0; n < 8; n++)
#pragma unroll
        for (int i = 0; i < 4; i++) om[n][i] = 0.f;
    float rm0 = -INFINITY, rm1 = -INFINITY, rl0 = 0.f, rl1 = 0.f;

    for (int tt = 0; tt < NTILE; tt++) {
        const int st = tt & 1;
        if (tt + 1 < NTILE) {
            const uint32_t* src = gblob + (size_t)(tt + 1) * TILE_U32;
            uint32_t dst = sbase + (uint32_t)((st ^ 1) * TILE_U32) * 4;
#pragma unroll
            for (int i = 0; i < 20; i++) {
                int cc = tid + i * 256;
                cp16(dst + cc * 16, src + cc * 4);
            }
            CP_COMMIT();
            CP_WAIT(1);
        } else {
            CP_WAIT(0);
        }
        __syncthreads();

        const uint32_t* Kh = sh + st * TILE_U32;
        const uint32_t* Kl = Kh + ARR_U32;
        const uint32_t* Vh = Kh + 2 * ARR_U32;
        const uint32_t* Vl = Kh + 3 * ARR_U32;

        // ---- S = Qs @ K^T (3xTF32) -----------------------------------------
        float s[8][4];
#pragma unroll
        for (int n = 0; n < 8; n++)
#pragma unroll
            for (int i = 0; i < 4; i++) s[n][i] = 0.f;
#pragma unroll
        for (int k0 = 0; k0 < 8; k0++) {
            uint32_t khw[16], klw[16];
            const uint32_t* kr = Kh + (k0 * 32 + lane) * ROWPAD;
            *(uint4*)&khw[0]  = *(const uint4*)(kr);
            *(uint4*)&khw[4]  = *(const uint4*)(kr + 4);
            *(uint4*)&khw[8]  = *(const uint4*)(kr + 8);
            *(uint4*)&khw[12] = *(const uint4*)(kr + 12);
            const uint32_t* lr = Kl + (k0 * 32 + lane) * ROWPAD;
            *(uint4*)&klw[0]  = *(const uint4*)(lr);
            *(uint4*)&klw[4]  = *(const uint4*)(lr + 4);
            *(uint4*)&klw[8]  = *(const uint4*)(lr + 8);
            *(uint4*)&klw[12] = *(const uint4*)(lr + 12);
#pragma unroll
            for (int n0 = 0; n0 < 8; n0++) {
                uint32_t bh2[2] = {khw[2 * n0], khw[2 * n0 + 1]};
                uint32_t bl2[2] = {klw[2 * n0], klw[2 * n0 + 1]};
                mma_tf32(s[n0], qh[k0], bl2);
                mma_tf32(s[n0], ql[k0], bh2);
                mma_tf32(s[n0], qh[k0], bh2);
            }
        }

        // ---- online softmax -------------------------------------------------
        float m0 = s[0][0], m1 = s[0][2];
#pragma unroll
        for (int n = 0; n < 8; n++) {
            m0 = fmaxf(m0, fmaxf(s[n][0], s[n][1]));
            m1 = fmaxf(m1, fmaxf(s[n][2], s[n][3]));
        }
        m0 = fmaxf(m0, __shfl_xor_sync(0xffffffff, m0, 1));
        m0 = fmaxf(m0, __shfl_xor_sync(0xffffffff, m0, 2));
        m1 = fmaxf(m1, __shfl_xor_sync(0xffffffff, m1, 1));
        m1 = fmaxf(m1, __shfl_xor_sync(0xffffffff, m1, 2));

        float mn0 = fmaxf(rm0, m0);
        float mn1 = fmaxf(rm1, m1);
        float corr0 = exp2f((rm0 - mn0) * LOG2E);
        float corr1 = exp2f((rm1 - mn1) * LOG2E);

        float sum0 = 0.f, sum1 = 0.f;
#pragma unroll
        for (int n = 0; n < 8; n++) {
            s[n][0] = exp2f((s[n][0] - mn0) * LOG2E);
            s[n][1] = exp2f((s[n][1] - mn0) * LOG2E);
            s[n][2] = exp2f((s[n][2] - mn1) * LOG2E);
            s[n][3] = exp2f((s[n][3] - mn1) * LOG2E);
            sum0 += s[n][0] + s[n][1];
            sum1 += s[n][2] + s[n][3];
        }
        sum0 += __shfl_xor_sync(0xffffffff, sum0, 1);
        sum0 += __shfl_xor_sync(0xffffffff, sum0, 2);
        sum1 += __shfl_xor_sync(0xffffffff, sum1, 1);
        sum1 += __shfl_xor_sync(0xffffffff, sum1, 2);
        rl0 = rl0 * corr0 + sum0;
        rl1 = rl1 * corr1 + sum1;
        rm0 = mn0; rm1 = mn1;

#pragma unroll
        for (int n = 0; n < 8; n++) {
            om[n][0] *= corr0; om[n][1] *= corr0;
            om[n][2] *= corr1; om[n][3] *= corr1;
        }

        // ---- O += P @ V (3xTF32); P C-frag -> A-frag via shuffles -----------
#pragma unroll
        for (int k0 = 0; k0 < 8; k0++) {
            int srcA = g * 4 + (t >> 1);
            int srcB = srcA + 2;
            float v00 = __shfl_sync(0xffffffff, s[k0][0], srcA);
            float v01 = __shfl_sync(0xffffffff, s[k0][1], srcA);
            float v02 = __shfl_sync(0xffffffff, s[k0][2], srcA);
            float v03 = __shfl_sync(0xffffffff, s[k0][3], srcA);
            float v10 = __shfl_sync(0xffffffff, s[k0][0], srcB);
            float v11 = __shfl_sync(0xffffffff, s[k0][1], srcB);
            float v12 = __shfl_sync(0xffffffff, s[k0][2], srcB);
            float v13 = __shfl_sync(0xffffffff, s[k0][3], srcB);
            bool odd = (t & 1);
            float a0 = odd ? v01 : v00;
            float a1 = odd ? v03 : v02;
            float a2 = odd ? v11 : v10;
            float a3 = odd ? v13 : v12;
            uint32_t ph[4], pl[4];
            split_tf32(a0, ph[0], pl[0]);
            split_tf32(a1, ph[1], pl[1]);
            split_tf32(a2, ph[2], pl[2]);
            split_tf32(a3, ph[3], pl[3]);

            uint32_t vhw[16], vlw[16];
            const uint32_t* vr = Vh + (k0 * 32 + lane) * ROWPAD;
            *(uint4*)&vhw[0]  = *(const uint4*)(vr);
            *(uint4*)&vhw[4]  = *(const uint4*)(vr + 4);
            *(uint4*)&vhw[8]  = *(const uint4*)(vr + 8);
            *(uint4*)&vhw[12] = *(const uint4*)(vr + 12);
            const uint32_t* wr = Vl + (k0 * 32 + lane) * ROWPAD;
            *(uint4*)&vlw[0]  = *(const uint4*)(wr);
            *(uint4*)&vlw[4]  = *(const uint4*)(wr + 4);
            *(uint4*)&vlw[8]  = *(const uint4*)(wr + 8);
            *(uint4*)&vlw[12] = *(const uint4*)(wr + 12);
#pragma unroll
            for (int n0 = 0; n0 < 8; n0++) {
                uint32_t bh2[2] = {vhw[2 * n0], vhw[2 * n0 + 1]};
                uint32_t bl2[2] = {vlw[2 * n0], vlw[2 * n0 + 1]};
                mma_tf32(om[n0], ph, bl2);
                mma_tf32(om[n0], pl, bh2);
                mma_tf32(om[n0], ph, bh2);
            }
        }
        __syncthreads();
    }

    float inv0 = 1.f / rl0;
    float inv1 = 1.f / rl1;
    float* ob0 = o + (size_t)(b * TT + q0 + w * 16 + g    ) * QKW + h * DH + 2 * t;
    float* ob1 = o + (size_t)(b * TT + q0 + w * 16 + g + 8) * QKW + h * DH + 2 * t;
#pragma unroll
    for (int n0 = 0; n0 < 8; n0++) {
        *(float2*)(ob0 + n0 * 8) = make_float2(om[n0][0] * inv0, om[n0][1] * inv0);
        *(float2*)(ob1 + n0 * 8) = make_float2(om[n0][2] * inv1, om[n0][3] * inv1);
    }
}

// -------- Y[t, e*64+j] = sum_h mask[t,h,e]*attn[t,h,j], split to hi/lo ---------
__global__ void combine_out_kernel(const float* __restrict__ attn,
                                   const float* __restrict__ masko,
                                   uint32_t* __restrict__ Yh,
                                   uint32_t* __restrict__ Yl) {
    int token = blockIdx.x;
    int t = threadIdx.x;            // 0..319
    int e = t / DH, j = t % DH;
    const float* ap = attn + (size_t)token * QKW;
    const float* mp = masko + (size_t)token * GW;
    float s = 0.f;
#pragma unroll
    for (int h = 0; h < HH; h++)
        s += mp[h * EE + e] * ap[h * DH + j];
    uint32_t hi, lo;
    split_tf32(s, hi, lo);
    Yh[(size_t)token * XVW + t] = hi;
    Yl[(size_t)token * XVW + t] = lo;
}

// ------------------------------- launch ----------------------------------------
extern "C" void kernel_launch(void* const* d_in, const int* in_sizes, int n_in,
                              void* d_out, int out_size) {
    const float* x  = (const float*)d_in[0];
    const float* Wq = (const float*)d_in[1];
    const float* Wk = (const float*)d_in[2];
    const float* Ws = (const float*)d_in[3];
    const float* Wd = (const float*)d_in[4];
    const float* Wv = (const float*)d_in[5];
    const float* Wo = (const float*)d_in[6];
    float* out = (float*)d_out;

    float *proj, *v, *attn, *mask;
    uint32_t *wallh, *walll, *xh, *xl, *yh, *yl, *woh, *wol, *blob;
    cudaGetSymbolAddress((void**)&proj,  g_proj);
    cudaGetSymbolAddress((void**)&wallh, g_wallh);
    cudaGetSymbolAddress((void**)&walll, g_walll);
    cudaGetSymbolAddress((void**)&xh,    g_xh);
    cudaGetSymbolAddress((void**)&xl,    g_xl);
    cudaGetSymbolAddress((void**)&v,     g_v);
    cudaGetSymbolAddress((void**)&attn,  g_attn);
    cudaGetSymbolAddress((void**)&mask,  g_mask);
    cudaGetSymbolAddress((void**)&yh,    g_yh);
    cudaGetSymbolAddress((void**)&yl,    g_yl);
    cudaGetSymbolAddress((void**)&woh,   g_woh);
    cudaGetSymbolAddress((void**)&wol,   g_wol);
    cudaGetSymbolAddress((void**)&blob,  g_blob);

    // pre-splits
    pack_wall_kernel<<<(DD * PW + 255) / 256, 256>>>(Wq, Wk, Ws, Wd, Wv, wallh, walll);
    split_x_kernel<<<(int)(((size_t)NTOK * DD + 255) / 256), 256>>>(x, xh, xl);
    split_wo_kernel<<<(XVW * DD + 255) / 256, 256>>>(Wo, woh, wol);

    size_t gsm = (size_t)2 * STG * sizeof(uint32_t);  // 143360
    cudaFuncSetAttribute(tgemm3s, cudaFuncAttributeMaxDynamicSharedMemorySize, (int)gsm);

    // fused projection GEMM: (8192x1024)@(1024x1536)
    dim3 gp(PW / 128, NTOK / 128);
    tgemm3s<<<gp, 256, gsm>>>(xh, xl, wallh, walll, proj, NTOK, PW, DD);

    // gating + V combine + out-mask
    gate_combine_kernel<<<NTOK, 256>>>(proj, v, mask);

    // K/V fragment blob
    size_t bsm = (size_t)TILE_U32 * sizeof(uint32_t);  // 81920
    cudaFuncSetAttribute(build_kv_kernel, cudaFuncAttributeMaxDynamicSharedMemorySize, (int)bsm);
    dim3 bg(NTILE, BB * HH);
    build_kv_kernel<<<bg, 256, bsm>>>(proj, v, blob);

    // attention
    size_t asmem = (size_t)2 * TILE_U32 * sizeof(uint32_t);  // 163840
    cudaFuncSetAttribute(attn2_kernel, cudaFuncAttributeMaxDynamicSharedMemorySize, (int)asmem);
    dim3 ag(TT / 128, BB * HH);
    attn2_kernel<<<ag, 256, asmem>>>(proj + OFF_Q, blob, attn);

    // masked combine (+split), then output GEMM: (8192x320)@(320x1024)
    combine_out_kernel<<<NTOK, XVW>>>(attn, mask, yh, yl);
    dim3 go(DD / 128, NTOK / 128);
    tgemm3s<<<go, 256, gsm>>>(yh, yl, woh, wol, out, NTOK, DD, XVW);
}

// round 8
// speedup vs baseline: 8.9166x; 1.6618x over previous
#include <cuda_runtime.h>
#include <cuda_bf16.h>
#include <math.h>
#include <stdint.h>

// Problem constants
#define BB 4
#define TT 2048
#define DD 1024
#define HH 8
#define DH 64
#define EE 5
#define NTOK (BB*TT)          // 8192
#define QKW (HH*DH)           // 512
#define GW  (HH*EE)           // 40
#define XVW (EE*DH)           // 320

// fused projection layout (row stride PW2): q[0:512) | k[512:1024) | xv[1024:1344)
#define PW2 1344
#define OFF_K 512
#define OFF_XV 1024

#define NG 128                 // gate GEMM padded width (glv 0..39, glo 40..79)
#define KSPL 4                 // gate GEMM split-K

// bf16 KV fragment blob: per (bh,tile64): [Kh|Kl|Vh|Vl], each 4 k0 x 32 lanes x 20 u32
#define ROWPAD 20
#define ARR2_U32 (4*32*ROWPAD)    // 2560
#define TILE2_U32 (4*ARR2_U32)    // 10240 u32 = 40KB
#define NTILE 32

// ---------------- scratch (device globals) ------------------------------------
__device__ float    g_proj [(size_t)NTOK*PW2];
__device__ __align__(16) uint32_t g_xbh [(size_t)NTOK*DD/2];   // bf16 pairs of x
__device__ __align__(16) uint32_t g_xbl [(size_t)NTOK*DD/2];
__device__ __align__(16) uint32_t g_wth [(size_t)PW2*DD/2];    // Wt[n][dpair] bf16
__device__ __align__(16) uint32_t g_wtl [(size_t)PW2*DD/2];
__device__ __align__(16) uint32_t g_xth [(size_t)NTOK*DD];     // tf32 hi of x (gates)
__device__ __align__(16) uint32_t g_xtl [(size_t)NTOK*DD];
__device__ __align__(16) uint32_t g_gwh [(size_t)DD*NG];       // tf32 gate weights
__device__ __align__(16) uint32_t g_gwl [(size_t)DD*NG];
__device__ float    g_glp  [(size_t)KSPL*NTOK*NG];             // gate partials
__device__ float    g_v    [(size_t)NTOK*QKW];
__device__ float    g_attn [(size_t)NTOK*QKW];
__device__ float    g_mask [(size_t)NTOK*GW];
__device__ __align__(16) uint32_t g_ybh [(size_t)NTOK*XVW/2];
__device__ __align__(16) uint32_t g_ybl [(size_t)NTOK*XVW/2];
__device__ __align__(16) uint32_t g_woth[(size_t)DD*XVW/2];    // WoT[n=d][kpair]
__device__ __align__(16) uint32_t g_wotl[(size_t)DD*XVW/2];
__device__ __align__(16) uint32_t g_blob[(size_t)BB*HH*NTILE*TILE2_U32];  // 42MB

// ---------------- helpers ------------------------------------------------------
__device__ __forceinline__ uint32_t f2tf32(float x) {
    uint32_t r;
    asm("cvt.rna.tf32.f32 %0, %1;" : "=r"(r) : "f"(x));
    return r;
}
__device__ __forceinline__ void split_tf32(float x, uint32_t& h, uint32_t& l) {
    h = f2tf32(x);
    l = f2tf32(x - __uint_as_float(h));
}
// split pair (a,b) into bf16x2 hi and lo words; a -> bits[15:0]
__device__ __forceinline__ void split2(float a, float b, uint32_t& h, uint32_t& l) {
    __nv_bfloat16 ha = __float2bfloat16(a);
    __nv_bfloat16 hb = __float2bfloat16(b);
    float ra = a - __bfloat162float(ha);
    float rb = b - __bfloat162float(hb);
    __nv_bfloat162 hh; hh.x = ha; hh.y = hb;
    __nv_bfloat162 ll; ll.x = __float2bfloat16(ra); ll.y = __float2bfloat16(rb);
    h = *reinterpret_cast<uint32_t*>(&hh);
    l = *reinterpret_cast<uint32_t*>(&ll);
}
__device__ __forceinline__ void mma_tf32(float c[4], const uint32_t a[4], const uint32_t b[2]) {
    asm volatile(
        "mma.sync.aligned.m16n8k8.row.col.f32.tf32.tf32.f32 "
        "{%0,%1,%2,%3},{%4,%5,%6,%7},{%8,%9},{%0,%1,%2,%3};"
        : "+f"(c[0]), "+f"(c[1]), "+f"(c[2]), "+f"(c[3])
        : "r"(a[0]), "r"(a[1]), "r"(a[2]), "r"(a[3]), "r"(b[0]), "r"(b[1]));
}
__device__ __forceinline__ void mma_bf16(float c[4], const uint32_t a[4], const uint32_t b[2]) {
    asm volatile(
        "mma.sync.aligned.m16n8k16.row.col.f32.bf16.bf16.f32 "
        "{%0,%1,%2,%3},{%4,%5,%6,%7},{%8,%9},{%0,%1,%2,%3};"
        : "+f"(c[0]), "+f"(c[1]), "+f"(c[2]), "+f"(c[3])
        : "r"(a[0]), "r"(a[1]), "r"(a[2]), "r"(a[3]), "r"(b[0]), "r"(b[1]));
}
__device__ __forceinline__ void cp16(uint32_t saddr, const void* g) {
    asm volatile("cp.async.cg.shared.global [%0], [%1], 16;\n" :: "r"(saddr), "l"(g));
}
#define CP_COMMIT() asm volatile("cp.async.commit_group;\n")
#define CP_WAIT(n)  asm volatile("cp.async.wait_group %0;\n" :: "n"(n))

// =============== pre-split / pack kernels ======================================
__global__ void split_x_bf16(const float* __restrict__ x,
                             uint32_t* __restrict__ xh, uint32_t* __restrict__ xl) {
    size_t i = (size_t)blockIdx.x * blockDim.x + threadIdx.x;
    if (i >= (size_t)NTOK * DD / 2) return;
    split2(x[2 * i], x[2 * i + 1], xh[i], xl[i]);
}
__global__ void split_x_tf32k(const float* __restrict__ x,
                              uint32_t* __restrict__ xh, uint32_t* __restrict__ xl) {
    size_t i = (size_t)blockIdx.x * blockDim.x + threadIdx.x;
    if (i >= (size_t)NTOK * DD) return;
    split_tf32(x[i], xh[i], xl[i]);
}
__global__ void pack_wt_bf16(const float* __restrict__ Wq, const float* __restrict__ Wk,
                             const float* __restrict__ Wv,
                             uint32_t* __restrict__ Wh, uint32_t* __restrict__ Wl) {
    size_t idx = (size_t)blockIdx.x * blockDim.x + threadIdx.x;
    if (idx >= (size_t)PW2 * DD / 2) return;
    int n = (int)(idx / (DD / 2));
    int dp = (int)(idx % (DD / 2));
    int d0 = 2 * dp;
    float va, vb;
    if (n < 512) {
        va = Wq[(size_t)d0 * 512 + n]; vb = Wq[(size_t)(d0 + 1) * 512 + n];
    } else if (n < 1024) {
        va = Wk[(size_t)d0 * 512 + (n - 512)]; vb = Wk[(size_t)(d0 + 1) * 512 + (n - 512)];
    } else {
        int e = (n - 1024) / DH, j = (n - 1024) % DH;
        va = Wv[((size_t)e * DD + d0) * DH + j];
        vb = Wv[((size_t)e * DD + d0 + 1) * DH + j];
    }
    split2(va, vb, Wh[idx], Wl[idx]);
}
__global__ void pack_gw_tf32(const float* __restrict__ Ws, const float* __restrict__ Wd,
                             uint32_t* __restrict__ Wh, uint32_t* __restrict__ Wl) {
    int idx = blockIdx.x * blockDim.x + threadIdx.x;
    if (idx >= DD * NG) return;
    int d = idx / NG, n = idx % NG;
    float val = 0.f;
    if (n < 40)      val = Ws[(size_t)d * GW + n];
    else if (n < 80) val = Wd[(size_t)d * GW + (n - 40)];
    split_tf32(val, Wh[idx], Wl[idx]);
}
__global__ void pack_wot_bf16(const float* __restrict__ Wo,
                              uint32_t* __restrict__ Wh, uint32_t* __restrict__ Wl) {
    size_t idx = (size_t)blockIdx.x * blockDim.x + threadIdx.x;
    if (idx >= (size_t)DD * XVW / 2) return;
    int n = (int)(idx / (XVW / 2));
    int kp = (int)(idx % (XVW / 2));
    int k0 = 2 * kp;
    int e = k0 >> 6, j = k0 & 63;
    float va = Wo[((size_t)(e * DH + j)) * DD + n];
    float vb = Wo[((size_t)(e * DH + j + 1)) * DD + n];
    split2(va, vb, Wh[idx], Wl[idx]);
}

// =============== bf16x3 GEMM: C=A@Bt^T, BM=128,BN=64,BK=32, 2 CTAs/SM ==========
// A: [M][K/2] u32 bf16-pairs (hi/lo arrays); Bt: [N][K/2] (transposed weights)
#define B3_OFF_AL 2560
#define B3_OFF_BH 5120
#define B3_OFF_BL 6400
#define B3_STG 7680

__global__ __launch_bounds__(256, 2)
void tgemmb3(const uint32_t* __restrict__ Agh, const uint32_t* __restrict__ Agl,
             const uint32_t* __restrict__ Bgh, const uint32_t* __restrict__ Bgl,
             float* __restrict__ C, int M, int N, int K) {
    extern __shared__ uint32_t sm2[];   // 2 stages x B3_STG
    const int tid = threadIdx.x;
    const int row0 = blockIdx.y * 128;
    const int col0 = blockIdx.x * 64;
    const int lane = tid & 31, w = tid >> 5;
    const int g = lane >> 2, t = lane & 3;
    const int wm = w >> 1, wn = w & 1;      // warp tile 32x32
    const int Ku = K / 2;

    const uint32_t sb = (uint32_t)__cvta_generic_to_shared(sm2);

    float c[2][4][4];
#pragma unroll
    for (int mt = 0; mt < 2; mt++)
#pragma unroll
        for (int nt = 0; nt < 4; nt++)
#pragma unroll
            for (int i = 0; i < 4; i++) c[mt][nt][i] = 0.f;

    const int nk = K / 32;

    // stage loader: A 512 chunks x2, B 256 chunks x2 => 6 cp16/thread
#define B3_LOAD(dst, kt)                                                          \
    {                                                                             \
        int ko = (kt) * 16;                                                       \
        _Pragma("unroll")                                                         \
        for (int it = 0; it < 2; it++) {                                          \
            int idx = it * 256 + tid;                                             \
            int r = idx >> 2, cc = idx & 3;                                       \
            cp16((dst) + (uint32_t)(r * ROWPAD + cc * 4) * 4,                     \
                 Agh + (size_t)(row0 + r) * Ku + ko + cc * 4);                    \
            cp16((dst) + (uint32_t)(B3_OFF_AL + r * ROWPAD + cc * 4) * 4,         \
                 Agl + (size_t)(row0 + r) * Ku + ko + cc * 4);                    \
        }                                                                         \
        {                                                                         \
            int r = tid >> 2, cc = tid & 3;                                       \
            cp16((dst) + (uint32_t)(B3_OFF_BH + r * ROWPAD + cc * 4) * 4,         \
                 Bgh + (size_t)(col0 + r) * Ku + ko + cc * 4);                    \
            cp16((dst) + (uint32_t)(B3_OFF_BL + r * ROWPAD + cc * 4) * 4,         \
                 Bgl + (size_t)(col0 + r) * Ku + ko + cc * 4);                    \
        }                                                                         \
    }

    B3_LOAD(sb, 0);
    CP_COMMIT();

    for (int kt = 0; kt < nk; kt++) {
        const int st = kt & 1;
        if (kt + 1 < nk) {
            uint32_t d2 = sb + (uint32_t)((st ^ 1) * B3_STG) * 4;
            B3_LOAD(d2, kt + 1);
            CP_COMMIT();
            CP_WAIT(1);
        } else {
            CP_WAIT(0);
        }
        __syncthreads();

        const uint32_t* Ah = sm2 + st * B3_STG;
        const uint32_t* Al = Ah + B3_OFF_AL;
        const uint32_t* Bh = Ah + B3_OFF_BH;
        const uint32_t* Bl = Ah + B3_OFF_BL;

#pragma unroll
        for (int kc = 0; kc < 2; kc++) {
            uint32_t afh[2][4], afl[2][4], bfh[4][2], bfl[4][2];
#pragma unroll
            for (int mt = 0; mt < 2; mt++) {
                int rb = wm * 32 + mt * 16;
                afh[mt][0] = Ah[(rb + g    ) * ROWPAD + kc * 8 + t];
                afh[mt][1] = Ah[(rb + g + 8) * ROWPAD + kc * 8 + t];
                afh[mt][2] = Ah[(rb + g    ) * ROWPAD + kc * 8 + t + 4];
                afh[mt][3] = Ah[(rb + g + 8) * ROWPAD + kc * 8 + t + 4];
                afl[mt][0] = Al[(rb + g    ) * ROWPAD + kc * 8 + t];
                afl[mt][1] = Al[(rb + g + 8) * ROWPAD + kc * 8 + t];
                afl[mt][2] = Al[(rb + g    ) * ROWPAD + kc * 8 + t + 4];
                afl[mt][3] = Al[(rb + g + 8) * ROWPAD + kc * 8 + t + 4];
            }
#pragma unroll
            for (int nt = 0; nt < 4; nt++) {
                int cb = wn * 32 + nt * 8;
                bfh[nt][0] = Bh[(cb + g) * ROWPAD + kc * 8 + t];
                bfh[nt][1] = Bh[(cb + g) * ROWPAD + kc * 8 + t + 4];
                bfl[nt][0] = Bl[(cb + g) * ROWPAD + kc * 8 + t];
                bfl[nt][1] = Bl[(cb + g) * ROWPAD + kc * 8 + t + 4];
            }
#pragma unroll
            for (int mt = 0; mt < 2; mt++)
#pragma unroll
                for (int nt = 0; nt < 4; nt++) {
                    mma_bf16(c[mt][nt], afh[mt], bfl[nt]);
                    mma_bf16(c[mt][nt], afl[mt], bfh[nt]);
                    mma_bf16(c[mt][nt], afh[mt], bfh[nt]);
                }
        }
        __syncthreads();
    }

#pragma unroll
    for (int mt = 0; mt < 2; mt++) {
        int r0 = row0 + wm * 32 + mt * 16;
#pragma unroll
        for (int nt = 0; nt < 4; nt++) {
            int cc = col0 + wn * 32 + nt * 8 + 2 * t;
            *(float2*)&C[(size_t)(r0 + g    ) * N + cc] = make_float2(c[mt][nt][0], c[mt][nt][1]);
            *(float2*)&C[(size_t)(r0 + g + 8) * N + cc] = make_float2(c[mt][nt][2], c[mt][nt][3]);
        }
    }
}

// =============== 3xTF32 GEMM (gates only), split-K via gridDim.z ===============
#define SA 36
#define SB 136
#define OFF_AL3 4608
#define OFF_BH3 9216
#define OFF_BL3 13568
#define STG3 17920

__device__ __forceinline__ void gemm3_stage_load(
    uint32_t dst, const uint32_t* __restrict__ Agh, const uint32_t* __restrict__ Agl,
    const uint32_t* __restrict__ Bgh, const uint32_t* __restrict__ Bgl,
    int row0, int col0, int k0, int K, int N, int tid) {
#pragma unroll
    for (int it = 0; it < 4; it++) {
        int idx = it * 1024 + tid * 4;
        int ar = idx >> 5, ac = idx & 31;
        cp16(dst + (uint32_t)(ar * SA + ac) * 4, Agh + (size_t)(row0 + ar) * K + k0 + ac);
        cp16(dst + (uint32_t)(OFF_AL3 + ar * SA + ac) * 4, Agl + (size_t)(row0 + ar) * K + k0 + ac);
        int br = idx >> 7, bc = idx & 127;
        cp16(dst + (uint32_t)(OFF_BH3 + br * SB + bc) * 4, Bgh + (size_t)(k0 + br) * N + col0 + bc);
        cp16(dst + (uint32_t)(OFF_BL3 + br * SB + bc) * 4, Bgl + (size_t)(k0 + br) * N + col0 + bc);
    }
}

__global__ __launch_bounds__(256)
void tgemm3s(const uint32_t* __restrict__ Agh, const uint32_t* __restrict__ Agl,
             const uint32_t* __restrict__ Bgh, const uint32_t* __restrict__ Bgl,
             float* __restrict__ C, int M, int N, int K) {
    extern __shared__ uint32_t sm[];
    const int tid = threadIdx.x;
    const int row0 = blockIdx.y * 128;
    const int col0 = blockIdx.x * 128;
    const int lane = tid & 31, w = tid >> 5;
    const int g = lane >> 2, t = lane & 3;
    const int wm = w >> 1, wn = w & 1;
    const int ksplit = gridDim.z;
    const int kb = blockIdx.z * (K / ksplit);
    const int nk = K / 32 / ksplit;
    float* Cz = C + (size_t)blockIdx.z * M * N;

    const uint32_t sb = (uint32_t)__cvta_generic_to_shared(sm);

    float c[2][8][4];
#pragma unroll
    for (int mt = 0; mt < 2; mt++)
#pragma unroll
        for (int nt = 0; nt < 8; nt++)
#pragma unroll
            for (int i = 0; i < 4; i++) c[mt][nt][i] = 0.f;

    gemm3_stage_load(sb, Agh, Agl, Bgh, Bgl, row0, col0, kb, K, N, tid);
    CP_COMMIT();

    for (int kt = 0; kt < nk; kt++) {
        const int st = kt & 1;
        if (kt + 1 < nk) {
            uint32_t d2 = sb + (uint32_t)((st ^ 1) * STG3) * 4;
            gemm3_stage_load(d2, Agh, Agl, Bgh, Bgl, row0, col0, kb + (kt + 1) * 32, K, N, tid);
            CP_COMMIT();
            CP_WAIT(1);
        } else {
            CP_WAIT(0);
        }
        __syncthreads();

        const uint32_t* Ah = sm + st * STG3;
        const uint32_t* Al = Ah + OFF_AL3;
        const uint32_t* Bh = Ah + OFF_BH3;
        const uint32_t* Bl = Ah + OFF_BL3;

#pragma unroll
        for (int kc = 0; kc < 4; kc++) {
            uint32_t afh[2][4], afl[2][4], bfh[8][2], bfl[8][2];
#pragma unroll
            for (int mt = 0; mt < 2; mt++) {
                int rb = wm * 32 + mt * 16;
                afh[mt][0] = Ah[(rb + g    ) * SA + kc * 8 + t];
                afh[mt][1] = Ah[(rb + g + 8) * SA + kc * 8 + t];
                afh[mt][2] = Ah[(rb + g    ) * SA + kc * 8 + t + 4];
                afh[mt][3] = Ah[(rb + g + 8) * SA + kc * 8 + t + 4];
                afl[mt][0] = Al[(rb + g    ) * SA + kc * 8 + t];
                afl[mt][1] = Al[(rb + g + 8) * SA + kc * 8 + t];
                afl[mt][2] = Al[(rb + g    ) * SA + kc * 8 + t + 4];
                afl[mt][3] = Al[(rb + g + 8) * SA + kc * 8 + t + 4];
            }
#pragma unroll
            for (int nt = 0; nt < 8; nt++) {
                int cb = wn * 64 + nt * 8;
                bfh[nt][0] = Bh[(kc * 8 + t    ) * SB + cb + g];
                bfh[nt][1] = Bh[(kc * 8 + t + 4) * SB + cb + g];
                bfl[nt][0] = Bl[(kc * 8 + t    ) * SB + cb + g];
                bfl[nt][1] = Bl[(kc * 8 + t + 4) * SB + cb + g];
            }
#pragma unroll
            for (int mt = 0; mt < 2; mt++)
#pragma unroll
                for (int nt = 0; nt < 8; nt++) {
                    mma_tf32(c[mt][nt], afh[mt], bfl[nt]);
                    mma_tf32(c[mt][nt], afl[mt], bfh[nt]);
                    mma_tf32(c[mt][nt], afh[mt], bfh[nt]);
                }
        }
        __syncthreads();
    }

#pragma unroll
    for (int mt = 0; mt < 2; mt++) {
        int r0 = row0 + wm * 32 + mt * 16;
#pragma unroll
        for (int nt = 0; nt < 8; nt++) {
            int cc = col0 + wn * 64 + nt * 8 + 2 * t;
            *(float2*)&Cz[(size_t)(r0 + g    ) * N + cc] = make_float2(c[mt][nt][0], c[mt][nt][1]);
            *(float2*)&Cz[(size_t)(r0 + g + 8) * N + cc] = make_float2(c[mt][nt][2], c[mt][nt][3]);
        }
    }
}

// -------- gating: sum split-K partials, top-2, V combine, out mask -------------
__global__ void gate_combine_kernel(const float* __restrict__ glp,
                                    const float* __restrict__ proj,
                                    float* __restrict__ v,
                                    float* __restrict__ masko) {
    int token = blockIdx.x;
    int w = threadIdx.x / 32;
    int lane = threadIdx.x % 32;

    float g[EE];
#pragma unroll
    for (int e = 0; e < EE; e++) {
        float s = 0.f;
#pragma unroll
        for (int z = 0; z < KSPL; z++)
            s += glp[((size_t)z * NTOK + token) * NG + w * EE + e];
        g[e] = s;
    }
    int i1 = 0;
#pragma unroll
    for (int e = 1; e < EE; e++) if (g[e] > g[i1]) i1 = e;
    int i2 = (i1 == 0) ? 1 : 0;
#pragma unroll
    for (int e = 0; e < EE; e++) if (e != i1 && g[e] > g[i2]) i2 = e;
    float w1 = 1.f / (1.f + __expf(-g[i1]));
    float w2 = 1.f / (1.f + __expf(-g[i2]));

    const float* xvt = proj + (size_t)token * PW2 + OFF_XV;
    float* vt = v + (size_t)token * QKW + w * DH;
#pragma unroll
    for (int d = lane; d < DH; d += 32)
        vt[d] = w1 * xvt[i1 * DH + d] + w2 * xvt[i2 * DH + d];

#pragma unroll
    for (int e = 0; e < EE; e++) {
        float s = 0.f;
#pragma unroll
        for (int z = 0; z < KSPL; z++)
            s += glp[((size_t)z * NTOK + token) * NG + 40 + w * EE + e];
        g[e] = s;
    }
    int o1 = 0;
#pragma unroll
    for (int e = 1; e < EE; e++) if (g[e] > g[o1]) o1 = e;
    int o2 = (o1 == 0) ? 1 : 0;
#pragma unroll
    for (int e = 0; e < EE; e++) if (e != o1 && g[e] > g[o2]) o2 = e;
    if (lane < EE)
        masko[((size_t)token * HH + w) * EE + lane] = (lane == o1 || lane == o2) ? 1.f : 0.f;
}

// =============== build bf16 K/V fragment blob ==================================
// K slot (row=k0*32+lane, col=n0*2+w2): {K[key=n0*8+g][d=k0*16+w2*8+2t], [d+1]}
// V slot: {V[key=k0*16+w2*8+2t][d=n0*8+g], V[key+1][d]}
__global__ void build_kv2_kernel(const float* __restrict__ proj,
                                 const float* __restrict__ v,
                                 uint32_t* __restrict__ blob) {
    __shared__ float Ks[64 * 68];
    __shared__ float Vs[64 * 68];
    const int tile = blockIdx.x, bh = blockIdx.y;
    const int b = bh / HH, h = bh % HH;
    const int tid = threadIdx.x;

#pragma unroll
    for (int it = 0; it < 4; it++) {
        int idx = it * 256 + tid;
        int r = (idx * 4) >> 6, d = (idx * 4) & 63;
        const float* kb = proj + (size_t)(b * TT + tile * 64 + r) * PW2 + OFF_K + h * DH;
        const float* vb = v    + (size_t)(b * TT + tile * 64 + r) * QKW + h * DH;
        *(float4*)&Ks[r * 68 + d] = *(const float4*)(kb + d);
        *(float4*)&Vs[r * 68 + d] = *(const float4*)(vb + d);
    }
    __syncthreads();

    uint32_t* dst = blob + ((size_t)bh * NTILE + tile) * TILE2_U32;
#pragma unroll
    for (int i = 0; i < 8; i++) {
        int oi = tid * 8 + i;            // 0..2047
        int row = oi >> 4;               // k0*32 + lane
        int col = oi & 15;               // n0*2 + w2
        int k0 = row >> 5, lane2 = row & 31;
        int g2 = lane2 >> 2, t2 = lane2 & 3;
        int n0 = col >> 1, w2 = col & 1;
        uint32_t hi, lo;
        // K
        int dK = k0 * 16 + w2 * 8 + 2 * t2;
        int keyK = n0 * 8 + g2;
        split2(Ks[keyK * 68 + dK], Ks[keyK * 68 + dK + 1], hi, lo);
        dst[row * ROWPAD + col] = hi;
        dst[ARR2_U32 + row * ROWPAD + col] = lo;
        // V
        int keyV = k0 * 16 + w2 * 8 + 2 * t2;
        int dV = n0 * 8 + g2;
        split2(Vs[keyV * 68 + dV], Vs[(keyV + 1) * 68 + dV], hi, lo);
        dst[2 * ARR2_U32 + row * ROWPAD + col] = hi;
        dst[3 * ARR2_U32 + row * ROWPAD + col] = lo;
    }
}

// =============== flash attention, bf16x3, fragment blob + cp.async =============
#define LOG2E 1.4426950408889634f

__global__ __launch_bounds__(256, 2)
void attn3_kernel(const float* __restrict__ qg,
                  const uint32_t* __restrict__ blob,
                  float* __restrict__ o) {
    extern __shared__ uint32_t sh[];     // 2 stages x TILE2_U32
    const int bh = blockIdx.y;
    const int b = bh / HH, h = bh % HH;
    const int q0 = blockIdx.x * 128;
    const int tid = threadIdx.x;
    const int lane = tid & 31, w = tid >> 5;
    const int g = lane >> 2, t = lane & 3;
    const float scale = 0.125f;

    const uint32_t* gblob = blob + (size_t)bh * NTILE * TILE2_U32;
    const uint32_t sbase = (uint32_t)__cvta_generic_to_shared(sh);

    // DMA tile 0 (2560 chunks / 256 threads = 10)
#pragma unroll
    for (int i = 0; i < 10; i++) {
        int cc = tid + i * 256;
        cp16(sbase + cc * 16, gblob + cc * 4);
    }
    CP_COMMIT();

    // Q fragments bf16 hi/lo, scale folded (exact pow2)
    const float* qb = qg + (size_t)(b * TT + q0 + w * 16) * PW2 + h * DH;
    uint32_t qah[4][4], qal[4][4];
#pragma unroll
    for (int k0 = 0; k0 < 4; k0++) {
        split2(scale * qb[(size_t)(g    ) * PW2 + k0 * 16 + 2 * t],
               scale * qb[(size_t)(g    ) * PW2 + k0 * 16 + 2 * t + 1], qah[k0][0], qal[k0][0]);
        split2(scale * qb[(size_t)(g + 8) * PW2 + k0 * 16 + 2 * t],
               scale * qb[(size_t)(g + 8) * PW2 + k0 * 16 + 2 * t + 1], qah[k0][1], qal[k0][1]);
        split2(scale * qb[(size_t)(g    ) * PW2 + k0 * 16 + 2 * t + 8],
               scale * qb[(size_t)(g    ) * PW2 + k0 * 16 + 2 * t + 9], qah[k0][2], qal[k0][2]);
        split2(scale * qb[(size_t)(g + 8) * PW2 + k0 * 16 + 2 * t + 8],
               scale * qb[(size_t)(g + 8) * PW2 + k0 * 16 + 2 * t + 9], qah[k0][3], qal[k0][3]);
    }

    float om[8][4];
#pragma unroll
    for (int n = 0; n < 8; n++)
#pragma unroll
        for (int i = 0; i < 4; i++) om[n][i] = 0.f;
    float rm0 = -INFINITY, rm1 = -INFINITY, rl0 = 0.f, rl1 = 0.f;

    for (int tt = 0; tt < NTILE; tt++) {
        const int st = tt & 1;
        if (tt + 1 < NTILE) {
            const uint32_t* src = gblob + (size_t)(tt + 1) * TILE2_U32;
            uint32_t dst = sbase + (uint32_t)((st ^ 1) * TILE2_U32) * 4;
#pragma unroll
            for (int i = 0; i < 10; i++) {
                int cc = tid + i * 256;
                cp16(dst + cc * 16, src + cc * 4);
            }
            CP_COMMIT();
            CP_WAIT(1);
        } else {
            CP_WAIT(0);
        }
        __syncthreads();

        const uint32_t* Kh = sh + st * TILE2_U32;
        const uint32_t* Kl = Kh + ARR2_U32;
        const uint32_t* Vh = Kh + 2 * ARR2_U32;
        const uint32_t* Vl = Kh + 3 * ARR2_U32;

        // ---- S = Qs @ K^T (bf16x3) -------------------------------------------
        float s[8][4];
#pragma unroll
        for (int n = 0; n < 8; n++)
#pragma unroll
            for (int i = 0; i < 4; i++) s[n][i] = 0.f;
#pragma unroll
        for (int k0 = 0; k0 < 4; k0++) {
            const uint32_t* kr = Kh + (k0 * 32 + lane) * ROWPAD;
            const uint32_t* lr = Kl + (k0 * 32 + lane) * ROWPAD;
#pragma unroll
            for (int np = 0; np < 4; np++) {
                uint4 kh4 = *(const uint4*)(kr + np * 4);
                uint4 kl4 = *(const uint4*)(lr + np * 4);
                uint32_t bh2[2] = {kh4.x, kh4.y};
                uint32_t bl2[2] = {kl4.x, kl4.y};
                mma_bf16(s[2 * np], qah[k0], bl2);
                mma_bf16(s[2 * np], qal[k0], bh2);
                mma_bf16(s[2 * np], qah[k0], bh2);
                uint32_t bh3[2] = {kh4.z, kh4.w};
                uint32_t bl3[2] = {kl4.z, kl4.w};
                mma_bf16(s[2 * np + 1], qah[k0], bl3);
                mma_bf16(s[2 * np + 1], qal[k0], bh3);
                mma_bf16(s[2 * np + 1], qah[k0], bh3);
            }
        }

        // ---- online softmax ----------------------------------------------------
        float m0 = s[0][0], m1 = s[0][2];
#pragma unroll
        for (int n = 0; n < 8; n++) {
            m0 = fmaxf(m0, fmaxf(s[n][0], s[n][1]));
            m1 = fmaxf(m1, fmaxf(s[n][2], s[n][3]));
        }
        m0 = fmaxf(m0, __shfl_xor_sync(0xffffffff, m0, 1));
        m0 = fmaxf(m0, __shfl_xor_sync(0xffffffff, m0, 2));
        m1 = fmaxf(m1, __shfl_xor_sync(0xffffffff, m1, 1));
        m1 = fmaxf(m1, __shfl_xor_sync(0xffffffff, m1, 2));

        float mn0 = fmaxf(rm0, m0);
        float mn1 = fmaxf(rm1, m1);
        float corr0 = exp2f((rm0 - mn0) * LOG2E);
        float corr1 = exp2f((rm1 - mn1) * LOG2E);

        float sum0 = 0.f, sum1 = 0.f;
#pragma unroll
        for (int n = 0; n < 8; n++) {
            s[n][0] = exp2f((s[n][0] - mn0) * LOG2E);
            s[n][1] = exp2f((s[n][1] - mn0) * LOG2E);
            s[n][2] = exp2f((s[n][2] - mn1) * LOG2E);
            s[n][3] = exp2f((s[n][3] - mn1) * LOG2E);
            sum0 += s[n][0] + s[n][1];
            sum1 += s[n][2] + s[n][3];
        }
        sum0 += __shfl_xor_sync(0xffffffff, sum0, 1);
        sum0 += __shfl_xor_sync(0xffffffff, sum0, 2);
        sum1 += __shfl_xor_sync(0xffffffff, sum1, 1);
        sum1 += __shfl_xor_sync(0xffffffff, sum1, 2);
        rl0 = rl0 * corr0 + sum0;
        rl1 = rl1 * corr1 + sum1;
        rm0 = mn0; rm1 = mn1;

#pragma unroll
        for (int n = 0; n < 8; n++) {
            om[n][0] *= corr0; om[n][1] *= corr0;
            om[n][2] *= corr1; om[n][3] *= corr1;
        }

        // ---- O += P @ V (bf16x3); P A-frag built locally (no shuffles) --------
#pragma unroll
        for (int k0 = 0; k0 < 4; k0++) {
            uint32_t ph[4], pl[4];
            split2(s[2 * k0][0],     s[2 * k0][1],     ph[0], pl[0]);
            split2(s[2 * k0][2],     s[2 * k0][3],     ph[1], pl[1]);
            split2(s[2 * k0 + 1][0], s[2 * k0 + 1][1], ph[2], pl[2]);
            split2(s[2 * k0 + 1][2], s[2 * k0 + 1][3], ph[3], pl[3]);
            const uint32_t* vr = Vh + (k0 * 32 + lane) * ROWPAD;
            const uint32_t* wr = Vl + (k0 * 32 + lane) * ROWPAD;
#pragma unroll
            for (int np = 0; np < 4; np++) {
                uint4 vh4 = *(const uint4*)(vr + np * 4);
                uint4 vl4 = *(const uint4*)(wr + np * 4);
                uint32_t bh2[2] = {vh4.x, vh4.y};
                uint32_t bl2[2] = {vl4.x, vl4.y};
                mma_bf16(om[2 * np], ph, bl2);
                mma_bf16(om[2 * np], pl, bh2);
                mma_bf16(om[2 * np], ph, bh2);
                uint32_t bh3[2] = {vh4.z, vh4.w};
                uint32_t bl3[2] = {vl4.z, vl4.w};
                mma_bf16(om[2 * np + 1], ph, bl3);
                mma_bf16(om[2 * np + 1], pl, bh3);
                mma_bf16(om[2 * np + 1], ph, bh3);
            }
        }
        __syncthreads();
    }

    float inv0 = 1.f / rl0;
    float inv1 = 1.f / rl1;
    float* ob0 = o + (size_t)(b * TT + q0 + w * 16 + g    ) * QKW + h * DH + 2 * t;
    float* ob1 = o + (size_t)(b * TT + q0 + w * 16 + g + 8) * QKW + h * DH + 2 * t;
#pragma unroll
    for (int n0 = 0; n0 < 8; n0++) {
        *(float2*)(ob0 + n0 * 8) = make_float2(om[n0][0] * inv0, om[n0][1] * inv0);
        *(float2*)(ob1 + n0 * 8) = make_float2(om[n0][2] * inv1, om[n0][3] * inv1);
    }
}

// -------- Y pairs: Y[t, 2i..2i+1] = sum_h mask*attn, split to bf16 hi/lo -------
__global__ void combine_out_kernel(const float* __restrict__ attn,
                                   const float* __restrict__ masko,
                                   uint32_t* __restrict__ Yh,
                                   uint32_t* __restrict__ Yl) {
    int token = blockIdx.x;
    int tid = threadIdx.x;          // 0..159
    int t0 = 2 * tid;
    int e = t0 >> 6, j = t0 & 63;
    const float* ap = attn + (size_t)token * QKW;
    const float* mp = masko + (size_t)token * GW;
    float s0 = 0.f, s1 = 0.f;
#pragma unroll
    for (int h = 0; h < HH; h++) {
        float m = mp[h * EE + e];
        s0 += m * ap[h * DH + j];
        s1 += m * ap[h * DH + j + 1];
    }
    uint32_t hi, lo;
    split2(s0, s1, hi, lo);
    Yh[(size_t)token * (XVW / 2) + tid] = hi;
    Yl[(size_t)token * (XVW / 2) + tid] = lo;
}

// ------------------------------- launch ----------------------------------------
extern "C" void kernel_launch(void* const* d_in, const int* in_sizes, int n_in,
                              void* d_out, int out_size) {
    const float* x  = (const float*)d_in[0];
    const float* Wq = (const float*)d_in[1];
    const float* Wk = (const float*)d_in[2];
    const float* Ws = (const float*)d_in[3];
    const float* Wd = (const float*)d_in[4];
    const float* Wv = (const float*)d_in[5];
    const float* Wo = (const float*)d_in[6];
    float* out = (float*)d_out;

    float *proj, *glp, *v, *attn, *mask;
    uint32_t *xbh, *xbl, *wth, *wtl, *xth, *xtl, *gwh, *gwl, *ybh, *ybl, *woth, *wotl, *blob;
    cudaGetSymbolAddress((void**)&proj, g_proj);
    cudaGetSymbolAddress((void**)&xbh,  g_xbh);
    cudaGetSymbolAddress((void**)&xbl,  g_xbl);
    cudaGetSymbolAddress((void**)&wth,  g_wth);
    cudaGetSymbolAddress((void**)&wtl,  g_wtl);
    cudaGetSymbolAddress((void**)&xth,  g_xth);
    cudaGetSymbolAddress((void**)&xtl,  g_xtl);
    cudaGetSymbolAddress((void**)&gwh,  g_gwh);
    cudaGetSymbolAddress((void**)&gwl,  g_gwl);
    cudaGetSymbolAddress((void**)&glp,  g_glp);
    cudaGetSymbolAddress((void**)&v,    g_v);
    cudaGetSymbolAddress((void**)&attn, g_attn);
    cudaGetSymbolAddress((void**)&mask, g_mask);
    cudaGetSymbolAddress((void**)&ybh,  g_ybh);
    cudaGetSymbolAddress((void**)&ybl,  g_ybl);
    cudaGetSymbolAddress((void**)&woth, g_woth);
    cudaGetSymbolAddress((void**)&wotl, g_wotl);
    cudaGetSymbolAddress((void**)&blob, g_blob);

    // pre-splits / packs
    split_x_bf16 <<<(int)(((size_t)NTOK * DD / 2 + 255) / 256), 256>>>(x, xbh, xbl);
    split_x_tf32k<<<(int)(((size_t)NTOK * DD + 255) / 256), 256>>>(x, xth, xtl);
    pack_wt_bf16 <<<(int)(((size_t)PW2 * DD / 2 + 255) / 256), 256>>>(Wq, Wk, Wv, wth, wtl);
    pack_gw_tf32 <<<(DD * NG + 255) / 256, 256>>>(Ws, Wd, gwh, gwl);
    pack_wot_bf16<<<(int)(((size_t)DD * XVW / 2 + 255) / 256), 256>>>(Wo, woth, wotl);

    // proj GEMM (bf16x3): (8192x1024)@(1024x1344)
    size_t bsm = (size_t)2 * B3_STG * sizeof(uint32_t);   // 61440
    cudaFuncSetAttribute(tgemmb3, cudaFuncAttributeMaxDynamicSharedMemorySize, (int)bsm);
    dim3 gp(PW2 / 64, NTOK / 128);
    tgemmb3<<<gp, 256, bsm>>>(xbh, xbl, wth, wtl, proj, NTOK, PW2, DD);

    // gate GEMM (3xTF32, split-K=4): (8192x1024)@(1024x128) -> partials
    size_t gsm = (size_t)2 * STG3 * sizeof(uint32_t);     // 143360
    cudaFuncSetAttribute(tgemm3s, cudaFuncAttributeMaxDynamicSharedMemorySize, (int)gsm);
    dim3 gg(NG / 128, NTOK / 128, KSPL);
    tgemm3s<<<gg, 256, gsm>>>(xth, xtl, gwh, gwl, glp, NTOK, NG, DD);

    // gating + V combine + out-mask
    gate_combine_kernel<<<NTOK, 256>>>(glp, proj, v, mask);

    // K/V fragment blob (bf16)
    dim3 bg(NTILE, BB * HH);
    build_kv2_kernel<<<bg, 256>>>(proj, v, blob);

    // attention
    size_t asmem = (size_t)2 * TILE2_U32 * sizeof(uint32_t);  // 81920
    cudaFuncSetAttribute(attn3_kernel, cudaFuncAttributeMaxDynamicSharedMemorySize, (int)asmem);
    dim3 ag(TT / 128, BB * HH);
    attn3_kernel<<<ag, 256, asmem>>>(proj, blob, attn);

    // masked combine (+bf16 split), then output GEMM: (8192x320)@(320x1024)
    combine_out_kernel<<<NTOK, XVW / 2>>>(attn, mask, ybh, ybl);
    dim3 go(DD / 64, NTOK / 128);
    tgemmb3<<<go, 256, bsm>>>(ybh, ybl, woth, wotl, out, NTOK, DD, XVW);
}

// round 9
// speedup vs baseline: 9.0728x; 1.0175x over previous
#include <cuda_runtime.h>
#include <cuda_bf16.h>
#include <math.h>
#include <stdint.h>

// Problem constants
#define BB 4
#define TT 2048
#define DD 1024
#define HH 8
#define DH 64
#define EE 5
#define NTOK (BB*TT)          // 8192
#define QKW (HH*DH)           // 512
#define GW  (HH*EE)           // 40
#define XVW (EE*DH)           // 320

// fused projection layout (row stride PW2): q[0:512) | k[512:1024) | xv[1024:1344)
#define PW2 1344
#define OFF_K 512
#define OFF_XV 1024

#define NG 128                 // gate GEMM padded width (glv 0..39, glo 40..79)
#define KSPL 4                 // gate GEMM split-K

// bf16 KV fragment blob: per (bh,tile64): [Kh|Kl|Vh|Vl], each 4 k0 x 32 lanes x 20 u32
#define ROWPAD 20
#define ARR2_U32 (4*32*ROWPAD)    // 2560
#define TILE2_U32 (4*ARR2_U32)    // 10240 u32 = 40KB
#define NTILE 32

// ---------------- scratch (device globals) ------------------------------------
__device__ float    g_proj [(size_t)NTOK*PW2];
__device__ __align__(16) uint32_t g_xbh [(size_t)NTOK*DD/2];   // bf16 pairs of x
__device__ __align__(16) uint32_t g_xbl [(size_t)NTOK*DD/2];
__device__ __align__(16) uint32_t g_wth [(size_t)PW2*DD/2];    // Wt[n][dpair] bf16
__device__ __align__(16) uint32_t g_wtl [(size_t)PW2*DD/2];
__device__ __align__(16) uint32_t g_xth [(size_t)NTOK*DD];     // tf32 hi of x (gates)
__device__ __align__(16) uint32_t g_xtl [(size_t)NTOK*DD];
__device__ __align__(16) uint32_t g_gwh [(size_t)DD*NG];       // tf32 gate weights
__device__ __align__(16) uint32_t g_gwl [(size_t)DD*NG];
__device__ float    g_glp  [(size_t)KSPL*NTOK*NG];             // gate partials
__device__ float    g_v    [(size_t)NTOK*QKW];
__device__ float    g_attn [(size_t)NTOK*QKW];
__device__ float    g_mask [(size_t)NTOK*GW];
__device__ __align__(16) uint32_t g_ybh [(size_t)NTOK*XVW/2];
__device__ __align__(16) uint32_t g_ybl [(size_t)NTOK*XVW/2];
__device__ __align__(16) uint32_t g_woth[(size_t)DD*XVW/2];    // WoT[n=d][kpair]
__device__ __align__(16) uint32_t g_wotl[(size_t)DD*XVW/2];
__device__ __align__(16) uint32_t g_blob[(size_t)BB*HH*NTILE*TILE2_U32];  // 42MB

// ---------------- helpers ------------------------------------------------------
__device__ __forceinline__ uint32_t f2tf32(float x) {
    uint32_t r;
    asm("cvt.rna.tf32.f32 %0, %1;" : "=r"(r) : "f"(x));
    return r;
}
__device__ __forceinline__ void split_tf32(float x, uint32_t& h, uint32_t& l) {
    h = f2tf32(x);
    l = f2tf32(x - __uint_as_float(h));
}
// split pair (a,b) into bf16x2 hi and lo words; a -> bits[15:0]
__device__ __forceinline__ void split2(float a, float b, uint32_t& h, uint32_t& l) {
    __nv_bfloat16 ha = __float2bfloat16(a);
    __nv_bfloat16 hb = __float2bfloat16(b);
    float ra = a - __bfloat162float(ha);
    float rb = b - __bfloat162float(hb);
    __nv_bfloat162 hh; hh.x = ha; hh.y = hb;
    __nv_bfloat162 ll; ll.x = __float2bfloat16(ra); ll.y = __float2bfloat16(rb);
    h = *reinterpret_cast<uint32_t*>(&hh);
    l = *reinterpret_cast<uint32_t*>(&ll);
}
__device__ __forceinline__ void mma_tf32(float c[4], const uint32_t a[4], const uint32_t b[2]) {
    asm volatile(
        "mma.sync.aligned.m16n8k8.row.col.f32.tf32.tf32.f32 "
        "{%0,%1,%2,%3},{%4,%5,%6,%7},{%8,%9},{%0,%1,%2,%3};"
        : "+f"(c[0]), "+f"(c[1]), "+f"(c[2]), "+f"(c[3])
        : "r"(a[0]), "r"(a[1]), "r"(a[2]), "r"(a[3]), "r"(b[0]), "r"(b[1]));
}
__device__ __forceinline__ void mma_bf16(float c[4], const uint32_t a[4], const uint32_t b[2]) {
    asm volatile(
        "mma.sync.aligned.m16n8k16.row.col.f32.bf16.bf16.f32 "
        "{%0,%1,%2,%3},{%4,%5,%6,%7},{%8,%9},{%0,%1,%2,%3};"
        : "+f"(c[0]), "+f"(c[1]), "+f"(c[2]), "+f"(c[3])
        : "r"(a[0]), "r"(a[1]), "r"(a[2]), "r"(a[3]), "r"(b[0]), "r"(b[1]));
}
__device__ __forceinline__ void cp16(uint32_t saddr, const void* g) {
    asm volatile("cp.async.cg.shared.global [%0], [%1], 16;\n" :: "r"(saddr), "l"(g));
}
#define CP_COMMIT() asm volatile("cp.async.commit_group;\n")
#define CP_WAIT(n)  asm volatile("cp.async.wait_group %0;\n" :: "n"(n))

// =============== pre-split / pack kernels ======================================
// fused: one read of x produces bf16 hi/lo pairs AND tf32 hi/lo
__global__ void split_x_all(const float* __restrict__ x,
                            uint32_t* __restrict__ xbh, uint32_t* __restrict__ xbl,
                            uint32_t* __restrict__ xth, uint32_t* __restrict__ xtl) {
    size_t i = (size_t)blockIdx.x * blockDim.x + threadIdx.x;
    if (i >= (size_t)NTOK * DD / 2) return;
    float a = x[2 * i], b = x[2 * i + 1];
    split2(a, b, xbh[i], xbl[i]);
    split_tf32(a, xth[2 * i], xtl[2 * i]);
    split_tf32(b, xth[2 * i + 1], xtl[2 * i + 1]);
}
__global__ void pack_wt_bf16(const float* __restrict__ Wq, const float* __restrict__ Wk,
                             const float* __restrict__ Wv,
                             uint32_t* __restrict__ Wh, uint32_t* __restrict__ Wl) {
    size_t idx = (size_t)blockIdx.x * blockDim.x + threadIdx.x;
    if (idx >= (size_t)PW2 * DD / 2) return;
    int n = (int)(idx / (DD / 2));
    int dp = (int)(idx % (DD / 2));
    int d0 = 2 * dp;
    float va, vb;
    if (n < 512) {
        va = Wq[(size_t)d0 * 512 + n]; vb = Wq[(size_t)(d0 + 1) * 512 + n];
    } else if (n < 1024) {
        va = Wk[(size_t)d0 * 512 + (n - 512)]; vb = Wk[(size_t)(d0 + 1) * 512 + (n - 512)];
    } else {
        int e = (n - 1024) / DH, j = (n - 1024) % DH;
        va = Wv[((size_t)e * DD + d0) * DH + j];
        vb = Wv[((size_t)e * DD + d0 + 1) * DH + j];
    }
    split2(va, vb, Wh[idx], Wl[idx]);
}
__global__ void pack_gw_tf32(const float* __restrict__ Ws, const float* __restrict__ Wd,
                             uint32_t* __restrict__ Wh, uint32_t* __restrict__ Wl) {
    int idx = blockIdx.x * blockDim.x + threadIdx.x;
    if (idx >= DD * NG) return;
    int d = idx / NG, n = idx % NG;
    float val = 0.f;
    if (n < 40)      val = Ws[(size_t)d * GW + n];
    else if (n < 80) val = Wd[(size_t)d * GW + (n - 40)];
    split_tf32(val, Wh[idx], Wl[idx]);
}
__global__ void pack_wot_bf16(const float* __restrict__ Wo,
                              uint32_t* __restrict__ Wh, uint32_t* __restrict__ Wl) {
    size_t idx = (size_t)blockIdx.x * blockDim.x + threadIdx.x;
    if (idx >= (size_t)DD * XVW / 2) return;
    int n = (int)(idx / (XVW / 2));
    int kp = (int)(idx % (XVW / 2));
    int k0 = 2 * kp;
    int e = k0 >> 6, j = k0 & 63;
    float va = Wo[((size_t)(e * DH + j)) * DD + n];
    float vb = Wo[((size_t)(e * DH + j + 1)) * DD + n];
    split2(va, vb, Wh[idx], Wl[idx]);
}

// =============== bf16x3 GEMM: C=A@Bt^T, BM=128,BN=64,BK=32, 3-stage, 2 CTA/SM ==
// A: [M][K/2] u32 bf16-pairs (hi/lo arrays); Bt: [N][K/2] (transposed weights)
#define B3_OFF_AL 2560
#define B3_OFF_BH 5120
#define B3_OFF_BL 6400
#define B3_STG 7680

__global__ __launch_bounds__(256, 2)
void tgemmb3(const uint32_t* __restrict__ Agh, const uint32_t* __restrict__ Agl,
             const uint32_t* __restrict__ Bgh, const uint32_t* __restrict__ Bgl,
             float* __restrict__ C, int M, int N, int K) {
    extern __shared__ uint32_t sm2[];   // 3 stages x B3_STG
    const int tid = threadIdx.x;
    const int row0 = blockIdx.y * 128;
    const int col0 = blockIdx.x * 64;
    const int lane = tid & 31, w = tid >> 5;
    const int g = lane >> 2, t = lane & 3;
    const int wm = w >> 1, wn = w & 1;      // warp tile 32x32
    const int Ku = K / 2;

    const uint32_t sb = (uint32_t)__cvta_generic_to_shared(sm2);

    float c[2][4][4];
#pragma unroll
    for (int mt = 0; mt < 2; mt++)
#pragma unroll
        for (int nt = 0; nt < 4; nt++)
#pragma unroll
            for (int i = 0; i < 4; i++) c[mt][nt][i] = 0.f;

    const int nk = K / 32;

    // stage loader: A 512 chunks x2, B 256 chunks x2 => 6 cp16/thread
#define B3_LOAD(dst, kt)                                                          \
    {                                                                             \
        int ko = (kt) * 16;                                                       \
        _Pragma("unroll")                                                         \
        for (int it = 0; it < 2; it++) {                                          \
            int idx = it * 256 + tid;                                             \
            int r = idx >> 2, cc = idx & 3;                                       \
            cp16((dst) + (uint32_t)(r * ROWPAD + cc * 4) * 4,                     \
                 Agh + (size_t)(row0 + r) * Ku + ko + cc * 4);                    \
            cp16((dst) + (uint32_t)(B3_OFF_AL + r * ROWPAD + cc * 4) * 4,         \
                 Agl + (size_t)(row0 + r) * Ku + ko + cc * 4);                    \
        }                                                                         \
        {                                                                         \
            int r = tid >> 2, cc = tid & 3;                                       \
            cp16((dst) + (uint32_t)(B3_OFF_BH + r * ROWPAD + cc * 4) * 4,         \
                 Bgh + (size_t)(col0 + r) * Ku + ko + cc * 4);                    \
            cp16((dst) + (uint32_t)(B3_OFF_BL + r * ROWPAD + cc * 4) * 4,         \
                 Bgl + (size_t)(col0 + r) * Ku + ko + cc * 4);                    \
        }                                                                         \
    }

    // prologue: stages 0,1 <- ktiles 0,1
    B3_LOAD(sb, 0);
    CP_COMMIT();
    if (nk > 1) {
        B3_LOAD(sb + (uint32_t)B3_STG * 4, 1);
        CP_COMMIT();
    }

    for (int kt = 0; kt < nk; kt++) {
        const int st = kt % 3;
        if (kt + 2 < nk) {
            uint32_t d2 = sb + (uint32_t)(((kt + 2) % 3) * B3_STG) * 4;
            B3_LOAD(d2, kt + 2);
            CP_COMMIT();
            CP_WAIT(2);
        } else if (kt + 1 < nk) {
            CP_WAIT(1);
        } else {
            CP_WAIT(0);
        }
        __syncthreads();

        const uint32_t* Ah = sm2 + st * B3_STG;
        const uint32_t* Al = Ah + B3_OFF_AL;
        const uint32_t* Bh = Ah + B3_OFF_BH;
        const uint32_t* Bl = Ah + B3_OFF_BL;

#pragma unroll
        for (int kc = 0; kc < 2; kc++) {
            uint32_t afh[2][4], afl[2][4], bfh[4][2], bfl[4][2];
#pragma unroll
            for (int mt = 0; mt < 2; mt++) {
                int rb = wm * 32 + mt * 16;
                afh[mt][0] = Ah[(rb + g    ) * ROWPAD + kc * 8 + t];
                afh[mt][1] = Ah[(rb + g + 8) * ROWPAD + kc * 8 + t];
                afh[mt][2] = Ah[(rb + g    ) * ROWPAD + kc * 8 + t + 4];
                afh[mt][3] = Ah[(rb + g + 8) * ROWPAD + kc * 8 + t + 4];
                afl[mt][0] = Al[(rb + g    ) * ROWPAD + kc * 8 + t];
                afl[mt][1] = Al[(rb + g + 8) * ROWPAD + kc * 8 + t];
                afl[mt][2] = Al[(rb + g    ) * ROWPAD + kc * 8 + t + 4];
                afl[mt][3] = Al[(rb + g + 8) * ROWPAD + kc * 8 + t + 4];
            }
#pragma unroll
            for (int nt = 0; nt < 4; nt++) {
                int cb = wn * 32 + nt * 8;
                bfh[nt][0] = Bh[(cb + g) * ROWPAD + kc * 8 + t];
                bfh[nt][1] = Bh[(cb + g) * ROWPAD + kc * 8 + t + 4];
                bfl[nt][0] = Bl[(cb + g) * ROWPAD + kc * 8 + t];
                bfl[nt][1] = Bl[(cb + g) * ROWPAD + kc * 8 + t + 4];
            }
#pragma unroll
            for (int mt = 0; mt < 2; mt++)
#pragma unroll
                for (int nt = 0; nt < 4; nt++) {
                    mma_bf16(c[mt][nt], afh[mt], bfl[nt]);
                    mma_bf16(c[mt][nt], afl[mt], bfh[nt]);
                    mma_bf16(c[mt][nt], afh[mt], bfh[nt]);
                }
        }
        __syncthreads();
    }

#pragma unroll
    for (int mt = 0; mt < 2; mt++) {
        int r0 = row0 + wm * 32 + mt * 16;
#pragma unroll
        for (int nt = 0; nt < 4; nt++) {
            int cc = col0 + wn * 32 + nt * 8 + 2 * t;
            *(float2*)&C[(size_t)(r0 + g    ) * N + cc] = make_float2(c[mt][nt][0], c[mt][nt][1]);
            *(float2*)&C[(size_t)(r0 + g + 8) * N + cc] = make_float2(c[mt][nt][2], c[mt][nt][3]);
        }
    }
}

// =============== 3xTF32 GEMM (gates only), split-K via gridDim.z ===============
#define SA 36
#define SB 136
#define OFF_AL3 4608
#define OFF_BH3 9216
#define OFF_BL3 13568
#define STG3 17920

__device__ __forceinline__ void gemm3_stage_load(
    uint32_t dst, const uint32_t* __restrict__ Agh, const uint32_t* __restrict__ Agl,
    const uint32_t* __restrict__ Bgh, const uint32_t* __restrict__ Bgl,
    int row0, int col0, int k0, int K, int N, int tid) {
#pragma unroll
    for (int it = 0; it < 4; it++) {
        int idx = it * 1024 + tid * 4;
        int ar = idx >> 5, ac = idx & 31;
        cp16(dst + (uint32_t)(ar * SA + ac) * 4, Agh + (size_t)(row0 + ar) * K + k0 + ac);
        cp16(dst + (uint32_t)(OFF_AL3 + ar * SA + ac) * 4, Agl + (size_t)(row0 + ar) * K + k0 + ac);
        int br = idx >> 7, bc = idx & 127;
        cp16(dst + (uint32_t)(OFF_BH3 + br * SB + bc) * 4, Bgh + (size_t)(k0 + br) * N + col0 + bc);
        cp16(dst + (uint32_t)(OFF_BL3 + br * SB + bc) * 4, Bgl + (size_t)(k0 + br) * N + col0 + bc);
    }
}

__global__ __launch_bounds__(256)
void tgemm3s(const uint32_t* __restrict__ Agh, const uint32_t* __restrict__ Agl,
             const uint32_t* __restrict__ Bgh, const uint32_t* __restrict__ Bgl,
             float* __restrict__ C, int M, int N, int K) {
    extern __shared__ uint32_t sm[];
    const int tid = threadIdx.x;
    const int row0 = blockIdx.y * 128;
    const int col0 = blockIdx.x * 128;
    const int lane = tid & 31, w = tid >> 5;
    const int g = lane >> 2, t = lane & 3;
    const int wm = w >> 1, wn = w & 1;
    const int ksplit = gridDim.z;
    const int kb = blockIdx.z * (K / ksplit);
    const int nk = K / 32 / ksplit;
    float* Cz = C + (size_t)blockIdx.z * M * N;

    const uint32_t sb = (uint32_t)__cvta_generic_to_shared(sm);

    float c[2][8][4];
#pragma unroll
    for (int mt = 0; mt < 2; mt++)
#pragma unroll
        for (int nt = 0; nt < 8; nt++)
#pragma unroll
            for (int i = 0; i < 4; i++) c[mt][nt][i] = 0.f;

    gemm3_stage_load(sb, Agh, Agl, Bgh, Bgl, row0, col0, kb, K, N, tid);
    CP_COMMIT();

    for (int kt = 0; kt < nk; kt++) {
        const int st = kt & 1;
        if (kt + 1 < nk) {
            uint32_t d2 = sb + (uint32_t)((st ^ 1) * STG3) * 4;
            gemm3_stage_load(d2, Agh, Agl, Bgh, Bgl, row0, col0, kb + (kt + 1) * 32, K, N, tid);
            CP_COMMIT();
            CP_WAIT(1);
        } else {
            CP_WAIT(0);
        }
        __syncthreads();

        const uint32_t* Ah = sm + st * STG3;
        const uint32_t* Al = Ah + OFF_AL3;
        const uint32_t* Bh = Ah + OFF_BH3;
        const uint32_t* Bl = Ah + OFF_BL3;

#pragma unroll
        for (int kc = 0; kc < 4; kc++) {
            uint32_t afh[2][4], afl[2][4], bfh[8][2], bfl[8][2];
#pragma unroll
            for (int mt = 0; mt < 2; mt++) {
                int rb = wm * 32 + mt * 16;
                afh[mt][0] = Ah[(rb + g    ) * SA + kc * 8 + t];
                afh[mt][1] = Ah[(rb + g + 8) * SA + kc * 8 + t];
                afh[mt][2] = Ah[(rb + g    ) * SA + kc * 8 + t + 4];
                afh[mt][3] = Ah[(rb + g + 8) * SA + kc * 8 + t + 4];
                afl[mt][0] = Al[(rb + g    ) * SA + kc * 8 + t];
                afl[mt][1] = Al[(rb + g + 8) * SA + kc * 8 + t];
                afl[mt][2] = Al[(rb + g    ) * SA + kc * 8 + t + 4];
                afl[mt][3] = Al[(rb + g + 8) * SA + kc * 8 + t + 4];
            }
#pragma unroll
            for (int nt = 0; nt < 8; nt++) {
                int cb = wn * 64 + nt * 8;
                bfh[nt][0] = Bh[(kc * 8 + t    ) * SB + cb + g];
                bfh[nt][1] = Bh[(kc * 8 + t + 4) * SB + cb + g];
                bfl[nt][0] = Bl[(kc * 8 + t    ) * SB + cb + g];
                bfl[nt][1] = Bl[(kc * 8 + t + 4) * SB + cb + g];
            }
#pragma unroll
            for (int mt = 0; mt < 2; mt++)
#pragma unroll
                for (int nt = 0; nt < 8; nt++) {
                    mma_tf32(c[mt][nt], afh[mt], bfl[nt]);
                    mma_tf32(c[mt][nt], afl[mt], bfh[nt]);
                    mma_tf32(c[mt][nt], afh[mt], bfh[nt]);
                }
        }
        __syncthreads();
    }

#pragma unroll
    for (int mt = 0; mt < 2; mt++) {
        int r0 = row0 + wm * 32 + mt * 16;
#pragma unroll
        for (int nt = 0; nt < 8; nt++) {
            int cc = col0 + wn * 64 + nt * 8 + 2 * t;
            *(float2*)&Cz[(size_t)(r0 + g    ) * N + cc] = make_float2(c[mt][nt][0], c[mt][nt][1]);
            *(float2*)&Cz[(size_t)(r0 + g + 8) * N + cc] = make_float2(c[mt][nt][2], c[mt][nt][3]);
        }
    }
}

// -------- gating: sum split-K partials, top-2, V combine, out mask -------------
__global__ void gate_combine_kernel(const float* __restrict__ glp,
                                    const float* __restrict__ proj,
                                    float* __restrict__ v,
                                    float* __restrict__ masko) {
    int token = blockIdx.x;
    int w = threadIdx.x / 32;
    int lane = threadIdx.x % 32;

    float g[EE];
#pragma unroll
    for (int e = 0; e < EE; e++) {
        float s = 0.f;
#pragma unroll
        for (int z = 0; z < KSPL; z++)
            s += glp[((size_t)z * NTOK + token) * NG + w * EE + e];
        g[e] = s;
    }
    int i1 = 0;
#pragma unroll
    for (int e = 1; e < EE; e++) if (g[e] > g[i1]) i1 = e;
    int i2 = (i1 == 0) ? 1 : 0;
#pragma unroll
    for (int e = 0; e < EE; e++) if (e != i1 && g[e] > g[i2]) i2 = e;
    float w1 = 1.f / (1.f + __expf(-g[i1]));
    float w2 = 1.f / (1.f + __expf(-g[i2]));

    const float* xvt = proj + (size_t)token * PW2 + OFF_XV;
    float* vt = v + (size_t)token * QKW + w * DH;
#pragma unroll
    for (int d = lane; d < DH; d += 32)
        vt[d] = w1 * xvt[i1 * DH + d] + w2 * xvt[i2 * DH + d];

#pragma unroll
    for (int e = 0; e < EE; e++) {
        float s = 0.f;
#pragma unroll
        for (int z = 0; z < KSPL; z++)
            s += glp[((size_t)z * NTOK + token) * NG + 40 + w * EE + e];
        g[e] = s;
    }
    int o1 = 0;
#pragma unroll
    for (int e = 1; e < EE; e++) if (g[e] > g[o1]) o1 = e;
    int o2 = (o1 == 0) ? 1 : 0;
#pragma unroll
    for (int e = 0; e < EE; e++) if (e != o1 && g[e] > g[o2]) o2 = e;
    if (lane < EE)
        masko[((size_t)token * HH + w) * EE + lane] = (lane == o1 || lane == o2) ? 1.f : 0.f;
}

// =============== build bf16 K/V fragment blob ==================================
// K slot (row=k0*32+lane, col=n0*2+w2): {K[key=n0*8+g][d=k0*16+w2*8+2t], [d+1]}
// V slot: {V[key=k0*16+w2*8+2t][d=n0*8+g], V[key+1][d]}
__global__ void build_kv2_kernel(const float* __restrict__ proj,
                                 const float* __restrict__ v,
                                 uint32_t* __restrict__ blob) {
    __shared__ float Ks[64 * 68];
    __shared__ float Vs[64 * 68];
    const int tile = blockIdx.x, bh = blockIdx.y;
    const int b = bh / HH, h = bh % HH;
    const int tid = threadIdx.x;

#pragma unroll
    for (int it = 0; it < 4; it++) {
        int idx = it * 256 + tid;
        int r = (idx * 4) >> 6, d = (idx * 4) & 63;
        const float* kb = proj + (size_t)(b * TT + tile * 64 + r) * PW2 + OFF_K + h * DH;
        const float* vb = v    + (size_t)(b * TT + tile * 64 + r) * QKW + h * DH;
        *(float4*)&Ks[r * 68 + d] = *(const float4*)(kb + d);
        *(float4*)&Vs[r * 68 + d] = *(const float4*)(vb + d);
    }
    __syncthreads();

    uint32_t* dst = blob + ((size_t)bh * NTILE + tile) * TILE2_U32;
#pragma unroll
    for (int i = 0; i < 8; i++) {
        int oi = tid * 8 + i;            // 0..2047
        int row = oi >> 4;               // k0*32 + lane
        int col = oi & 15;               // n0*2 + w2
        int k0 = row >> 5, lane2 = row & 31;
        int g2 = lane2 >> 2, t2 = lane2 & 3;
        int n0 = col >> 1, w2 = col & 1;
        uint32_t hi, lo;
        // K
        int dK = k0 * 16 + w2 * 8 + 2 * t2;
        int keyK = n0 * 8 + g2;
        split2(Ks[keyK * 68 + dK], Ks[keyK * 68 + dK + 1], hi, lo);
        dst[row * ROWPAD + col] = hi;
        dst[ARR2_U32 + row * ROWPAD + col] = lo;
        // V
        int keyV = k0 * 16 + w2 * 8 + 2 * t2;
        int dV = n0 * 8 + g2;
        split2(Vs[keyV * 68 + dV], Vs[(keyV + 1) * 68 + dV], hi, lo);
        dst[2 * ARR2_U32 + row * ROWPAD + col] = hi;
        dst[3 * ARR2_U32 + row * ROWPAD + col] = lo;
    }
}

// =============== flash attention, bf16x3, fragment blob + cp.async =============
#define LOG2E 1.4426950408889634f

__global__ __launch_bounds__(256, 2)
void attn3_kernel(const float* __restrict__ qg,
                  const uint32_t* __restrict__ blob,
                  float* __restrict__ o) {
    extern __shared__ uint32_t sh[];     // 2 stages x TILE2_U32
    const int bh = blockIdx.y;
    const int b = bh / HH, h = bh % HH;
    const int q0 = blockIdx.x * 128;
    const int tid = threadIdx.x;
    const int lane = tid & 31, w = tid >> 5;
    const int g = lane >> 2, t = lane & 3;
    const float scale = 0.125f;

    const uint32_t* gblob = blob + (size_t)bh * NTILE * TILE2_U32;
    const uint32_t sbase = (uint32_t)__cvta_generic_to_shared(sh);

    // DMA tile 0 (2560 chunks / 256 threads = 10)
#pragma unroll
    for (int i = 0; i < 10; i++) {
        int cc = tid + i * 256;
        cp16(sbase + cc * 16, gblob + cc * 4);
    }
    CP_COMMIT();

    // Q fragments bf16 hi/lo, scale folded (exact pow2)
    const float* qb = qg + (size_t)(b * TT + q0 + w * 16) * PW2 + h * DH;
    uint32_t qah[4][4], qal[4][4];
#pragma unroll
    for (int k0 = 0; k0 < 4; k0++) {
        split2(scale * qb[(size_t)(g    ) * PW2 + k0 * 16 + 2 * t],
               scale * qb[(size_t)(g    ) * PW2 + k0 * 16 + 2 * t + 1], qah[k0][0], qal[k0][0]);
        split2(scale * qb[(size_t)(g + 8) * PW2 + k0 * 16 + 2 * t],
               scale * qb[(size_t)(g + 8) * PW2 + k0 * 16 + 2 * t + 1], qah[k0][1], qal[k0][1]);
        split2(scale * qb[(size_t)(g    ) * PW2 + k0 * 16 + 2 * t + 8],
               scale * qb[(size_t)(g    ) * PW2 + k0 * 16 + 2 * t + 9], qah[k0][2], qal[k0][2]);
        split2(scale * qb[(size_t)(g + 8) * PW2 + k0 * 16 + 2 * t + 8],
               scale * qb[(size_t)(g + 8) * PW2 + k0 * 16 + 2 * t + 9], qah[k0][3], qal[k0][3]);
    }

    float om[8][4];
#pragma unroll
    for (int n = 0; n < 8; n++)
#pragma unroll
        for (int i = 0; i < 4; i++) om[n][i] = 0.f;
    float rm0 = -INFINITY, rm1 = -INFINITY, rl0 = 0.f, rl1 = 0.f;

    for (int tt = 0; tt < NTILE; tt++) {
        const int st = tt & 1;
        if (tt + 1 < NTILE) {
            const uint32_t* src = gblob + (size_t)(tt + 1) * TILE2_U32;
            uint32_t dst = sbase + (uint32_t)((st ^ 1) * TILE2_U32) * 4;
#pragma unroll
            for (int i = 0; i < 10; i++) {
                int cc = tid + i * 256;
                cp16(dst + cc * 16, src + cc * 4);
            }
            CP_COMMIT();
            CP_WAIT(1);
        } else {
            CP_WAIT(0);
        }
        __syncthreads();

        const uint32_t* Kh = sh + st * TILE2_U32;
        const uint32_t* Kl = Kh + ARR2_U32;
        const uint32_t* Vh = Kh + 2 * ARR2_U32;
        const uint32_t* Vl = Kh + 3 * ARR2_U32;

        // ---- S = Qs @ K^T (bf16x3) -------------------------------------------
        float s[8][4];
#pragma unroll
        for (int n = 0; n < 8; n++)
#pragma unroll
            for (int i = 0; i < 4; i++) s[n][i] = 0.f;
#pragma unroll
        for (int k0 = 0; k0 < 4; k0++) {
            const uint32_t* kr = Kh + (k0 * 32 + lane) * ROWPAD;
            const uint32_t* lr = Kl + (k0 * 32 + lane) * ROWPAD;
#pragma unroll
            for (int np = 0; np < 4; np++) {
                uint4 kh4 = *(const uint4*)(kr + np * 4);
                uint4 kl4 = *(const uint4*)(lr + np * 4);
                uint32_t bh2[2] = {kh4.x, kh4.y};
                uint32_t bl2[2] = {kl4.x, kl4.y};
                mma_bf16(s[2 * np], qah[k0], bl2);
                mma_bf16(s[2 * np], qal[k0], bh2);
                mma_bf16(s[2 * np], qah[k0], bh2);
                uint32_t bh3[2] = {kh4.z, kh4.w};
                uint32_t bl3[2] = {kl4.z, kl4.w};
                mma_bf16(s[2 * np + 1], qah[k0], bl3);
                mma_bf16(s[2 * np + 1], qal[k0], bh3);
                mma_bf16(s[2 * np + 1], qah[k0], bh3);
            }
        }

        // ---- online softmax ----------------------------------------------------
        float m0 = s[0][0], m1 = s[0][2];
#pragma unroll
        for (int n = 0; n < 8; n++) {
            m0 = fmaxf(m0, fmaxf(s[n][0], s[n][1]));
            m1 = fmaxf(m1, fmaxf(s[n][2], s[n][3]));
        }
        m0 = fmaxf(m0, __shfl_xor_sync(0xffffffff, m0, 1));
        m0 = fmaxf(m0, __shfl_xor_sync(0xffffffff, m0, 2));
        m1 = fmaxf(m1, __shfl_xor_sync(0xffffffff, m1, 1));
        m1 = fmaxf(m1, __shfl_xor_sync(0xffffffff, m1, 2));

        float mn0 = fmaxf(rm0, m0);
        float mn1 = fmaxf(rm1, m1);
        float corr0 = exp2f((rm0 - mn0) * LOG2E);
        float corr1 = exp2f((rm1 - mn1) * LOG2E);

        float sum0 = 0.f, sum1 = 0.f;
#pragma unroll
        for (int n = 0; n < 8; n++) {
            s[n][0] = exp2f((s[n][0] - mn0) * LOG2E);
            s[n][1] = exp2f((s[n][1] - mn0) * LOG2E);
            s[n][2] = exp2f((s[n][2] - mn1) * LOG2E);
            s[n][3] = exp2f((s[n][3] - mn1) * LOG2E);
            sum0 += s[n][0] + s[n][1];
            sum1 += s[n][2] + s[n][3];
        }
        sum0 += __shfl_xor_sync(0xffffffff, sum0, 1);
        sum0 += __shfl_xor_sync(0xffffffff, sum0, 2);
        sum1 += __shfl_xor_sync(0xffffffff, sum1, 1);
        sum1 += __shfl_xor_sync(0xffffffff, sum1, 2);
        rl0 = rl0 * corr0 + sum0;
        rl1 = rl1 * corr1 + sum1;
        rm0 = mn0; rm1 = mn1;

#pragma unroll
        for (int n = 0; n < 8; n++) {
            om[n][0] *= corr0; om[n][1] *= corr0;
            om[n][2] *= corr1; om[n][3] *= corr1;
        }

        // ---- O += P @ V (bf16x3); P A-frag built locally (no shuffles) --------
#pragma unroll
        for (int k0 = 0; k0 < 4; k0++) {
            uint32_t ph[4], pl[4];
            split2(s[2 * k0][0],     s[2 * k0][1],     ph[0], pl[0]);
            split2(s[2 * k0][2],     s[2 * k0][3],     ph[1], pl[1]);
            split2(s[2 * k0 + 1][0], s[2 * k0 + 1][1], ph[2], pl[2]);
            split2(s[2 * k0 + 1][2], s[2 * k0 + 1][3], ph[3], pl[3]);
            const uint32_t* vr = Vh + (k0 * 32 + lane) * ROWPAD;
            const uint32_t* wr = Vl + (k0 * 32 + lane) * ROWPAD;
#pragma unroll
            for (int np = 0; np < 4; np++) {
                uint4 vh4 = *(const uint4*)(vr + np * 4);
                uint4 vl4 = *(const uint4*)(wr + np * 4);
                uint32_t bh2[2] = {vh4.x, vh4.y};
                uint32_t bl2[2] = {vl4.x, vl4.y};
                mma_bf16(om[2 * np], ph, bl2);
                mma_bf16(om[2 * np], pl, bh2);
                mma_bf16(om[2 * np], ph, bh2);
                uint32_t bh3[2] = {vh4.z, vh4.w};
                uint32_t bl3[2] = {vl4.z, vl4.w};
                mma_bf16(om[2 * np + 1], ph, bl3);
                mma_bf16(om[2 * np + 1], pl, bh3);
                mma_bf16(om[2 * np + 1], ph, bh3);
            }
        }
        __syncthreads();
    }

    float inv0 = 1.f / rl0;
    float inv1 = 1.f / rl1;
    float* ob0 = o + (size_t)(b * TT + q0 + w * 16 + g    ) * QKW + h * DH + 2 * t;
    float* ob1 = o + (size_t)(b * TT + q0 + w * 16 + g + 8) * QKW + h * DH + 2 * t;
#pragma unroll
    for (int n0 = 0; n0 < 8; n0++) {
        *(float2*)(ob0 + n0 * 8) = make_float2(om[n0][0] * inv0, om[n0][1] * inv0);
        *(float2*)(ob1 + n0 * 8) = make_float2(om[n0][2] * inv1, om[n0][3] * inv1);
    }
}

// -------- Y pairs: Y[t, 2i..2i+1] = sum_h mask*attn, split to bf16 hi/lo -------
__global__ void combine_out_kernel(const float* __restrict__ attn,
                                   const float* __restrict__ masko,
                                   uint32_t* __restrict__ Yh,
                                   uint32_t* __restrict__ Yl) {
    int token = blockIdx.x;
    int tid = threadIdx.x;          // 0..159
    int t0 = 2 * tid;
    int e = t0 >> 6, j = t0 & 63;
    const float* ap = attn + (size_t)token * QKW;
    const float* mp = masko + (size_t)token * GW;
    float s0 = 0.f, s1 = 0.f;
#pragma unroll
    for (int h = 0; h < HH; h++) {
        float m = mp[h * EE + e];
        s0 += m * ap[h * DH + j];
        s1 += m * ap[h * DH + j + 1];
    }
    uint32_t hi, lo;
    split2(s0, s1, hi, lo);
    Yh[(size_t)token * (XVW / 2) + tid] = hi;
    Yl[(size_t)token * (XVW / 2) + tid] = lo;
}

// ------------------------------- launch ----------------------------------------
extern "C" void kernel_launch(void* const* d_in, const int* in_sizes, int n_in,
                              void* d_out, int out_size) {
    const float* x  = (const float*)d_in[0];
    const float* Wq = (const float*)d_in[1];
    const float* Wk = (const float*)d_in[2];
    const float* Ws = (const float*)d_in[3];
    const float* Wd = (const float*)d_in[4];
    const float* Wv = (const float*)d_in[5];
    const float* Wo = (const float*)d_in[6];
    float* out = (float*)d_out;

    float *proj, *glp, *v, *attn, *mask;
    uint32_t *xbh, *xbl, *wth, *wtl, *xth, *xtl, *gwh, *gwl, *ybh, *ybl, *woth, *wotl, *blob;
    cudaGetSymbolAddress((void**)&proj, g_proj);
    cudaGetSymbolAddress((void**)&xbh,  g_xbh);
    cudaGetSymbolAddress((void**)&xbl,  g_xbl);
    cudaGetSymbolAddress((void**)&wth,  g_wth);
    cudaGetSymbolAddress((void**)&wtl,  g_wtl);
    cudaGetSymbolAddress((void**)&xth,  g_xth);
    cudaGetSymbolAddress((void**)&xtl,  g_xtl);
    cudaGetSymbolAddress((void**)&gwh,  g_gwh);
    cudaGetSymbolAddress((void**)&gwl,  g_gwl);
    cudaGetSymbolAddress((void**)&glp,  g_glp);
    cudaGetSymbolAddress((void**)&v,    g_v);
    cudaGetSymbolAddress((void**)&attn, g_attn);
    cudaGetSymbolAddress((void**)&mask, g_mask);
    cudaGetSymbolAddress((void**)&ybh,  g_ybh);
    cudaGetSymbolAddress((void**)&ybl,  g_ybl);
    cudaGetSymbolAddress((void**)&woth, g_woth);
    cudaGetSymbolAddress((void**)&wotl, g_wotl);
    cudaGetSymbolAddress((void**)&blob, g_blob);

    // pre-splits / packs (x read once)
    split_x_all  <<<(int)(((size_t)NTOK * DD / 2 + 255) / 256), 256>>>(x, xbh, xbl, xth, xtl);
    pack_wt_bf16 <<<(int)(((size_t)PW2 * DD / 2 + 255) / 256), 256>>>(Wq, Wk, Wv, wth, wtl);
    pack_gw_tf32 <<<(DD * NG + 255) / 256, 256>>>(Ws, Wd, gwh, gwl);
    pack_wot_bf16<<<(int)(((size_t)DD * XVW / 2 + 255) / 256), 256>>>(Wo, woth, wotl);

    // proj GEMM (bf16x3, 3-stage): (8192x1024)@(1024x1344)
    size_t bsm = (size_t)3 * B3_STG * sizeof(uint32_t);   // 92160
    cudaFuncSetAttribute(tgemmb3, cudaFuncAttributeMaxDynamicSharedMemorySize, (int)bsm);
    dim3 gp(PW2 / 64, NTOK / 128);
    tgemmb3<<<gp, 256, bsm>>>(xbh, xbl, wth, wtl, proj, NTOK, PW2, DD);

    // gate GEMM (3xTF32, split-K=4): (8192x1024)@(1024x128) -> partials
    size_t gsm = (size_t)2 * STG3 * sizeof(uint32_t);     // 143360
    cudaFuncSetAttribute(tgemm3s, cudaFuncAttributeMaxDynamicSharedMemorySize, (int)gsm);
    dim3 gg(NG / 128, NTOK / 128, KSPL);
    tgemm3s<<<gg, 256, gsm>>>(xth, xtl, gwh, gwl, glp, NTOK, NG, DD);

    // gating + V combine + out-mask
    gate_combine_kernel<<<NTOK, 256>>>(glp, proj, v, mask);

    // K/V fragment blob (bf16)
    dim3 bg(NTILE, BB * HH);
    build_kv2_kernel<<<bg, 256>>>(proj, v, blob);

    // attention
    size_t asmem = (size_t)2 * TILE2_U32 * sizeof(uint32_t);  // 81920
    cudaFuncSetAttribute(attn3_kernel, cudaFuncAttributeMaxDynamicSharedMemorySize, (int)asmem);
    dim3 ag(TT / 128, BB * HH);
    attn3_kernel<<<ag, 256, asmem>>>(proj, blob, attn);

    // masked combine (+bf16 split), then output GEMM: (8192x320)@(320x1024)
    combine_out_kernel<<<NTOK, XVW / 2>>>(attn, mask, ybh, ybl);
    dim3 go(DD / 64, NTOK / 128);
    tgemmb3<<<go, 256, bsm>>>(ybh, ybl, woth, wotl, out, NTOK, DD, XVW);
}

// round 10
// speedup vs baseline: 11.8534x; 1.3065x over previous
#include <cuda_runtime.h>
#include <cuda_bf16.h>
#include <cuda_fp16.h>
#include <math.h>
#include <stdint.h>

// Problem constants
#define BB 4
#define TT 2048
#define DD 1024
#define HH 8
#define DH 64
#define EE 5
#define NTOK (BB*TT)          // 8192
#define QKW (HH*DH)           // 512
#define GW  (HH*EE)           // 40
#define XVW (EE*DH)           // 320

// fused projection layout (row stride PW2): q[0:512) | k[512:1024) | xv[1024:1344)
#define PW2 1344
#define OFF_K 512
#define OFF_XV 1024

#define NG 128                 // gate GEMM padded width (glv 0..39, glo 40..79)
#define KSPL 4                 // gate GEMM split-K

// fp16 KV fragment blob: per (bh,tile64): [K | Vh | Vl], each 4 k0 x 32 lanes x 20 u32
#define ROWPAD 20
#define ARR2_U32 (4*32*ROWPAD)    // 2560
#define TILE3_U32 (3*ARR2_U32)    // 7680 u32 = 30KB
#define NTILE 32

// ---------------- scratch (device globals) ------------------------------------
__device__ float    g_proj [(size_t)NTOK*PW2];
__device__ __align__(16) uint32_t g_xbh [(size_t)NTOK*DD/2];   // fp16 hi pairs of x
__device__ __align__(16) uint32_t g_xbl [(size_t)NTOK*DD/2];   // fp16 lo pairs
__device__ __align__(16) uint32_t g_wt  [(size_t)PW2*DD/2];    // Wt[n][dpair] fp16 (single)
__device__ __align__(16) uint32_t g_xth [(size_t)NTOK*DD];     // tf32 hi of x (gates)
__device__ __align__(16) uint32_t g_xtl [(size_t)NTOK*DD];
__device__ __align__(16) uint32_t g_gwh [(size_t)DD*NG];       // tf32 gate weights
__device__ __align__(16) uint32_t g_gwl [(size_t)DD*NG];
__device__ float    g_glp  [(size_t)KSPL*NTOK*NG];             // gate partials
__device__ float    g_v    [(size_t)NTOK*QKW];
__device__ float    g_attn [(size_t)NTOK*QKW];
__device__ float    g_mask [(size_t)NTOK*GW];
__device__ __align__(16) uint32_t g_ybh [(size_t)NTOK*XVW/2];  // fp16 hi pairs of Y
__device__ __align__(16) uint32_t g_ybl [(size_t)NTOK*XVW/2];
__device__ __align__(16) uint32_t g_wot [(size_t)DD*XVW/2];    // WoT[n=d][kpair] fp16
__device__ __align__(16) uint32_t g_blob[(size_t)BB*HH*NTILE*TILE3_U32];  // ~31MB

// ---------------- helpers ------------------------------------------------------
__device__ __forceinline__ uint32_t f2tf32(float x) {
    uint32_t r;
    asm("cvt.rna.tf32.f32 %0, %1;" : "=r"(r) : "f"(x));
    return r;
}
__device__ __forceinline__ void split_tf32(float x, uint32_t& h, uint32_t& l) {
    h = f2tf32(x);
    l = f2tf32(x - __uint_as_float(h));
}
// pack (a,b) into fp16x2 word; a -> bits[15:0]
__device__ __forceinline__ uint32_t packh2(float a, float b) {
    __half2 h = __floats2half2_rn(a, b);
    return *reinterpret_cast<uint32_t*>(&h);
}
// split pair (a,b) into fp16x2 hi and lo words
__device__ __forceinline__ void splith2(float a, float b, uint32_t& h, uint32_t& l) {
    __half ha = __float2half_rn(a);
    __half hb = __float2half_rn(b);
    float ra = a - __half2float(ha);
    float rb = b - __half2float(hb);
    __half2 hh; hh.x = ha; hh.y = hb;
    __half2 ll; ll.x = __float2half_rn(ra); ll.y = __float2half_rn(rb);
    h = *reinterpret_cast<uint32_t*>(&hh);
    l = *reinterpret_cast<uint32_t*>(&ll);
}
__device__ __forceinline__ void mma_tf32(float c[4], const uint32_t a[4], const uint32_t b[2]) {
    asm volatile(
        "mma.sync.aligned.m16n8k8.row.col.f32.tf32.tf32.f32 "
        "{%0,%1,%2,%3},{%4,%5,%6,%7},{%8,%9},{%0,%1,%2,%3};"
        : "+f"(c[0]), "+f"(c[1]), "+f"(c[2]), "+f"(c[3])
        : "r"(a[0]), "r"(a[1]), "r"(a[2]), "r"(a[3]), "r"(b[0]), "r"(b[1]));
}
__device__ __forceinline__ void mma_f16(float c[4], const uint32_t a[4], const uint32_t b[2]) {
    asm volatile(
        "mma.sync.aligned.m16n8k16.row.col.f32.f16.f16.f32 "
        "{%0,%1,%2,%3},{%4,%5,%6,%7},{%8,%9},{%0,%1,%2,%3};"
        : "+f"(c[0]), "+f"(c[1]), "+f"(c[2]), "+f"(c[3])
        : "r"(a[0]), "r"(a[1]), "r"(a[2]), "r"(a[3]), "r"(b[0]), "r"(b[1]));
}
__device__ __forceinline__ void cp16(uint32_t saddr, const void* g) {
    asm volatile("cp.async.cg.shared.global [%0], [%1], 16;\n" :: "r"(saddr), "l"(g));
}
#define CP_COMMIT() asm volatile("cp.async.commit_group;\n")
#define CP_WAIT(n)  asm volatile("cp.async.wait_group %0;\n" :: "n"(n))

// =============== pre-split / pack kernels ======================================
__global__ void split_x_all(const float* __restrict__ x,
                            uint32_t* __restrict__ xbh, uint32_t* __restrict__ xbl,
                            uint32_t* __restrict__ xth, uint32_t* __restrict__ xtl) {
    size_t i = (size_t)blockIdx.x * blockDim.x + threadIdx.x;
    if (i >= (size_t)NTOK * DD / 2) return;
    float a = x[2 * i], b = x[2 * i + 1];
    splith2(a, b, xbh[i], xbl[i]);
    split_tf32(a, xth[2 * i], xtl[2 * i]);
    split_tf32(b, xth[2 * i + 1], xtl[2 * i + 1]);
}
__global__ void pack_wt_f16(const float* __restrict__ Wq, const float* __restrict__ Wk,
                            const float* __restrict__ Wv, uint32_t* __restrict__ Wt) {
    size_t idx = (size_t)blockIdx.x * blockDim.x + threadIdx.x;
    if (idx >= (size_t)PW2 * DD / 2) return;
    int n = (int)(idx / (DD / 2));
    int dp = (int)(idx % (DD / 2));
    int d0 = 2 * dp;
    float va, vb;
    if (n < 512) {
        va = Wq[(size_t)d0 * 512 + n]; vb = Wq[(size_t)(d0 + 1) * 512 + n];
    } else if (n < 1024) {
        va = Wk[(size_t)d0 * 512 + (n - 512)]; vb = Wk[(size_t)(d0 + 1) * 512 + (n - 512)];
    } else {
        int e = (n - 1024) / DH, j = (n - 1024) % DH;
        va = Wv[((size_t)e * DD + d0) * DH + j];
        vb = Wv[((size_t)e * DD + d0 + 1) * DH + j];
    }
    Wt[idx] = packh2(va, vb);
}
__global__ void pack_gw_tf32(const float* __restrict__ Ws, const float* __restrict__ Wd,
                             uint32_t* __restrict__ Wh, uint32_t* __restrict__ Wl) {
    int idx = blockIdx.x * blockDim.x + threadIdx.x;
    if (idx >= DD * NG) return;
    int d = idx / NG, n = idx % NG;
    float val = 0.f;
    if (n < 40)      val = Ws[(size_t)d * GW + n];
    else if (n < 80) val = Wd[(size_t)d * GW + (n - 40)];
    split_tf32(val, Wh[idx], Wl[idx]);
}
__global__ void pack_wot_f16(const float* __restrict__ Wo, uint32_t* __restrict__ Wt) {
    size_t idx = (size_t)blockIdx.x * blockDim.x + threadIdx.x;
    if (idx >= (size_t)DD * XVW / 2) return;
    int n = (int)(idx / (XVW / 2));
    int kp = (int)(idx % (XVW / 2));
    int k0 = 2 * kp;
    int e = k0 >> 6, j = k0 & 63;
    float va = Wo[((size_t)(e * DH + j)) * DD + n];
    float vb = Wo[((size_t)(e * DH + j + 1)) * DD + n];
    Wt[idx] = packh2(va, vb);
}

// =============== fp16 2-term GEMM: C=A@Bt^T, BM=128,BN=64,BK=32, 3-stage =======
// A: [M][K/2] u32 fp16-pairs (hi/lo arrays); Bt: [N][K/2] fp16-pairs (single)
#define H2_OFF_AL 2560
#define H2_OFF_B  5120
#define H2_STG    6400     // u32 per stage (25.6KB)

__global__ __launch_bounds__(256, 2)
void tgemmh2(const uint32_t* __restrict__ Agh, const uint32_t* __restrict__ Agl,
             const uint32_t* __restrict__ Bg,
             float* __restrict__ C, int M, int N, int K) {
    extern __shared__ uint32_t sm2[];   // 3 stages x H2_STG
    const int tid = threadIdx.x;
    const int row0 = blockIdx.y * 128;
    const int col0 = blockIdx.x * 64;
    const int lane = tid & 31, w = tid >> 5;
    const int g = lane >> 2, t = lane & 3;
    const int wm = w >> 1, wn = w & 1;      // warp tile 32x32
    const int Ku = K / 2;

    const uint32_t sb = (uint32_t)__cvta_generic_to_shared(sm2);

    float c[2][4][4];
#pragma unroll
    for (int mt = 0; mt < 2; mt++)
#pragma unroll
        for (int nt = 0; nt < 4; nt++)
#pragma unroll
            for (int i = 0; i < 4; i++) c[mt][nt][i] = 0.f;

    const int nk = K / 32;

#define H2_LOAD(dst, kt)                                                          \
    {                                                                             \
        int ko = (kt) * 16;                                                       \
        _Pragma("unroll")                                                         \
        for (int it = 0; it < 2; it++) {                                          \
            int idx = it * 256 + tid;                                             \
            int r = idx >> 2, cc = idx & 3;                                       \
            cp16((dst) + (uint32_t)(r * ROWPAD + cc * 4) * 4,                     \
                 Agh + (size_t)(row0 + r) * Ku + ko + cc * 4);                    \
            cp16((dst) + (uint32_t)(H2_OFF_AL + r * ROWPAD + cc * 4) * 4,         \
                 Agl + (size_t)(row0 + r) * Ku + ko + cc * 4);                    \
        }                                                                         \
        {                                                                         \
            int r = tid >> 2, cc = tid & 3;                                       \
            cp16((dst) + (uint32_t)(H2_OFF_B + r * ROWPAD + cc * 4) * 4,          \
                 Bg + (size_t)(col0 + r) * Ku + ko + cc * 4);                     \
        }                                                                         \
    }

    // prologue: stages 0,1 <- ktiles 0,1
    H2_LOAD(sb, 0);
    CP_COMMIT();
    if (nk > 1) {
        H2_LOAD(sb + (uint32_t)H2_STG * 4, 1);
        CP_COMMIT();
    }

    for (int kt = 0; kt < nk; kt++) {
        const int st = kt % 3;
        if (kt + 2 < nk) {
            uint32_t d2 = sb + (uint32_t)(((kt + 2) % 3) * H2_STG) * 4;
            H2_LOAD(d2, kt + 2);
            CP_COMMIT();
            CP_WAIT(2);
        } else if (kt + 1 < nk) {
            CP_WAIT(1);
        } else {
            CP_WAIT(0);
        }
        __syncthreads();

        const uint32_t* Ah = sm2 + st * H2_STG;
        const uint32_t* Al = Ah + H2_OFF_AL;
        const uint32_t* Bs = Ah + H2_OFF_B;

#pragma unroll
        for (int kc = 0; kc < 2; kc++) {
            uint32_t afh[2][4], afl[2][4], bf[4][2];
#pragma unroll
            for (int mt = 0; mt < 2; mt++) {
                int rb = wm * 32 + mt * 16;
                afh[mt][0] = Ah[(rb + g    ) * ROWPAD + kc * 8 + t];
                afh[mt][1] = Ah[(rb + g + 8) * ROWPAD + kc * 8 + t];
                afh[mt][2] = Ah[(rb + g    ) * ROWPAD + kc * 8 + t + 4];
                afh[mt][3] = Ah[(rb + g + 8) * ROWPAD + kc * 8 + t + 4];
                afl[mt][0] = Al[(rb + g    ) * ROWPAD + kc * 8 + t];
                afl[mt][1] = Al[(rb + g + 8) * ROWPAD + kc * 8 + t];
                afl[mt][2] = Al[(rb + g    ) * ROWPAD + kc * 8 + t + 4];
                afl[mt][3] = Al[(rb + g + 8) * ROWPAD + kc * 8 + t + 4];
            }
#pragma unroll
            for (int nt = 0; nt < 4; nt++) {
                int cb = wn * 32 + nt * 8;
                bf[nt][0] = Bs[(cb + g) * ROWPAD + kc * 8 + t];
                bf[nt][1] = Bs[(cb + g) * ROWPAD + kc * 8 + t + 4];
            }
#pragma unroll
            for (int mt = 0; mt < 2; mt++)
#pragma unroll
                for (int nt = 0; nt < 4; nt++) {
                    mma_f16(c[mt][nt], afl[mt], bf[nt]);
                    mma_f16(c[mt][nt], afh[mt], bf[nt]);
                }
        }
        __syncthreads();
    }

#pragma unroll
    for (int mt = 0; mt < 2; mt++) {
        int r0 = row0 + wm * 32 + mt * 16;
#pragma unroll
        for (int nt = 0; nt < 4; nt++) {
            int cc = col0 + wn * 32 + nt * 8 + 2 * t;
            *(float2*)&C[(size_t)(r0 + g    ) * N + cc] = make_float2(c[mt][nt][0], c[mt][nt][1]);
            *(float2*)&C[(size_t)(r0 + g + 8) * N + cc] = make_float2(c[mt][nt][2], c[mt][nt][3]);
        }
    }
}

// =============== 3xTF32 GEMM (gates only), split-K via gridDim.z ===============
#define SA 36
#define SB 136
#define OFF_AL3 4608
#define OFF_BH3 9216
#define OFF_BL3 13568
#define STG3 17920

__device__ __forceinline__ void gemm3_stage_load(
    uint32_t dst, const uint32_t* __restrict__ Agh, const uint32_t* __restrict__ Agl,
    const uint32_t* __restrict__ Bgh, const uint32_t* __restrict__ Bgl,
    int row0, int col0, int k0, int K, int N, int tid) {
#pragma unroll
    for (int it = 0; it < 4; it++) {
        int idx = it * 1024 + tid * 4;
        int ar = idx >> 5, ac = idx & 31;
        cp16(dst + (uint32_t)(ar * SA + ac) * 4, Agh + (size_t)(row0 + ar) * K + k0 + ac);
        cp16(dst + (uint32_t)(OFF_AL3 + ar * SA + ac) * 4, Agl + (size_t)(row0 + ar) * K + k0 + ac);
        int br = idx >> 7, bc = idx & 127;
        cp16(dst + (uint32_t)(OFF_BH3 + br * SB + bc) * 4, Bgh + (size_t)(k0 + br) * N + col0 + bc);
        cp16(dst + (uint32_t)(OFF_BL3 + br * SB + bc) * 4, Bgl + (size_t)(k0 + br) * N + col0 + bc);
    }
}

__global__ __launch_bounds__(256)
void tgemm3s(const uint32_t* __restrict__ Agh, const uint32_t* __restrict__ Agl,
             const uint32_t* __restrict__ Bgh, const uint32_t* __restrict__ Bgl,
             float* __restrict__ C, int M, int N, int K) {
    extern __shared__ uint32_t sm[];
    const int tid = threadIdx.x;
    const int row0 = blockIdx.y * 128;
    const int col0 = blockIdx.x * 128;
    const int lane = tid & 31, w = tid >> 5;
    const int g = lane >> 2, t = lane & 3;
    const int wm = w >> 1, wn = w & 1;
    const int ksplit = gridDim.z;
    const int kb = blockIdx.z * (K / ksplit);
    const int nk = K / 32 / ksplit;
    float* Cz = C + (size_t)blockIdx.z * M * N;

    const uint32_t sb = (uint32_t)__cvta_generic_to_shared(sm);

    float c[2][8][4];
#pragma unroll
    for (int mt = 0; mt < 2; mt++)
#pragma unroll
        for (int nt = 0; nt < 8; nt++)
#pragma unroll
            for (int i = 0; i < 4; i++) c[mt][nt][i] = 0.f;

    gemm3_stage_load(sb, Agh, Agl, Bgh, Bgl, row0, col0, kb, K, N, tid);
    CP_COMMIT();

    for (int kt = 0; kt < nk; kt++) {
        const int st = kt & 1;
        if (kt + 1 < nk) {
            uint32_t d2 = sb + (uint32_t)((st ^ 1) * STG3) * 4;
            gemm3_stage_load(d2, Agh, Agl, Bgh, Bgl, row0, col0, kb + (kt + 1) * 32, K, N, tid);
            CP_COMMIT();
            CP_WAIT(1);
        } else {
            CP_WAIT(0);
        }
        __syncthreads();

        const uint32_t* Ah = sm + st * STG3;
        const uint32_t* Al = Ah + OFF_AL3;
        const uint32_t* Bh = Ah + OFF_BH3;
        const uint32_t* Bl = Ah + OFF_BL3;

#pragma unroll
        for (int kc = 0; kc < 4; kc++) {
            uint32_t afh[2][4], afl[2][4], bfh[8][2], bfl[8][2];
#pragma unroll
            for (int mt = 0; mt < 2; mt++) {
                int rb = wm * 32 + mt * 16;
                afh[mt][0] = Ah[(rb + g    ) * SA + kc * 8 + t];
                afh[mt][1] = Ah[(rb + g + 8) * SA + kc * 8 + t];
                afh[mt][2] = Ah[(rb + g    ) * SA + kc * 8 + t + 4];
                afh[mt][3] = Ah[(rb + g + 8) * SA + kc * 8 + t + 4];
                afl[mt][0] = Al[(rb + g    ) * SA + kc * 8 + t];
                afl[mt][1] = Al[(rb + g + 8) * SA + kc * 8 + t];
                afl[mt][2] = Al[(rb + g    ) * SA + kc * 8 + t + 4];
                afl[mt][3] = Al[(rb + g + 8) * SA + kc * 8 + t + 4];
            }
#pragma unroll
            for (int nt = 0; nt < 8; nt++) {
                int cb = wn * 64 + nt * 8;
                bfh[nt][0] = Bh[(kc * 8 + t    ) * SB + cb + g];
                bfh[nt][1] = Bh[(kc * 8 + t + 4) * SB + cb + g];
                bfl[nt][0] = Bl[(kc * 8 + t    ) * SB + cb + g];
                bfl[nt][1] = Bl[(kc * 8 + t + 4) * SB + cb + g];
            }
#pragma unroll
            for (int mt = 0; mt < 2; mt++)
#pragma unroll
                for (int nt = 0; nt < 8; nt++) {
                    mma_tf32(c[mt][nt], afh[mt], bfl[nt]);
                    mma_tf32(c[mt][nt], afl[mt], bfh[nt]);
                    mma_tf32(c[mt][nt], afh[mt], bfh[nt]);
                }
        }
        __syncthreads();
    }

#pragma unroll
    for (int mt = 0; mt < 2; mt++) {
        int r0 = row0 + wm * 32 + mt * 16;
#pragma unroll
        for (int nt = 0; nt < 8; nt++) {
            int cc = col0 + wn * 64 + nt * 8 + 2 * t;
            *(float2*)&Cz[(size_t)(r0 + g    ) * N + cc] = make_float2(c[mt][nt][0], c[mt][nt][1]);
            *(float2*)&Cz[(size_t)(r0 + g + 8) * N + cc] = make_float2(c[mt][nt][2], c[mt][nt][3]);
        }
    }
}

// -------- gating: sum split-K partials, top-2, V combine, out mask -------------
__global__ void gate_combine_kernel(const float* __restrict__ glp,
                                    const float* __restrict__ proj,
                                    float* __restrict__ v,
                                    float* __restrict__ masko) {
    int token = blockIdx.x;
    int w = threadIdx.x / 32;
    int lane = threadIdx.x % 32;

    float g[EE];
#pragma unroll
    for (int e = 0; e < EE; e++) {
        float s = 0.f;
#pragma unroll
        for (int z = 0; z < KSPL; z++)
            s += glp[((size_t)z * NTOK + token) * NG + w * EE + e];
        g[e] = s;
    }
    int i1 = 0;
#pragma unroll
    for (int e = 1; e < EE; e++) if (g[e] > g[i1]) i1 = e;
    int i2 = (i1 == 0) ? 1 : 0;
#pragma unroll
    for (int e = 0; e < EE; e++) if (e != i1 && g[e] > g[i2]) i2 = e;
    float w1 = 1.f / (1.f + __expf(-g[i1]));
    float w2 = 1.f / (1.f + __expf(-g[i2]));

    const float* xvt = proj + (size_t)token * PW2 + OFF_XV;
    float* vt = v + (size_t)token * QKW + w * DH;
#pragma unroll
    for (int d = lane; d < DH; d += 32)
        vt[d] = w1 * xvt[i1 * DH + d] + w2 * xvt[i2 * DH + d];

#pragma unroll
    for (int e = 0; e < EE; e++) {
        float s = 0.f;
#pragma unroll
        for (int z = 0; z < KSPL; z++)
            s += glp[((size_t)z * NTOK + token) * NG + 40 + w * EE + e];
        g[e] = s;
    }
    int o1 = 0;
#pragma unroll
    for (int e = 1; e < EE; e++) if (g[e] > g[o1]) o1 = e;
    int o2 = (o1 == 0) ? 1 : 0;
#pragma unroll
    for (int e = 0; e < EE; e++) if (e != o1 && g[e] > g[o2]) o2 = e;
    if (lane < EE)
        masko[((size_t)token * HH + w) * EE + lane] = (lane == o1 || lane == o2) ? 1.f : 0.f;
}

// =============== build fp16 K/V fragment blob ==================================
// K slot (row=k0*32+lane, col=n0*2+w2): fp16x2 {K[key=n0*8+g][d=k0*16+w2*8+2t], [d+1]}
// V slots: Vh/Vl fp16x2 {V[key=k0*16+w2*8+2t][d=n0*8+g], V[key+1][d]}
__global__ void build_kv3_kernel(const float* __restrict__ proj,
                                 const float* __restrict__ v,
                                 uint32_t* __restrict__ blob) {
    __shared__ float Ks[64 * 68];
    __shared__ float Vs[64 * 68];
    const int tile = blockIdx.x, bh = blockIdx.y;
    const int b = bh / HH, h = bh % HH;
    const int tid = threadIdx.x;

#pragma unroll
    for (int it = 0; it < 4; it++) {
        int idx = it * 256 + tid;
        int r = (idx * 4) >> 6, d = (idx * 4) & 63;
        const float* kb = proj + (size_t)(b * TT + tile * 64 + r) * PW2 + OFF_K + h * DH;
        const float* vb = v    + (size_t)(b * TT + tile * 64 + r) * QKW + h * DH;
        *(float4*)&Ks[r * 68 + d] = *(const float4*)(kb + d);
        *(float4*)&Vs[r * 68 + d] = *(const float4*)(vb + d);
    }
    __syncthreads();

    uint32_t* dst = blob + ((size_t)bh * NTILE + tile) * TILE3_U32;
#pragma unroll
    for (int i = 0; i < 8; i++) {
        int oi = tid * 8 + i;            // 0..2047
        int row = oi >> 4;               // k0*32 + lane
        int col = oi & 15;               // n0*2 + w2
        int k0 = row >> 5, lane2 = row & 31;
        int g2 = lane2 >> 2, t2 = lane2 & 3;
        int n0 = col >> 1, w2 = col & 1;
        // K (single fp16)
        int dK = k0 * 16 + w2 * 8 + 2 * t2;
        int keyK = n0 * 8 + g2;
        dst[row * ROWPAD + col] = packh2(Ks[keyK * 68 + dK], Ks[keyK * 68 + dK + 1]);
        // V (fp16 hi/lo)
        int keyV = k0 * 16 + w2 * 8 + 2 * t2;
        int dV = n0 * 8 + g2;
        uint32_t hi, lo;
        splith2(Vs[keyV * 68 + dV], Vs[(keyV + 1) * 68 + dV], hi, lo);
        dst[ARR2_U32 + row * ROWPAD + col] = hi;
        dst[2 * ARR2_U32 + row * ROWPAD + col] = lo;
    }
}

// =============== flash attention, fp16 2-term, fragment blob + cp.async ========
#define LOG2E 1.4426950408889634f
#define SCLG2E (0.125f * LOG2E)      // fold attention scale into exp2 exponent
#define BLOB_CHUNKS (TILE3_U32/4)    // 1920

__global__ __launch_bounds__(256, 2)
void attn4_kernel(const float* __restrict__ qg,
                  const uint32_t* __restrict__ blob,
                  float* __restrict__ o) {
    extern __shared__ uint32_t sh[];     // 3 stages x TILE3_U32
    const int bh = blockIdx.y;
    const int b = bh / HH, h = bh % HH;
    const int q0 = blockIdx.x * 128;
    const int tid = threadIdx.x;
    const int lane = tid & 31, w = tid >> 5;
    const int g = lane >> 2, t = lane & 3;

    const uint32_t* gblob = blob + (size_t)bh * NTILE * TILE3_U32;
    const uint32_t sbase = (uint32_t)__cvta_generic_to_shared(sh);

#define BLOB_DMA(dstoff, srct)                                                   \
    {                                                                            \
        const uint32_t* src = gblob + (size_t)(srct) * TILE3_U32;                \
        _Pragma("unroll")                                                        \
        for (int i = 0; i < 8; i++) {                                            \
            int cc = tid + i * 256;                                              \
            if (cc < BLOB_CHUNKS) cp16(sbase + (uint32_t)(dstoff + cc * 4) * 4, src + cc * 4); \
        }                                                                        \
    }

    // prologue: stages 0,1 <- tiles 0,1
    BLOB_DMA(0, 0);
    CP_COMMIT();
    BLOB_DMA(TILE3_U32, 1);
    CP_COMMIT();

    // Q fragments fp16 hi/lo (no scale folding; scale applied in exponent)
    const float* qb = qg + (size_t)(b * TT + q0 + w * 16) * PW2 + h * DH;
    uint32_t qah[4][4], qal[4][4];
#pragma unroll
    for (int k0 = 0; k0 < 4; k0++) {
        splith2(qb[(size_t)(g    ) * PW2 + k0 * 16 + 2 * t],
                qb[(size_t)(g    ) * PW2 + k0 * 16 + 2 * t + 1], qah[k0][0], qal[k0][0]);
        splith2(qb[(size_t)(g + 8) * PW2 + k0 * 16 + 2 * t],
                qb[(size_t)(g + 8) * PW2 + k0 * 16 + 2 * t + 1], qah[k0][1], qal[k0][1]);
        splith2(qb[(size_t)(g    ) * PW2 + k0 * 16 + 2 * t + 8],
                qb[(size_t)(g    ) * PW2 + k0 * 16 + 2 * t + 9], qah[k0][2], qal[k0][2]);
        splith2(qb[(size_t)(g + 8) * PW2 + k0 * 16 + 2 * t + 8],
                qb[(size_t)(g + 8) * PW2 + k0 * 16 + 2 * t + 9], qah[k0][3], qal[k0][3]);
    }

    float om[8][4];
#pragma unroll
    for (int n = 0; n < 8; n++)
#pragma unroll
        for (int i = 0; i < 4; i++) om[n][i] = 0.f;
    float rm0 = -INFINITY, rm1 = -INFINITY, rl0 = 0.f, rl1 = 0.f;

    for (int tt = 0; tt < NTILE; tt++) {
        const int st = tt % 3;
        if (tt + 2 < NTILE) {
            BLOB_DMA(((tt + 2) % 3) * TILE3_U32, tt + 2);
            CP_COMMIT();
            CP_WAIT(2);
        } else if (tt + 1 < NTILE) {
            CP_WAIT(1);
        } else {
            CP_WAIT(0);
        }
        __syncthreads();

        const uint32_t* Kf = sh + st * TILE3_U32;
        const uint32_t* Vh = Kf + ARR2_U32;
        const uint32_t* Vl = Kf + 2 * ARR2_U32;

        // ---- S_raw = Q @ K^T (fp16 2-term) ------------------------------------
        float s[8][4];
#pragma unroll
        for (int n = 0; n < 8; n++)
#pragma unroll
            for (int i = 0; i < 4; i++) s[n][i] = 0.f;
#pragma unroll
        for (int k0 = 0; k0 < 4; k0++) {
            const uint32_t* kr = Kf + (k0 * 32 + lane) * ROWPAD;
#pragma unroll
            for (int np = 0; np < 4; np++) {
                uint4 k4 = *(const uint4*)(kr + np * 4);
                uint32_t b2[2] = {k4.x, k4.y};
                mma_f16(s[2 * np], qal[k0], b2);
                mma_f16(s[2 * np], qah[k0], b2);
                uint32_t b3[2] = {k4.z, k4.w};
                mma_f16(s[2 * np + 1], qal[k0], b3);
                mma_f16(s[2 * np + 1], qah[k0], b3);
            }
        }

        // ---- online softmax (scale folded into exponent constant) -------------
        float m0 = s[0][0], m1 = s[0][2];
#pragma unroll
        for (int n = 0; n < 8; n++) {
            m0 = fmaxf(m0, fmaxf(s[n][0], s[n][1]));
            m1 = fmaxf(m1, fmaxf(s[n][2], s[n][3]));
        }
        m0 = fmaxf(m0, __shfl_xor_sync(0xffffffff, m0, 1));
        m0 = fmaxf(m0, __shfl_xor_sync(0xffffffff, m0, 2));
        m1 = fmaxf(m1, __shfl_xor_sync(0xffffffff, m1, 1));
        m1 = fmaxf(m1, __shfl_xor_sync(0xffffffff, m1, 2));

        float mn0 = fmaxf(rm0, m0);
        float mn1 = fmaxf(rm1, m1);
        float corr0 = exp2f((rm0 - mn0) * SCLG2E);
        float corr1 = exp2f((rm1 - mn1) * SCLG2E);

        float sum0 = 0.f, sum1 = 0.f;
#pragma unroll
        for (int n = 0; n < 8; n++) {
            s[n][0] = exp2f((s[n][0] - mn0) * SCLG2E);
            s[n][1] = exp2f((s[n][1] - mn0) * SCLG2E);
            s[n][2] = exp2f((s[n][2] - mn1) * SCLG2E);
            s[n][3] = exp2f((s[n][3] - mn1) * SCLG2E);
            sum0 += s[n][0] + s[n][1];
            sum1 += s[n][2] + s[n][3];
        }
        sum0 += __shfl_xor_sync(0xffffffff, sum0, 1);
        sum0 += __shfl_xor_sync(0xffffffff, sum0, 2);
        sum1 += __shfl_xor_sync(0xffffffff, sum1, 1);
        sum1 += __shfl_xor_sync(0xffffffff, sum1, 2);
        rl0 = rl0 * corr0 + sum0;
        rl1 = rl1 * corr1 + sum1;
        rm0 = mn0; rm1 = mn1;

#pragma unroll
        for (int n = 0; n < 8; n++) {
            om[n][0] *= corr0; om[n][1] *= corr0;
            om[n][2] *= corr1; om[n][3] *= corr1;
        }

        // ---- O += P @ (Vh+Vl) (fp16 2-term); P A-frag built locally ------------
#pragma unroll
        for (int k0 = 0; k0 < 4; k0++) {
            uint32_t ph[4];
            ph[0] = packh2(s[2 * k0][0],     s[2 * k0][1]);
            ph[1] = packh2(s[2 * k0][2],     s[2 * k0][3]);
            ph[2] = packh2(s[2 * k0 + 1][0], s[2 * k0 + 1][1]);
            ph[3] = packh2(s[2 * k0 + 1][2], s[2 * k0 + 1][3]);
            const uint32_t* vr = Vh + (k0 * 32 + lane) * ROWPAD;
            const uint32_t* wr = Vl + (k0 * 32 + lane) * ROWPAD;
#pragma unroll
            for (int np = 0; np < 4; np++) {
                uint4 vh4 = *(const uint4*)(vr + np * 4);
                uint4 vl4 = *(const uint4*)(wr + np * 4);
                uint32_t b2[2] = {vl4.x, vl4.y};
                mma_f16(om[2 * np], ph, b2);
                uint32_t b2h[2] = {vh4.x, vh4.y};
                mma_f16(om[2 * np], ph, b2h);
                uint32_t b3[2] = {vl4.z, vl4.w};
                mma_f16(om[2 * np + 1], ph, b3);
                uint32_t b3h[2] = {vh4.z, vh4.w};
                mma_f16(om[2 * np + 1], ph, b3h);
            }
        }
        __syncthreads();
    }

    float inv0 = 1.f / rl0;
    float inv1 = 1.f / rl1;
    float* ob0 = o + (size_t)(b * TT + q0 + w * 16 + g    ) * QKW + h * DH + 2 * t;
    float* ob1 = o + (size_t)(b * TT + q0 + w * 16 + g + 8) * QKW + h * DH + 2 * t;
#pragma unroll
    for (int n0 = 0; n0 < 8; n0++) {
        *(float2*)(ob0 + n0 * 8) = make_float2(om[n0][0] * inv0, om[n0][1] * inv0);
        *(float2*)(ob1 + n0 * 8) = make_float2(om[n0][2] * inv1, om[n0][3] * inv1);
    }
}

// -------- Y pairs: Y[t, 2i..2i+1] = sum_h mask*attn, split to fp16 hi/lo -------
__global__ void combine_out_kernel(const float* __restrict__ attn,
                                   const float* __restrict__ masko,
                                   uint32_t* __restrict__ Yh,
                                   uint32_t* __restrict__ Yl) {
    int token = blockIdx.x;
    int tid = threadIdx.x;          // 0..159
    int t0 = 2 * tid;
    int e = t0 >> 6, j = t0 & 63;
    const float* ap = attn + (size_t)token * QKW;
    const float* mp = masko + (size_t)token * GW;
    float s0 = 0.f, s1 = 0.f;
#pragma unroll
    for (int h = 0; h < HH; h++) {
        float m = mp[h * EE + e];
        s0 += m * ap[h * DH + j];
        s1 += m * ap[h * DH + j + 1];
    }
    uint32_t hi, lo;
    splith2(s0, s1, hi, lo);
    Yh[(size_t)token * (XVW / 2) + tid] = hi;
    Yl[(size_t)token * (XVW / 2) + tid] = lo;
}

// ------------------------------- launch ----------------------------------------
extern "C" void kernel_launch(void* const* d_in, const int* in_sizes, int n_in,
                              void* d_out, int out_size) {
    const float* x  = (const float*)d_in[0];
    const float* Wq = (const float*)d_in[1];
    const float* Wk = (const float*)d_in[2];
    const float* Ws = (const float*)d_in[3];
    const float* Wd = (const float*)d_in[4];
    const float* Wv = (const float*)d_in[5];
    const float* Wo = (const float*)d_in[6];
    float* out = (float*)d_out;

    float *proj, *glp, *v, *attn, *mask;
    uint32_t *xbh, *xbl, *wt, *xth, *xtl, *gwh, *gwl, *ybh, *ybl, *wot, *blob;
    cudaGetSymbolAddress((void**)&proj, g_proj);
    cudaGetSymbolAddress((void**)&xbh,  g_xbh);
    cudaGetSymbolAddress((void**)&xbl,  g_xbl);
    cudaGetSymbolAddress((void**)&wt,   g_wt);
    cudaGetSymbolAddress((void**)&xth,  g_xth);
    cudaGetSymbolAddress((void**)&xtl,  g_xtl);
    cudaGetSymbolAddress((void**)&gwh,  g_gwh);
    cudaGetSymbolAddress((void**)&gwl,  g_gwl);
    cudaGetSymbolAddress((void**)&glp,  g_glp);
    cudaGetSymbolAddress((void**)&v,    g_v);
    cudaGetSymbolAddress((void**)&attn, g_attn);
    cudaGetSymbolAddress((void**)&mask, g_mask);
    cudaGetSymbolAddress((void**)&ybh,  g_ybh);
    cudaGetSymbolAddress((void**)&ybl,  g_ybl);
    cudaGetSymbolAddress((void**)&wot,  g_wot);
    cudaGetSymbolAddress((void**)&blob, g_blob);

    // pre-splits / packs (x read once)
    split_x_all <<<(int)(((size_t)NTOK * DD / 2 + 255) / 256), 256>>>(x, xbh, xbl, xth, xtl);
    pack_wt_f16 <<<(int)(((size_t)PW2 * DD / 2 + 255) / 256), 256>>>(Wq, Wk, Wv, wt);
    pack_gw_tf32<<<(DD * NG + 255) / 256, 256>>>(Ws, Wd, gwh, gwl);
    pack_wot_f16<<<(int)(((size_t)DD * XVW / 2 + 255) / 256), 256>>>(Wo, wot);

    // proj GEMM (fp16 2-term, 3-stage): (8192x1024)@(1024x1344)
    size_t hsm = (size_t)3 * H2_STG * sizeof(uint32_t);   // 76800
    cudaFuncSetAttribute(tgemmh2, cudaFuncAttributeMaxDynamicSharedMemorySize, (int)hsm);
    dim3 gp(PW2 / 64, NTOK / 128);
    tgemmh2<<<gp, 256, hsm>>>(xbh, xbl, wt, proj, NTOK, PW2, DD);

    // gate GEMM (3xTF32, split-K=4): (8192x1024)@(1024x128) -> partials
    size_t gsm = (size_t)2 * STG3 * sizeof(uint32_t);     // 143360
    cudaFuncSetAttribute(tgemm3s, cudaFuncAttributeMaxDynamicSharedMemorySize, (int)gsm);
    dim3 gg(NG / 128, NTOK / 128, KSPL);
    tgemm3s<<<gg, 256, gsm>>>(xth, xtl, gwh, gwl, glp, NTOK, NG, DD);

    // gating + V combine + out-mask
    gate_combine_kernel<<<NTOK, 256>>>(glp, proj, v, mask);

    // K/V fragment blob (fp16)
    dim3 bg(NTILE, BB * HH);
    build_kv3_kernel<<<bg, 256>>>(proj, v, blob);

    // attention (fp16 2-term, 3-stage)
    size_t asmem = (size_t)3 * TILE3_U32 * sizeof(uint32_t);  // 92160
    cudaFuncSetAttribute(attn4_kernel, cudaFuncAttributeMaxDynamicSharedMemorySize, (int)asmem);
    dim3 ag(TT / 128, BB * HH);
    attn4_kernel<<<ag, 256, asmem>>>(proj, blob, attn);

    // masked combine (+fp16 split), then output GEMM: (8192x320)@(320x1024)
    combine_out_kernel<<<NTOK, XVW / 2>>>(attn, mask, ybh, ybl);
    dim3 go(DD / 64, NTOK / 128);
    tgemmh2<<<go, 256, hsm>>>(ybh, ybl, wot, out, NTOK, DD, XVW);
}

// round 11
// speedup vs baseline: 13.8591x; 1.1692x over previous
#include <cuda_runtime.h>
#include <cuda_bf16.h>
#include <cuda_fp16.h>
#include <math.h>
#include <stdint.h>

// Problem constants
#define BB 4
#define TT 2048
#define DD 1024
#define HH 8
#define DH 64
#define EE 5
#define NTOK (BB*TT)          // 8192
#define QKW (HH*DH)           // 512
#define GW  (HH*EE)           // 40
#define XVW (EE*DH)           // 320

// fused projection layout (row stride PW2): q[0:512) | k[512:1024) | xv[1024:1344)
#define PW2 1344
#define OFF_K 512
#define OFF_XV 1024

#define NG 128                 // gate GEMM padded width (glv 0..39, glo 40..79)
#define KSPL 4                 // gate GEMM split-K

// fp16 KV fragment blob: per (bh,tile64): [K | V], each 4 k0 x 32 lanes x 20 u32
#define ROWPAD 20
#define ARR2_U32 (4*32*ROWPAD)    // 2560
#define TILE4_U32 (2*ARR2_U32)    // 5120 u32 = 20KB
#define NTILE 32

// ---------------- scratch (device globals) ------------------------------------
__device__ float    g_proj [(size_t)NTOK*PW2];
__device__ __align__(16) uint32_t g_xbh [(size_t)NTOK*DD/2];   // fp16 hi pairs of x
__device__ __align__(16) uint32_t g_xbl [(size_t)NTOK*DD/2];   // fp16 lo pairs
__device__ __align__(16) uint32_t g_wt  [(size_t)PW2*DD/2];    // Wt[n][dpair] fp16 (single)
__device__ __align__(16) uint32_t g_xth [(size_t)NTOK*DD];     // tf32 hi of x (gates)
__device__ __align__(16) uint32_t g_xtl [(size_t)NTOK*DD];
__device__ __align__(16) uint32_t g_gwh [(size_t)DD*NG];       // tf32 gate weights
__device__ __align__(16) uint32_t g_gwl [(size_t)DD*NG];
__device__ float    g_glp  [(size_t)KSPL*NTOK*NG];             // gate partials
__device__ float    g_v    [(size_t)NTOK*QKW];
__device__ float    g_attn [(size_t)NTOK*QKW];
__device__ float    g_mask [(size_t)NTOK*GW];
__device__ __align__(16) uint32_t g_ybh [(size_t)NTOK*XVW/2];  // fp16 hi pairs of Y
__device__ __align__(16) uint32_t g_ybl [(size_t)NTOK*XVW/2];
__device__ __align__(16) uint32_t g_wot [(size_t)DD*XVW/2];    // WoT[n=d][kpair] fp16
__device__ __align__(16) uint32_t g_blob[(size_t)BB*HH*NTILE*TILE4_U32];  // ~21MB

// ---------------- helpers ------------------------------------------------------
__device__ __forceinline__ uint32_t f2tf32(float x) {
    uint32_t r;
    asm("cvt.rna.tf32.f32 %0, %1;" : "=r"(r) : "f"(x));
    return r;
}
__device__ __forceinline__ void split_tf32(float x, uint32_t& h, uint32_t& l) {
    h = f2tf32(x);
    l = f2tf32(x - __uint_as_float(h));
}
// pack (a,b) into fp16x2 word; a -> bits[15:0]
__device__ __forceinline__ uint32_t packh2(float a, float b) {
    __half2 h = __floats2half2_rn(a, b);
    return *reinterpret_cast<uint32_t*>(&h);
}
// split pair (a,b) into fp16x2 hi and lo words
__device__ __forceinline__ void splith2(float a, float b, uint32_t& h, uint32_t& l) {
    __half ha = __float2half_rn(a);
    __half hb = __float2half_rn(b);
    float ra = a - __half2float(ha);
    float rb = b - __half2float(hb);
    __half2 hh; hh.x = ha; hh.y = hb;
    __half2 ll; ll.x = __float2half_rn(ra); ll.y = __float2half_rn(rb);
    h = *reinterpret_cast<uint32_t*>(&hh);
    l = *reinterpret_cast<uint32_t*>(&ll);
}
__device__ __forceinline__ void mma_tf32(float c[4], const uint32_t a[4], const uint32_t b[2]) {
    asm volatile(
        "mma.sync.aligned.m16n8k8.row.col.f32.tf32.tf32.f32 "
        "{%0,%1,%2,%3},{%4,%5,%6,%7},{%8,%9},{%0,%1,%2,%3};"
        : "+f"(c[0]), "+f"(c[1]), "+f"(c[2]), "+f"(c[3])
        : "r"(a[0]), "r"(a[1]), "r"(a[2]), "r"(a[3]), "r"(b[0]), "r"(b[1]));
}
__device__ __forceinline__ void mma_f16(float c[4], const uint32_t a[4], const uint32_t b[2]) {
    asm volatile(
        "mma.sync.aligned.m16n8k16.row.col.f32.f16.f16.f32 "
        "{%0,%1,%2,%3},{%4,%5,%6,%7},{%8,%9},{%0,%1,%2,%3};"
        : "+f"(c[0]), "+f"(c[1]), "+f"(c[2]), "+f"(c[3])
        : "r"(a[0]), "r"(a[1]), "r"(a[2]), "r"(a[3]), "r"(b[0]), "r"(b[1]));
}
__device__ __forceinline__ void cp16(uint32_t saddr, const void* g) {
    asm volatile("cp.async.cg.shared.global [%0], [%1], 16;\n" :: "r"(saddr), "l"(g));
}
#define CP_COMMIT() asm volatile("cp.async.commit_group;\n")
#define CP_WAIT(n)  asm volatile("cp.async.wait_group %0;\n" :: "n"(n))

// =============== pre-split / pack kernels ======================================
__global__ void split_x_all(const float* __restrict__ x,
                            uint32_t* __restrict__ xbh, uint32_t* __restrict__ xbl,
                            uint32_t* __restrict__ xth, uint32_t* __restrict__ xtl) {
    size_t i = (size_t)blockIdx.x * blockDim.x + threadIdx.x;
    if (i >= (size_t)NTOK * DD / 2) return;
    float a = x[2 * i], b = x[2 * i + 1];
    splith2(a, b, xbh[i], xbl[i]);
    split_tf32(a, xth[2 * i], xtl[2 * i]);
    split_tf32(b, xth[2 * i + 1], xtl[2 * i + 1]);
}
__global__ void pack_wt_f16(const float* __restrict__ Wq, const float* __restrict__ Wk,
                            const float* __restrict__ Wv, uint32_t* __restrict__ Wt) {
    size_t idx = (size_t)blockIdx.x * blockDim.x + threadIdx.x;
    if (idx >= (size_t)PW2 * DD / 2) return;
    int n = (int)(idx / (DD / 2));
    int dp = (int)(idx % (DD / 2));
    int d0 = 2 * dp;
    float va, vb;
    if (n < 512) {
        va = Wq[(size_t)d0 * 512 + n]; vb = Wq[(size_t)(d0 + 1) * 512 + n];
    } else if (n < 1024) {
        va = Wk[(size_t)d0 * 512 + (n - 512)]; vb = Wk[(size_t)(d0 + 1) * 512 + (n - 512)];
    } else {
        int e = (n - 1024) / DH, j = (n - 1024) % DH;
        va = Wv[((size_t)e * DD + d0) * DH + j];
        vb = Wv[((size_t)e * DD + d0 + 1) * DH + j];
    }
    Wt[idx] = packh2(va, vb);
}
__global__ void pack_gw_tf32(const float* __restrict__ Ws, const float* __restrict__ Wd,
                             uint32_t* __restrict__ Wh, uint32_t* __restrict__ Wl) {
    int idx = blockIdx.x * blockDim.x + threadIdx.x;
    if (idx >= DD * NG) return;
    int d = idx / NG, n = idx % NG;
    float val = 0.f;
    if (n < 40)      val = Ws[(size_t)d * GW + n];
    else if (n < 80) val = Wd[(size_t)d * GW + (n - 40)];
    split_tf32(val, Wh[idx], Wl[idx]);
}
__global__ void pack_wot_f16(const float* __restrict__ Wo, uint32_t* __restrict__ Wt) {
    size_t idx = (size_t)blockIdx.x * blockDim.x + threadIdx.x;
    if (idx >= (size_t)DD * XVW / 2) return;
    int n = (int)(idx / (XVW / 2));
    int kp = (int)(idx % (XVW / 2));
    int k0 = 2 * kp;
    int e = k0 >> 6, j = k0 & 63;
    float va = Wo[((size_t)(e * DH + j)) * DD + n];
    float vb = Wo[((size_t)(e * DH + j + 1)) * DD + n];
    Wt[idx] = packh2(va, vb);
}

// =============== fp16 2-term GEMM: C=A@Bt^T, BM=128,BN=64,BK=32, 3-stage =======
// A: [M][K/2] u32 fp16-pairs (hi/lo arrays); Bt: [N][K/2] fp16-pairs (single)
#define H2_OFF_AL 2560
#define H2_OFF_B  5120
#define H2_STG    6400     // u32 per stage (25.6KB)

__global__ __launch_bounds__(256, 2)
void tgemmh2(const uint32_t* __restrict__ Agh, const uint32_t* __restrict__ Agl,
             const uint32_t* __restrict__ Bg,
             float* __restrict__ C, int M, int N, int K) {
    extern __shared__ uint32_t sm2[];   // 3 stages x H2_STG
    const int tid = threadIdx.x;
    const int row0 = blockIdx.y * 128;
    const int col0 = blockIdx.x * 64;
    const int lane = tid & 31, w = tid >> 5;
    const int g = lane >> 2, t = lane & 3;
    const int wm = w >> 1, wn = w & 1;      // warp tile 32x32
    const int Ku = K / 2;

    const uint32_t sb = (uint32_t)__cvta_generic_to_shared(sm2);

    float c[2][4][4];
#pragma unroll
    for (int mt = 0; mt < 2; mt++)
#pragma unroll
        for (int nt = 0; nt < 4; nt++)
#pragma unroll
            for (int i = 0; i < 4; i++) c[mt][nt][i] = 0.f;

    const int nk = K / 32;

#define H2_LOAD(dst, kt)                                                          \
    {                                                                             \
        int ko = (kt) * 16;                                                       \
        _Pragma("unroll")                                                         \
        for (int it = 0; it < 2; it++) {                                          \
            int idx = it * 256 + tid;                                             \
            int r = idx >> 2, cc = idx & 3;                                       \
            cp16((dst) + (uint32_t)(r * ROWPAD + cc * 4) * 4,                     \
                 Agh + (size_t)(row0 + r) * Ku + ko + cc * 4);                    \
            cp16((dst) + (uint32_t)(H2_OFF_AL + r * ROWPAD + cc * 4) * 4,         \
                 Agl + (size_t)(row0 + r) * Ku + ko + cc * 4);                    \
        }                                                                         \
        {                                                                         \
            int r = tid >> 2, cc = tid & 3;                                       \
            cp16((dst) + (uint32_t)(H2_OFF_B + r * ROWPAD + cc * 4) * 4,          \
                 Bg + (size_t)(col0 + r) * Ku + ko + cc * 4);                     \
        }                                                                         \
    }

    // prologue: stages 0,1 <- ktiles 0,1
    H2_LOAD(sb, 0);
    CP_COMMIT();
    if (nk > 1) {
        H2_LOAD(sb + (uint32_t)H2_STG * 4, 1);
        CP_COMMIT();
    }

    for (int kt = 0; kt < nk; kt++) {
        const int st = kt % 3;
        if (kt + 2 < nk) {
            uint32_t d2 = sb + (uint32_t)(((kt + 2) % 3) * H2_STG) * 4;
            H2_LOAD(d2, kt + 2);
            CP_COMMIT();
            CP_WAIT(2);
        } else if (kt + 1 < nk) {
            CP_WAIT(1);
        } else {
            CP_WAIT(0);
        }
        __syncthreads();

        const uint32_t* Ah = sm2 + st * H2_STG;
        const uint32_t* Al = Ah + H2_OFF_AL;
        const uint32_t* Bs = Ah + H2_OFF_B;

#pragma unroll
        for (int kc = 0; kc < 2; kc++) {
            uint32_t afh[2][4], afl[2][4], bf[4][2];
#pragma unroll
            for (int mt = 0; mt < 2; mt++) {
                int rb = wm * 32 + mt * 16;
                afh[mt][0] = Ah[(rb + g    ) * ROWPAD + kc * 8 + t];
                afh[mt][1] = Ah[(rb + g + 8) * ROWPAD + kc * 8 + t];
                afh[mt][2] = Ah[(rb + g    ) * ROWPAD + kc * 8 + t + 4];
                afh[mt][3] = Ah[(rb + g + 8) * ROWPAD + kc * 8 + t + 4];
                afl[mt][0] = Al[(rb + g    ) * ROWPAD + kc * 8 + t];
                afl[mt][1] = Al[(rb + g + 8) * ROWPAD + kc * 8 + t];
                afl[mt][2] = Al[(rb + g    ) * ROWPAD + kc * 8 + t + 4];
                afl[mt][3] = Al[(rb + g + 8) * ROWPAD + kc * 8 + t + 4];
            }
#pragma unroll
            for (int nt = 0; nt < 4; nt++) {
                int cb = wn * 32 + nt * 8;
                bf[nt][0] = Bs[(cb + g) * ROWPAD + kc * 8 + t];
                bf[nt][1] = Bs[(cb + g) * ROWPAD + kc * 8 + t + 4];
            }
#pragma unroll
            for (int mt = 0; mt < 2; mt++)
#pragma unroll
                for (int nt = 0; nt < 4; nt++) {
                    mma_f16(c[mt][nt], afl[mt], bf[nt]);
                    mma_f16(c[mt][nt], afh[mt], bf[nt]);
                }
        }
        __syncthreads();
    }

#pragma unroll
    for (int mt = 0; mt < 2; mt++) {
        int r0 = row0 + wm * 32 + mt * 16;
#pragma unroll
        for (int nt = 0; nt < 4; nt++) {
            int cc = col0 + wn * 32 + nt * 8 + 2 * t;
            *(float2*)&C[(size_t)(r0 + g    ) * N + cc] = make_float2(c[mt][nt][0], c[mt][nt][1]);
            *(float2*)&C[(size_t)(r0 + g + 8) * N + cc] = make_float2(c[mt][nt][2], c[mt][nt][3]);
        }
    }
}

// =============== 3xTF32 GEMM (gates only), split-K via gridDim.z ===============
#define SA 36
#define SB 136
#define OFF_AL3 4608
#define OFF_BH3 9216
#define OFF_BL3 13568
#define STG3 17920

__device__ __forceinline__ void gemm3_stage_load(
    uint32_t dst, const uint32_t* __restrict__ Agh, const uint32_t* __restrict__ Agl,
    const uint32_t* __restrict__ Bgh, const uint32_t* __restrict__ Bgl,
    int row0, int col0, int k0, int K, int N, int tid) {
#pragma unroll
    for (int it = 0; it < 4; it++) {
        int idx = it * 1024 + tid * 4;
        int ar = idx >> 5, ac = idx & 31;
        cp16(dst + (uint32_t)(ar * SA + ac) * 4, Agh + (size_t)(row0 + ar) * K + k0 + ac);
        cp16(dst + (uint32_t)(OFF_AL3 + ar * SA + ac) * 4, Agl + (size_t)(row0 + ar) * K + k0 + ac);
        int br = idx >> 7, bc = idx & 127;
        cp16(dst + (uint32_t)(OFF_BH3 + br * SB + bc) * 4, Bgh + (size_t)(k0 + br) * N + col0 + bc);
        cp16(dst + (uint32_t)(OFF_BL3 + br * SB + bc) * 4, Bgl + (size_t)(k0 + br) * N + col0 + bc);
    }
}

__global__ __launch_bounds__(256)
void tgemm3s(const uint32_t* __restrict__ Agh, const uint32_t* __restrict__ Agl,
             const uint32_t* __restrict__ Bgh, const uint32_t* __restrict__ Bgl,
             float* __restrict__ C, int M, int N, int K) {
    extern __shared__ uint32_t sm[];
    const int tid = threadIdx.x;
    const int row0 = blockIdx.y * 128;
    const int col0 = blockIdx.x * 128;
    const int lane = tid & 31, w = tid >> 5;
    const int g = lane >> 2, t = lane & 3;
    const int wm = w >> 1, wn = w & 1;
    const int ksplit = gridDim.z;
    const int kb = blockIdx.z * (K / ksplit);
    const int nk = K / 32 / ksplit;
    float* Cz = C + (size_t)blockIdx.z * M * N;

    const uint32_t sb = (uint32_t)__cvta_generic_to_shared(sm);

    float c[2][8][4];
#pragma unroll
    for (int mt = 0; mt < 2; mt++)
#pragma unroll
        for (int nt = 0; nt < 8; nt++)
#pragma unroll
            for (int i = 0; i < 4; i++) c[mt][nt][i] = 0.f;

    gemm3_stage_load(sb, Agh, Agl, Bgh, Bgl, row0, col0, kb, K, N, tid);
    CP_COMMIT();

    for (int kt = 0; kt < nk; kt++) {
        const int st = kt & 1;
        if (kt + 1 < nk) {
            uint32_t d2 = sb + (uint32_t)((st ^ 1) * STG3) * 4;
            gemm3_stage_load(d2, Agh, Agl, Bgh, Bgl, row0, col0, kb + (kt + 1) * 32, K, N, tid);
            CP_COMMIT();
            CP_WAIT(1);
        } else {
            CP_WAIT(0);
        }
        __syncthreads();

        const uint32_t* Ah = sm + st * STG3;
        const uint32_t* Al = Ah + OFF_AL3;
        const uint32_t* Bh = Ah + OFF_BH3;
        const uint32_t* Bl = Ah + OFF_BL3;

#pragma unroll
        for (int kc = 0; kc < 4; kc++) {
            uint32_t afh[2][4], afl[2][4], bfh[8][2], bfl[8][2];
#pragma unroll
            for (int mt = 0; mt < 2; mt++) {
                int rb = wm * 32 + mt * 16;
                afh[mt][0] = Ah[(rb + g    ) * SA + kc * 8 + t];
                afh[mt][1] = Ah[(rb + g + 8) * SA + kc * 8 + t];
                afh[mt][2] = Ah[(rb + g    ) * SA + kc * 8 + t + 4];
                afh[mt][3] = Ah[(rb + g + 8) * SA + kc * 8 + t + 4];
                afl[mt][0] = Al[(rb + g    ) * SA + kc * 8 + t];
                afl[mt][1] = Al[(rb + g + 8) * SA + kc * 8 + t];
                afl[mt][2] = Al[(rb + g    ) * SA + kc * 8 + t + 4];
                afl[mt][3] = Al[(rb + g + 8) * SA + kc * 8 + t + 4];
            }
#pragma unroll
            for (int nt = 0; nt < 8; nt++) {
                int cb = wn * 64 + nt * 8;
                bfh[nt][0] = Bh[(kc * 8 + t    ) * SB + cb + g];
                bfh[nt][1] = Bh[(kc * 8 + t + 4) * SB + cb + g];
                bfl[nt][0] = Bl[(kc * 8 + t    ) * SB + cb + g];
                bfl[nt][1] = Bl[(kc * 8 + t + 4) * SB + cb + g];
            }
#pragma unroll
            for (int mt = 0; mt < 2; mt++)
#pragma unroll
                for (int nt = 0; nt < 8; nt++) {
                    mma_tf32(c[mt][nt], afh[mt], bfl[nt]);
                    mma_tf32(c[mt][nt], afl[mt], bfh[nt]);
                    mma_tf32(c[mt][nt], afh[mt], bfh[nt]);
                }
        }
        __syncthreads();
    }

#pragma unroll
    for (int mt = 0; mt < 2; mt++) {
        int r0 = row0 + wm * 32 + mt * 16;
#pragma unroll
        for (int nt = 0; nt < 8; nt++) {
            int cc = col0 + wn * 64 + nt * 8 + 2 * t;
            *(float2*)&Cz[(size_t)(r0 + g    ) * N + cc] = make_float2(c[mt][nt][0], c[mt][nt][1]);
            *(float2*)&Cz[(size_t)(r0 + g + 8) * N + cc] = make_float2(c[mt][nt][2], c[mt][nt][3]);
        }
    }
}

// -------- gating: sum split-K partials, top-2, V combine, out mask -------------
__global__ void gate_combine_kernel(const float* __restrict__ glp,
                                    const float* __restrict__ proj,
                                    float* __restrict__ v,
                                    float* __restrict__ masko) {
    int token = blockIdx.x;
    int w = threadIdx.x / 32;
    int lane = threadIdx.x % 32;

    float g[EE];
#pragma unroll
    for (int e = 0; e < EE; e++) {
        float s = 0.f;
#pragma unroll
        for (int z = 0; z < KSPL; z++)
            s += glp[((size_t)z * NTOK + token) * NG + w * EE + e];
        g[e] = s;
    }
    int i1 = 0;
#pragma unroll
    for (int e = 1; e < EE; e++) if (g[e] > g[i1]) i1 = e;
    int i2 = (i1 == 0) ? 1 : 0;
#pragma unroll
    for (int e = 0; e < EE; e++) if (e != i1 && g[e] > g[i2]) i2 = e;
    float w1 = 1.f / (1.f + __expf(-g[i1]));
    float w2 = 1.f / (1.f + __expf(-g[i2]));

    const float* xvt = proj + (size_t)token * PW2 + OFF_XV;
    float* vt = v + (size_t)token * QKW + w * DH;
#pragma unroll
    for (int d = lane; d < DH; d += 32)
        vt[d] = w1 * xvt[i1 * DH + d] + w2 * xvt[i2 * DH + d];

#pragma unroll
    for (int e = 0; e < EE; e++) {
        float s = 0.f;
#pragma unroll
        for (int z = 0; z < KSPL; z++)
            s += glp[((size_t)z * NTOK + token) * NG + 40 + w * EE + e];
        g[e] = s;
    }
    int o1 = 0;
#pragma unroll
    for (int e = 1; e < EE; e++) if (g[e] > g[o1]) o1 = e;
    int o2 = (o1 == 0) ? 1 : 0;
#pragma unroll
    for (int e = 0; e < EE; e++) if (e != o1 && g[e] > g[o2]) o2 = e;
    if (lane < EE)
        masko[((size_t)token * HH + w) * EE + lane] = (lane == o1 || lane == o2) ? 1.f : 0.f;
}

// =============== build fp16 K/V fragment blob (single-precision fp16) ==========
// K slot (row=k0*32+lane, col=n0*2+w2): fp16x2 {K[key=n0*8+g][d=k0*16+w2*8+2t], [d+1]}
// V slot: fp16x2 {V[key=k0*16+w2*8+2t][d=n0*8+g], V[key+1][d]}
__global__ void build_kv4_kernel(const float* __restrict__ proj,
                                 const float* __restrict__ v,
                                 uint32_t* __restrict__ blob) {
    __shared__ float Ks[64 * 68];
    __shared__ float Vs[64 * 68];
    const int tile = blockIdx.x, bh = blockIdx.y;
    const int b = bh / HH, h = bh % HH;
    const int tid = threadIdx.x;

#pragma unroll
    for (int it = 0; it < 4; it++) {
        int idx = it * 256 + tid;
        int r = (idx * 4) >> 6, d = (idx * 4) & 63;
        const float* kb = proj + (size_t)(b * TT + tile * 64 + r) * PW2 + OFF_K + h * DH;
        const float* vb = v    + (size_t)(b * TT + tile * 64 + r) * QKW + h * DH;
        *(float4*)&Ks[r * 68 + d] = *(const float4*)(kb + d);
        *(float4*)&Vs[r * 68 + d] = *(const float4*)(vb + d);
    }
    __syncthreads();

    uint32_t* dst = blob + ((size_t)bh * NTILE + tile) * TILE4_U32;
#pragma unroll
    for (int i = 0; i < 8; i++) {
        int oi = tid * 8 + i;            // 0..2047
        int row = oi >> 4;               // k0*32 + lane
        int col = oi & 15;               // n0*2 + w2
        int k0 = row >> 5, lane2 = row & 31;
        int g2 = lane2 >> 2, t2 = lane2 & 3;
        int n0 = col >> 1, w2 = col & 1;
        // K
        int dK = k0 * 16 + w2 * 8 + 2 * t2;
        int keyK = n0 * 8 + g2;
        dst[row * ROWPAD + col] = packh2(Ks[keyK * 68 + dK], Ks[keyK * 68 + dK + 1]);
        // V
        int keyV = k0 * 16 + w2 * 8 + 2 * t2;
        int dV = n0 * 8 + g2;
        dst[ARR2_U32 + row * ROWPAD + col] = packh2(Vs[keyV * 68 + dV], Vs[(keyV + 1) * 68 + dV]);
    }
}

// =============== flash attention, pure fp16, fragment blob + cp.async ==========
#define LOG2E 1.4426950408889634f
#define SCLG2E (0.125f * LOG2E)      // fold attention scale into exp2 exponent
#define BLOB_CHUNKS (TILE4_U32/4)    // 1280

__global__ __launch_bounds__(256, 2)
void attn5_kernel(const float* __restrict__ qg,
                  const uint32_t* __restrict__ blob,
                  float* __restrict__ o) {
    extern __shared__ uint32_t sh[];     // 3 stages x TILE4_U32
    const int bh = blockIdx.y;
    const int b = bh / HH, h = bh % HH;
    const int q0 = blockIdx.x * 128;
    const int tid = threadIdx.x;
    const int lane = tid & 31, w = tid >> 5;
    const int g = lane >> 2, t = lane & 3;

    const uint32_t* gblob = blob + (size_t)bh * NTILE * TILE4_U32;
    const uint32_t sbase = (uint32_t)__cvta_generic_to_shared(sh);

#define BLOB_DMA(dstoff, srct)                                                   \
    {                                                                            \
        const uint32_t* src = gblob + (size_t)(srct) * TILE4_U32;                \
        _Pragma("unroll")                                                        \
        for (int i = 0; i < 5; i++) {                                            \
            int cc = tid + i * 256;                                              \
            cp16(sbase + (uint32_t)((dstoff) + cc * 4) * 4, src + cc * 4);       \
        }                                                                        \
    }

    // prologue: stages 0,1 <- tiles 0,1
    BLOB_DMA(0, 0);
    CP_COMMIT();
    BLOB_DMA(TILE4_U32, 1);
    CP_COMMIT();

    // Q fragments (single fp16; scale applied in exponent)
    const float* qb = qg + (size_t)(b * TT + q0 + w * 16) * PW2 + h * DH;
    uint32_t qa[4][4];
#pragma unroll
    for (int k0 = 0; k0 < 4; k0++) {
        qa[k0][0] = packh2(qb[(size_t)(g    ) * PW2 + k0 * 16 + 2 * t],
                           qb[(size_t)(g    ) * PW2 + k0 * 16 + 2 * t + 1]);
        qa[k0][1] = packh2(qb[(size_t)(g + 8) * PW2 + k0 * 16 + 2 * t],
                           qb[(size_t)(g + 8) * PW2 + k0 * 16 + 2 * t + 1]);
        qa[k0][2] = packh2(qb[(size_t)(g    ) * PW2 + k0 * 16 + 2 * t + 8],
                           qb[(size_t)(g    ) * PW2 + k0 * 16 + 2 * t + 9]);
        qa[k0][3] = packh2(qb[(size_t)(g + 8) * PW2 + k0 * 16 + 2 * t + 8],
                           qb[(size_t)(g + 8) * PW2 + k0 * 16 + 2 * t + 9]);
    }

    float om[8][4];
#pragma unroll
    for (int n = 0; n < 8; n++)
#pragma unroll
        for (int i = 0; i < 4; i++) om[n][i] = 0.f;
    float rm0 = -INFINITY, rm1 = -INFINITY, rl0 = 0.f, rl1 = 0.f;

    for (int tt = 0; tt < NTILE; tt++) {
        const int st = tt % 3;
        if (tt + 2 < NTILE) {
            BLOB_DMA(((tt + 2) % 3) * TILE4_U32, tt + 2);
            CP_COMMIT();
            CP_WAIT(2);
        } else if (tt + 1 < NTILE) {
            CP_WAIT(1);
        } else {
            CP_WAIT(0);
        }
        __syncthreads();

        const uint32_t* Kf = sh + st * TILE4_U32;
        const uint32_t* Vf = Kf + ARR2_U32;

        // ---- S_raw = Q @ K^T (fp16) -------------------------------------------
        float s[8][4];
#pragma unroll
        for (int n = 0; n < 8; n++)
#pragma unroll
            for (int i = 0; i < 4; i++) s[n][i] = 0.f;
#pragma unroll
        for (int k0 = 0; k0 < 4; k0++) {
            const uint32_t* kr = Kf + (k0 * 32 + lane) * ROWPAD;
#pragma unroll
            for (int np = 0; np < 4; np++) {
                uint4 k4 = *(const uint4*)(kr + np * 4);
                uint32_t b2[2] = {k4.x, k4.y};
                mma_f16(s[2 * np], qa[k0], b2);
                uint32_t b3[2] = {k4.z, k4.w};
                mma_f16(s[2 * np + 1], qa[k0], b3);
            }
        }

        // ---- online softmax (scale folded into exponent constant) -------------
        float m0 = s[0][0], m1 = s[0][2];
#pragma unroll
        for (int n = 0; n < 8; n++) {
            m0 = fmaxf(m0, fmaxf(s[n][0], s[n][1]));
            m1 = fmaxf(m1, fmaxf(s[n][2], s[n][3]));
        }
        m0 = fmaxf(m0, __shfl_xor_sync(0xffffffff, m0, 1));
        m0 = fmaxf(m0, __shfl_xor_sync(0xffffffff, m0, 2));
        m1 = fmaxf(m1, __shfl_xor_sync(0xffffffff, m1, 1));
        m1 = fmaxf(m1, __shfl_xor_sync(0xffffffff, m1, 2));

        float mn0 = fmaxf(rm0, m0);
        float mn1 = fmaxf(rm1, m1);
        float corr0 = exp2f((rm0 - mn0) * SCLG2E);
        float corr1 = exp2f((rm1 - mn1) * SCLG2E);

        float sum0 = 0.f, sum1 = 0.f;
#pragma unroll
        for (int n = 0; n < 8; n++) {
            s[n][0] = exp2f((s[n][0] - mn0) * SCLG2E);
            s[n][1] = exp2f((s[n][1] - mn0) * SCLG2E);
            s[n][2] = exp2f((s[n][2] - mn1) * SCLG2E);
            s[n][3] = exp2f((s[n][3] - mn1) * SCLG2E);
            sum0 += s[n][0] + s[n][1];
            sum1 += s[n][2] + s[n][3];
        }
        sum0 += __shfl_xor_sync(0xffffffff, sum0, 1);
        sum0 += __shfl_xor_sync(0xffffffff, sum0, 2);
        sum1 += __shfl_xor_sync(0xffffffff, sum1, 1);
        sum1 += __shfl_xor_sync(0xffffffff, sum1, 2);
        rl0 = rl0 * corr0 + sum0;
        rl1 = rl1 * corr1 + sum1;
        rm0 = mn0; rm1 = mn1;

#pragma unroll
        for (int n = 0; n < 8; n++) {
            om[n][0] *= corr0; om[n][1] *= corr0;
            om[n][2] *= corr1; om[n][3] *= corr1;
        }

        // ---- O += P @ V (fp16); P A-frag built locally --------------------------
#pragma unroll
        for (int k0 = 0; k0 < 4; k0++) {
            uint32_t ph[4];
            ph[0] = packh2(s[2 * k0][0],     s[2 * k0][1]);
            ph[1] = packh2(s[2 * k0][2],     s[2 * k0][3]);
            ph[2] = packh2(s[2 * k0 + 1][0], s[2 * k0 + 1][1]);
            ph[3] = packh2(s[2 * k0 + 1][2], s[2 * k0 + 1][3]);
            const uint32_t* vr = Vf + (k0 * 32 + lane) * ROWPAD;
#pragma unroll
            for (int np = 0; np < 4; np++) {
                uint4 v4 = *(const uint4*)(vr + np * 4);
                uint32_t b2[2] = {v4.x, v4.y};
                mma_f16(om[2 * np], ph, b2);
                uint32_t b3[2] = {v4.z, v4.w};
                mma_f16(om[2 * np + 1], ph, b3);
            }
        }
        __syncthreads();
    }

    float inv0 = 1.f / rl0;
    float inv1 = 1.f / rl1;
    float* ob0 = o + (size_t)(b * TT + q0 + w * 16 + g    ) * QKW + h * DH + 2 * t;
    float* ob1 = o + (size_t)(b * TT + q0 + w * 16 + g + 8) * QKW + h * DH + 2 * t;
#pragma unroll
    for (int n0 = 0; n0 < 8; n0++) {
        *(float2*)(ob0 + n0 * 8) = make_float2(om[n0][0] * inv0, om[n0][1] * inv0);
        *(float2*)(ob1 + n0 * 8) = make_float2(om[n0][2] * inv1, om[n0][3] * inv1);
    }
}

// -------- Y pairs: Y[t, 2i..2i+1] = sum_h mask*attn, split to fp16 hi/lo -------
__global__ void combine_out_kernel(const float* __restrict__ attn,
                                   const float* __restrict__ masko,
                                   uint32_t* __restrict__ Yh,
                                   uint32_t* __restrict__ Yl) {
    int token = blockIdx.x;
    int tid = threadIdx.x;          // 0..159
    int t0 = 2 * tid;
    int e = t0 >> 6, j = t0 & 63;
    const float* ap = attn + (size_t)token * QKW;
    const float* mp = masko + (size_t)token * GW;
    float s0 = 0.f, s1 = 0.f;
#pragma unroll
    for (int h = 0; h < HH; h++) {
        float m = mp[h * EE + e];
        s0 += m * ap[h * DH + j];
        s1 += m * ap[h * DH + j + 1];
    }
    uint32_t hi, lo;
    splith2(s0, s1, hi, lo);
    Yh[(size_t)token * (XVW / 2) + tid] = hi;
    Yl[(size_t)token * (XVW / 2) + tid] = lo;
}

// ------------------------------- launch ----------------------------------------
extern "C" void kernel_launch(void* const* d_in, const int* in_sizes, int n_in,
                              void* d_out, int out_size) {
    const float* x  = (const float*)d_in[0];
    const float* Wq = (const float*)d_in[1];
    const float* Wk = (const float*)d_in[2];
    const float* Ws = (const float*)d_in[3];
    const float* Wd = (const float*)d_in[4];
    const float* Wv = (const float*)d_in[5];
    const float* Wo = (const float*)d_in[6];
    float* out = (float*)d_out;

    float *proj, *glp, *v, *attn, *mask;
    uint32_t *xbh, *xbl, *wt, *xth, *xtl, *gwh, *gwl, *ybh, *ybl, *wot, *blob;
    cudaGetSymbolAddress((void**)&proj, g_proj);
    cudaGetSymbolAddress((void**)&xbh,  g_xbh);
    cudaGetSymbolAddress((void**)&xbl,  g_xbl);
    cudaGetSymbolAddress((void**)&wt,   g_wt);
    cudaGetSymbolAddress((void**)&xth,  g_xth);
    cudaGetSymbolAddress((void**)&xtl,  g_xtl);
    cudaGetSymbolAddress((void**)&gwh,  g_gwh);
    cudaGetSymbolAddress((void**)&gwl,  g_gwl);
    cudaGetSymbolAddress((void**)&glp,  g_glp);
    cudaGetSymbolAddress((void**)&v,    g_v);
    cudaGetSymbolAddress((void**)&attn, g_attn);
    cudaGetSymbolAddress((void**)&mask, g_mask);
    cudaGetSymbolAddress((void**)&ybh,  g_ybh);
    cudaGetSymbolAddress((void**)&ybl,  g_ybl);
    cudaGetSymbolAddress((void**)&wot,  g_wot);
    cudaGetSymbolAddress((void**)&blob, g_blob);

    // pre-splits / packs (x read once)
    split_x_all <<<(int)(((size_t)NTOK * DD / 2 + 255) / 256), 256>>>(x, xbh, xbl, xth, xtl);
    pack_wt_f16 <<<(int)(((size_t)PW2 * DD / 2 + 255) / 256), 256>>>(Wq, Wk, Wv, wt);
    pack_gw_tf32<<<(DD * NG + 255) / 256, 256>>>(Ws, Wd, gwh, gwl);
    pack_wot_f16<<<(int)(((size_t)DD * XVW / 2 + 255) / 256), 256>>>(Wo, wot);

    // proj GEMM (fp16 2-term, 3-stage): (8192x1024)@(1024x1344)
    size_t hsm = (size_t)3 * H2_STG * sizeof(uint32_t);   // 76800
    cudaFuncSetAttribute(tgemmh2, cudaFuncAttributeMaxDynamicSharedMemorySize, (int)hsm);
    dim3 gp(PW2 / 64, NTOK / 128);
    tgemmh2<<<gp, 256, hsm>>>(xbh, xbl, wt, proj, NTOK, PW2, DD);

    // gate GEMM (3xTF32, split-K=4): (8192x1024)@(1024x128) -> partials
    size_t gsm = (size_t)2 * STG3 * sizeof(uint32_t);     // 143360
    cudaFuncSetAttribute(tgemm3s, cudaFuncAttributeMaxDynamicSharedMemorySize, (int)gsm);
    dim3 gg(NG / 128, NTOK / 128, KSPL);
    tgemm3s<<<gg, 256, gsm>>>(xth, xtl, gwh, gwl, glp, NTOK, NG, DD);

    // gating + V combine + out-mask
    gate_combine_kernel<<<NTOK, 256>>>(glp, proj, v, mask);

    // K/V fragment blob (fp16 single)
    dim3 bg(NTILE, BB * HH);
    build_kv4_kernel<<<bg, 256>>>(proj, v, blob);

    // attention (pure fp16, 3-stage)
    size_t asmem = (size_t)3 * TILE4_U32 * sizeof(uint32_t);  // 61440
    cudaFuncSetAttribute(attn5_kernel, cudaFuncAttributeMaxDynamicSharedMemorySize, (int)asmem);
    dim3 ag(TT / 128, BB * HH);
    attn5_kernel<<<ag, 256, asmem>>>(proj, blob, attn);

    // masked combine (+fp16 split), then output GEMM: (8192x320)@(320x1024)
    combine_out_kernel<<<NTOK, XVW / 2>>>(attn, mask, ybh, ybl);
    dim3 go(DD / 64, NTOK / 128);
    tgemmh2<<<go, 256, hsm>>>(ybh, ybl, wot, out, NTOK, DD, XVW);
}

// round 12
// speedup vs baseline: 15.2947x; 1.1036x over previous
#include <cuda_runtime.h>
#include <cuda_bf16.h>
#include <cuda_fp16.h>
#include <math.h>
#include <stdint.h>

// Problem constants
#define BB 4
#define TT 2048
#define DD 1024
#define HH 8
#define DH 64
#define EE 5
#define NTOK (BB*TT)          // 8192
#define QKW (HH*DH)           // 512
#define GW  (HH*EE)           // 40
#define XVW (EE*DH)           // 320

// fused projection layout (row stride PW2): q[0:512) | k[512:1024) | xv[1024:1344)
#define PW2 1344
#define OFF_K 512
#define OFF_XV 1024

#define NG 128                 // gate GEMM padded width (glv 0..39, glo 40..79)
#define KSPL 2                 // gate GEMM split-K

// fp16 KV fragment blob: per (bh,tile64): [K | V], each 4 k0 x 32 lanes x 20 u32
#define ROWPAD 20
#define ARR2_U32 (4*32*ROWPAD)    // 2560
#define TILE4_U32 (2*ARR2_U32)    // 5120 u32 = 20KB
#define NTILE 32

// ---------------- scratch (device globals) ------------------------------------
__device__ float    g_proj [(size_t)NTOK*PW2];
__device__ float    g_xvlo [(size_t)NTOK*XVW];                 // xl @ Wv correction
__device__ __align__(16) uint32_t g_xbh [(size_t)NTOK*DD/2];   // fp16 hi pairs of x
__device__ __align__(16) uint32_t g_xbl [(size_t)NTOK*DD/2];   // fp16 lo pairs
__device__ __align__(16) uint32_t g_wt  [(size_t)PW2*DD/2];    // Wt[n][dpair] fp16 (single)
__device__ __align__(16) uint32_t g_gwh [(size_t)NG*DD/2];     // gate weights fp16 hi, [n][dpair]
__device__ __align__(16) uint32_t g_gwl [(size_t)NG*DD/2];     // lo
__device__ float    g_glp  [(size_t)KSPL*NTOK*NG];             // gate partials
__device__ float    g_v    [(size_t)NTOK*QKW];
__device__ float    g_attn [(size_t)NTOK*QKW];
__device__ float    g_mask [(size_t)NTOK*GW];
__device__ __align__(16) uint32_t g_ybh [(size_t)NTOK*XVW/2];  // fp16 hi pairs of Y
__device__ __align__(16) uint32_t g_ybl [(size_t)NTOK*XVW/2];
__device__ __align__(16) uint32_t g_wot [(size_t)DD*XVW/2];    // WoT[n=d][kpair] fp16
__device__ __align__(16) uint32_t g_blob[(size_t)BB*HH*NTILE*TILE4_U32];  // ~21MB

// ---------------- helpers ------------------------------------------------------
// pack (a,b) into fp16x2 word; a -> bits[15:0]
__device__ __forceinline__ uint32_t packh2(float a, float b) {
    __half2 h = __floats2half2_rn(a, b);
    return *reinterpret_cast<uint32_t*>(&h);
}
// split pair (a,b) into fp16x2 hi and lo words
__device__ __forceinline__ void splith2(float a, float b, uint32_t& h, uint32_t& l) {
    __half ha = __float2half_rn(a);
    __half hb = __float2half_rn(b);
    float ra = a - __half2float(ha);
    float rb = b - __half2float(hb);
    __half2 hh; hh.x = ha; hh.y = hb;
    __half2 ll; ll.x = __float2half_rn(ra); ll.y = __float2half_rn(rb);
    h = *reinterpret_cast<uint32_t*>(&hh);
    l = *reinterpret_cast<uint32_t*>(&ll);
}
__device__ __forceinline__ void mma_f16(float c[4], const uint32_t a[4], const uint32_t b[2]) {
    asm volatile(
        "mma.sync.aligned.m16n8k16.row.col.f32.f16.f16.f32 "
        "{%0,%1,%2,%3},{%4,%5,%6,%7},{%8,%9},{%0,%1,%2,%3};"
        : "+f"(c[0]), "+f"(c[1]), "+f"(c[2]), "+f"(c[3])
        : "r"(a[0]), "r"(a[1]), "r"(a[2]), "r"(a[3]), "r"(b[0]), "r"(b[1]));
}
__device__ __forceinline__ void cp16(uint32_t saddr, const void* g) {
    asm volatile("cp.async.cg.shared.global [%0], [%1], 16;\n" :: "r"(saddr), "l"(g));
}
#define CP_COMMIT() asm volatile("cp.async.commit_group;\n")
#define CP_WAIT(n)  asm volatile("cp.async.wait_group %0;\n" :: "n"(n))

// =============== pre-split / pack kernels ======================================
__global__ void split_x_f16(const float* __restrict__ x,
                            uint32_t* __restrict__ xbh, uint32_t* __restrict__ xbl) {
    size_t i = (size_t)blockIdx.x * blockDim.x + threadIdx.x;
    if (i >= (size_t)NTOK * DD / 2) return;
    splith2(x[2 * i], x[2 * i + 1], xbh[i], xbl[i]);
}
__global__ void pack_wt_f16(const float* __restrict__ Wq, const float* __restrict__ Wk,
                            const float* __restrict__ Wv, uint32_t* __restrict__ Wt) {
    size_t idx = (size_t)blockIdx.x * blockDim.x + threadIdx.x;
    if (idx >= (size_t)PW2 * DD / 2) return;
    int n = (int)(idx / (DD / 2));
    int dp = (int)(idx % (DD / 2));
    int d0 = 2 * dp;
    float va, vb;
    if (n < 512) {
        va = Wq[(size_t)d0 * 512 + n]; vb = Wq[(size_t)(d0 + 1) * 512 + n];
    } else if (n < 1024) {
        va = Wk[(size_t)d0 * 512 + (n - 512)]; vb = Wk[(size_t)(d0 + 1) * 512 + (n - 512)];
    } else {
        int e = (n - 1024) / DH, j = (n - 1024) % DH;
        va = Wv[((size_t)e * DD + d0) * DH + j];
        vb = Wv[((size_t)e * DD + d0 + 1) * DH + j];
    }
    Wt[idx] = packh2(va, vb);
}
__global__ void pack_gw_f16(const float* __restrict__ Ws, const float* __restrict__ Wd,
                            uint32_t* __restrict__ Wh, uint32_t* __restrict__ Wl) {
    size_t idx = (size_t)blockIdx.x * blockDim.x + threadIdx.x;
    if (idx >= (size_t)NG * DD / 2) return;
    int n = (int)(idx / (DD / 2));
    int dp = (int)(idx % (DD / 2));
    int d0 = 2 * dp;
    float va = 0.f, vb = 0.f;
    if (n < 40)      { va = Ws[(size_t)d0 * GW + n];        vb = Ws[(size_t)(d0 + 1) * GW + n]; }
    else if (n < 80) { va = Wd[(size_t)d0 * GW + (n - 40)]; vb = Wd[(size_t)(d0 + 1) * GW + (n - 40)]; }
    splith2(va, vb, Wh[idx], Wl[idx]);
}
__global__ void pack_wot_f16(const float* __restrict__ Wo, uint32_t* __restrict__ Wt) {
    size_t idx = (size_t)blockIdx.x * blockDim.x + threadIdx.x;
    if (idx >= (size_t)DD * XVW / 2) return;
    int n = (int)(idx / (XVW / 2));
    int kp = (int)(idx % (XVW / 2));
    int k0 = 2 * kp;
    int e = k0 >> 6, j = k0 & 63;
    float va = Wo[((size_t)(e * DH + j)) * DD + n];
    float vb = Wo[((size_t)(e * DH + j + 1)) * DD + n];
    Wt[idx] = packh2(va, vb);
}

// =============== single-term fp16 GEMM: C=A@Bt^T, BM=128,BN=64,BK=32, 3-stage ==
// A: [M][K/2] fp16-pairs; Bt: [N][K/2] fp16-pairs (caller may offset Bt rows)
#define H1_OFF_B 2560
#define H1_STG   3840     // 15KB/stage

__global__ __launch_bounds__(256, 2)
void tgemmh1(const uint32_t* __restrict__ Ag, const uint32_t* __restrict__ Bg,
             float* __restrict__ C, int M, int N, int K) {
    extern __shared__ uint32_t sm1[];   // 3 stages x H1_STG
    const int tid = threadIdx.x;
    const int row0 = blockIdx.y * 128;
    const int col0 = blockIdx.x * 64;
    const int lane = tid & 31, w = tid >> 5;
    const int g = lane >> 2, t = lane & 3;
    const int wm = w >> 1, wn = w & 1;      // warp tile 32x32
    const int Ku = K / 2;

    const uint32_t sb = (uint32_t)__cvta_generic_to_shared(sm1);

    float c[2][4][4];
#pragma unroll
    for (int mt = 0; mt < 2; mt++)
#pragma unroll
        for (int nt = 0; nt < 4; nt++)
#pragma unroll
            for (int i = 0; i < 4; i++) c[mt][nt][i] = 0.f;

    const int nk = K / 32;

#define H1_LOAD(dst, kt)                                                          \
    {                                                                             \
        int ko = (kt) * 16;                                                       \
        _Pragma("unroll")                                                         \
        for (int it = 0; it < 2; it++) {                                          \
            int idx = it * 256 + tid;                                             \
            int r = idx >> 2, cc = idx & 3;                                       \
            cp16((dst) + (uint32_t)(r * ROWPAD + cc * 4) * 4,                     \
                 Ag + (size_t)(row0 + r) * Ku + ko + cc * 4);                     \
        }                                                                         \
        {                                                                         \
            int r = tid >> 2, cc = tid & 3;                                       \
            cp16((dst) + (uint32_t)(H1_OFF_B + r * ROWPAD + cc * 4) * 4,          \
                 Bg + (size_t)(col0 + r) * Ku + ko + cc * 4);                     \
        }                                                                         \
    }

    H1_LOAD(sb, 0);
    CP_COMMIT();
    if (nk > 1) {
        H1_LOAD(sb + (uint32_t)H1_STG * 4, 1);
        CP_COMMIT();
    }

    for (int kt = 0; kt < nk; kt++) {
        const int st = kt % 3;
        if (kt + 2 < nk) {
            uint32_t d2 = sb + (uint32_t)(((kt + 2) % 3) * H1_STG) * 4;
            H1_LOAD(d2, kt + 2);
            CP_COMMIT();
            CP_WAIT(2);
        } else if (kt + 1 < nk) {
            CP_WAIT(1);
        } else {
            CP_WAIT(0);
        }
        __syncthreads();

        const uint32_t* Ah = sm1 + st * H1_STG;
        const uint32_t* Bs = Ah + H1_OFF_B;

#pragma unroll
        for (int kc = 0; kc < 2; kc++) {
            uint32_t af[2][4], bf[4][2];
#pragma unroll
            for (int mt = 0; mt < 2; mt++) {
                int rb = wm * 32 + mt * 16;
                af[mt][0] = Ah[(rb + g    ) * ROWPAD + kc * 8 + t];
                af[mt][1] = Ah[(rb + g + 8) * ROWPAD + kc * 8 + t];
                af[mt][2] = Ah[(rb + g    ) * ROWPAD + kc * 8 + t + 4];
                af[mt][3] = Ah[(rb + g + 8) * ROWPAD + kc * 8 + t + 4];
            }
#pragma unroll
            for (int nt = 0; nt < 4; nt++) {
                int cb = wn * 32 + nt * 8;
                bf[nt][0] = Bs[(cb + g) * ROWPAD + kc * 8 + t];
                bf[nt][1] = Bs[(cb + g) * ROWPAD + kc * 8 + t + 4];
            }
#pragma unroll
            for (int mt = 0; mt < 2; mt++)
#pragma unroll
                for (int nt = 0; nt < 4; nt++)
                    mma_f16(c[mt][nt], af[mt], bf[nt]);
        }
        __syncthreads();
    }

#pragma unroll
    for (int mt = 0; mt < 2; mt++) {
        int r0 = row0 + wm * 32 + mt * 16;
#pragma unroll
        for (int nt = 0; nt < 4; nt++) {
            int cc = col0 + wn * 32 + nt * 8 + 2 * t;
            *(float2*)&C[(size_t)(r0 + g    ) * N + cc] = make_float2(c[mt][nt][0], c[mt][nt][1]);
            *(float2*)&C[(size_t)(r0 + g + 8) * N + cc] = make_float2(c[mt][nt][2], c[mt][nt][3]);
        }
    }
}

// =============== fp16 2-term GEMM (out GEMM): A hi/lo, B single ================
#define H2_OFF_AL 2560
#define H2_OFF_B  5120
#define H2_STG    6400

__global__ __launch_bounds__(256, 2)
void tgemmh2(const uint32_t* __restrict__ Agh, const uint32_t* __restrict__ Agl,
             const uint32_t* __restrict__ Bg,
             float* __restrict__ C, int M, int N, int K) {
    extern __shared__ uint32_t sm2[];   // 3 stages x H2_STG
    const int tid = threadIdx.x;
    const int row0 = blockIdx.y * 128;
    const int col0 = blockIdx.x * 64;
    const int lane = tid & 31, w = tid >> 5;
    const int g = lane >> 2, t = lane & 3;
    const int wm = w >> 1, wn = w & 1;
    const int Ku = K / 2;

    const uint32_t sb = (uint32_t)__cvta_generic_to_shared(sm2);

    float c[2][4][4];
#pragma unroll
    for (int mt = 0; mt < 2; mt++)
#pragma unroll
        for (int nt = 0; nt < 4; nt++)
#pragma unroll
            for (int i = 0; i < 4; i++) c[mt][nt][i] = 0.f;

    const int nk = K / 32;

#define H2_LOAD(dst, kt)                                                          \
    {                                                                             \
        int ko = (kt) * 16;                                                       \
        _Pragma("unroll")                                                         \
        for (int it = 0; it < 2; it++) {                                          \
            int idx = it * 256 + tid;                                             \
            int r = idx >> 2, cc = idx & 3;                                       \
            cp16((dst) + (uint32_t)(r * ROWPAD + cc * 4) * 4,                     \
                 Agh + (size_t)(row0 + r) * Ku + ko + cc * 4);                    \
            cp16((dst) + (uint32_t)(H2_OFF_AL + r * ROWPAD + cc * 4) * 4,         \
                 Agl + (size_t)(row0 + r) * Ku + ko + cc * 4);                    \
        }                                                                         \
        {                                                                         \
            int r = tid >> 2, cc = tid & 3;                                       \
            cp16((dst) + (uint32_t)(H2_OFF_B + r * ROWPAD + cc * 4) * 4,          \
                 Bg + (size_t)(col0 + r) * Ku + ko + cc * 4);                     \
        }                                                                         \
    }

    H2_LOAD(sb, 0);
    CP_COMMIT();
    if (nk > 1) {
        H2_LOAD(sb + (uint32_t)H2_STG * 4, 1);
        CP_COMMIT();
    }

    for (int kt = 0; kt < nk; kt++) {
        const int st = kt % 3;
        if (kt + 2 < nk) {
            uint32_t d2 = sb + (uint32_t)(((kt + 2) % 3) * H2_STG) * 4;
            H2_LOAD(d2, kt + 2);
            CP_COMMIT();
            CP_WAIT(2);
        } else if (kt + 1 < nk) {
            CP_WAIT(1);
        } else {
            CP_WAIT(0);
        }
        __syncthreads();

        const uint32_t* Ah = sm2 + st * H2_STG;
        const uint32_t* Al = Ah + H2_OFF_AL;
        const uint32_t* Bs = Ah + H2_OFF_B;

#pragma unroll
        for (int kc = 0; kc < 2; kc++) {
            uint32_t afh[2][4], afl[2][4], bf[4][2];
#pragma unroll
            for (int mt = 0; mt < 2; mt++) {
                int rb = wm * 32 + mt * 16;
                afh[mt][0] = Ah[(rb + g    ) * ROWPAD + kc * 8 + t];
                afh[mt][1] = Ah[(rb + g + 8) * ROWPAD + kc * 8 + t];
                afh[mt][2] = Ah[(rb + g    ) * ROWPAD + kc * 8 + t + 4];
                afh[mt][3] = Ah[(rb + g + 8) * ROWPAD + kc * 8 + t + 4];
                afl[mt][0] = Al[(rb + g    ) * ROWPAD + kc * 8 + t];
                afl[mt][1] = Al[(rb + g + 8) * ROWPAD + kc * 8 + t];
                afl[mt][2] = Al[(rb + g    ) * ROWPAD + kc * 8 + t + 4];
                afl[mt][3] = Al[(rb + g + 8) * ROWPAD + kc * 8 + t + 4];
            }
#pragma unroll
            for (int nt = 0; nt < 4; nt++) {
                int cb = wn * 32 + nt * 8;
                bf[nt][0] = Bs[(cb + g) * ROWPAD + kc * 8 + t];
                bf[nt][1] = Bs[(cb + g) * ROWPAD + kc * 8 + t + 4];
            }
#pragma unroll
            for (int mt = 0; mt < 2; mt++)
#pragma unroll
                for (int nt = 0; nt < 4; nt++) {
                    mma_f16(c[mt][nt], afl[mt], bf[nt]);
                    mma_f16(c[mt][nt], afh[mt], bf[nt]);
                }
        }
        __syncthreads();
    }

#pragma unroll
    for (int mt = 0; mt < 2; mt++) {
        int r0 = row0 + wm * 32 + mt * 16;
#pragma unroll
        for (int nt = 0; nt < 4; nt++) {
            int cc = col0 + wn * 32 + nt * 8 + 2 * t;
            *(float2*)&C[(size_t)(r0 + g    ) * N + cc] = make_float2(c[mt][nt][0], c[mt][nt][1]);
            *(float2*)&C[(size_t)(r0 + g + 8) * N + cc] = make_float2(c[mt][nt][2], c[mt][nt][3]);
        }
    }
}

// =============== fp16 3-term GEMM (gates): A hi/lo, B hi/lo, split-K ===========
#define H3_OFF_AL 2560
#define H3_OFF_BH 5120
#define H3_OFF_BL 6400
#define H3_STG    7680

__global__ __launch_bounds__(256, 2)
void tgemmh3(const uint32_t* __restrict__ Agh, const uint32_t* __restrict__ Agl,
             const uint32_t* __restrict__ Bgh, const uint32_t* __restrict__ Bgl,
             float* __restrict__ C, int M, int N, int K) {
    extern __shared__ uint32_t sm3[];   // 3 stages x H3_STG
    const int tid = threadIdx.x;
    const int row0 = blockIdx.y * 128;
    const int col0 = blockIdx.x * 64;
    const int lane = tid & 31, w = tid >> 5;
    const int g = lane >> 2, t = lane & 3;
    const int wm = w >> 1, wn = w & 1;
    const int Ku = K / 2;
    const int ksplit = gridDim.z;
    const int kb = blockIdx.z * (K / 32 / ksplit);   // starting k-chunk
    const int nk = K / 32 / ksplit;
    float* Cz = C + (size_t)blockIdx.z * M * N;

    const uint32_t sb = (uint32_t)__cvta_generic_to_shared(sm3);

    float c[2][4][4];
#pragma unroll
    for (int mt = 0; mt < 2; mt++)
#pragma unroll
        for (int nt = 0; nt < 4; nt++)
#pragma unroll
            for (int i = 0; i < 4; i++) c[mt][nt][i] = 0.f;

#define H3_LOAD(dst, kt)                                                          \
    {                                                                             \
        int ko = (kb + (kt)) * 16;                                                \
        _Pragma("unroll")                                                         \
        for (int it = 0; it < 2; it++) {                                          \
            int idx = it * 256 + tid;                                             \
            int r = idx >> 2, cc = idx & 3;                                       \
            cp16((dst) + (uint32_t)(r * ROWPAD + cc * 4) * 4,                     \
                 Agh + (size_t)(row0 + r) * Ku + ko + cc * 4);                    \
            cp16((dst) + (uint32_t)(H3_OFF_AL + r * ROWPAD + cc * 4) * 4,         \
                 Agl + (size_t)(row0 + r) * Ku + ko + cc * 4);                    \
        }                                                                         \
        {                                                                         \
            int r = tid >> 2, cc = tid & 3;                                       \
            cp16((dst) + (uint32_t)(H3_OFF_BH + r * ROWPAD + cc * 4) * 4,         \
                 Bgh + (size_t)(col0 + r) * Ku + ko + cc * 4);                    \
            cp16((dst) + (uint32_t)(H3_OFF_BL + r * ROWPAD + cc * 4) * 4,         \
                 Bgl + (size_t)(col0 + r) * Ku + ko + cc * 4);                    \
        }                                                                         \
    }

    H3_LOAD(sb, 0);
    CP_COMMIT();
    if (nk > 1) {
        H3_LOAD(sb + (uint32_t)H3_STG * 4, 1);
        CP_COMMIT();
    }

    for (int kt = 0; kt < nk; kt++) {
        const int st = kt % 3;
        if (kt + 2 < nk) {
            uint32_t d2 = sb + (uint32_t)(((kt + 2) % 3) * H3_STG) * 4;
            H3_LOAD(d2, kt + 2);
            CP_COMMIT();
            CP_WAIT(2);
        } else if (kt + 1 < nk) {
            CP_WAIT(1);
        } else {
            CP_WAIT(0);
        }
        __syncthreads();

        const uint32_t* Ah = sm3 + st * H3_STG;
        const uint32_t* Al = Ah + H3_OFF_AL;
        const uint32_t* Bh = Ah + H3_OFF_BH;
        const uint32_t* Bl = Ah + H3_OFF_BL;

#pragma unroll
        for (int kc = 0; kc < 2; kc++) {
            uint32_t afh[2][4], afl[2][4], bfh[4][2], bfl[4][2];
#pragma unroll
            for (int mt = 0; mt < 2; mt++) {
                int rb = wm * 32 + mt * 16;
                afh[mt][0] = Ah[(rb + g    ) * ROWPAD + kc * 8 + t];
                afh[mt][1] = Ah[(rb + g + 8) * ROWPAD + kc * 8 + t];
                afh[mt][2] = Ah[(rb + g    ) * ROWPAD + kc * 8 + t + 4];
                afh[mt][3] = Ah[(rb + g + 8) * ROWPAD + kc * 8 + t + 4];
                afl[mt][0] = Al[(rb + g    ) * ROWPAD + kc * 8 + t];
                afl[mt][1] = Al[(rb + g + 8) * ROWPAD + kc * 8 + t];
                afl[mt][2] = Al[(rb + g    ) * ROWPAD + kc * 8 + t + 4];
                afl[mt][3] = Al[(rb + g + 8) * ROWPAD + kc * 8 + t + 4];
            }
#pragma unroll
            for (int nt = 0; nt < 4; nt++) {
                int cb = wn * 32 + nt * 8;
                bfh[nt][0] = Bh[(cb + g) * ROWPAD + kc * 8 + t];
                bfh[nt][1] = Bh[(cb + g) * ROWPAD + kc * 8 + t + 4];
                bfl[nt][0] = Bl[(cb + g) * ROWPAD + kc * 8 + t];
                bfl[nt][1] = Bl[(cb + g) * ROWPAD + kc * 8 + t + 4];
            }
#pragma unroll
            for (int mt = 0; mt < 2; mt++)
#pragma unroll
                for (int nt = 0; nt < 4; nt++) {
                    mma_f16(c[mt][nt], afh[mt], bfl[nt]);
                    mma_f16(c[mt][nt], afl[mt], bfh[nt]);
                    mma_f16(c[mt][nt], afh[mt], bfh[nt]);
                }
        }
        __syncthreads();
    }

#pragma unroll
    for (int mt = 0; mt < 2; mt++) {
        int r0 = row0 + wm * 32 + mt * 16;
#pragma unroll
        for (int nt = 0; nt < 4; nt++) {
            int cc = col0 + wn * 32 + nt * 8 + 2 * t;
            *(float2*)&Cz[(size_t)(r0 + g    ) * N + cc] = make_float2(c[mt][nt][0], c[mt][nt][1]);
            *(float2*)&Cz[(size_t)(r0 + g + 8) * N + cc] = make_float2(c[mt][nt][2], c[mt][nt][3]);
        }
    }
}

// -------- gating: sum split-K partials, top-2, V combine (+xv lo), out mask ----
__global__ void gate_combine_kernel(const float* __restrict__ glp,
                                    const float* __restrict__ proj,
                                    const float* __restrict__ xvlo,
                                    float* __restrict__ v,
                                    float* __restrict__ masko) {
    int token = blockIdx.x;
    int w = threadIdx.x / 32;
    int lane = threadIdx.x % 32;

    float g[EE];
#pragma unroll
    for (int e = 0; e < EE; e++) {
        float s = 0.f;
#pragma unroll
        for (int z = 0; z < KSPL; z++)
            s += glp[((size_t)z * NTOK + token) * NG + w * EE + e];
        g[e] = s;
    }
    int i1 = 0;
#pragma unroll
    for (int e = 1; e < EE; e++) if (g[e] > g[i1]) i1 = e;
    int i2 = (i1 == 0) ? 1 : 0;
#pragma unroll
    for (int e = 0; e < EE; e++) if (e != i1 && g[e] > g[i2]) i2 = e;
    float w1 = 1.f / (1.f + __expf(-g[i1]));
    float w2 = 1.f / (1.f + __expf(-g[i2]));

    const float* xvt = proj + (size_t)token * PW2 + OFF_XV;
    const float* xlt = xvlo + (size_t)token * XVW;
    float* vt = v + (size_t)token * QKW + w * DH;
#pragma unroll
    for (int d = lane; d < DH; d += 32)
        vt[d] = w1 * (xvt[i1 * DH + d] + xlt[i1 * DH + d])
              + w2 * (xvt[i2 * DH + d] + xlt[i2 * DH + d]);

#pragma unroll
    for (int e = 0; e < EE; e++) {
        float s = 0.f;
#pragma unroll
        for (int z = 0; z < KSPL; z++)
            s += glp[((size_t)z * NTOK + token) * NG + 40 + w * EE + e];
        g[e] = s;
    }
    int o1 = 0;
#pragma unroll
    for (int e = 1; e < EE; e++) if (g[e] > g[o1]) o1 = e;
    int o2 = (o1 == 0) ? 1 : 0;
#pragma unroll
    for (int e = 0; e < EE; e++) if (e != o1 && g[e] > g[o2]) o2 = e;
    if (lane < EE)
        masko[((size_t)token * HH + w) * EE + lane] = (lane == o1 || lane == o2) ? 1.f : 0.f;
}

// =============== build fp16 K/V fragment blob ==================================
__global__ void build_kv4_kernel(const float* __restrict__ proj,
                                 const float* __restrict__ v,
                                 uint32_t* __restrict__ blob) {
    __shared__ float Ks[64 * 68];
    __shared__ float Vs[64 * 68];
    const int tile = blockIdx.x, bh = blockIdx.y;
    const int b = bh / HH, h = bh % HH;
    const int tid = threadIdx.x;

#pragma unroll
    for (int it = 0; it < 4; it++) {
        int idx = it * 256 + tid;
        int r = (idx * 4) >> 6, d = (idx * 4) & 63;
        const float* kb = proj + (size_t)(b * TT + tile * 64 + r) * PW2 + OFF_K + h * DH;
        const float* vb = v    + (size_t)(b * TT + tile * 64 + r) * QKW + h * DH;
        *(float4*)&Ks[r * 68 + d] = *(const float4*)(kb + d);
        *(float4*)&Vs[r * 68 + d] = *(const float4*)(vb + d);
    }
    __syncthreads();

    uint32_t* dst = blob + ((size_t)bh * NTILE + tile) * TILE4_U32;
#pragma unroll
    for (int i = 0; i < 8; i++) {
        int oi = tid * 8 + i;
        int row = oi >> 4;
        int col = oi & 15;
        int k0 = row >> 5, lane2 = row & 31;
        int g2 = lane2 >> 2, t2 = lane2 & 3;
        int n0 = col >> 1, w2 = col & 1;
        int dK = k0 * 16 + w2 * 8 + 2 * t2;
        int keyK = n0 * 8 + g2;
        dst[row * ROWPAD + col] = packh2(Ks[keyK * 68 + dK], Ks[keyK * 68 + dK + 1]);
        int keyV = k0 * 16 + w2 * 8 + 2 * t2;
        int dV = n0 * 8 + g2;
        dst[ARR2_U32 + row * ROWPAD + col] = packh2(Vs[keyV * 68 + dV], Vs[(keyV + 1) * 68 + dV]);
    }
}

// =============== flash attention, pure fp16, fragment blob + cp.async ==========
#define LOG2E 1.4426950408889634f
#define SCLG2E (0.125f * LOG2E)

__global__ __launch_bounds__(256, 2)
void attn5_kernel(const float* __restrict__ qg,
                  const uint32_t* __restrict__ blob,
                  float* __restrict__ o) {
    extern __shared__ uint32_t sh[];     // 3 stages x TILE4_U32
    const int bh = blockIdx.y;
    const int b = bh / HH, h = bh % HH;
    const int q0 = blockIdx.x * 128;
    const int tid = threadIdx.x;
    const int lane = tid & 31, w = tid >> 5;
    const int g = lane >> 2, t = lane & 3;

    const uint32_t* gblob = blob + (size_t)bh * NTILE * TILE4_U32;
    const uint32_t sbase = (uint32_t)__cvta_generic_to_shared(sh);

#define BLOB_DMA(dstoff, srct)                                                   \
    {                                                                            \
        const uint32_t* src = gblob + (size_t)(srct) * TILE4_U32;                \
        _Pragma("unroll")                                                        \
        for (int i = 0; i < 5; i++) {                                            \
            int cc = tid + i * 256;                                              \
            cp16(sbase + (uint32_t)((dstoff) + cc * 4) * 4, src + cc * 4);       \
        }                                                                        \
    }

    BLOB_DMA(0, 0);
    CP_COMMIT();
    BLOB_DMA(TILE4_U32, 1);
    CP_COMMIT();

    const float* qb = qg + (size_t)(b * TT + q0 + w * 16) * PW2 + h * DH;
    uint32_t qa[4][4];
#pragma unroll
    for (int k0 = 0; k0 < 4; k0++) {
        qa[k0][0] = packh2(qb[(size_t)(g    ) * PW2 + k0 * 16 + 2 * t],
                           qb[(size_t)(g    ) * PW2 + k0 * 16 + 2 * t + 1]);
        qa[k0][1] = packh2(qb[(size_t)(g + 8) * PW2 + k0 * 16 + 2 * t],
                           qb[(size_t)(g + 8) * PW2 + k0 * 16 + 2 * t + 1]);
        qa[k0][2] = packh2(qb[(size_t)(g    ) * PW2 + k0 * 16 + 2 * t + 8],
                           qb[(size_t)(g    ) * PW2 + k0 * 16 + 2 * t + 9]);
        qa[k0][3] = packh2(qb[(size_t)(g + 8) * PW2 + k0 * 16 + 2 * t + 8],
                           qb[(size_t)(g + 8) * PW2 + k0 * 16 + 2 * t + 9]);
    }

    float om[8][4];
#pragma unroll
    for (int n = 0; n < 8; n++)
#pragma unroll
        for (int i = 0; i < 4; i++) om[n][i] = 0.f;
    float rm0 = -INFINITY, rm1 = -INFINITY, rl0 = 0.f, rl1 = 0.f;

    for (int tt = 0; tt < NTILE; tt++) {
        const int st = tt % 3;
        if (tt + 2 < NTILE) {
            BLOB_DMA(((tt + 2) % 3) * TILE4_U32, tt + 2);
            CP_COMMIT();
            CP_WAIT(2);
        } else if (tt + 1 < NTILE) {
            CP_WAIT(1);
        } else {
            CP_WAIT(0);
        }
        __syncthreads();

        const uint32_t* Kf = sh + st * TILE4_U32;
        const uint32_t* Vf = Kf + ARR2_U32;

        float s[8][4];
#pragma unroll
        for (int n = 0; n < 8; n++)
#pragma unroll
            for (int i = 0; i < 4; i++) s[n][i] = 0.f;
#pragma unroll
        for (int k0 = 0; k0 < 4; k0++) {
            const uint32_t* kr = Kf + (k0 * 32 + lane) * ROWPAD;
#pragma unroll
            for (int np = 0; np < 4; np++) {
                uint4 k4 = *(const uint4*)(kr + np * 4);
                uint32_t b2[2] = {k4.x, k4.y};
                mma_f16(s[2 * np], qa[k0], b2);
                uint32_t b3[2] = {k4.z, k4.w};
                mma_f16(s[2 * np + 1], qa[k0], b3);
            }
        }

        float m0 = s[0][0], m1 = s[0][2];
#pragma unroll
        for (int n = 0; n < 8; n++) {
            m0 = fmaxf(m0, fmaxf(s[n][0], s[n][1]));
            m1 = fmaxf(m1, fmaxf(s[n][2], s[n][3]));
        }
        m0 = fmaxf(m0, __shfl_xor_sync(0xffffffff, m0, 1));
        m0 = fmaxf(m0, __shfl_xor_sync(0xffffffff, m0, 2));
        m1 = fmaxf(m1, __shfl_xor_sync(0xffffffff, m1, 1));
        m1 = fmaxf(m1, __shfl_xor_sync(0xffffffff, m1, 2));

        float mn0 = fmaxf(rm0, m0);
        float mn1 = fmaxf(rm1, m1);
        float corr0 = exp2f((rm0 - mn0) * SCLG2E);
        float corr1 = exp2f((rm1 - mn1) * SCLG2E);

        float sum0 = 0.f, sum1 = 0.f;
#pragma unroll
        for (int n = 0; n < 8; n++) {
            s[n][0] = exp2f((s[n][0] - mn0) * SCLG2E);
            s[n][1] = exp2f((s[n][1] - mn0) * SCLG2E);
            s[n][2] = exp2f((s[n][2] - mn1) * SCLG2E);
            s[n][3] = exp2f((s[n][3] - mn1) * SCLG2E);
            sum0 += s[n][0] + s[n][1];
            sum1 += s[n][2] + s[n][3];
        }
        sum0 += __shfl_xor_sync(0xffffffff, sum0, 1);
        sum0 += __shfl_xor_sync(0xffffffff, sum0, 2);
        sum1 += __shfl_xor_sync(0xffffffff, sum1, 1);
        sum1 += __shfl_xor_sync(0xffffffff, sum1, 2);
        rl0 = rl0 * corr0 + sum0;
        rl1 = rl1 * corr1 + sum1;
        rm0 = mn0; rm1 = mn1;

#pragma unroll
        for (int n = 0; n < 8; n++) {
            om[n][0] *= corr0; om[n][1] *= corr0;
            om[n][2] *= corr1; om[n][3] *= corr1;
        }

#pragma unroll
        for (int k0 = 0; k0 < 4; k0++) {
            uint32_t ph[4];
            ph[0] = packh2(s[2 * k0][0],     s[2 * k0][1]);
            ph[1] = packh2(s[2 * k0][2],     s[2 * k0][3]);
            ph[2] = packh2(s[2 * k0 + 1][0], s[2 * k0 + 1][1]);
            ph[3] = packh2(s[2 * k0 + 1][2], s[2 * k0 + 1][3]);
            const uint32_t* vr = Vf + (k0 * 32 + lane) * ROWPAD;
#pragma unroll
            for (int np = 0; np < 4; np++) {
                uint4 v4 = *(const uint4*)(vr + np * 4);
                uint32_t b2[2] = {v4.x, v4.y};
                mma_f16(om[2 * np], ph, b2);
                uint32_t b3[2] = {v4.z, v4.w};
                mma_f16(om[2 * np + 1], ph, b3);
            }
        }
        __syncthreads();
    }

    float inv0 = 1.f / rl0;
    float inv1 = 1.f / rl1;
    float* ob0 = o + (size_t)(b * TT + q0 + w * 16 + g    ) * QKW + h * DH + 2 * t;
    float* ob1 = o + (size_t)(b * TT + q0 + w * 16 + g + 8) * QKW + h * DH + 2 * t;
#pragma unroll
    for (int n0 = 0; n0 < 8; n0++) {
        *(float2*)(ob0 + n0 * 8) = make_float2(om[n0][0] * inv0, om[n0][1] * inv0);
        *(float2*)(ob1 + n0 * 8) = make_float2(om[n0][2] * inv1, om[n0][3] * inv1);
    }
}

// -------- Y pairs: Y[t, 2i..2i+1] = sum_h mask*attn, split to fp16 hi/lo -------
__global__ void combine_out_kernel(const float* __restrict__ attn,
                                   const float* __restrict__ masko,
                                   uint32_t* __restrict__ Yh,
                                   uint32_t* __restrict__ Yl) {
    int token = blockIdx.x;
    int tid = threadIdx.x;          // 0..159
    int t0 = 2 * tid;
    int e = t0 >> 6, j = t0 & 63;
    const float* ap = attn + (size_t)token * QKW;
    const float* mp = masko + (size_t)token * GW;
    float s0 = 0.f, s1 = 0.f;
#pragma unroll
    for (int h = 0; h < HH; h++) {
        float m = mp[h * EE + e];
        s0 += m * ap[h * DH + j];
        s1 += m * ap[h * DH + j + 1];
    }
    uint32_t hi, lo;
    splith2(s0, s1, hi, lo);
    Yh[(size_t)token * (XVW / 2) + tid] = hi;
    Yl[(size_t)token * (XVW / 2) + tid] = lo;
}

// ------------------------------- launch ----------------------------------------
extern "C" void kernel_launch(void* const* d_in, const int* in_sizes, int n_in,
                              void* d_out, int out_size) {
    const float* x  = (const float*)d_in[0];
    const float* Wq = (const float*)d_in[1];
    const float* Wk = (const float*)d_in[2];
    const float* Ws = (const float*)d_in[3];
    const float* Wd = (const float*)d_in[4];
    const float* Wv = (const float*)d_in[5];
    const float* Wo = (const float*)d_in[6];
    float* out = (float*)d_out;

    float *proj, *xvlo, *glp, *v, *attn, *mask;
    uint32_t *xbh, *xbl, *wt, *gwh, *gwl, *ybh, *ybl, *wot, *blob;
    cudaGetSymbolAddress((void**)&proj, g_proj);
    cudaGetSymbolAddress((void**)&xvlo, g_xvlo);
    cudaGetSymbolAddress((void**)&xbh,  g_xbh);
    cudaGetSymbolAddress((void**)&xbl,  g_xbl);
    cudaGetSymbolAddress((void**)&wt,   g_wt);
    cudaGetSymbolAddress((void**)&gwh,  g_gwh);
    cudaGetSymbolAddress((void**)&gwl,  g_gwl);
    cudaGetSymbolAddress((void**)&glp,  g_glp);
    cudaGetSymbolAddress((void**)&v,    g_v);
    cudaGetSymbolAddress((void**)&attn, g_attn);
    cudaGetSymbolAddress((void**)&mask, g_mask);
    cudaGetSymbolAddress((void**)&ybh,  g_ybh);
    cudaGetSymbolAddress((void**)&ybl,  g_ybl);
    cudaGetSymbolAddress((void**)&wot,  g_wot);
    cudaGetSymbolAddress((void**)&blob, g_blob);

    // pre-splits / packs
    split_x_f16 <<<(int)(((size_t)NTOK * DD / 2 + 255) / 256), 256>>>(x, xbh, xbl);
    pack_wt_f16 <<<(int)(((size_t)PW2 * DD / 2 + 255) / 256), 256>>>(Wq, Wk, Wv, wt);
    pack_gw_f16 <<<(int)(((size_t)NG * DD / 2 + 255) / 256), 256>>>(Ws, Wd, gwh, gwl);
    pack_wot_f16<<<(int)(((size_t)DD * XVW / 2 + 255) / 256), 256>>>(Wo, wot);

    // proj GEMM (single fp16, 3-stage): (8192x1024)@(1024x1344)
    size_t h1sm = (size_t)3 * H1_STG * sizeof(uint32_t);   // 46080
    cudaFuncSetAttribute(tgemmh1, cudaFuncAttributeMaxDynamicSharedMemorySize, (int)h1sm);
    dim3 gp(PW2 / 64, NTOK / 128);
    tgemmh1<<<gp, 256, h1sm>>>(xbh, wt, proj, NTOK, PW2, DD);

    // xv lo-correction GEMM: xl @ Wv (N=320, B rows offset 1024)
    dim3 gl(XVW / 64, NTOK / 128);
    tgemmh1<<<gl, 256, h1sm>>>(xbl, wt + (size_t)1024 * (DD / 2), xvlo, NTOK, XVW, DD);

    // gate GEMM (fp16 3-term, split-K=2): (8192x1024)@(1024x128) -> partials
    size_t h3sm = (size_t)3 * H3_STG * sizeof(uint32_t);   // 92160
    cudaFuncSetAttribute(tgemmh3, cudaFuncAttributeMaxDynamicSharedMemorySize, (int)h3sm);
    dim3 gg(NG / 64, NTOK / 128, KSPL);
    tgemmh3<<<gg, 256, h3sm>>>(xbh, xbl, gwh, gwl, glp, NTOK, NG, DD);

    // gating + V combine (+lo correction) + out-mask
    gate_combine_kernel<<<NTOK, 256>>>(glp, proj, xvlo, v, mask);

    // K/V fragment blob (fp16)
    dim3 bg(NTILE, BB * HH);
    build_kv4_kernel<<<bg, 256>>>(proj, v, blob);

    // attention (pure fp16, 3-stage)
    size_t asmem = (size_t)3 * TILE4_U32 * sizeof(uint32_t);  // 61440
    cudaFuncSetAttribute(attn5_kernel, cudaFuncAttributeMaxDynamicSharedMemorySize, (int)asmem);
    dim3 ag(TT / 128, BB * HH);
    attn5_kernel<<<ag, 256, asmem>>>(proj, blob, attn);

    // masked combine (+fp16 split), then output GEMM (2-term): (8192x320)@(320x1024)
    size_t h2sm = (size_t)3 * H2_STG * sizeof(uint32_t);   // 76800
    cudaFuncSetAttribute(tgemmh2, cudaFuncAttributeMaxDynamicSharedMemorySize, (int)h2sm);
    combine_out_kernel<<<NTOK, XVW / 2>>>(attn, mask, ybh, ybl);
    dim3 go(DD / 64, NTOK / 128);
    tgemmh2<<<go, 256, h2sm>>>(ybh, ybl, wot, out, NTOK, DD, XVW);
}

// round 13
// speedup vs baseline: 17.5323x; 1.1463x over previous
#include <cuda_runtime.h>
#include <cuda_bf16.h>
#include <cuda_fp16.h>
#include <math.h>
#include <stdint.h>

// Problem constants
#define BB 4
#define TT 2048
#define DD 1024
#define HH 8
#define DH 64
#define EE 5
#define NTOK (BB*TT)          // 8192
#define QKW (HH*DH)           // 512
#define GW  (HH*EE)           // 40
#define XVW (EE*DH)           // 320

// fused projection layout (row stride PW2): q[0:512) | k[512:1024) | xv[1024:1344)
#define PW2 1344
#define OFF_K 512
#define OFF_XV 1024

#define NG 128                 // gate GEMM padded width (glv 0..39, glo 40..79)
#define KSPL 2                 // gate GEMM split-K

// fp16 KV fragment blob: per (bh,tile64): [K | V], each 4 k0 x 32 lanes x 20 u32
#define ROWPAD 20
#define ARR2_U32 (4*32*ROWPAD)    // 2560
#define TILE4_U32 (2*ARR2_U32)    // 5120 u32 = 20KB
#define NTILE 32

// ---------------- scratch (device globals) ------------------------------------
__device__ float    g_proj [(size_t)NTOK*PW2];
__device__ __align__(16) uint32_t g_xbh [(size_t)NTOK*DD/2];   // fp16 hi pairs of x
__device__ __align__(16) uint32_t g_xbl [(size_t)NTOK*DD/2];   // fp16 lo pairs (gates)
__device__ __align__(16) uint32_t g_wt  [(size_t)PW2*DD/2];    // Wt[n][dpair] fp16 (single)
__device__ __align__(16) uint32_t g_gwh [(size_t)NG*DD/2];     // gate weights fp16 hi, [n][dpair]
__device__ __align__(16) uint32_t g_gwl [(size_t)NG*DD/2];     // lo
__device__ float    g_glp  [(size_t)KSPL*NTOK*NG];             // gate partials
__device__ float    g_v    [(size_t)NTOK*QKW];
__device__ float    g_attn [(size_t)NTOK*QKW];
__device__ float    g_mask [(size_t)NTOK*GW];
__device__ __align__(16) uint32_t g_yb  [(size_t)NTOK*XVW/2];  // fp16 pairs of Y (single)
__device__ __align__(16) uint32_t g_wot [(size_t)DD*XVW/2];    // WoT[n=d][kpair] fp16
__device__ __align__(16) uint32_t g_blob[(size_t)BB*HH*NTILE*TILE4_U32];  // ~21MB

// ---------------- helpers ------------------------------------------------------
// pack (a,b) into fp16x2 word; a -> bits[15:0]
__device__ __forceinline__ uint32_t packh2(float a, float b) {
    __half2 h = __floats2half2_rn(a, b);
    return *reinterpret_cast<uint32_t*>(&h);
}
// split pair (a,b) into fp16x2 hi and lo words
__device__ __forceinline__ void splith2(float a, float b, uint32_t& h, uint32_t& l) {
    __half ha = __float2half_rn(a);
    __half hb = __float2half_rn(b);
    float ra = a - __half2float(ha);
    float rb = b - __half2float(hb);
    __half2 hh; hh.x = ha; hh.y = hb;
    __half2 ll; ll.x = __float2half_rn(ra); ll.y = __float2half_rn(rb);
    h = *reinterpret_cast<uint32_t*>(&hh);
    l = *reinterpret_cast<uint32_t*>(&ll);
}
__device__ __forceinline__ void mma_f16(float c[4], const uint32_t a[4], const uint32_t b[2]) {
    asm volatile(
        "mma.sync.aligned.m16n8k16.row.col.f32.f16.f16.f32 "
        "{%0,%1,%2,%3},{%4,%5,%6,%7},{%8,%9},{%0,%1,%2,%3};"
        : "+f"(c[0]), "+f"(c[1]), "+f"(c[2]), "+f"(c[3])
        : "r"(a[0]), "r"(a[1]), "r"(a[2]), "r"(a[3]), "r"(b[0]), "r"(b[1]));
}
__device__ __forceinline__ void cp16(uint32_t saddr, const void* g) {
    asm volatile("cp.async.cg.shared.global [%0], [%1], 16;\n" :: "r"(saddr), "l"(g));
}
#define CP_COMMIT() asm volatile("cp.async.commit_group;\n")
#define CP_WAIT(n)  asm volatile("cp.async.wait_group %0;\n" :: "n"(n))

// =============== pre-split / pack kernels ======================================
__global__ void split_x_f16(const float* __restrict__ x,
                            uint32_t* __restrict__ xbh, uint32_t* __restrict__ xbl) {
    size_t i = (size_t)blockIdx.x * blockDim.x + threadIdx.x;
    if (i >= (size_t)NTOK * DD / 2) return;
    splith2(x[2 * i], x[2 * i + 1], xbh[i], xbl[i]);
}
__global__ void pack_wt_f16(const float* __restrict__ Wq, const float* __restrict__ Wk,
                            const float* __restrict__ Wv, uint32_t* __restrict__ Wt) {
    size_t idx = (size_t)blockIdx.x * blockDim.x + threadIdx.x;
    if (idx >= (size_t)PW2 * DD / 2) return;
    int n = (int)(idx / (DD / 2));
    int dp = (int)(idx % (DD / 2));
    int d0 = 2 * dp;
    float va, vb;
    if (n < 512) {
        va = Wq[(size_t)d0 * 512 + n]; vb = Wq[(size_t)(d0 + 1) * 512 + n];
    } else if (n < 1024) {
        va = Wk[(size_t)d0 * 512 + (n - 512)]; vb = Wk[(size_t)(d0 + 1) * 512 + (n - 512)];
    } else {
        int e = (n - 1024) / DH, j = (n - 1024) % DH;
        va = Wv[((size_t)e * DD + d0) * DH + j];
        vb = Wv[((size_t)e * DD + d0 + 1) * DH + j];
    }
    Wt[idx] = packh2(va, vb);
}
__global__ void pack_gw_f16(const float* __restrict__ Ws, const float* __restrict__ Wd,
                            uint32_t* __restrict__ Wh, uint32_t* __restrict__ Wl) {
    size_t idx = (size_t)blockIdx.x * blockDim.x + threadIdx.x;
    if (idx >= (size_t)NG * DD / 2) return;
    int n = (int)(idx / (DD / 2));
    int dp = (int)(idx % (DD / 2));
    int d0 = 2 * dp;
    float va = 0.f, vb = 0.f;
    if (n < 40)      { va = Ws[(size_t)d0 * GW + n];        vb = Ws[(size_t)(d0 + 1) * GW + n]; }
    else if (n < 80) { va = Wd[(size_t)d0 * GW + (n - 40)]; vb = Wd[(size_t)(d0 + 1) * GW + (n - 40)]; }
    splith2(va, vb, Wh[idx], Wl[idx]);
}
__global__ void pack_wot_f16(const float* __restrict__ Wo, uint32_t* __restrict__ Wt) {
    size_t idx = (size_t)blockIdx.x * blockDim.x + threadIdx.x;
    if (idx >= (size_t)DD * XVW / 2) return;
    int n = (int)(idx / (XVW / 2));
    int kp = (int)(idx % (XVW / 2));
    int k0 = 2 * kp;
    int e = k0 >> 6, j = k0 & 63;
    float va = Wo[((size_t)(e * DH + j)) * DD + n];
    float vb = Wo[((size_t)(e * DH + j + 1)) * DD + n];
    Wt[idx] = packh2(va, vb);
}

// =============== single-term fp16 GEMM: C=A@Bt^T, BM=128,BN=64,BK=32, 3-stage ==
// A: [M][K/2] fp16-pairs; Bt: [N][K/2] fp16-pairs
#define H1_OFF_B 2560
#define H1_STG   3840     // 15KB/stage

__global__ __launch_bounds__(256, 2)
void tgemmh1(const uint32_t* __restrict__ Ag, const uint32_t* __restrict__ Bg,
             float* __restrict__ C, int M, int N, int K) {
    extern __shared__ uint32_t sm1[];   // 3 stages x H1_STG
    const int tid = threadIdx.x;
    const int row0 = blockIdx.y * 128;
    const int col0 = blockIdx.x * 64;
    const int lane = tid & 31, w = tid >> 5;
    const int g = lane >> 2, t = lane & 3;
    const int wm = w >> 1, wn = w & 1;      // warp tile 32x32
    const int Ku = K / 2;

    const uint32_t sb = (uint32_t)__cvta_generic_to_shared(sm1);

    float c[2][4][4];
#pragma unroll
    for (int mt = 0; mt < 2; mt++)
#pragma unroll
        for (int nt = 0; nt < 4; nt++)
#pragma unroll
            for (int i = 0; i < 4; i++) c[mt][nt][i] = 0.f;

    const int nk = K / 32;

#define H1_LOAD(dst, kt)                                                          \
    {                                                                             \
        int ko = (kt) * 16;                                                       \
        _Pragma("unroll")                                                         \
        for (int it = 0; it < 2; it++) {                                          \
            int idx = it * 256 + tid;                                             \
            int r = idx >> 2, cc = idx & 3;                                       \
            cp16((dst) + (uint32_t)(r * ROWPAD + cc * 4) * 4,                     \
                 Ag + (size_t)(row0 + r) * Ku + ko + cc * 4);                     \
        }                                                                         \
        {                                                                         \
            int r = tid >> 2, cc = tid & 3;                                       \
            cp16((dst) + (uint32_t)(H1_OFF_B + r * ROWPAD + cc * 4) * 4,          \
                 Bg + (size_t)(col0 + r) * Ku + ko + cc * 4);                     \
        }                                                                         \
    }

    H1_LOAD(sb, 0);
    CP_COMMIT();
    if (nk > 1) {
        H1_LOAD(sb + (uint32_t)H1_STG * 4, 1);
        CP_COMMIT();
    }

    for (int kt = 0; kt < nk; kt++) {
        const int st = kt % 3;
        if (kt + 2 < nk) {
            uint32_t d2 = sb + (uint32_t)(((kt + 2) % 3) * H1_STG) * 4;
            H1_LOAD(d2, kt + 2);
            CP_COMMIT();
            CP_WAIT(2);
        } else if (kt + 1 < nk) {
            CP_WAIT(1);
        } else {
            CP_WAIT(0);
        }
        __syncthreads();

        const uint32_t* Ah = sm1 + st * H1_STG;
        const uint32_t* Bs = Ah + H1_OFF_B;

#pragma unroll
        for (int kc = 0; kc < 2; kc++) {
            uint32_t af[2][4], bf[4][2];
#pragma unroll
            for (int mt = 0; mt < 2; mt++) {
                int rb = wm * 32 + mt * 16;
                af[mt][0] = Ah[(rb + g    ) * ROWPAD + kc * 8 + t];
                af[mt][1] = Ah[(rb + g + 8) * ROWPAD + kc * 8 + t];
                af[mt][2] = Ah[(rb + g    ) * ROWPAD + kc * 8 + t + 4];
                af[mt][3] = Ah[(rb + g + 8) * ROWPAD + kc * 8 + t + 4];
            }
#pragma unroll
            for (int nt = 0; nt < 4; nt++) {
                int cb = wn * 32 + nt * 8;
                bf[nt][0] = Bs[(cb + g) * ROWPAD + kc * 8 + t];
                bf[nt][1] = Bs[(cb + g) * ROWPAD + kc * 8 + t + 4];
            }
#pragma unroll
            for (int mt = 0; mt < 2; mt++)
#pragma unroll
                for (int nt = 0; nt < 4; nt++)
                    mma_f16(c[mt][nt], af[mt], bf[nt]);
        }
        __syncthreads();
    }

#pragma unroll
    for (int mt = 0; mt < 2; mt++) {
        int r0 = row0 + wm * 32 + mt * 16;
#pragma unroll
        for (int nt = 0; nt < 4; nt++) {
            int cc = col0 + wn * 32 + nt * 8 + 2 * t;
            *(float2*)&C[(size_t)(r0 + g    ) * N + cc] = make_float2(c[mt][nt][0], c[mt][nt][1]);
            *(float2*)&C[(size_t)(r0 + g + 8) * N + cc] = make_float2(c[mt][nt][2], c[mt][nt][3]);
        }
    }
}

// =============== fp16 3-term GEMM (gates): A hi/lo, B hi/lo, split-K ===========
#define H3_OFF_AL 2560
#define H3_OFF_BH 5120
#define H3_OFF_BL 6400
#define H3_STG    7680

__global__ __launch_bounds__(256, 2)
void tgemmh3(const uint32_t* __restrict__ Agh, const uint32_t* __restrict__ Agl,
             const uint32_t* __restrict__ Bgh, const uint32_t* __restrict__ Bgl,
             float* __restrict__ C, int M, int N, int K) {
    extern __shared__ uint32_t sm3[];   // 3 stages x H3_STG
    const int tid = threadIdx.x;
    const int row0 = blockIdx.y * 128;
    const int col0 = blockIdx.x * 64;
    const int lane = tid & 31, w = tid >> 5;
    const int g = lane >> 2, t = lane & 3;
    const int wm = w >> 1, wn = w & 1;
    const int Ku = K / 2;
    const int ksplit = gridDim.z;
    const int kb = blockIdx.z * (K / 32 / ksplit);   // starting k-chunk
    const int nk = K / 32 / ksplit;
    float* Cz = C + (size_t)blockIdx.z * M * N;

    const uint32_t sb = (uint32_t)__cvta_generic_to_shared(sm3);

    float c[2][4][4];
#pragma unroll
    for (int mt = 0; mt < 2; mt++)
#pragma unroll
        for (int nt = 0; nt < 4; nt++)
#pragma unroll
            for (int i = 0; i < 4; i++) c[mt][nt][i] = 0.f;

#define H3_LOAD(dst, kt)                                                          \
    {                                                                             \
        int ko = (kb + (kt)) * 16;                                                \
        _Pragma("unroll")                                                         \
        for (int it = 0; it < 2; it++) {                                          \
            int idx = it * 256 + tid;                                             \
            int r = idx >> 2, cc = idx & 3;                                       \
            cp16((dst) + (uint32_t)(r * ROWPAD + cc * 4) * 4,                     \
                 Agh + (size_t)(row0 + r) * Ku + ko + cc * 4);                    \
            cp16((dst) + (uint32_t)(H3_OFF_AL + r * ROWPAD + cc * 4) * 4,         \
                 Agl + (size_t)(row0 + r) * Ku + ko + cc * 4);                    \
        }                                                                         \
        {                                                                         \
            int r = tid >> 2, cc = tid & 3;                                       \
            cp16((dst) + (uint32_t)(H3_OFF_BH + r * ROWPAD + cc * 4) * 4,         \
                 Bgh + (size_t)(col0 + r) * Ku + ko + cc * 4);                    \
            cp16((dst) + (uint32_t)(H3_OFF_BL + r * ROWPAD + cc * 4) * 4,         \
                 Bgl + (size_t)(col0 + r) * Ku + ko + cc * 4);                    \
        }                                                                         \
    }

    H3_LOAD(sb, 0);
    CP_COMMIT();
    if (nk > 1) {
        H3_LOAD(sb + (uint32_t)H3_STG * 4, 1);
        CP_COMMIT();
    }

    for (int kt = 0; kt < nk; kt++) {
        const int st = kt % 3;
        if (kt + 2 < nk) {
            uint32_t d2 = sb + (uint32_t)(((kt + 2) % 3) * H3_STG) * 4;
            H3_LOAD(d2, kt + 2);
            CP_COMMIT();
            CP_WAIT(2);
        } else if (kt + 1 < nk) {
            CP_WAIT(1);
        } else {
            CP_WAIT(0);
        }
        __syncthreads();

        const uint32_t* Ah = sm3 + st * H3_STG;
        const uint32_t* Al = Ah + H3_OFF_AL;
        const uint32_t* Bh = Ah + H3_OFF_BH;
        const uint32_t* Bl = Ah + H3_OFF_BL;

#pragma unroll
        for (int kc = 0; kc < 2; kc++) {
            uint32_t afh[2][4], afl[2][4], bfh[4][2], bfl[4][2];
#pragma unroll
            for (int mt = 0; mt < 2; mt++) {
                int rb = wm * 32 + mt * 16;
                afh[mt][0] = Ah[(rb + g    ) * ROWPAD + kc * 8 + t];
                afh[mt][1] = Ah[(rb + g + 8) * ROWPAD + kc * 8 + t];
                afh[mt][2] = Ah[(rb + g    ) * ROWPAD + kc * 8 + t + 4];
                afh[mt][3] = Ah[(rb + g + 8) * ROWPAD + kc * 8 + t + 4];
                afl[mt][0] = Al[(rb + g    ) * ROWPAD + kc * 8 + t];
                afl[mt][1] = Al[(rb + g + 8) * ROWPAD + kc * 8 + t];
                afl[mt][2] = Al[(rb + g    ) * ROWPAD + kc * 8 + t + 4];
                afl[mt][3] = Al[(rb + g + 8) * ROWPAD + kc * 8 + t + 4];
            }
#pragma unroll
            for (int nt = 0; nt < 4; nt++) {
                int cb = wn * 32 + nt * 8;
                bfh[nt][0] = Bh[(cb + g) * ROWPAD + kc * 8 + t];
                bfh[nt][1] = Bh[(cb + g) * ROWPAD + kc * 8 + t + 4];
                bfl[nt][0] = Bl[(cb + g) * ROWPAD + kc * 8 + t];
                bfl[nt][1] = Bl[(cb + g) * ROWPAD + kc * 8 + t + 4];
            }
#pragma unroll
            for (int mt = 0; mt < 2; mt++)
#pragma unroll
                for (int nt = 0; nt < 4; nt++) {
                    mma_f16(c[mt][nt], afh[mt], bfl[nt]);
                    mma_f16(c[mt][nt], afl[mt], bfh[nt]);
                    mma_f16(c[mt][nt], afh[mt], bfh[nt]);
                }
        }
        __syncthreads();
    }

#pragma unroll
    for (int mt = 0; mt < 2; mt++) {
        int r0 = row0 + wm * 32 + mt * 16;
#pragma unroll
        for (int nt = 0; nt < 4; nt++) {
            int cc = col0 + wn * 32 + nt * 8 + 2 * t;
            *(float2*)&Cz[(size_t)(r0 + g    ) * N + cc] = make_float2(c[mt][nt][0], c[mt][nt][1]);
            *(float2*)&Cz[(size_t)(r0 + g + 8) * N + cc] = make_float2(c[mt][nt][2], c[mt][nt][3]);
        }
    }
}

// -------- gating: sum split-K partials, top-2, V combine, out mask -------------
__global__ void gate_combine_kernel(const float* __restrict__ glp,
                                    const float* __restrict__ proj,
                                    float* __restrict__ v,
                                    float* __restrict__ masko) {
    int token = blockIdx.x;
    int w = threadIdx.x / 32;
    int lane = threadIdx.x % 32;

    float g[EE];
#pragma unroll
    for (int e = 0; e < EE; e++) {
        float s = 0.f;
#pragma unroll
        for (int z = 0; z < KSPL; z++)
            s += glp[((size_t)z * NTOK + token) * NG + w * EE + e];
        g[e] = s;
    }
    int i1 = 0;
#pragma unroll
    for (int e = 1; e < EE; e++) if (g[e] > g[i1]) i1 = e;
    int i2 = (i1 == 0) ? 1 : 0;
#pragma unroll
    for (int e = 0; e < EE; e++) if (e != i1 && g[e] > g[i2]) i2 = e;
    float w1 = 1.f / (1.f + __expf(-g[i1]));
    float w2 = 1.f / (1.f + __expf(-g[i2]));

    const float* xvt = proj + (size_t)token * PW2 + OFF_XV;
    float* vt = v + (size_t)token * QKW + w * DH;
#pragma unroll
    for (int d = lane; d < DH; d += 32)
        vt[d] = w1 * xvt[i1 * DH + d] + w2 * xvt[i2 * DH + d];

#pragma unroll
    for (int e = 0; e < EE; e++) {
        float s = 0.f;
#pragma unroll
        for (int z = 0; z < KSPL; z++)
            s += glp[((size_t)z * NTOK + token) * NG + 40 + w * EE + e];
        g[e] = s;
    }
    int o1 = 0;
#pragma unroll
    for (int e = 1; e < EE; e++) if (g[e] > g[o1]) o1 = e;
    int o2 = (o1 == 0) ? 1 : 0;
#pragma unroll
    for (int e = 0; e < EE; e++) if (e != o1 && g[e] > g[o2]) o2 = e;
    if (lane < EE)
        masko[((size_t)token * HH + w) * EE + lane] = (lane == o1 || lane == o2) ? 1.f : 0.f;
}

// =============== build fp16 K/V fragment blob ==================================
__global__ void build_kv4_kernel(const float* __restrict__ proj,
                                 const float* __restrict__ v,
                                 uint32_t* __restrict__ blob) {
    __shared__ float Ks[64 * 68];
    __shared__ float Vs[64 * 68];
    const int tile = blockIdx.x, bh = blockIdx.y;
    const int b = bh / HH, h = bh % HH;
    const int tid = threadIdx.x;

#pragma unroll
    for (int it = 0; it < 4; it++) {
        int idx = it * 256 + tid;
        int r = (idx * 4) >> 6, d = (idx * 4) & 63;
        const float* kb = proj + (size_t)(b * TT + tile * 64 + r) * PW2 + OFF_K + h * DH;
        const float* vb = v    + (size_t)(b * TT + tile * 64 + r) * QKW + h * DH;
        *(float4*)&Ks[r * 68 + d] = *(const float4*)(kb + d);
        *(float4*)&Vs[r * 68 + d] = *(const float4*)(vb + d);
    }
    __syncthreads();

    uint32_t* dst = blob + ((size_t)bh * NTILE + tile) * TILE4_U32;
#pragma unroll
    for (int i = 0; i < 8; i++) {
        int oi = tid * 8 + i;
        int row = oi >> 4;
        int col = oi & 15;
        int k0 = row >> 5, lane2 = row & 31;
        int g2 = lane2 >> 2, t2 = lane2 & 3;
        int n0 = col >> 1, w2 = col & 1;
        int dK = k0 * 16 + w2 * 8 + 2 * t2;
        int keyK = n0 * 8 + g2;
        dst[row * ROWPAD + col] = packh2(Ks[keyK * 68 + dK], Ks[keyK * 68 + dK + 1]);
        int keyV = k0 * 16 + w2 * 8 + 2 * t2;
        int dV = n0 * 8 + g2;
        dst[ARR2_U32 + row * ROWPAD + col] = packh2(Vs[keyV * 68 + dV], Vs[(keyV + 1) * 68 + dV]);
    }
}

// =============== flash attention, pure fp16, fragment blob + cp.async ==========
#define LOG2E 1.4426950408889634f
#define SCLG2E (0.125f * LOG2E)

__global__ __launch_bounds__(256, 2)
void attn5_kernel(const float* __restrict__ qg,
                  const uint32_t* __restrict__ blob,
                  float* __restrict__ o) {
    extern __shared__ uint32_t sh[];     // 3 stages x TILE4_U32
    const int bh = blockIdx.y;
    const int b = bh / HH, h = bh % HH;
    const int q0 = blockIdx.x * 128;
    const int tid = threadIdx.x;
    const int lane = tid & 31, w = tid >> 5;
    const int g = lane >> 2, t = lane & 3;

    const uint32_t* gblob = blob + (size_t)bh * NTILE * TILE4_U32;
    const uint32_t sbase = (uint32_t)__cvta_generic_to_shared(sh);

#define BLOB_DMA(dstoff, srct)                                                   \
    {                                                                            \
        const uint32_t* src = gblob + (size_t)(srct) * TILE4_U32;                \
        _Pragma("unroll")                                                        \
        for (int i = 0; i < 5; i++) {                                            \
            int cc = tid + i * 256;                                              \
            cp16(sbase + (uint32_t)((dstoff) + cc * 4) * 4, src + cc * 4);       \
        }                                                                        \
    }

    BLOB_DMA(0, 0);
    CP_COMMIT();
    BLOB_DMA(TILE4_U32, 1);
    CP_COMMIT();

    const float* qb = qg + (size_t)(b * TT + q0 + w * 16) * PW2 + h * DH;
    uint32_t qa[4][4];
#pragma unroll
    for (int k0 = 0; k0 < 4; k0++) {
        qa[k0][0] = packh2(qb[(size_t)(g    ) * PW2 + k0 * 16 + 2 * t],
                           qb[(size_t)(g    ) * PW2 + k0 * 16 + 2 * t + 1]);
        qa[k0][1] = packh2(qb[(size_t)(g + 8) * PW2 + k0 * 16 + 2 * t],
                           qb[(size_t)(g + 8) * PW2 + k0 * 16 + 2 * t + 1]);
        qa[k0][2] = packh2(qb[(size_t)(g    ) * PW2 + k0 * 16 + 2 * t + 8],
                           qb[(size_t)(g    ) * PW2 + k0 * 16 + 2 * t + 9]);
        qa[k0][3] = packh2(qb[(size_t)(g + 8) * PW2 + k0 * 16 + 2 * t + 8],
                           qb[(size_t)(g + 8) * PW2 + k0 * 16 + 2 * t + 9]);
    }

    float om[8][4];
#pragma unroll
    for (int n = 0; n < 8; n++)
#pragma unroll
        for (int i = 0; i < 4; i++) om[n][i] = 0.f;
    float rm0 = -INFINITY, rm1 = -INFINITY, rl0 = 0.f, rl1 = 0.f;

    for (int tt = 0; tt < NTILE; tt++) {
        const int st = tt % 3;
        if (tt + 2 < NTILE) {
            BLOB_DMA(((tt + 2) % 3) * TILE4_U32, tt + 2);
            CP_COMMIT();
            CP_WAIT(2);
        } else if (tt + 1 < NTILE) {
            CP_WAIT(1);
        } else {
            CP_WAIT(0);
        }
        __syncthreads();

        const uint32_t* Kf = sh + st * TILE4_U32;
        const uint32_t* Vf = Kf + ARR2_U32;

        float s[8][4];
#pragma unroll
        for (int n = 0; n < 8; n++)
#pragma unroll
            for (int i = 0; i < 4; i++) s[n][i] = 0.f;
#pragma unroll
        for (int k0 = 0; k0 < 4; k0++) {
            const uint32_t* kr = Kf + (k0 * 32 + lane) * ROWPAD;
#pragma unroll
            for (int np = 0; np < 4; np++) {
                uint4 k4 = *(const uint4*)(kr + np * 4);
                uint32_t b2[2] = {k4.x, k4.y};
                mma_f16(s[2 * np], qa[k0], b2);
                uint32_t b3[2] = {k4.z, k4.w};
                mma_f16(s[2 * np + 1], qa[k0], b3);
            }
        }

        float m0 = s[0][0], m1 = s[0][2];
#pragma unroll
        for (int n = 0; n < 8; n++) {
            m0 = fmaxf(m0, fmaxf(s[n][0], s[n][1]));
            m1 = fmaxf(m1, fmaxf(s[n][2], s[n][3]));
        }
        m0 = fmaxf(m0, __shfl_xor_sync(0xffffffff, m0, 1));
        m0 = fmaxf(m0, __shfl_xor_sync(0xffffffff, m0, 2));
        m1 = fmaxf(m1, __shfl_xor_sync(0xffffffff, m1, 1));
        m1 = fmaxf(m1, __shfl_xor_sync(0xffffffff, m1, 2));

        float mn0 = fmaxf(rm0, m0);
        float mn1 = fmaxf(rm1, m1);
        float corr0 = exp2f((rm0 - mn0) * SCLG2E);
        float corr1 = exp2f((rm1 - mn1) * SCLG2E);

        float sum0 = 0.f, sum1 = 0.f;
#pragma unroll
        for (int n = 0; n < 8; n++) {
            s[n][0] = exp2f((s[n][0] - mn0) * SCLG2E);
            s[n][1] = exp2f((s[n][1] - mn0) * SCLG2E);
            s[n][2] = exp2f((s[n][2] - mn1) * SCLG2E);
            s[n][3] = exp2f((s[n][3] - mn1) * SCLG2E);
            sum0 += s[n][0] + s[n][1];
            sum1 += s[n][2] + s[n][3];
        }
        sum0 += __shfl_xor_sync(0xffffffff, sum0, 1);
        sum0 += __shfl_xor_sync(0xffffffff, sum0, 2);
        sum1 += __shfl_xor_sync(0xffffffff, sum1, 1);
        sum1 += __shfl_xor_sync(0xffffffff, sum1, 2);
        rl0 = rl0 * corr0 + sum0;
        rl1 = rl1 * corr1 + sum1;
        rm0 = mn0; rm1 = mn1;

#pragma unroll
        for (int n = 0; n < 8; n++) {
            om[n][0] *= corr0; om[n][1] *= corr0;
            om[n][2] *= corr1; om[n][3] *= corr1;
        }

#pragma unroll
        for (int k0 = 0; k0 < 4; k0++) {
            uint32_t ph[4];
            ph[0] = packh2(s[2 * k0][0],     s[2 * k0][1]);
            ph[1] = packh2(s[2 * k0][2],     s[2 * k0][3]);
            ph[2] = packh2(s[2 * k0 + 1][0], s[2 * k0 + 1][1]);
            ph[3] = packh2(s[2 * k0 + 1][2], s[2 * k0 + 1][3]);
            const uint32_t* vr = Vf + (k0 * 32 + lane) * ROWPAD;
#pragma unroll
            for (int np = 0; np < 4; np++) {
                uint4 v4 = *(const uint4*)(vr + np * 4);
                uint32_t b2[2] = {v4.x, v4.y};
                mma_f16(om[2 * np], ph, b2);
                uint32_t b3[2] = {v4.z, v4.w};
                mma_f16(om[2 * np + 1], ph, b3);
            }
        }
        __syncthreads();
    }

    float inv0 = 1.f / rl0;
    float inv1 = 1.f / rl1;
    float* ob0 = o + (size_t)(b * TT + q0 + w * 16 + g    ) * QKW + h * DH + 2 * t;
    float* ob1 = o + (size_t)(b * TT + q0 + w * 16 + g + 8) * QKW + h * DH + 2 * t;
#pragma unroll
    for (int n0 = 0; n0 < 8; n0++) {
        *(float2*)(ob0 + n0 * 8) = make_float2(om[n0][0] * inv0, om[n0][1] * inv0);
        *(float2*)(ob1 + n0 * 8) = make_float2(om[n0][2] * inv1, om[n0][3] * inv1);
    }
}

// -------- Y pairs: Y[t, 2i..2i+1] = sum_h mask*attn -> single fp16 -------------
__global__ void combine_out_kernel(const float* __restrict__ attn,
                                   const float* __restrict__ masko,
                                   uint32_t* __restrict__ Y) {
    int token = blockIdx.x;
    int tid = threadIdx.x;          // 0..159
    int t0 = 2 * tid;
    int e = t0 >> 6, j = t0 & 63;
    const float* ap = attn + (size_t)token * QKW;
    const float* mp = masko + (size_t)token * GW;
    float s0 = 0.f, s1 = 0.f;
#pragma unroll
    for (int h = 0; h < HH; h++) {
        float m = mp[h * EE + e];
        s0 += m * ap[h * DH + j];
        s1 += m * ap[h * DH + j + 1];
    }
    Y[(size_t)token * (XVW / 2) + tid] = packh2(s0, s1);
}

// ------------------------------- launch ----------------------------------------
extern "C" void kernel_launch(void* const* d_in, const int* in_sizes, int n_in,
                              void* d_out, int out_size) {
    const float* x  = (const float*)d_in[0];
    const float* Wq = (const float*)d_in[1];
    const float* Wk = (const float*)d_in[2];
    const float* Ws = (const float*)d_in[3];
    const float* Wd = (const float*)d_in[4];
    const float* Wv = (const float*)d_in[5];
    const float* Wo = (const float*)d_in[6];
    float* out = (float*)d_out;

    float *proj, *glp, *v, *attn, *mask;
    uint32_t *xbh, *xbl, *wt, *gwh, *gwl, *yb, *wot, *blob;
    cudaGetSymbolAddress((void**)&proj, g_proj);
    cudaGetSymbolAddress((void**)&xbh,  g_xbh);
    cudaGetSymbolAddress((void**)&xbl,  g_xbl);
    cudaGetSymbolAddress((void**)&wt,   g_wt);
    cudaGetSymbolAddress((void**)&gwh,  g_gwh);
    cudaGetSymbolAddress((void**)&gwl,  g_gwl);
    cudaGetSymbolAddress((void**)&glp,  g_glp);
    cudaGetSymbolAddress((void**)&v,    g_v);
    cudaGetSymbolAddress((void**)&attn, g_attn);
    cudaGetSymbolAddress((void**)&mask, g_mask);
    cudaGetSymbolAddress((void**)&yb,   g_yb);
    cudaGetSymbolAddress((void**)&wot,  g_wot);
    cudaGetSymbolAddress((void**)&blob, g_blob);

    // pre-splits / packs
    split_x_f16 <<<(int)(((size_t)NTOK * DD / 2 + 255) / 256), 256>>>(x, xbh, xbl);
    pack_wt_f16 <<<(int)(((size_t)PW2 * DD / 2 + 255) / 256), 256>>>(Wq, Wk, Wv, wt);
    pack_gw_f16 <<<(int)(((size_t)NG * DD / 2 + 255) / 256), 256>>>(Ws, Wd, gwh, gwl);
    pack_wot_f16<<<(int)(((size_t)DD * XVW / 2 + 255) / 256), 256>>>(Wo, wot);

    // proj GEMM (single fp16, 3-stage): (8192x1024)@(1024x1344)
    size_t h1sm = (size_t)3 * H1_STG * sizeof(uint32_t);   // 46080
    cudaFuncSetAttribute(tgemmh1, cudaFuncAttributeMaxDynamicSharedMemorySize, (int)h1sm);
    dim3 gp(PW2 / 64, NTOK / 128);
    tgemmh1<<<gp, 256, h1sm>>>(xbh, wt, proj, NTOK, PW2, DD);

    // gate GEMM (fp16 3-term, split-K=2): (8192x1024)@(1024x128) -> partials
    size_t h3sm = (size_t)3 * H3_STG * sizeof(uint32_t);   // 92160
    cudaFuncSetAttribute(tgemmh3, cudaFuncAttributeMaxDynamicSharedMemorySize, (int)h3sm);
    dim3 gg(NG / 64, NTOK / 128, KSPL);
    tgemmh3<<<gg, 256, h3sm>>>(xbh, xbl, gwh, gwl, glp, NTOK, NG, DD);

    // gating + V combine + out-mask
    gate_combine_kernel<<<NTOK, 256>>>(glp, proj, v, mask);

    // K/V fragment blob (fp16)
    dim3 bg(NTILE, BB * HH);
    build_kv4_kernel<<<bg, 256>>>(proj, v, blob);

    // attention (pure fp16, 3-stage)
    size_t asmem = (size_t)3 * TILE4_U32 * sizeof(uint32_t);  // 61440
    cudaFuncSetAttribute(attn5_kernel, cudaFuncAttributeMaxDynamicSharedMemorySize, (int)asmem);
    dim3 ag(TT / 128, BB * HH);
    attn5_kernel<<<ag, 256, asmem>>>(proj, blob, attn);

    // masked combine (single fp16), then output GEMM (single-term)
    combine_out_kernel<<<NTOK, XVW / 2>>>(attn, mask, yb);
    dim3 go(DD / 64, NTOK / 128);
    tgemmh1<<<go, 256, h1sm>>>(yb, wot, out, NTOK, DD, XVW);
}

// round 14
// speedup vs baseline: 18.1384x; 1.0346x over previous
#include <cuda_runtime.h>
#include <cuda_bf16.h>
#include <cuda_fp16.h>
#include <math.h>
#include <stdint.h>

// Problem constants
#define BB 4
#define TT 2048
#define DD 1024
#define HH 8
#define DH 64
#define EE 5
#define NTOK (BB*TT)          // 8192
#define QKW (HH*DH)           // 512
#define GW  (HH*EE)           // 40
#define XVW (EE*DH)           // 320

// fused projection layout (row stride PW2): q[0:512) | k[512:1024) | xv[1024:1344)
#define PW2 1344
#define OFF_K 512
#define OFF_XV 1024

#define NG 128                 // gate GEMM padded width (glv 0..39, glo 40..79)
#define KSPL 2                 // gate GEMM split-K

// fp16 KV fragment blob: per (bh,tile64): [K | V], each 4 k0 x 32 lanes x 20 u32
#define ROWPAD 20
#define ARR2_U32 (4*32*ROWPAD)    // 2560
#define TILE4_U32 (2*ARR2_U32)    // 5120 u32 = 20KB
#define NTILE 32

// ---------------- scratch (device globals) ------------------------------------
__device__ float    g_proj [(size_t)NTOK*PW2];
__device__ __align__(16) uint32_t g_xbh [(size_t)NTOK*DD/2];   // fp16 hi pairs of x
__device__ __align__(16) uint32_t g_xbl [(size_t)NTOK*DD/2];   // fp16 lo pairs (gates)
__device__ __align__(16) uint32_t g_wt  [(size_t)PW2*DD/2];    // Wt[n][dpair] fp16 (single)
__device__ __align__(16) uint32_t g_gwh [(size_t)NG*DD/2];     // gate weights fp16 hi
__device__ __align__(16) uint32_t g_gwl [(size_t)NG*DD/2];     // lo
__device__ float    g_glp  [(size_t)KSPL*NTOK*NG];             // gate partials
__device__ __align__(16) uint32_t g_attnh[(size_t)NTOK*QKW/2]; // attn out, fp16 pairs
__device__ float    g_mask [(size_t)NTOK*GW];
__device__ __align__(16) uint32_t g_yb  [(size_t)NTOK*XVW/2];  // fp16 pairs of Y
__device__ __align__(16) uint32_t g_wot [(size_t)DD*XVW/2];    // WoT[n=d][kpair] fp16
__device__ __align__(16) uint32_t g_blob[(size_t)BB*HH*NTILE*TILE4_U32];  // ~21MB

// ---------------- helpers ------------------------------------------------------
__device__ __forceinline__ uint32_t packh2(float a, float b) {
    __half2 h = __floats2half2_rn(a, b);
    return *reinterpret_cast<uint32_t*>(&h);
}
__device__ __forceinline__ void splith2(float a, float b, uint32_t& h, uint32_t& l) {
    __half ha = __float2half_rn(a);
    __half hb = __float2half_rn(b);
    float ra = a - __half2float(ha);
    float rb = b - __half2float(hb);
    __half2 hh; hh.x = ha; hh.y = hb;
    __half2 ll; ll.x = __float2half_rn(ra); ll.y = __float2half_rn(rb);
    h = *reinterpret_cast<uint32_t*>(&hh);
    l = *reinterpret_cast<uint32_t*>(&ll);
}
__device__ __forceinline__ void mma_f16(float c[4], const uint32_t a[4], const uint32_t b[2]) {
    asm volatile(
        "mma.sync.aligned.m16n8k16.row.col.f32.f16.f16.f32 "
        "{%0,%1,%2,%3},{%4,%5,%6,%7},{%8,%9},{%0,%1,%2,%3};"
        : "+f"(c[0]), "+f"(c[1]), "+f"(c[2]), "+f"(c[3])
        : "r"(a[0]), "r"(a[1]), "r"(a[2]), "r"(a[3]), "r"(b[0]), "r"(b[1]));
}
__device__ __forceinline__ void cp16(uint32_t saddr, const void* g) {
    asm volatile("cp.async.cg.shared.global [%0], [%1], 16;\n" :: "r"(saddr), "l"(g));
}
#define CP_COMMIT() asm volatile("cp.async.commit_group;\n")
#define CP_WAIT(n)  asm volatile("cp.async.wait_group %0;\n" :: "n"(n))

// =============== pre-split / pack kernels ======================================
__global__ void split_x_f16(const float* __restrict__ x,
                            uint32_t* __restrict__ xbh, uint32_t* __restrict__ xbl) {
    size_t i = (size_t)blockIdx.x * blockDim.x + threadIdx.x;
    if (i >= (size_t)NTOK * DD / 2) return;
    splith2(x[2 * i], x[2 * i + 1], xbh[i], xbl[i]);
}
__global__ void pack_wt_f16(const float* __restrict__ Wq, const float* __restrict__ Wk,
                            const float* __restrict__ Wv, uint32_t* __restrict__ Wt) {
    size_t idx = (size_t)blockIdx.x * blockDim.x + threadIdx.x;
    if (idx >= (size_t)PW2 * DD / 2) return;
    int n = (int)(idx / (DD / 2));
    int dp = (int)(idx % (DD / 2));
    int d0 = 2 * dp;
    float va, vb;
    if (n < 512) {
        va = Wq[(size_t)d0 * 512 + n]; vb = Wq[(size_t)(d0 + 1) * 512 + n];
    } else if (n < 1024) {
        va = Wk[(size_t)d0 * 512 + (n - 512)]; vb = Wk[(size_t)(d0 + 1) * 512 + (n - 512)];
    } else {
        int e = (n - 1024) / DH, j = (n - 1024) % DH;
        va = Wv[((size_t)e * DD + d0) * DH + j];
        vb = Wv[((size_t)e * DD + d0 + 1) * DH + j];
    }
    Wt[idx] = packh2(va, vb);
}
__global__ void pack_gw_f16(const float* __restrict__ Ws, const float* __restrict__ Wd,
                            uint32_t* __restrict__ Wh, uint32_t* __restrict__ Wl) {
    size_t idx = (size_t)blockIdx.x * blockDim.x + threadIdx.x;
    if (idx >= (size_t)NG * DD / 2) return;
    int n = (int)(idx / (DD / 2));
    int dp = (int)(idx % (DD / 2));
    int d0 = 2 * dp;
    float va = 0.f, vb = 0.f;
    if (n < 40)      { va = Ws[(size_t)d0 * GW + n];        vb = Ws[(size_t)(d0 + 1) * GW + n]; }
    else if (n < 80) { va = Wd[(size_t)d0 * GW + (n - 40)]; vb = Wd[(size_t)(d0 + 1) * GW + (n - 40)]; }
    splith2(va, vb, Wh[idx], Wl[idx]);
}
__global__ void pack_wot_f16(const float* __restrict__ Wo, uint32_t* __restrict__ Wt) {
    size_t idx = (size_t)blockIdx.x * blockDim.x + threadIdx.x;
    if (idx >= (size_t)DD * XVW / 2) return;
    int n = (int)(idx / (XVW / 2));
    int kp = (int)(idx % (XVW / 2));
    int k0 = 2 * kp;
    int e = k0 >> 6, j = k0 & 63;
    float va = Wo[((size_t)(e * DH + j)) * DD + n];
    float vb = Wo[((size_t)(e * DH + j + 1)) * DD + n];
    Wt[idx] = packh2(va, vb);
}

// =============== single-term fp16 GEMM: C=A@Bt^T, BM=128,BN=64,BK=32, 3-stage ==
#define H1_OFF_B 2560
#define H1_STG   3840     // 15KB/stage

__global__ __launch_bounds__(256, 2)
void tgemmh1(const uint32_t* __restrict__ Ag, const uint32_t* __restrict__ Bg,
             float* __restrict__ C, int M, int N, int K) {
    extern __shared__ uint32_t sm1[];   // 3 stages x H1_STG
    const int tid = threadIdx.x;
    const int row0 = blockIdx.y * 128;
    const int col0 = blockIdx.x * 64;
    const int lane = tid & 31, w = tid >> 5;
    const int g = lane >> 2, t = lane & 3;
    const int wm = w >> 1, wn = w & 1;
    const int Ku = K / 2;

    const uint32_t sb = (uint32_t)__cvta_generic_to_shared(sm1);

    float c[2][4][4];
#pragma unroll
    for (int mt = 0; mt < 2; mt++)
#pragma unroll
        for (int nt = 0; nt < 4; nt++)
#pragma unroll
            for (int i = 0; i < 4; i++) c[mt][nt][i] = 0.f;

    const int nk = K / 32;

#define H1_LOAD(dst, kt)                                                          \
    {                                                                             \
        int ko = (kt) * 16;                                                       \
        _Pragma("unroll")                                                         \
        for (int it = 0; it < 2; it++) {                                          \
            int idx = it * 256 + tid;                                             \
            int r = idx >> 2, cc = idx & 3;                                       \
            cp16((dst) + (uint32_t)(r * ROWPAD + cc * 4) * 4,                     \
                 Ag + (size_t)(row0 + r) * Ku + ko + cc * 4);                     \
        }                                                                         \
        {                                                                         \
            int r = tid >> 2, cc = tid & 3;                                       \
            cp16((dst) + (uint32_t)(H1_OFF_B + r * ROWPAD + cc * 4) * 4,          \
                 Bg + (size_t)(col0 + r) * Ku + ko + cc * 4);                     \
        }                                                                         \
    }

    H1_LOAD(sb, 0);
    CP_COMMIT();
    if (nk > 1) {
        H1_LOAD(sb + (uint32_t)H1_STG * 4, 1);
        CP_COMMIT();
    }

    for (int kt = 0; kt < nk; kt++) {
        const int st = kt % 3;
        if (kt + 2 < nk) {
            uint32_t d2 = sb + (uint32_t)(((kt + 2) % 3) * H1_STG) * 4;
            H1_LOAD(d2, kt + 2);
            CP_COMMIT();
            CP_WAIT(2);
        } else if (kt + 1 < nk) {
            CP_WAIT(1);
        } else {
            CP_WAIT(0);
        }
        __syncthreads();

        const uint32_t* Ah = sm1 + st * H1_STG;
        const uint32_t* Bs = Ah + H1_OFF_B;

#pragma unroll
        for (int kc = 0; kc < 2; kc++) {
            uint32_t af[2][4], bf[4][2];
#pragma unroll
            for (int mt = 0; mt < 2; mt++) {
                int rb = wm * 32 + mt * 16;
                af[mt][0] = Ah[(rb + g    ) * ROWPAD + kc * 8 + t];
                af[mt][1] = Ah[(rb + g + 8) * ROWPAD + kc * 8 + t];
                af[mt][2] = Ah[(rb + g    ) * ROWPAD + kc * 8 + t + 4];
                af[mt][3] = Ah[(rb + g + 8) * ROWPAD + kc * 8 + t + 4];
            }
#pragma unroll
            for (int nt = 0; nt < 4; nt++) {
                int cb = wn * 32 + nt * 8;
                bf[nt][0] = Bs[(cb + g) * ROWPAD + kc * 8 + t];
                bf[nt][1] = Bs[(cb + g) * ROWPAD + kc * 8 + t + 4];
            }
#pragma unroll
            for (int mt = 0; mt < 2; mt++)
#pragma unroll
                for (int nt = 0; nt < 4; nt++)
                    mma_f16(c[mt][nt], af[mt], bf[nt]);
        }
        __syncthreads();
    }

#pragma unroll
    for (int mt = 0; mt < 2; mt++) {
        int r0 = row0 + wm * 32 + mt * 16;
#pragma unroll
        for (int nt = 0; nt < 4; nt++) {
            int cc = col0 + wn * 32 + nt * 8 + 2 * t;
            *(float2*)&C[(size_t)(r0 + g    ) * N + cc] = make_float2(c[mt][nt][0], c[mt][nt][1]);
            *(float2*)&C[(size_t)(r0 + g + 8) * N + cc] = make_float2(c[mt][nt][2], c[mt][nt][3]);
        }
    }
}

// =============== fp16 3-term GEMM (gates): A hi/lo, B hi/lo, split-K ===========
#define H3_OFF_AL 2560
#define H3_OFF_BH 5120
#define H3_OFF_BL 6400
#define H3_STG    7680

__global__ __launch_bounds__(256, 2)
void tgemmh3(const uint32_t* __restrict__ Agh, const uint32_t* __restrict__ Agl,
             const uint32_t* __restrict__ Bgh, const uint32_t* __restrict__ Bgl,
             float* __restrict__ C, int M, int N, int K) {
    extern __shared__ uint32_t sm3[];   // 3 stages x H3_STG
    const int tid = threadIdx.x;
    const int row0 = blockIdx.y * 128;
    const int col0 = blockIdx.x * 64;
    const int lane = tid & 31, w = tid >> 5;
    const int g = lane >> 2, t = lane & 3;
    const int wm = w >> 1, wn = w & 1;
    const int Ku = K / 2;
    const int ksplit = gridDim.z;
    const int kb = blockIdx.z * (K / 32 / ksplit);
    const int nk = K / 32 / ksplit;
    float* Cz = C + (size_t)blockIdx.z * M * N;

    const uint32_t sb = (uint32_t)__cvta_generic_to_shared(sm3);

    float c[2][4][4];
#pragma unroll
    for (int mt = 0; mt < 2; mt++)
#pragma unroll
        for (int nt = 0; nt < 4; nt++)
#pragma unroll
            for (int i = 0; i < 4; i++) c[mt][nt][i] = 0.f;

#define H3_LOAD(dst, kt)                                                          \
    {                                                                             \
        int ko = (kb + (kt)) * 16;                                                \
        _Pragma("unroll")                                                         \
        for (int it = 0; it < 2; it++) {                                          \
            int idx = it * 256 + tid;                                             \
            int r = idx >> 2, cc = idx & 3;                                       \
            cp16((dst) + (uint32_t)(r * ROWPAD + cc * 4) * 4,                     \
                 Agh + (size_t)(row0 + r) * Ku + ko + cc * 4);                    \
            cp16((dst) + (uint32_t)(H3_OFF_AL + r * ROWPAD + cc * 4) * 4,         \
                 Agl + (size_t)(row0 + r) * Ku + ko + cc * 4);                    \
        }                                                                         \
        {                                                                         \
            int r = tid >> 2, cc = tid & 3;                                       \
            cp16((dst) + (uint32_t)(H3_OFF_BH + r * ROWPAD + cc * 4) * 4,         \
                 Bgh + (size_t)(col0 + r) * Ku + ko + cc * 4);                    \
            cp16((dst) + (uint32_t)(H3_OFF_BL + r * ROWPAD + cc * 4) * 4,         \
                 Bgl + (size_t)(col0 + r) * Ku + ko + cc * 4);                    \
        }                                                                         \
    }

    H3_LOAD(sb, 0);
    CP_COMMIT();
    if (nk > 1) {
        H3_LOAD(sb + (uint32_t)H3_STG * 4, 1);
        CP_COMMIT();
    }

    for (int kt = 0; kt < nk; kt++) {
        const int st = kt % 3;
        if (kt + 2 < nk) {
            uint32_t d2 = sb + (uint32_t)(((kt + 2) % 3) * H3_STG) * 4;
            H3_LOAD(d2, kt + 2);
            CP_COMMIT();
            CP_WAIT(2);
        } else if (kt + 1 < nk) {
            CP_WAIT(1);
        } else {
            CP_WAIT(0);
        }
        __syncthreads();

        const uint32_t* Ah = sm3 + st * H3_STG;
        const uint32_t* Al = Ah + H3_OFF_AL;
        const uint32_t* Bh = Ah + H3_OFF_BH;
        const uint32_t* Bl = Ah + H3_OFF_BL;

#pragma unroll
        for (int kc = 0; kc < 2; kc++) {
            uint32_t afh[2][4], afl[2][4], bfh[4][2], bfl[4][2];
#pragma unroll
            for (int mt = 0; mt < 2; mt++) {
                int rb = wm * 32 + mt * 16;
                afh[mt][0] = Ah[(rb + g    ) * ROWPAD + kc * 8 + t];
                afh[mt][1] = Ah[(rb + g + 8) * ROWPAD + kc * 8 + t];
                afh[mt][2] = Ah[(rb + g    ) * ROWPAD + kc * 8 + t + 4];
                afh[mt][3] = Ah[(rb + g + 8) * ROWPAD + kc * 8 + t + 4];
                afl[mt][0] = Al[(rb + g    ) * ROWPAD + kc * 8 + t];
                afl[mt][1] = Al[(rb + g + 8) * ROWPAD + kc * 8 + t];
                afl[mt][2] = Al[(rb + g    ) * ROWPAD + kc * 8 + t + 4];
                afl[mt][3] = Al[(rb + g + 8) * ROWPAD + kc * 8 + t + 4];
            }
#pragma unroll
            for (int nt = 0; nt < 4; nt++) {
                int cb = wn * 32 + nt * 8;
                bfh[nt][0] = Bh[(cb + g) * ROWPAD + kc * 8 + t];
                bfh[nt][1] = Bh[(cb + g) * ROWPAD + kc * 8 + t + 4];
                bfl[nt][0] = Bl[(cb + g) * ROWPAD + kc * 8 + t];
                bfl[nt][1] = Bl[(cb + g) * ROWPAD + kc * 8 + t + 4];
            }
#pragma unroll
            for (int mt = 0; mt < 2; mt++)
#pragma unroll
                for (int nt = 0; nt < 4; nt++) {
                    mma_f16(c[mt][nt], afh[mt], bfl[nt]);
                    mma_f16(c[mt][nt], afl[mt], bfh[nt]);
                    mma_f16(c[mt][nt], afh[mt], bfh[nt]);
                }
        }
        __syncthreads();
    }

#pragma unroll
    for (int mt = 0; mt < 2; mt++) {
        int r0 = row0 + wm * 32 + mt * 16;
#pragma unroll
        for (int nt = 0; nt < 4; nt++) {
            int cc = col0 + wn * 32 + nt * 8 + 2 * t;
            *(float2*)&Cz[(size_t)(r0 + g    ) * N + cc] = make_float2(c[mt][nt][0], c[mt][nt][1]);
            *(float2*)&Cz[(size_t)(r0 + g + 8) * N + cc] = make_float2(c[mt][nt][2], c[mt][nt][3]);
        }
    }
}

// ====== fused gating + V combine + K/V blob build + out-mask ===================
// grid (NTILE, BB*HH), 256 threads. Each block: 64 tokens x head h.
__global__ void gate_kv_kernel(const float* __restrict__ glp,
                               const float* __restrict__ proj,
                               uint32_t* __restrict__ blob,
                               float* __restrict__ masko) {
    __shared__ float Ks[64 * 68];
    __shared__ float Vs[64 * 68];
    const int tile = blockIdx.x, bh = blockIdx.y;
    const int b = bh / HH, h = bh % HH;
    const int tid = threadIdx.x;
    const int tok = tid >> 2;          // 0..63
    const int q = tid & 3;
    const int token = b * TT + tile * 64 + tok;

    // load K rows (fp32, coalesced float4)
#pragma unroll
    for (int it = 0; it < 4; it++) {
        int idx = it * 256 + tid;
        int r = (idx * 4) >> 6, d = (idx * 4) & 63;
        const float* kb = proj + (size_t)(b * TT + tile * 64 + r) * PW2 + OFF_K + h * DH;
        *(float4*)&Ks[r * 68 + d] = *(const float4*)(kb + d);
    }

    // ---- V gate (computed redundantly by 4 threads of each token) -----------
    float gv[EE];
#pragma unroll
    for (int e = 0; e < EE; e++)
        gv[e] = glp[(size_t)token * NG + h * EE + e]
              + glp[((size_t)NTOK + token) * NG + h * EE + e];
    int i1 = 0;
#pragma unroll
    for (int e = 1; e < EE; e++) if (gv[e] > gv[i1]) i1 = e;
    int i2 = (i1 == 0) ? 1 : 0;
#pragma unroll
    for (int e = 0; e < EE; e++) if (e != i1 && gv[e] > gv[i2]) i2 = e;
    float w1 = 1.f / (1.f + __expf(-gv[i1]));
    float w2 = 1.f / (1.f + __expf(-gv[i2]));

    const float* xvt = proj + (size_t)token * PW2 + OFF_XV;
    int d0 = q * 16;
#pragma unroll
    for (int j = 0; j < 4; j++) {
        float4 a4 = *(const float4*)(xvt + i1 * DH + d0 + 4 * j);
        float4 c4 = *(const float4*)(xvt + i2 * DH + d0 + 4 * j);
        float4 r4 = make_float4(w1 * a4.x + w2 * c4.x, w1 * a4.y + w2 * c4.y,
                                w1 * a4.z + w2 * c4.z, w1 * a4.w + w2 * c4.w);
        *(float4*)&Vs[tok * 68 + d0 + 4 * j] = r4;
    }

    // ---- out-mask (one thread per token) -------------------------------------
    if (q == 0) {
        float go[EE];
#pragma unroll
        for (int e = 0; e < EE; e++)
            go[e] = glp[(size_t)token * NG + 40 + h * EE + e]
                  + glp[((size_t)NTOK + token) * NG + 40 + h * EE + e];
        int o1 = 0;
#pragma unroll
        for (int e = 1; e < EE; e++) if (go[e] > go[o1]) o1 = e;
        int o2 = (o1 == 0) ? 1 : 0;
#pragma unroll
        for (int e = 0; e < EE; e++) if (e != o1 && go[e] > go[o2]) o2 = e;
#pragma unroll
        for (int e = 0; e < EE; e++)
            masko[((size_t)token * HH + h) * EE + e] = (e == o1 || e == o2) ? 1.f : 0.f;
    }
    __syncthreads();

    // ---- pack fp16 K/V fragment blob -----------------------------------------
    uint32_t* dst = blob + ((size_t)bh * NTILE + tile) * TILE4_U32;
#pragma unroll
    for (int i = 0; i < 8; i++) {
        int oi = tid * 8 + i;
        int row = oi >> 4;
        int col = oi & 15;
        int k0 = row >> 5, lane2 = row & 31;
        int g2 = lane2 >> 2, t2 = lane2 & 3;
        int n0 = col >> 1, w2 = col & 1;
        int dK = k0 * 16 + w2 * 8 + 2 * t2;
        int keyK = n0 * 8 + g2;
        dst[row * ROWPAD + col] = packh2(Ks[keyK * 68 + dK], Ks[keyK * 68 + dK + 1]);
        int keyV = k0 * 16 + w2 * 8 + 2 * t2;
        int dV = n0 * 8 + g2;
        dst[ARR2_U32 + row * ROWPAD + col] = packh2(Vs[keyV * 68 + dV], Vs[(keyV + 1) * 68 + dV]);
    }
}

// =============== flash attention, pure fp16, fp16 output =======================
#define LOG2E 1.4426950408889634f
#define SCLG2E (0.125f * LOG2E)

__global__ __launch_bounds__(256, 2)
void attn5_kernel(const float* __restrict__ qg,
                  const uint32_t* __restrict__ blob,
                  uint32_t* __restrict__ oh) {
    extern __shared__ uint32_t sh[];     // 3 stages x TILE4_U32
    const int bh = blockIdx.y;
    const int b = bh / HH, h = bh % HH;
    const int q0 = blockIdx.x * 128;
    const int tid = threadIdx.x;
    const int lane = tid & 31, w = tid >> 5;
    const int g = lane >> 2, t = lane & 3;

    const uint32_t* gblob = blob + (size_t)bh * NTILE * TILE4_U32;
    const uint32_t sbase = (uint32_t)__cvta_generic_to_shared(sh);

#define BLOB_DMA(dstoff, srct)                                                   \
    {                                                                            \
        const uint32_t* src = gblob + (size_t)(srct) * TILE4_U32;                \
        _Pragma("unroll")                                                        \
        for (int i = 0; i < 5; i++) {                                            \
            int cc = tid + i * 256;                                              \
            cp16(sbase + (uint32_t)((dstoff) + cc * 4) * 4, src + cc * 4);       \
        }                                                                        \
    }

    BLOB_DMA(0, 0);
    CP_COMMIT();
    BLOB_DMA(TILE4_U32, 1);
    CP_COMMIT();

    const float* qb = qg + (size_t)(b * TT + q0 + w * 16) * PW2 + h * DH;
    uint32_t qa[4][4];
#pragma unroll
    for (int k0 = 0; k0 < 4; k0++) {
        qa[k0][0] = packh2(qb[(size_t)(g    ) * PW2 + k0 * 16 + 2 * t],
                           qb[(size_t)(g    ) * PW2 + k0 * 16 + 2 * t + 1]);
        qa[k0][1] = packh2(qb[(size_t)(g + 8) * PW2 + k0 * 16 + 2 * t],
                           qb[(size_t)(g + 8) * PW2 + k0 * 16 + 2 * t + 1]);
        qa[k0][2] = packh2(qb[(size_t)(g    ) * PW2 + k0 * 16 + 2 * t + 8],
                           qb[(size_t)(g    ) * PW2 + k0 * 16 + 2 * t + 9]);
        qa[k0][3] = packh2(qb[(size_t)(g + 8) * PW2 + k0 * 16 + 2 * t + 8],
                           qb[(size_t)(g + 8) * PW2 + k0 * 16 + 2 * t + 9]);
    }

    float om[8][4];
#pragma unroll
    for (int n = 0; n < 8; n++)
#pragma unroll
        for (int i = 0; i < 4; i++) om[n][i] = 0.f;
    float rm0 = -INFINITY, rm1 = -INFINITY, rl0 = 0.f, rl1 = 0.f;

    for (int tt = 0; tt < NTILE; tt++) {
        const int st = tt % 3;
        if (tt + 2 < NTILE) {
            BLOB_DMA(((tt + 2) % 3) * TILE4_U32, tt + 2);
            CP_COMMIT();
            CP_WAIT(2);
        } else if (tt + 1 < NTILE) {
            CP_WAIT(1);
        } else {
            CP_WAIT(0);
        }
        __syncthreads();

        const uint32_t* Kf = sh + st * TILE4_U32;
        const uint32_t* Vf = Kf + ARR2_U32;

        float s[8][4];
#pragma unroll
        for (int n = 0; n < 8; n++)
#pragma unroll
            for (int i = 0; i < 4; i++) s[n][i] = 0.f;
#pragma unroll
        for (int k0 = 0; k0 < 4; k0++) {
            const uint32_t* kr = Kf + (k0 * 32 + lane) * ROWPAD;
#pragma unroll
            for (int np = 0; np < 4; np++) {
                uint4 k4 = *(const uint4*)(kr + np * 4);
                uint32_t b2[2] = {k4.x, k4.y};
                mma_f16(s[2 * np], qa[k0], b2);
                uint32_t b3[2] = {k4.z, k4.w};
                mma_f16(s[2 * np + 1], qa[k0], b3);
            }
        }

        float m0 = s[0][0], m1 = s[0][2];
#pragma unroll
        for (int n = 0; n < 8; n++) {
            m0 = fmaxf(m0, fmaxf(s[n][0], s[n][1]));
            m1 = fmaxf(m1, fmaxf(s[n][2], s[n][3]));
        }
        m0 = fmaxf(m0, __shfl_xor_sync(0xffffffff, m0, 1));
        m0 = fmaxf(m0, __shfl_xor_sync(0xffffffff, m0, 2));
        m1 = fmaxf(m1, __shfl_xor_sync(0xffffffff, m1, 1));
        m1 = fmaxf(m1, __shfl_xor_sync(0xffffffff, m1, 2));

        float mn0 = fmaxf(rm0, m0);
        float mn1 = fmaxf(rm1, m1);
        float corr0 = exp2f((rm0 - mn0) * SCLG2E);
        float corr1 = exp2f((rm1 - mn1) * SCLG2E);

        float sum0 = 0.f, sum1 = 0.f;
#pragma unroll
        for (int n = 0; n < 8; n++) {
            s[n][0] = exp2f((s[n][0] - mn0) * SCLG2E);
            s[n][1] = exp2f((s[n][1] - mn0) * SCLG2E);
            s[n][2] = exp2f((s[n][2] - mn1) * SCLG2E);
            s[n][3] = exp2f((s[n][3] - mn1) * SCLG2E);
            sum0 += s[n][0] + s[n][1];
            sum1 += s[n][2] + s[n][3];
        }
        sum0 += __shfl_xor_sync(0xffffffff, sum0, 1);
        sum0 += __shfl_xor_sync(0xffffffff, sum0, 2);
        sum1 += __shfl_xor_sync(0xffffffff, sum1, 1);
        sum1 += __shfl_xor_sync(0xffffffff, sum1, 2);
        rl0 = rl0 * corr0 + sum0;
        rl1 = rl1 * corr1 + sum1;
        rm0 = mn0; rm1 = mn1;

#pragma unroll
        for (int n = 0; n < 8; n++) {
            om[n][0] *= corr0; om[n][1] *= corr0;
            om[n][2] *= corr1; om[n][3] *= corr1;
        }

#pragma unroll
        for (int k0 = 0; k0 < 4; k0++) {
            uint32_t ph[4];
            ph[0] = packh2(s[2 * k0][0],     s[2 * k0][1]);
            ph[1] = packh2(s[2 * k0][2],     s[2 * k0][3]);
            ph[2] = packh2(s[2 * k0 + 1][0], s[2 * k0 + 1][1]);
            ph[3] = packh2(s[2 * k0 + 1][2], s[2 * k0 + 1][3]);
            const uint32_t* vr = Vf + (k0 * 32 + lane) * ROWPAD;
#pragma unroll
            for (int np = 0; np < 4; np++) {
                uint4 v4 = *(const uint4*)(vr + np * 4);
                uint32_t b2[2] = {v4.x, v4.y};
                mma_f16(om[2 * np], ph, b2);
                uint32_t b3[2] = {v4.z, v4.w};
                mma_f16(om[2 * np + 1], ph, b3);
            }
        }
        __syncthreads();
    }

    float inv0 = 1.f / rl0;
    float inv1 = 1.f / rl1;
    // fp16 pair layout: oh[token*256 + h*32 + n0*4 + t]
    uint32_t* ob0 = oh + (size_t)(b * TT + q0 + w * 16 + g    ) * (QKW / 2) + h * 32 + t;
    uint32_t* ob1 = oh + (size_t)(b * TT + q0 + w * 16 + g + 8) * (QKW / 2) + h * 32 + t;
#pragma unroll
    for (int n0 = 0; n0 < 8; n0++) {
        ob0[n0 * 4] = packh2(om[n0][0] * inv0, om[n0][1] * inv0);
        ob1[n0 * 4] = packh2(om[n0][2] * inv1, om[n0][3] * inv1);
    }
}

// -------- Y pairs: Y[t, 2i..2i+1] = sum_h mask*attn(fp16) -> single fp16 -------
__global__ void combine_out_kernel(const uint32_t* __restrict__ attnh,
                                   const float* __restrict__ masko,
                                   uint32_t* __restrict__ Y) {
    int token = blockIdx.x;
    int tid = threadIdx.x;          // 0..159
    int t0 = 2 * tid;
    int e = t0 >> 6, j = t0 & 63;   // j even
    const uint32_t* ap = attnh + (size_t)token * (QKW / 2);
    const float* mp = masko + (size_t)token * GW;
    float s0 = 0.f, s1 = 0.f;
#pragma unroll
    for (int h = 0; h < HH; h++) {
        float m = mp[h * EE + e];
        uint32_t u = ap[h * 32 + (j >> 1)];
        __half2 hv = *reinterpret_cast<__half2*>(&u);
        s0 += m * __low2float(hv);
        s1 += m * __high2float(hv);
    }
    Y[(size_t)token * (XVW / 2) + tid] = packh2(s0, s1);
}

// ------------------------------- launch ----------------------------------------
extern "C" void kernel_launch(void* const* d_in, const int* in_sizes, int n_in,
                              void* d_out, int out_size) {
    const float* x  = (const float*)d_in[0];
    const float* Wq = (const float*)d_in[1];
    const float* Wk = (const float*)d_in[2];
    const float* Ws = (const float*)d_in[3];
    const float* Wd = (const float*)d_in[4];
    const float* Wv = (const float*)d_in[5];
    const float* Wo = (const float*)d_in[6];
    float* out = (float*)d_out;

    float *proj, *glp, *mask;
    uint32_t *xbh, *xbl, *wt, *gwh, *gwl, *attnh, *yb, *wot, *blob;
    cudaGetSymbolAddress((void**)&proj,  g_proj);
    cudaGetSymbolAddress((void**)&xbh,   g_xbh);
    cudaGetSymbolAddress((void**)&xbl,   g_xbl);
    cudaGetSymbolAddress((void**)&wt,    g_wt);
    cudaGetSymbolAddress((void**)&gwh,   g_gwh);
    cudaGetSymbolAddress((void**)&gwl,   g_gwl);
    cudaGetSymbolAddress((void**)&glp,   g_glp);
    cudaGetSymbolAddress((void**)&attnh, g_attnh);
    cudaGetSymbolAddress((void**)&mask,  g_mask);
    cudaGetSymbolAddress((void**)&yb,    g_yb);
    cudaGetSymbolAddress((void**)&wot,   g_wot);
    cudaGetSymbolAddress((void**)&blob,  g_blob);

    // pre-splits / packs
    split_x_f16 <<<(int)(((size_t)NTOK * DD / 2 + 255) / 256), 256>>>(x, xbh, xbl);
    pack_wt_f16 <<<(int)(((size_t)PW2 * DD / 2 + 255) / 256), 256>>>(Wq, Wk, Wv, wt);
    pack_gw_f16 <<<(int)(((size_t)NG * DD / 2 + 255) / 256), 256>>>(Ws, Wd, gwh, gwl);
    pack_wot_f16<<<(int)(((size_t)DD * XVW / 2 + 255) / 256), 256>>>(Wo, wot);

    // proj GEMM (single fp16, 3-stage): (8192x1024)@(1024x1344)
    size_t h1sm = (size_t)3 * H1_STG * sizeof(uint32_t);   // 46080
    cudaFuncSetAttribute(tgemmh1, cudaFuncAttributeMaxDynamicSharedMemorySize, (int)h1sm);
    dim3 gp(PW2 / 64, NTOK / 128);
    tgemmh1<<<gp, 256, h1sm>>>(xbh, wt, proj, NTOK, PW2, DD);

    // gate GEMM (fp16 3-term, split-K=2): (8192x1024)@(1024x128) -> partials
    size_t h3sm = (size_t)3 * H3_STG * sizeof(uint32_t);   // 92160
    cudaFuncSetAttribute(tgemmh3, cudaFuncAttributeMaxDynamicSharedMemorySize, (int)h3sm);
    dim3 gg(NG / 64, NTOK / 128, KSPL);
    tgemmh3<<<gg, 256, h3sm>>>(xbh, xbl, gwh, gwl, glp, NTOK, NG, DD);

    // fused gating + V combine + K/V blob + out-mask
    dim3 bg(NTILE, BB * HH);
    gate_kv_kernel<<<bg, 256>>>(glp, proj, blob, mask);

    // attention (pure fp16, 3-stage, fp16 output)
    size_t asmem = (size_t)3 * TILE4_U32 * sizeof(uint32_t);  // 61440
    cudaFuncSetAttribute(attn5_kernel, cudaFuncAttributeMaxDynamicSharedMemorySize, (int)asmem);
    dim3 ag(TT / 128, BB * HH);
    attn5_kernel<<<ag, 256, asmem>>>(proj, blob, attnh);

    // masked combine (fp16 in/out), then output GEMM (single-term)
    combine_out_kernel<<<NTOK, XVW / 2>>>(attnh, mask, yb);
    dim3 go(DD / 64, NTOK / 128);
    tgemmh1<<<go, 256, h1sm>>>(yb, wot, out, NTOK, DD, XVW);
}

// round 15
// speedup vs baseline: 18.4541x; 1.0174x over previous
#include <cuda_runtime.h>
#include <cuda_bf16.h>
#include <cuda_fp16.h>
#include <math.h>
#include <stdint.h>

// Problem constants
#define BB 4
#define TT 2048
#define DD 1024
#define HH 8
#define DH 64
#define EE 5
#define NTOK (BB*TT)          // 8192
#define QKW (HH*DH)           // 512
#define GW  (HH*EE)           // 40
#define XVW (EE*DH)           // 320

// fused projection layout (row stride PW2): q[0:512) | k[512:1024) | xv[1024:1344)
#define PW2 1344
#define PWU (PW2/2)            // 672 u32 pairs per row
#define OFF_KU 256             // K offset in pairs
#define OFF_XVU 512            // xv offset in pairs

#define NG 128                 // gate GEMM padded width (glv 0..39, glo 40..79)
#define KSPL 2                 // gate GEMM split-K

// fp16 KV fragment blob: per (bh,tile64): [K | V], each 4 k0 x 32 lanes x 20 u32
#define ROWPAD 20
#define ARR2_U32 (4*32*ROWPAD)    // 2560
#define TILE4_U32 (2*ARR2_U32)    // 5120 u32 = 20KB
#define NTILE 32

// ---------------- scratch (device globals) ------------------------------------
__device__ __align__(16) uint32_t g_projh[(size_t)NTOK*PWU];   // proj, fp16 pairs
__device__ __align__(16) uint32_t g_xbh [(size_t)NTOK*DD/2];   // fp16 hi pairs of x
__device__ __align__(16) uint32_t g_xbl [(size_t)NTOK*DD/2];   // fp16 lo pairs (gates)
__device__ __align__(16) uint32_t g_wt  [(size_t)PW2*DD/2];    // Wt[n][dpair] fp16
__device__ __align__(16) uint32_t g_gwh [(size_t)NG*DD/2];     // gate weights fp16 hi
__device__ __align__(16) uint32_t g_gwl [(size_t)NG*DD/2];     // lo
__device__ float    g_glp  [(size_t)KSPL*NTOK*NG];             // gate partials
__device__ __align__(16) uint32_t g_attnh[(size_t)NTOK*QKW/2]; // attn out, fp16 pairs
__device__ float    g_mask [(size_t)NTOK*GW];
__device__ __align__(16) uint32_t g_yb  [(size_t)NTOK*XVW/2];  // fp16 pairs of Y
__device__ __align__(16) uint32_t g_wot [(size_t)DD*XVW/2];    // WoT[n=d][kpair] fp16
__device__ __align__(16) uint32_t g_blob[(size_t)BB*HH*NTILE*TILE4_U32];  // ~21MB

// ---------------- helpers ------------------------------------------------------
__device__ __forceinline__ uint32_t packh2(float a, float b) {
    __half2 h = __floats2half2_rn(a, b);
    return *reinterpret_cast<uint32_t*>(&h);
}
__device__ __forceinline__ void splith2(float a, float b, uint32_t& h, uint32_t& l) {
    __half ha = __float2half_rn(a);
    __half hb = __float2half_rn(b);
    float ra = a - __half2float(ha);
    float rb = b - __half2float(hb);
    __half2 hh; hh.x = ha; hh.y = hb;
    __half2 ll; ll.x = __float2half_rn(ra); ll.y = __float2half_rn(rb);
    h = *reinterpret_cast<uint32_t*>(&hh);
    l = *reinterpret_cast<uint32_t*>(&ll);
}
__device__ __forceinline__ void mma_f16(float c[4], const uint32_t a[4], const uint32_t b[2]) {
    asm volatile(
        "mma.sync.aligned.m16n8k16.row.col.f32.f16.f16.f32 "
        "{%0,%1,%2,%3},{%4,%5,%6,%7},{%8,%9},{%0,%1,%2,%3};"
        : "+f"(c[0]), "+f"(c[1]), "+f"(c[2]), "+f"(c[3])
        : "r"(a[0]), "r"(a[1]), "r"(a[2]), "r"(a[3]), "r"(b[0]), "r"(b[1]));
}
__device__ __forceinline__ void cp16(uint32_t saddr, const void* g) {
    asm volatile("cp.async.cg.shared.global [%0], [%1], 16;\n" :: "r"(saddr), "l"(g));
}
#define CP_COMMIT() asm volatile("cp.async.commit_group;\n")
#define CP_WAIT(n)  asm volatile("cp.async.wait_group %0;\n" :: "n"(n))

// =============== pre-split / pack kernels ======================================
__global__ void split_x_f16(const float* __restrict__ x,
                            uint32_t* __restrict__ xbh, uint32_t* __restrict__ xbl) {
    size_t i = (size_t)blockIdx.x * blockDim.x + threadIdx.x;
    if (i >= (size_t)NTOK * DD / 2) return;
    splith2(x[2 * i], x[2 * i + 1], xbh[i], xbl[i]);
}
__global__ void pack_wt_f16(const float* __restrict__ Wq, const float* __restrict__ Wk,
                            const float* __restrict__ Wv, uint32_t* __restrict__ Wt) {
    size_t idx = (size_t)blockIdx.x * blockDim.x + threadIdx.x;
    if (idx >= (size_t)PW2 * DD / 2) return;
    int n = (int)(idx / (DD / 2));
    int dp = (int)(idx % (DD / 2));
    int d0 = 2 * dp;
    float va, vb;
    if (n < 512) {
        va = Wq[(size_t)d0 * 512 + n]; vb = Wq[(size_t)(d0 + 1) * 512 + n];
    } else if (n < 1024) {
        va = Wk[(size_t)d0 * 512 + (n - 512)]; vb = Wk[(size_t)(d0 + 1) * 512 + (n - 512)];
    } else {
        int e = (n - 1024) / DH, j = (n - 1024) % DH;
        va = Wv[((size_t)e * DD + d0) * DH + j];
        vb = Wv[((size_t)e * DD + d0 + 1) * DH + j];
    }
    Wt[idx] = packh2(va, vb);
}
__global__ void pack_gw_f16(const float* __restrict__ Ws, const float* __restrict__ Wd,
                            uint32_t* __restrict__ Wh, uint32_t* __restrict__ Wl) {
    size_t idx = (size_t)blockIdx.x * blockDim.x + threadIdx.x;
    if (idx >= (size_t)NG * DD / 2) return;
    int n = (int)(idx / (DD / 2));
    int dp = (int)(idx % (DD / 2));
    int d0 = 2 * dp;
    float va = 0.f, vb = 0.f;
    if (n < 40)      { va = Ws[(size_t)d0 * GW + n];        vb = Ws[(size_t)(d0 + 1) * GW + n]; }
    else if (n < 80) { va = Wd[(size_t)d0 * GW + (n - 40)]; vb = Wd[(size_t)(d0 + 1) * GW + (n - 40)]; }
    splith2(va, vb, Wh[idx], Wl[idx]);
}
__global__ void pack_wot_f16(const float* __restrict__ Wo, uint32_t* __restrict__ Wt) {
    size_t idx = (size_t)blockIdx.x * blockDim.x + threadIdx.x;
    if (idx >= (size_t)DD * XVW / 2) return;
    int n = (int)(idx / (XVW / 2));
    int kp = (int)(idx % (XVW / 2));
    int k0 = 2 * kp;
    int e = k0 >> 6, j = k0 & 63;
    float va = Wo[((size_t)(e * DH + j)) * DD + n];
    float vb = Wo[((size_t)(e * DH + j + 1)) * DD + n];
    Wt[idx] = packh2(va, vb);
}

// =============== single-term fp16 GEMM core (shared by both epilogues) =========
#define H1_OFF_B 2560
#define H1_STG   3840     // 15KB/stage

#define H1_LOAD(dst, kt)                                                          \
    {                                                                             \
        int ko = (kt) * 16;                                                       \
        _Pragma("unroll")                                                         \
        for (int it = 0; it < 2; it++) {                                          \
            int idx = it * 256 + tid;                                             \
            int r = idx >> 2, cc = idx & 3;                                       \
            cp16((dst) + (uint32_t)(r * ROWPAD + cc * 4) * 4,                     \
                 Ag + (size_t)(row0 + r) * Ku + ko + cc * 4);                     \
        }                                                                         \
        {                                                                         \
            int r = tid >> 2, cc = tid & 3;                                       \
            cp16((dst) + (uint32_t)(H1_OFF_B + r * ROWPAD + cc * 4) * 4,          \
                 Bg + (size_t)(col0 + r) * Ku + ko + cc * 4);                     \
        }                                                                         \
    }

#define H1_BODY                                                                   \
    const int tid = threadIdx.x;                                                  \
    const int row0 = blockIdx.y * 128;                                            \
    const int col0 = blockIdx.x * 64;                                             \
    const int lane = tid & 31, w = tid >> 5;                                      \
    const int g = lane >> 2, t = lane & 3;                                        \
    const int wm = w >> 1, wn = w & 1;                                            \
    const int Ku = K / 2;                                                         \
    const uint32_t sb = (uint32_t)__cvta_generic_to_shared(sm1);                  \
    float c[2][4][4];                                                             \
    _Pragma("unroll")                                                             \
    for (int mt = 0; mt < 2; mt++)                                                \
        _Pragma("unroll")                                                         \
        for (int nt = 0; nt < 4; nt++)                                            \
            _Pragma("unroll")                                                     \
            for (int i = 0; i < 4; i++) c[mt][nt][i] = 0.f;                       \
    const int nk = K / 32;                                                        \
    H1_LOAD(sb, 0);                                                               \
    CP_COMMIT();                                                                  \
    if (nk > 1) { H1_LOAD(sb + (uint32_t)H1_STG * 4, 1); CP_COMMIT(); }           \
    for (int kt = 0; kt < nk; kt++) {                                             \
        const int st = kt % 3;                                                    \
        if (kt + 2 < nk) {                                                        \
            uint32_t d2 = sb + (uint32_t)(((kt + 2) % 3) * H1_STG) * 4;           \
            H1_LOAD(d2, kt + 2);                                                  \
            CP_COMMIT();                                                          \
            CP_WAIT(2);                                                           \
        } else if (kt + 1 < nk) { CP_WAIT(1); } else { CP_WAIT(0); }              \
        __syncthreads();                                                          \
        const uint32_t* Ah = sm1 + st * H1_STG;                                   \
        const uint32_t* Bs = Ah + H1_OFF_B;                                       \
        _Pragma("unroll")                                                         \
        for (int kc = 0; kc < 2; kc++) {                                          \
            uint32_t af[2][4], bf[4][2];                                          \
            _Pragma("unroll")                                                     \
            for (int mt = 0; mt < 2; mt++) {                                      \
                int rb = wm * 32 + mt * 16;                                       \
                af[mt][0] = Ah[(rb + g    ) * ROWPAD + kc * 8 + t];               \
                af[mt][1] = Ah[(rb + g + 8) * ROWPAD + kc * 8 + t];               \
                af[mt][2] = Ah[(rb + g    ) * ROWPAD + kc * 8 + t + 4];           \
                af[mt][3] = Ah[(rb + g + 8) * ROWPAD + kc * 8 + t + 4];           \
            }                                                                     \
            _Pragma("unroll")                                                     \
            for (int nt = 0; nt < 4; nt++) {                                      \
                int cb = wn * 32 + nt * 8;                                        \
                bf[nt][0] = Bs[(cb + g) * ROWPAD + kc * 8 + t];                   \
                bf[nt][1] = Bs[(cb + g) * ROWPAD + kc * 8 + t + 4];               \
            }                                                                     \
            _Pragma("unroll")                                                     \
            for (int mt = 0; mt < 2; mt++)                                        \
                _Pragma("unroll")                                                 \
                for (int nt = 0; nt < 4; nt++)                                    \
                    mma_f16(c[mt][nt], af[mt], bf[nt]);                           \
        }                                                                         \
        __syncthreads();                                                          \
    }

// fp32-output variant (final out GEMM)
__global__ __launch_bounds__(256, 2)
void tgemmh1(const uint32_t* __restrict__ Ag, const uint32_t* __restrict__ Bg,
             float* __restrict__ C, int M, int N, int K) {
    extern __shared__ uint32_t sm1[];
    H1_BODY
#pragma unroll
    for (int mt = 0; mt < 2; mt++) {
        int r0 = row0 + wm * 32 + mt * 16;
#pragma unroll
        for (int nt = 0; nt < 4; nt++) {
            int cc = col0 + wn * 32 + nt * 8 + 2 * t;
            *(float2*)&C[(size_t)(r0 + g    ) * N + cc] = make_float2(c[mt][nt][0], c[mt][nt][1]);
            *(float2*)&C[(size_t)(r0 + g + 8) * N + cc] = make_float2(c[mt][nt][2], c[mt][nt][3]);
        }
    }
}

// fp16-pair-output variant (proj GEMM)
__global__ __launch_bounds__(256, 2)
void tgemmh1p(const uint32_t* __restrict__ Ag, const uint32_t* __restrict__ Bg,
              uint32_t* __restrict__ Cp, int M, int N, int K) {
    extern __shared__ uint32_t sm1[];
    H1_BODY
    const int Nu = N / 2;
#pragma unroll
    for (int mt = 0; mt < 2; mt++) {
        int r0 = row0 + wm * 32 + mt * 16;
#pragma unroll
        for (int nt = 0; nt < 4; nt++) {
            int cp = (col0 + wn * 32 + nt * 8 + 2 * t) >> 1;
            Cp[(size_t)(r0 + g    ) * Nu + cp] = packh2(c[mt][nt][0], c[mt][nt][1]);
            Cp[(size_t)(r0 + g + 8) * Nu + cp] = packh2(c[mt][nt][2], c[mt][nt][3]);
        }
    }
}

// =============== fp16 3-term GEMM (gates): A hi/lo, B hi/lo, split-K ===========
#define H3_OFF_AL 2560
#define H3_OFF_BH 5120
#define H3_OFF_BL 6400
#define H3_STG    7680

__global__ __launch_bounds__(256, 2)
void tgemmh3(const uint32_t* __restrict__ Agh, const uint32_t* __restrict__ Agl,
             const uint32_t* __restrict__ Bgh, const uint32_t* __restrict__ Bgl,
             float* __restrict__ C, int M, int N, int K) {
    extern __shared__ uint32_t sm3[];
    const int tid = threadIdx.x;
    const int row0 = blockIdx.y * 128;
    const int col0 = blockIdx.x * 64;
    const int lane = tid & 31, w = tid >> 5;
    const int g = lane >> 2, t = lane & 3;
    const int wm = w >> 1, wn = w & 1;
    const int Ku = K / 2;
    const int ksplit = gridDim.z;
    const int kb = blockIdx.z * (K / 32 / ksplit);
    const int nk = K / 32 / ksplit;
    float* Cz = C + (size_t)blockIdx.z * M * N;

    const uint32_t sb = (uint32_t)__cvta_generic_to_shared(sm3);

    float c[2][4][4];
#pragma unroll
    for (int mt = 0; mt < 2; mt++)
#pragma unroll
        for (int nt = 0; nt < 4; nt++)
#pragma unroll
            for (int i = 0; i < 4; i++) c[mt][nt][i] = 0.f;

#define H3_LOAD(dst, kt)                                                          \
    {                                                                             \
        int ko = (kb + (kt)) * 16;                                                \
        _Pragma("unroll")                                                         \
        for (int it = 0; it < 2; it++) {                                          \
            int idx = it * 256 + tid;                                             \
            int r = idx >> 2, cc = idx & 3;                                       \
            cp16((dst) + (uint32_t)(r * ROWPAD + cc * 4) * 4,                     \
                 Agh + (size_t)(row0 + r) * Ku + ko + cc * 4);                    \
            cp16((dst) + (uint32_t)(H3_OFF_AL + r * ROWPAD + cc * 4) * 4,         \
                 Agl + (size_t)(row0 + r) * Ku + ko + cc * 4);                    \
        }                                                                         \
        {                                                                         \
            int r = tid >> 2, cc = tid & 3;                                       \
            cp16((dst) + (uint32_t)(H3_OFF_BH + r * ROWPAD + cc * 4) * 4,         \
                 Bgh + (size_t)(col0 + r) * Ku + ko + cc * 4);                    \
            cp16((dst) + (uint32_t)(H3_OFF_BL + r * ROWPAD + cc * 4) * 4,         \
                 Bgl + (size_t)(col0 + r) * Ku + ko + cc * 4);                    \
        }                                                                         \
    }

    H3_LOAD(sb, 0);
    CP_COMMIT();
    if (nk > 1) {
        H3_LOAD(sb + (uint32_t)H3_STG * 4, 1);
        CP_COMMIT();
    }

    for (int kt = 0; kt < nk; kt++) {
        const int st = kt % 3;
        if (kt + 2 < nk) {
            uint32_t d2 = sb + (uint32_t)(((kt + 2) % 3) * H3_STG) * 4;
            H3_LOAD(d2, kt + 2);
            CP_COMMIT();
            CP_WAIT(2);
        } else if (kt + 1 < nk) {
            CP_WAIT(1);
        } else {
            CP_WAIT(0);
        }
        __syncthreads();

        const uint32_t* Ah = sm3 + st * H3_STG;
        const uint32_t* Al = Ah + H3_OFF_AL;
        const uint32_t* Bh = Ah + H3_OFF_BH;
        const uint32_t* Bl = Ah + H3_OFF_BL;

#pragma unroll
        for (int kc = 0; kc < 2; kc++) {
            uint32_t afh[2][4], afl[2][4], bfh[4][2], bfl[4][2];
#pragma unroll
            for (int mt = 0; mt < 2; mt++) {
                int rb = wm * 32 + mt * 16;
                afh[mt][0] = Ah[(rb + g    ) * ROWPAD + kc * 8 + t];
                afh[mt][1] = Ah[(rb + g + 8) * ROWPAD + kc * 8 + t];
                afh[mt][2] = Ah[(rb + g    ) * ROWPAD + kc * 8 + t + 4];
                afh[mt][3] = Ah[(rb + g + 8) * ROWPAD + kc * 8 + t + 4];
                afl[mt][0] = Al[(rb + g    ) * ROWPAD + kc * 8 + t];
                afl[mt][1] = Al[(rb + g + 8) * ROWPAD + kc * 8 + t];
                afl[mt][2] = Al[(rb + g    ) * ROWPAD + kc * 8 + t + 4];
                afl[mt][3] = Al[(rb + g + 8) * ROWPAD + kc * 8 + t + 4];
            }
#pragma unroll
            for (int nt = 0; nt < 4; nt++) {
                int cb = wn * 32 + nt * 8;
                bfh[nt][0] = Bh[(cb + g) * ROWPAD + kc * 8 + t];
                bfh[nt][1] = Bh[(cb + g) * ROWPAD + kc * 8 + t + 4];
                bfl[nt][0] = Bl[(cb + g) * ROWPAD + kc * 8 + t];
                bfl[nt][1] = Bl[(cb + g) * ROWPAD + kc * 8 + t + 4];
            }
#pragma unroll
            for (int mt = 0; mt < 2; mt++)
#pragma unroll
                for (int nt = 0; nt < 4; nt++) {
                    mma_f16(c[mt][nt], afh[mt], bfl[nt]);
                    mma_f16(c[mt][nt], afl[mt], bfh[nt]);
                    mma_f16(c[mt][nt], afh[mt], bfh[nt]);
                }
        }
        __syncthreads();
    }

#pragma unroll
    for (int mt = 0; mt < 2; mt++) {
        int r0 = row0 + wm * 32 + mt * 16;
#pragma unroll
        for (int nt = 0; nt < 4; nt++) {
            int cc = col0 + wn * 32 + nt * 8 + 2 * t;
            *(float2*)&Cz[(size_t)(r0 + g    ) * N + cc] = make_float2(c[mt][nt][0], c[mt][nt][1]);
            *(float2*)&Cz[(size_t)(r0 + g + 8) * N + cc] = make_float2(c[mt][nt][2], c[mt][nt][3]);
        }
    }
}

// ====== fused gating + V combine + K/V blob build + out-mask ===================
// grid (NTILE, BB*HH), 256 threads. proj is fp16 pairs.
__global__ void gate_kv_kernel(const float* __restrict__ glp,
                               const uint32_t* __restrict__ projh,
                               uint32_t* __restrict__ blob,
                               float* __restrict__ masko) {
    __shared__ uint32_t Ks[64 * 36];   // K pairs [row][pair 0..31], pad 36
    __shared__ float    Vs[64 * 68];   // V floats [row][d]
    const int tile = blockIdx.x, bh = blockIdx.y;
    const int b = bh / HH, h = bh % HH;
    const int tid = threadIdx.x;
    const int tok = tid >> 2;          // 0..63
    const int q = tid & 3;
    const int token = b * TT + tile * 64 + tok;

    // load K pairs (u32, coalesced)
#pragma unroll
    for (int it = 0; it < 8; it++) {
        int idx = it * 256 + tid;
        int r = idx >> 5, p = idx & 31;
        Ks[r * 36 + p] = projh[(size_t)(b * TT + tile * 64 + r) * PWU + OFF_KU + h * 32 + p];
    }

    // ---- V gate ----------------------------------------------------------------
    float gv[EE];
#pragma unroll
    for (int e = 0; e < EE; e++)
        gv[e] = glp[(size_t)token * NG + h * EE + e]
              + glp[((size_t)NTOK + token) * NG + h * EE + e];
    int i1 = 0;
#pragma unroll
    for (int e = 1; e < EE; e++) if (gv[e] > gv[i1]) i1 = e;
    int i2 = (i1 == 0) ? 1 : 0;
#pragma unroll
    for (int e = 0; e < EE; e++) if (e != i1 && gv[e] > gv[i2]) i2 = e;
    float w1 = 1.f / (1.f + __expf(-gv[i1]));
    float w2 = 1.f / (1.f + __expf(-gv[i2]));

    const uint32_t* xvt = projh + (size_t)token * PWU + OFF_XVU;
    int p0 = q * 8;                    // pair index base (d0 = q*16)
#pragma unroll
    for (int j = 0; j < 8; j++) {
        uint32_t u1 = xvt[i1 * 32 + p0 + j];
        uint32_t u2 = xvt[i2 * 32 + p0 + j];
        __half2 h1 = *reinterpret_cast<__half2*>(&u1);
        __half2 h2 = *reinterpret_cast<__half2*>(&u2);
        Vs[tok * 68 + 2 * (p0 + j)    ] = w1 * __low2float(h1)  + w2 * __low2float(h2);
        Vs[tok * 68 + 2 * (p0 + j) + 1] = w1 * __high2float(h1) + w2 * __high2float(h2);
    }

    // ---- out-mask ----------------------------------------------------------------
    if (q == 0) {
        float go[EE];
#pragma unroll
        for (int e = 0; e < EE; e++)
            go[e] = glp[(size_t)token * NG + 40 + h * EE + e]
                  + glp[((size_t)NTOK + token) * NG + 40 + h * EE + e];
        int o1 = 0;
#pragma unroll
        for (int e = 1; e < EE; e++) if (go[e] > go[o1]) o1 = e;
        int o2 = (o1 == 0) ? 1 : 0;
#pragma unroll
        for (int e = 0; e < EE; e++) if (e != o1 && go[e] > go[o2]) o2 = e;
#pragma unroll
        for (int e = 0; e < EE; e++)
            masko[((size_t)token * HH + h) * EE + e] = (e == o1 || e == o2) ? 1.f : 0.f;
    }
    __syncthreads();

    // ---- pack fp16 K/V fragment blob ------------------------------------------
    uint32_t* dst = blob + ((size_t)bh * NTILE + tile) * TILE4_U32;
#pragma unroll
    for (int i = 0; i < 8; i++) {
        int oi = tid * 8 + i;
        int row = oi >> 4;
        int col = oi & 15;
        int k0 = row >> 5, lane2 = row & 31;
        int g2 = lane2 >> 2, t2 = lane2 & 3;
        int n0 = col >> 1, w2 = col & 1;
        // K: pair already formed in proj
        int keyK = n0 * 8 + g2;
        dst[row * ROWPAD + col] = Ks[keyK * 36 + k0 * 8 + w2 * 4 + t2];
        // V: pair across adjacent keys
        int keyV = k0 * 16 + w2 * 8 + 2 * t2;
        int dV = n0 * 8 + g2;
        dst[ARR2_U32 + row * ROWPAD + col] = packh2(Vs[keyV * 68 + dV], Vs[(keyV + 1) * 68 + dV]);
    }
}

// =============== flash attention, pure fp16, fp16 in/out =======================
#define LOG2E 1.4426950408889634f
#define SCLG2E (0.125f * LOG2E)

__global__ __launch_bounds__(256, 2)
void attn5_kernel(const uint32_t* __restrict__ qg,
                  const uint32_t* __restrict__ blob,
                  uint32_t* __restrict__ oh) {
    extern __shared__ uint32_t sh[];     // 3 stages x TILE4_U32
    const int bh = blockIdx.y;
    const int b = bh / HH, h = bh % HH;
    const int q0 = blockIdx.x * 128;
    const int tid = threadIdx.x;
    const int lane = tid & 31, w = tid >> 5;
    const int g = lane >> 2, t = lane & 3;

    const uint32_t* gblob = blob + (size_t)bh * NTILE * TILE4_U32;
    const uint32_t sbase = (uint32_t)__cvta_generic_to_shared(sh);

#define BLOB_DMA(dstoff, srct)                                                   \
    {                                                                            \
        const uint32_t* src = gblob + (size_t)(srct) * TILE4_U32;                \
        _Pragma("unroll")                                                        \
        for (int i = 0; i < 5; i++) {                                            \
            int cc = tid + i * 256;                                              \
            cp16(sbase + (uint32_t)((dstoff) + cc * 4) * 4, src + cc * 4);       \
        }                                                                        \
    }

    BLOB_DMA(0, 0);
    CP_COMMIT();
    BLOB_DMA(TILE4_U32, 1);
    CP_COMMIT();

    // Q fragments: direct u32 pair loads from fp16 proj
    const uint32_t* qb = qg + (size_t)(b * TT + q0 + w * 16) * PWU + h * 32;
    uint32_t qa[4][4];
#pragma unroll
    for (int k0 = 0; k0 < 4; k0++) {
        qa[k0][0] = qb[(size_t)(g    ) * PWU + k0 * 8 + t];
        qa[k0][1] = qb[(size_t)(g + 8) * PWU + k0 * 8 + t];
        qa[k0][2] = qb[(size_t)(g    ) * PWU + k0 * 8 + t + 4];
        qa[k0][3] = qb[(size_t)(g + 8) * PWU + k0 * 8 + t + 4];
    }

    float om[8][4];
#pragma unroll
    for (int n = 0; n < 8; n++)
#pragma unroll
        for (int i = 0; i < 4; i++) om[n][i] = 0.f;
    float rm0 = -INFINITY, rm1 = -INFINITY, rl0 = 0.f, rl1 = 0.f;

    for (int tt = 0; tt < NTILE; tt++) {
        const int st = tt % 3;
        if (tt + 2 < NTILE) {
            BLOB_DMA(((tt + 2) % 3) * TILE4_U32, tt + 2);
            CP_COMMIT();
            CP_WAIT(2);
        } else if (tt + 1 < NTILE) {
            CP_WAIT(1);
        } else {
            CP_WAIT(0);
        }
        __syncthreads();

        const uint32_t* Kf = sh + st * TILE4_U32;
        const uint32_t* Vf = Kf + ARR2_U32;

        float s[8][4];
#pragma unroll
        for (int n = 0; n < 8; n++)
#pragma unroll
            for (int i = 0; i < 4; i++) s[n][i] = 0.f;
#pragma unroll
        for (int k0 = 0; k0 < 4; k0++) {
            const uint32_t* kr = Kf + (k0 * 32 + lane) * ROWPAD;
#pragma unroll
            for (int np = 0; np < 4; np++) {
                uint4 k4 = *(const uint4*)(kr + np * 4);
                uint32_t b2[2] = {k4.x, k4.y};
                mma_f16(s[2 * np], qa[k0], b2);
                uint32_t b3[2] = {k4.z, k4.w};
                mma_f16(s[2 * np + 1], qa[k0], b3);
            }
        }

        float m0 = s[0][0], m1 = s[0][2];
#pragma unroll
        for (int n = 0; n < 8; n++) {
            m0 = fmaxf(m0, fmaxf(s[n][0], s[n][1]));
            m1 = fmaxf(m1, fmaxf(s[n][2], s[n][3]));
        }
        m0 = fmaxf(m0, __shfl_xor_sync(0xffffffff, m0, 1));
        m0 = fmaxf(m0, __shfl_xor_sync(0xffffffff, m0, 2));
        m1 = fmaxf(m1, __shfl_xor_sync(0xffffffff, m1, 1));
        m1 = fmaxf(m1, __shfl_xor_sync(0xffffffff, m1, 2));

        float mn0 = fmaxf(rm0, m0);
        float mn1 = fmaxf(rm1, m1);
        float corr0 = exp2f((rm0 - mn0) * SCLG2E);
        float corr1 = exp2f((rm1 - mn1) * SCLG2E);

        float sum0 = 0.f, sum1 = 0.f;
#pragma unroll
        for (int n = 0; n < 8; n++) {
            s[n][0] = exp2f((s[n][0] - mn0) * SCLG2E);
            s[n][1] = exp2f((s[n][1] - mn0) * SCLG2E);
            s[n][2] = exp2f((s[n][2] - mn1) * SCLG2E);
            s[n][3] = exp2f((s[n][3] - mn1) * SCLG2E);
            sum0 += s[n][0] + s[n][1];
            sum1 += s[n][2] + s[n][3];
        }
        sum0 += __shfl_xor_sync(0xffffffff, sum0, 1);
        sum0 += __shfl_xor_sync(0xffffffff, sum0, 2);
        sum1 += __shfl_xor_sync(0xffffffff, sum1, 1);
        sum1 += __shfl_xor_sync(0xffffffff, sum1, 2);
        rl0 = rl0 * corr0 + sum0;
        rl1 = rl1 * corr1 + sum1;
        rm0 = mn0; rm1 = mn1;

#pragma unroll
        for (int n = 0; n < 8; n++) {
            om[n][0] *= corr0; om[n][1] *= corr0;
            om[n][2] *= corr1; om[n][3] *= corr1;
        }

#pragma unroll
        for (int k0 = 0; k0 < 4; k0++) {
            uint32_t ph[4];
            ph[0] = packh2(s[2 * k0][0],     s[2 * k0][1]);
            ph[1] = packh2(s[2 * k0][2],     s[2 * k0][3]);
            ph[2] = packh2(s[2 * k0 + 1][0], s[2 * k0 + 1][1]);
            ph[3] = packh2(s[2 * k0 + 1][2], s[2 * k0 + 1][3]);
            const uint32_t* vr = Vf + (k0 * 32 + lane) * ROWPAD;
#pragma unroll
            for (int np = 0; np < 4; np++) {
                uint4 v4 = *(const uint4*)(vr + np * 4);
                uint32_t b2[2] = {v4.x, v4.y};
                mma_f16(om[2 * np], ph, b2);
                uint32_t b3[2] = {v4.z, v4.w};
                mma_f16(om[2 * np + 1], ph, b3);
            }
        }
        __syncthreads();
    }

    float inv0 = 1.f / rl0;
    float inv1 = 1.f / rl1;
    uint32_t* ob0 = oh + (size_t)(b * TT + q0 + w * 16 + g    ) * (QKW / 2) + h * 32 + t;
    uint32_t* ob1 = oh + (size_t)(b * TT + q0 + w * 16 + g + 8) * (QKW / 2) + h * 32 + t;
#pragma unroll
    for (int n0 = 0; n0 < 8; n0++) {
        ob0[n0 * 4] = packh2(om[n0][0] * inv0, om[n0][1] * inv0);
        ob1[n0 * 4] = packh2(om[n0][2] * inv1, om[n0][3] * inv1);
    }
}

// -------- Y pairs: Y[t, 2i..2i+1] = sum_h mask*attn(fp16) -> single fp16 -------
__global__ void combine_out_kernel(const uint32_t* __restrict__ attnh,
                                   const float* __restrict__ masko,
                                   uint32_t* __restrict__ Y) {
    int token = blockIdx.x;
    int tid = threadIdx.x;          // 0..159
    int t0 = 2 * tid;
    int e = t0 >> 6, j = t0 & 63;
    const uint32_t* ap = attnh + (size_t)token * (QKW / 2);
    const float* mp = masko + (size_t)token * GW;
    float s0 = 0.f, s1 = 0.f;
#pragma unroll
    for (int h = 0; h < HH; h++) {
        float m = mp[h * EE + e];
        uint32_t u = ap[h * 32 + (j >> 1)];
        __half2 hv = *reinterpret_cast<__half2*>(&u);
        s0 += m * __low2float(hv);
        s1 += m * __high2float(hv);
    }
    Y[(size_t)token * (XVW / 2) + tid] = packh2(s0, s1);
}

// ------------------------------- launch ----------------------------------------
extern "C" void kernel_launch(void* const* d_in, const int* in_sizes, int n_in,
                              void* d_out, int out_size) {
    const float* x  = (const float*)d_in[0];
    const float* Wq = (const float*)d_in[1];
    const float* Wk = (const float*)d_in[2];
    const float* Ws = (const float*)d_in[3];
    const float* Wd = (const float*)d_in[4];
    const float* Wv = (const float*)d_in[5];
    const float* Wo = (const float*)d_in[6];
    float* out = (float*)d_out;

    float *glp, *mask;
    uint32_t *projh, *xbh, *xbl, *wt, *gwh, *gwl, *attnh, *yb, *wot, *blob;
    cudaGetSymbolAddress((void**)&projh, g_projh);
    cudaGetSymbolAddress((void**)&xbh,   g_xbh);
    cudaGetSymbolAddress((void**)&xbl,   g_xbl);
    cudaGetSymbolAddress((void**)&wt,    g_wt);
    cudaGetSymbolAddress((void**)&gwh,   g_gwh);
    cudaGetSymbolAddress((void**)&gwl,   g_gwl);
    cudaGetSymbolAddress((void**)&glp,   g_glp);
    cudaGetSymbolAddress((void**)&attnh, g_attnh);
    cudaGetSymbolAddress((void**)&mask,  g_mask);
    cudaGetSymbolAddress((void**)&yb,    g_yb);
    cudaGetSymbolAddress((void**)&wot,   g_wot);
    cudaGetSymbolAddress((void**)&blob,  g_blob);

    // pre-splits / packs
    split_x_f16 <<<(int)(((size_t)NTOK * DD / 2 + 255) / 256), 256>>>(x, xbh, xbl);
    pack_wt_f16 <<<(int)(((size_t)PW2 * DD / 2 + 255) / 256), 256>>>(Wq, Wk, Wv, wt);
    pack_gw_f16 <<<(int)(((size_t)NG * DD / 2 + 255) / 256), 256>>>(Ws, Wd, gwh, gwl);
    pack_wot_f16<<<(int)(((size_t)DD * XVW / 2 + 255) / 256), 256>>>(Wo, wot);

    size_t h1sm = (size_t)3 * H1_STG * sizeof(uint32_t);   // 46080
    cudaFuncSetAttribute(tgemmh1,  cudaFuncAttributeMaxDynamicSharedMemorySize, (int)h1sm);
    cudaFuncSetAttribute(tgemmh1p, cudaFuncAttributeMaxDynamicSharedMemorySize, (int)h1sm);

    // proj GEMM (single fp16, fp16 output): (8192x1024)@(1024x1344)
    dim3 gp(PW2 / 64, NTOK / 128);
    tgemmh1p<<<gp, 256, h1sm>>>(xbh, wt, projh, NTOK, PW2, DD);

    // gate GEMM (fp16 3-term, split-K=2): (8192x1024)@(1024x128) -> partials
    size_t h3sm = (size_t)3 * H3_STG * sizeof(uint32_t);   // 92160
    cudaFuncSetAttribute(tgemmh3, cudaFuncAttributeMaxDynamicSharedMemorySize, (int)h3sm);
    dim3 gg(NG / 64, NTOK / 128, KSPL);
    tgemmh3<<<gg, 256, h3sm>>>(xbh, xbl, gwh, gwl, glp, NTOK, NG, DD);

    // fused gating + V combine + K/V blob + out-mask
    dim3 bg(NTILE, BB * HH);
    gate_kv_kernel<<<bg, 256>>>(glp, projh, blob, mask);

    // attention (pure fp16, fp16 in/out)
    size_t asmem = (size_t)3 * TILE4_U32 * sizeof(uint32_t);  // 61440
    cudaFuncSetAttribute(attn5_kernel, cudaFuncAttributeMaxDynamicSharedMemorySize, (int)asmem);
    dim3 ag(TT / 128, BB * HH);
    attn5_kernel<<<ag, 256, asmem>>>(projh, blob, attnh);

    // masked combine (fp16 in/out), then output GEMM (fp32 out)
    combine_out_kernel<<<NTOK, XVW / 2>>>(attnh, mask, yb);
    dim3 go(DD / 64, NTOK / 128);
    tgemmh1<<<go, 256, h1sm>>>(yb, wot, out, NTOK, DD, XVW);
}

// round 17
// speedup vs baseline: 18.6103x; 1.0085x over previous
#include <cuda_runtime.h>
#include <cuda_bf16.h>
#include <cuda_fp16.h>
#include <math.h>
#include <stdint.h>

// Problem constants
#define BB 4
#define TT 2048
#define DD 1024
#define HH 8
#define DH 64
#define EE 5
#define NTOK (BB*TT)          // 8192
#define QKW (HH*DH)           // 512
#define GW  (HH*EE)           // 40
#define XVW (EE*DH)           // 320

// fused projection layout (row stride PW2): q[0:512) | k[512:1024) | xv[1024:1344)
#define PW2 1344
#define PWU (PW2/2)            // 672 u32 pairs per row
#define OFF_KU 256             // K offset in pairs
#define OFF_XVU 512            // xv offset in pairs

#define NG 128                 // gate GEMM padded width (glv 0..39, glo 40..79)
#define KSPL 2                 // gate GEMM split-K

// fp16 KV fragment blob: per (bh,tile64): [K | V], each 4 k0 x 32 lanes x 20 u32
#define ROWPAD 20
#define ARR2_U32 (4*32*ROWPAD)    // 2560
#define TILE4_U32 (2*ARR2_U32)    // 5120 u32 = 20KB
#define NTILE 32

// ---------------- scratch (device globals) ------------------------------------
__device__ __align__(16) uint32_t g_projh[(size_t)NTOK*PWU];   // proj, fp16 pairs
__device__ __align__(16) uint32_t g_xbh [(size_t)NTOK*DD/2];   // fp16 hi pairs of x
__device__ __align__(16) uint32_t g_xbl [(size_t)NTOK*DD/2];   // fp16 lo pairs (gates)
__device__ __align__(16) uint32_t g_wt  [(size_t)PW2*DD/2];    // Wt[n][dpair] fp16
__device__ __align__(16) uint32_t g_gwh [(size_t)NG*DD/2];     // gate weights fp16 hi
__device__ __align__(16) uint32_t g_gwl [(size_t)NG*DD/2];     // lo
__device__ float    g_glp  [(size_t)KSPL*NTOK*NG];             // gate partials
__device__ __align__(16) uint32_t g_attnh[(size_t)NTOK*QKW/2]; // attn out, fp16 pairs
__device__ float    g_mask [(size_t)NTOK*GW];
__device__ __align__(16) uint32_t g_yb  [(size_t)NTOK*XVW/2];  // fp16 pairs of Y
__device__ __align__(16) uint32_t g_wot [(size_t)DD*XVW/2];    // WoT[n=d][kpair] fp16
__device__ __align__(16) uint32_t g_blob[(size_t)BB*HH*NTILE*TILE4_U32];  // ~21MB

// ---------------- helpers ------------------------------------------------------
__device__ __forceinline__ uint32_t packh2(float a, float b) {
    __half2 h = __floats2half2_rn(a, b);
    return *reinterpret_cast<uint32_t*>(&h);
}
__device__ __forceinline__ void splith2(float a, float b, uint32_t& h, uint32_t& l) {
    __half ha = __float2half_rn(a);
    __half hb = __float2half_rn(b);
    float ra = a - __half2float(ha);
    float rb = b - __half2float(hb);
    __half2 hh; hh.x = ha; hh.y = hb;
    __half2 ll; ll.x = __float2half_rn(ra); ll.y = __float2half_rn(rb);
    h = *reinterpret_cast<uint32_t*>(&hh);
    l = *reinterpret_cast<uint32_t*>(&ll);
}
__device__ __forceinline__ void mma_f16(float c[4], const uint32_t a[4], const uint32_t b[2]) {
    asm volatile(
        "mma.sync.aligned.m16n8k16.row.col.f32.f16.f16.f32 "
        "{%0,%1,%2,%3},{%4,%5,%6,%7},{%8,%9},{%0,%1,%2,%3};"
        : "+f"(c[0]), "+f"(c[1]), "+f"(c[2]), "+f"(c[3])
        : "r"(a[0]), "r"(a[1]), "r"(a[2]), "r"(a[3]), "r"(b[0]), "r"(b[1]));
}
__device__ __forceinline__ void cp16(uint32_t saddr, const void* g) {
    asm volatile("cp.async.cg.shared.global [%0], [%1], 16;\n" :: "r"(saddr), "l"(g));
}
#define CP_COMMIT() asm volatile("cp.async.commit_group;\n")
#define CP_WAIT(n)  asm volatile("cp.async.wait_group %0;\n" :: "n"(n))

// =============== fused pack kernel =============================================
// one grid covers: [0, XN) x-split | [XN, XN+WN) Wt | [.., +GN) gate W | [.., +ON) WoT
#define XN ((size_t)NTOK*DD/2)           // 4194304
#define WN ((size_t)PW2*DD/2)            // 688128
#define GN ((size_t)NG*DD/2)             // 65536
#define ON ((size_t)DD*XVW/2)            // 163840
#define PACK_TOTAL (XN+WN+GN+ON)

__global__ void pack_all(const float* __restrict__ x,
                         const float* __restrict__ Wq, const float* __restrict__ Wk,
                         const float* __restrict__ Wv,
                         const float* __restrict__ Ws, const float* __restrict__ Wd,
                         const float* __restrict__ Wo,
                         uint32_t* __restrict__ xbh, uint32_t* __restrict__ xbl,
                         uint32_t* __restrict__ wt,
                         uint32_t* __restrict__ gwh, uint32_t* __restrict__ gwl,
                         uint32_t* __restrict__ wot) {
    size_t i = (size_t)blockIdx.x * blockDim.x + threadIdx.x;
    if (i < XN) {
        splith2(x[2 * i], x[2 * i + 1], xbh[i], xbl[i]);
        return;
    }
    i -= XN;
    if (i < WN) {
        int n = (int)(i / (DD / 2));
        int d0 = 2 * (int)(i % (DD / 2));
        float va, vb;
        if (n < 512) {
            va = Wq[(size_t)d0 * 512 + n]; vb = Wq[(size_t)(d0 + 1) * 512 + n];
        } else if (n < 1024) {
            va = Wk[(size_t)d0 * 512 + (n - 512)]; vb = Wk[(size_t)(d0 + 1) * 512 + (n - 512)];
        } else {
            int e = (n - 1024) / DH, j = (n - 1024) % DH;
            va = Wv[((size_t)e * DD + d0) * DH + j];
            vb = Wv[((size_t)e * DD + d0 + 1) * DH + j];
        }
        wt[i] = packh2(va, vb);
        return;
    }
    i -= WN;
    if (i < GN) {
        int n = (int)(i / (DD / 2));
        int d0 = 2 * (int)(i % (DD / 2));
        float va = 0.f, vb = 0.f;
        if (n < 40)      { va = Ws[(size_t)d0 * GW + n];        vb = Ws[(size_t)(d0 + 1) * GW + n]; }
        else if (n < 80) { va = Wd[(size_t)d0 * GW + (n - 40)]; vb = Wd[(size_t)(d0 + 1) * GW + (n - 40)]; }
        splith2(va, vb, gwh[i], gwl[i]);
        return;
    }
    i -= GN;
    if (i < ON) {
        int n = (int)(i / (XVW / 2));
        int k0 = 2 * (int)(i % (XVW / 2));
        int e = k0 >> 6, j = k0 & 63;
        float va = Wo[((size_t)(e * DH + j)) * DD + n];
        float vb = Wo[((size_t)(e * DH + j + 1)) * DD + n];
        wot[i] = packh2(va, vb);
    }
}

// =============== single-term fp16 GEMM core (shared by both epilogues) =========
#define H1_OFF_B 2560
#define H1_STG   3840     // 15KB/stage

#define H1_LOAD(dst, kt)                                                          \
    {                                                                             \
        int ko = (kt) * 16;                                                       \
        _Pragma("unroll")                                                         \
        for (int it = 0; it < 2; it++) {                                          \
            int idx = it * 256 + tid;                                             \
            int r = idx >> 2, cc = idx & 3;                                       \
            cp16((dst) + (uint32_t)(r * ROWPAD + cc * 4) * 4,                     \
                 Ag + (size_t)(row0 + r) * Ku + ko + cc * 4);                     \
        }                                                                         \
        {                                                                         \
            int r = tid >> 2, cc = tid & 3;                                       \
            cp16((dst) + (uint32_t)(H1_OFF_B + r * ROWPAD + cc * 4) * 4,          \
                 Bg + (size_t)(col0 + r) * Ku + ko + cc * 4);                     \
        }                                                                         \
    }

#define H1_BODY                                                                   \
    const int tid = threadIdx.x;                                                  \
    const int row0 = blockIdx.y * 128;                                            \
    const int col0 = blockIdx.x * 64;                                             \
    const int lane = tid & 31, w = tid >> 5;                                      \
    const int g = lane >> 2, t = lane & 3;                                        \
    const int wm = w >> 1, wn = w & 1;                                            \
    const int Ku = K / 2;                                                         \
    const uint32_t sb = (uint32_t)__cvta_generic_to_shared(sm1);                  \
    float c[2][4][4];                                                             \
    _Pragma("unroll")                                                             \
    for (int mt = 0; mt < 2; mt++)                                                \
        _Pragma("unroll")                                                         \
        for (int nt = 0; nt < 4; nt++)                                            \
            _Pragma("unroll")                                                     \
            for (int i = 0; i < 4; i++) c[mt][nt][i] = 0.f;                       \
    const int nk = K / 32;                                                        \
    H1_LOAD(sb, 0);                                                               \
    CP_COMMIT();                                                                  \
    if (nk > 1) { H1_LOAD(sb + (uint32_t)H1_STG * 4, 1); CP_COMMIT(); }           \
    for (int kt = 0; kt < nk; kt++) {                                             \
        const int st = kt % 3;                                                    \
        if (kt + 2 < nk) {                                                        \
            uint32_t d2 = sb + (uint32_t)(((kt + 2) % 3) * H1_STG) * 4;           \
            H1_LOAD(d2, kt + 2);                                                  \
            CP_COMMIT();                                                          \
            CP_WAIT(2);                                                           \
        } else if (kt + 1 < nk) { CP_WAIT(1); } else { CP_WAIT(0); }              \
        __syncthreads();                                                          \
        const uint32_t* Ah = sm1 + st * H1_STG;                                   \
        const uint32_t* Bs = Ah + H1_OFF_B;                                       \
        _Pragma("unroll")                                                         \
        for (int kc = 0; kc < 2; kc++) {                                          \
            uint32_t af[2][4], bf[4][2];                                          \
            _Pragma("unroll")                                                     \
            for (int mt = 0; mt < 2; mt++) {                                      \
                int rb = wm * 32 + mt * 16;                                       \
                af[mt][0] = Ah[(rb + g    ) * ROWPAD + kc * 8 + t];               \
                af[mt][1] = Ah[(rb + g + 8) * ROWPAD + kc * 8 + t];               \
                af[mt][2] = Ah[(rb + g    ) * ROWPAD + kc * 8 + t + 4];           \
                af[mt][3] = Ah[(rb + g + 8) * ROWPAD + kc * 8 + t + 4];           \
            }                                                                     \
            _Pragma("unroll")                                                     \
            for (int nt = 0; nt < 4; nt++) {                                      \
                int cb = wn * 32 + nt * 8;                                        \
                bf[nt][0] = Bs[(cb + g) * ROWPAD + kc * 8 + t];                   \
                bf[nt][1] = Bs[(cb + g) * ROWPAD + kc * 8 + t + 4];               \
            }                                                                     \
            _Pragma("unroll")                                                     \
            for (int mt = 0; mt < 2; mt++)                                        \
                _Pragma("unroll")                                                 \
                for (int nt = 0; nt < 4; nt++)                                    \
                    mma_f16(c[mt][nt], af[mt], bf[nt]);                           \
        }                                                                         \
        __syncthreads();                                                          \
    }

// fp32-output variant (final out GEMM)
__global__ __launch_bounds__(256, 2)
void tgemmh1(const uint32_t* __restrict__ Ag, const uint32_t* __restrict__ Bg,
             float* __restrict__ C, int M, int N, int K) {
    extern __shared__ uint32_t sm1[];
    H1_BODY
#pragma unroll
    for (int mt = 0; mt < 2; mt++) {
        int r0 = row0 + wm * 32 + mt * 16;
#pragma unroll
        for (int nt = 0; nt < 4; nt++) {
            int cc = col0 + wn * 32 + nt * 8 + 2 * t;
            *(float2*)&C[(size_t)(r0 + g    ) * N + cc] = make_float2(c[mt][nt][0], c[mt][nt][1]);
            *(float2*)&C[(size_t)(r0 + g + 8) * N + cc] = make_float2(c[mt][nt][2], c[mt][nt][3]);
        }
    }
}

// fp16-pair-output variant (proj GEMM)
__global__ __launch_bounds__(256, 2)
void tgemmh1p(const uint32_t* __restrict__ Ag, const uint32_t* __restrict__ Bg,
              uint32_t* __restrict__ Cp, int M, int N, int K) {
    extern __shared__ uint32_t sm1[];
    H1_BODY
    const int Nu = N / 2;
#pragma unroll
    for (int mt = 0; mt < 2; mt++) {
        int r0 = row0 + wm * 32 + mt * 16;
#pragma unroll
        for (int nt = 0; nt < 4; nt++) {
            int cp = (col0 + wn * 32 + nt * 8 + 2 * t) >> 1;
            Cp[(size_t)(r0 + g    ) * Nu + cp] = packh2(c[mt][nt][0], c[mt][nt][1]);
            Cp[(size_t)(r0 + g + 8) * Nu + cp] = packh2(c[mt][nt][2], c[mt][nt][3]);
        }
    }
}

// =============== fp16 3-term GEMM (gates): A hi/lo, B hi/lo, split-K ===========
#define H3_OFF_AL 2560
#define H3_OFF_BH 5120
#define H3_OFF_BL 6400
#define H3_STG    7680

__global__ __launch_bounds__(256, 2)
void tgemmh3(const uint32_t* __restrict__ Agh, const uint32_t* __restrict__ Agl,
             const uint32_t* __restrict__ Bgh, const uint32_t* __restrict__ Bgl,
             float* __restrict__ C, int M, int N, int K) {
    extern __shared__ uint32_t sm3[];
    const int tid = threadIdx.x;
    const int row0 = blockIdx.y * 128;
    const int col0 = blockIdx.x * 64;
    const int lane = tid & 31, w = tid >> 5;
    const int g = lane >> 2, t = lane & 3;
    const int wm = w >> 1, wn = w & 1;
    const int Ku = K / 2;
    const int ksplit = gridDim.z;
    const int kb = blockIdx.z * (K / 32 / ksplit);
    const int nk = K / 32 / ksplit;
    float* Cz = C + (size_t)blockIdx.z * M * N;

    const uint32_t sb = (uint32_t)__cvta_generic_to_shared(sm3);

    float c[2][4][4];
#pragma unroll
    for (int mt = 0; mt < 2; mt++)
#pragma unroll
        for (int nt = 0; nt < 4; nt++)
#pragma unroll
            for (int i = 0; i < 4; i++) c[mt][nt][i] = 0.f;

#define H3_LOAD(dst, kt)                                                          \
    {                                                                             \
        int ko = (kb + (kt)) * 16;                                                \
        _Pragma("unroll")                                                         \
        for (int it = 0; it < 2; it++) {                                          \
            int idx = it * 256 + tid;                                             \
            int r = idx >> 2, cc = idx & 3;                                       \
            cp16((dst) + (uint32_t)(r * ROWPAD + cc * 4) * 4,                     \
                 Agh + (size_t)(row0 + r) * Ku + ko + cc * 4);                    \
            cp16((dst) + (uint32_t)(H3_OFF_AL + r * ROWPAD + cc * 4) * 4,         \
                 Agl + (size_t)(row0 + r) * Ku + ko + cc * 4);                    \
        }                                                                         \
        {                                                                         \
            int r = tid >> 2, cc = tid & 3;                                       \
            cp16((dst) + (uint32_t)(H3_OFF_BH + r * ROWPAD + cc * 4) * 4,         \
                 Bgh + (size_t)(col0 + r) * Ku + ko + cc * 4);                    \
            cp16((dst) + (uint32_t)(H3_OFF_BL + r * ROWPAD + cc * 4) * 4,         \
                 Bgl + (size_t)(col0 + r) * Ku + ko + cc * 4);                    \
        }                                                                         \
    }

    H3_LOAD(sb, 0);
    CP_COMMIT();
    if (nk > 1) {
        H3_LOAD(sb + (uint32_t)H3_STG * 4, 1);
        CP_COMMIT();
    }

    for (int kt = 0; kt < nk; kt++) {
        const int st = kt % 3;
        if (kt + 2 < nk) {
            uint32_t d2 = sb + (uint32_t)(((kt + 2) % 3) * H3_STG) * 4;
            H3_LOAD(d2, kt + 2);
            CP_COMMIT();
            CP_WAIT(2);
        } else if (kt + 1 < nk) {
            CP_WAIT(1);
        } else {
            CP_WAIT(0);
        }
        __syncthreads();

        const uint32_t* Ah = sm3 + st * H3_STG;
        const uint32_t* Al = Ah + H3_OFF_AL;
        const uint32_t* Bh = Ah + H3_OFF_BH;
        const uint32_t* Bl = Ah + H3_OFF_BL;

#pragma unroll
        for (int kc = 0; kc < 2; kc++) {
            uint32_t afh[2][4], afl[2][4], bfh[4][2], bfl[4][2];
#pragma unroll
            for (int mt = 0; mt < 2; mt++) {
                int rb = wm * 32 + mt * 16;
                afh[mt][0] = Ah[(rb + g    ) * ROWPAD + kc * 8 + t];
                afh[mt][1] = Ah[(rb + g + 8) * ROWPAD + kc * 8 + t];
                afh[mt][2] = Ah[(rb + g    ) * ROWPAD + kc * 8 + t + 4];
                afh[mt][3] = Ah[(rb + g + 8) * ROWPAD + kc * 8 + t + 4];
                afl[mt][0] = Al[(rb + g    ) * ROWPAD + kc * 8 + t];
                afl[mt][1] = Al[(rb + g + 8) * ROWPAD + kc * 8 + t];
                afl[mt][2] = Al[(rb + g    ) * ROWPAD + kc * 8 + t + 4];
                afl[mt][3] = Al[(rb + g + 8) * ROWPAD + kc * 8 + t + 4];
            }
#pragma unroll
            for (int nt = 0; nt < 4; nt++) {
                int cb = wn * 32 + nt * 8;
                bfh[nt][0] = Bh[(cb + g) * ROWPAD + kc * 8 + t];
                bfh[nt][1] = Bh[(cb + g) * ROWPAD + kc * 8 + t + 4];
                bfl[nt][0] = Bl[(cb + g) * ROWPAD + kc * 8 + t];
                bfl[nt][1] = Bl[(cb + g) * ROWPAD + kc * 8 + t + 4];
            }
#pragma unroll
            for (int mt = 0; mt < 2; mt++)
#pragma unroll
                for (int nt = 0; nt < 4; nt++) {
                    mma_f16(c[mt][nt], afh[mt], bfl[nt]);
                    mma_f16(c[mt][nt], afl[mt], bfh[nt]);
                    mma_f16(c[mt][nt], afh[mt], bfh[nt]);
                }
        }
        __syncthreads();
    }

#pragma unroll
    for (int mt = 0; mt < 2; mt++) {
        int r0 = row0 + wm * 32 + mt * 16;
#pragma unroll
        for (int nt = 0; nt < 4; nt++) {
            int cc = col0 + wn * 32 + nt * 8 + 2 * t;
            *(float2*)&Cz[(size_t)(r0 + g    ) * N + cc] = make_float2(c[mt][nt][0], c[mt][nt][1]);
            *(float2*)&Cz[(size_t)(r0 + g + 8) * N + cc] = make_float2(c[mt][nt][2], c[mt][nt][3]);
        }
    }
}

// ====== fused gating + V combine + K/V blob build + out-mask ===================
__global__ void gate_kv_kernel(const float* __restrict__ glp,
                               const uint32_t* __restrict__ projh,
                               uint32_t* __restrict__ blob,
                               float* __restrict__ masko) {
    __shared__ uint32_t Ks[64 * 36];
    __shared__ float    Vs[64 * 68];
    const int tile = blockIdx.x, bh = blockIdx.y;
    const int b = bh / HH, h = bh % HH;
    const int tid = threadIdx.x;
    const int tok = tid >> 2;
    const int q = tid & 3;
    const int token = b * TT + tile * 64 + tok;

#pragma unroll
    for (int it = 0; it < 8; it++) {
        int idx = it * 256 + tid;
        int r = idx >> 5, p = idx & 31;
        Ks[r * 36 + p] = projh[(size_t)(b * TT + tile * 64 + r) * PWU + OFF_KU + h * 32 + p];
    }

    float gv[EE];
#pragma unroll
    for (int e = 0; e < EE; e++)
        gv[e] = glp[(size_t)token * NG + h * EE + e]
              + glp[((size_t)NTOK + token) * NG + h * EE + e];
    int i1 = 0;
#pragma unroll
    for (int e = 1; e < EE; e++) if (gv[e] > gv[i1]) i1 = e;
    int i2 = (i1 == 0) ? 1 : 0;
#pragma unroll
    for (int e = 0; e < EE; e++) if (e != i1 && gv[e] > gv[i2]) i2 = e;
    float w1 = 1.f / (1.f + __expf(-gv[i1]));
    float w2 = 1.f / (1.f + __expf(-gv[i2]));

    const uint32_t* xvt = projh + (size_t)token * PWU + OFF_XVU;
    int p0 = q * 8;
#pragma unroll
    for (int j = 0; j < 8; j++) {
        uint32_t u1 = xvt[i1 * 32 + p0 + j];
        uint32_t u2 = xvt[i2 * 32 + p0 + j];
        __half2 h1 = *reinterpret_cast<__half2*>(&u1);
        __half2 h2 = *reinterpret_cast<__half2*>(&u2);
        Vs[tok * 68 + 2 * (p0 + j)    ] = w1 * __low2float(h1)  + w2 * __low2float(h2);
        Vs[tok * 68 + 2 * (p0 + j) + 1] = w1 * __high2float(h1) + w2 * __high2float(h2);
    }

    if (q == 0) {
        float go[EE];
#pragma unroll
        for (int e = 0; e < EE; e++)
            go[e] = glp[(size_t)token * NG + 40 + h * EE + e]
                  + glp[((size_t)NTOK + token) * NG + 40 + h * EE + e];
        int o1 = 0;
#pragma unroll
        for (int e = 1; e < EE; e++) if (go[e] > go[o1]) o1 = e;
        int o2 = (o1 == 0) ? 1 : 0;
#pragma unroll
        for (int e = 0; e < EE; e++) if (e != o1 && go[e] > go[o2]) o2 = e;
#pragma unroll
        for (int e = 0; e < EE; e++)
            masko[((size_t)token * HH + h) * EE + e] = (e == o1 || e == o2) ? 1.f : 0.f;
    }
    __syncthreads();

    uint32_t* dst = blob + ((size_t)bh * NTILE + tile) * TILE4_U32;
#pragma unroll
    for (int i = 0; i < 8; i++) {
        int oi = tid * 8 + i;
        int row = oi >> 4;
        int col = oi & 15;
        int k0 = row >> 5, lane2 = row & 31;
        int g2 = lane2 >> 2, t2 = lane2 & 3;
        int n0 = col >> 1, w2 = col & 1;
        int keyK = n0 * 8 + g2;
        dst[row * ROWPAD + col] = Ks[keyK * 36 + k0 * 8 + w2 * 4 + t2];
        int keyV = k0 * 16 + w2 * 8 + 2 * t2;
        int dV = n0 * 8 + g2;
        dst[ARR2_U32 + row * ROWPAD + col] = packh2(Vs[keyV * 68 + dV], Vs[(keyV + 1) * 68 + dV]);
    }
}

// =============== flash attention, pure fp16, fp16 in/out =======================
#define LOG2E 1.4426950408889634f
#define SCLG2E (0.125f * LOG2E)

__global__ __launch_bounds__(256, 2)
void attn5_kernel(const uint32_t* __restrict__ qg,
                  const uint32_t* __restrict__ blob,
                  uint32_t* __restrict__ oh) {
    extern __shared__ uint32_t sh[];
    const int bh = blockIdx.y;
    const int b = bh / HH, h = bh % HH;
    const int q0 = blockIdx.x * 128;
    const int tid = threadIdx.x;
    const int lane = tid & 31, w = tid >> 5;
    const int g = lane >> 2, t = lane & 3;

    const uint32_t* gblob = blob + (size_t)bh * NTILE * TILE4_U32;
    const uint32_t sbase = (uint32_t)__cvta_generic_to_shared(sh);

#define BLOB_DMA(dstoff, srct)                                                   \
    {                                                                            \
        const uint32_t* src = gblob + (size_t)(srct) * TILE4_U32;                \
        _Pragma("unroll")                                                        \
        for (int i = 0; i < 5; i++) {                                            \
            int cc = tid + i * 256;                                              \
            cp16(sbase + (uint32_t)((dstoff) + cc * 4) * 4, src + cc * 4);       \
        }                                                                        \
    }

    BLOB_DMA(0, 0);
    CP_COMMIT();
    BLOB_DMA(TILE4_U32, 1);
    CP_COMMIT();

    const uint32_t* qb = qg + (size_t)(b * TT + q0 + w * 16) * PWU + h * 32;
    uint32_t qa[4][4];
#pragma unroll
    for (int k0 = 0; k0 < 4; k0++) {
        qa[k0][0] = qb[(size_t)(g    ) * PWU + k0 * 8 + t];
        qa[k0][1] = qb[(size_t)(g + 8) * PWU + k0 * 8 + t];
        qa[k0][2] = qb[(size_t)(g    ) * PWU + k0 * 8 + t + 4];
        qa[k0][3] = qb[(size_t)(g + 8) * PWU + k0 * 8 + t + 4];
    }

    float om[8][4];
#pragma unroll
    for (int n = 0; n < 8; n++)
#pragma unroll
        for (int i = 0; i < 4; i++) om[n][i] = 0.f;
    float rm0 = -INFINITY, rm1 = -INFINITY, rl0 = 0.f, rl1 = 0.f;

    for (int tt = 0; tt < NTILE; tt++) {
        const int st = tt % 3;
        if (tt + 2 < NTILE) {
            BLOB_DMA(((tt + 2) % 3) * TILE4_U32, tt + 2);
            CP_COMMIT();
            CP_WAIT(2);
        } else if (tt + 1 < NTILE) {
            CP_WAIT(1);
        } else {
            CP_WAIT(0);
        }
        __syncthreads();

        const uint32_t* Kf = sh + st * TILE4_U32;
        const uint32_t* Vf = Kf + ARR2_U32;

        float s[8][4];
#pragma unroll
        for (int n = 0; n < 8; n++)
#pragma unroll
            for (int i = 0; i < 4; i++) s[n][i] = 0.f;
#pragma unroll
        for (int k0 = 0; k0 < 4; k0++) {
            const uint32_t* kr = Kf + (k0 * 32 + lane) * ROWPAD;
#pragma unroll
            for (int np = 0; np < 4; np++) {
                uint4 k4 = *(const uint4*)(kr + np * 4);
                uint32_t b2[2] = {k4.x, k4.y};
                mma_f16(s[2 * np], qa[k0], b2);
                uint32_t b3[2] = {k4.z, k4.w};
                mma_f16(s[2 * np + 1], qa[k0], b3);
            }
        }

        float m0 = s[0][0], m1 = s[0][2];
#pragma unroll
        for (int n = 0; n < 8; n++) {
            m0 = fmaxf(m0, fmaxf(s[n][0], s[n][1]));
            m1 = fmaxf(m1, fmaxf(s[n][2], s[n][3]));
        }
        m0 = fmaxf(m0, __shfl_xor_sync(0xffffffff, m0, 1));
        m0 = fmaxf(m0, __shfl_xor_sync(0xffffffff, m0, 2));
        m1 = fmaxf(m1, __shfl_xor_sync(0xffffffff, m1, 1));
        m1 = fmaxf(m1, __shfl_xor_sync(0xffffffff, m1, 2));

        float mn0 = fmaxf(rm0, m0);
        float mn1 = fmaxf(rm1, m1);
        float corr0 = exp2f((rm0 - mn0) * SCLG2E);
        float corr1 = exp2f((rm1 - mn1) * SCLG2E);

        float sum0 = 0.f, sum1 = 0.f;
#pragma unroll
        for (int n = 0; n < 8; n++) {
            s[n][0] = exp2f((s[n][0] - mn0) * SCLG2E);
            s[n][1] = exp2f((s[n][1] - mn0) * SCLG2E);
            s[n][2] = exp2f((s[n][2] - mn1) * SCLG2E);
            s[n][3] = exp2f((s[n][3] - mn1) * SCLG2E);
            sum0 += s[n][0] + s[n][1];
            sum1 += s[n][2] + s[n][3];
        }
        sum0 += __shfl_xor_sync(0xffffffff, sum0, 1);
        sum0 += __shfl_xor_sync(0xffffffff, sum0, 2);
        sum1 += __shfl_xor_sync(0xffffffff, sum1, 1);
        sum1 += __shfl_xor_sync(0xffffffff, sum1, 2);
        rl0 = rl0 * corr0 + sum0;
        rl1 = rl1 * corr1 + sum1;
        rm0 = mn0; rm1 = mn1;

#pragma unroll
        for (int n = 0; n < 8; n++) {
            om[n][0] *= corr0; om[n][1] *= corr0;
            om[n][2] *= corr1; om[n][3] *= corr1;
        }

#pragma unroll
        for (int k0 = 0; k0 < 4; k0++) {
            uint32_t ph[4];
            ph[0] = packh2(s[2 * k0][0],     s[2 * k0][1]);
            ph[1] = packh2(s[2 * k0][2],     s[2 * k0][3]);
            ph[2] = packh2(s[2 * k0 + 1][0], s[2 * k0 + 1][1]);
            ph[3] = packh2(s[2 * k0 + 1][2], s[2 * k0 + 1][3]);
            const uint32_t* vr = Vf + (k0 * 32 + lane) * ROWPAD;
#pragma unroll
            for (int np = 0; np < 4; np++) {
                uint4 v4 = *(const uint4*)(vr + np * 4);
                uint32_t b2[2] = {v4.x, v4.y};
                mma_f16(om[2 * np], ph, b2);
                uint32_t b3[2] = {v4.z, v4.w};
                mma_f16(om[2 * np + 1], ph, b3);
            }
        }
        __syncthreads();
    }

    float inv0 = 1.f / rl0;
    float inv1 = 1.f / rl1;
    uint32_t* ob0 = oh + (size_t)(b * TT + q0 + w * 16 + g    ) * (QKW / 2) + h * 32 + t;
    uint32_t* ob1 = oh + (size_t)(b * TT + q0 + w * 16 + g + 8) * (QKW / 2) + h * 32 + t;
#pragma unroll
    for (int n0 = 0; n0 < 8; n0++) {
        ob0[n0 * 4] = packh2(om[n0][0] * inv0, om[n0][1] * inv0);
        ob1[n0 * 4] = packh2(om[n0][2] * inv1, om[n0][3] * inv1);
    }
}

// -------- Y pairs: Y[t, 2i..2i+1] = sum_h mask*attn(fp16) -> single fp16 -------
__global__ void combine_out_kernel(const uint32_t* __restrict__ attnh,
                                   const float* __restrict__ masko,
                                   uint32_t* __restrict__ Y) {
    int token = blockIdx.x;
    int tid = threadIdx.x;          // 0..159
    int t0 = 2 * tid;
    int e = t0 >> 6, j = t0 & 63;
    const uint32_t* ap = attnh + (size_t)token * (QKW / 2);
    const float* mp = masko + (size_t)token * GW;
    float s0 = 0.f, s1 = 0.f;
#pragma unroll
    for (int h = 0; h < HH; h++) {
        float m = mp[h * EE + e];
        uint32_t u = ap[h * 32 + (j >> 1)];
        __half2 hv = *reinterpret_cast<__half2*>(&u);
        s0 += m * __low2float(hv);
        s1 += m * __high2float(hv);
    }
    Y[(size_t)token * (XVW / 2) + tid] = packh2(s0, s1);
}

// ------------------------------- launch ----------------------------------------
extern "C" void kernel_launch(void* const* d_in, const int* in_sizes, int n_in,
                              void* d_out, int out_size) {
    const float* x  = (const float*)d_in[0];
    const float* Wq = (const float*)d_in[1];
    const float* Wk = (const float*)d_in[2];
    const float* Ws = (const float*)d_in[3];
    const float* Wd = (const float*)d_in[4];
    const float* Wv = (const float*)d_in[5];
    const float* Wo = (const float*)d_in[6];
    float* out = (float*)d_out;

    float *glp, *mask;
    uint32_t *projh, *xbh, *xbl, *wt, *gwh, *gwl, *attnh, *yb, *wot, *blob;
    cudaGetSymbolAddress((void**)&projh, g_projh);
    cudaGetSymbolAddress((void**)&xbh,   g_xbh);
    cudaGetSymbolAddress((void**)&xbl,   g_xbl);
    cudaGetSymbolAddress((void**)&wt,    g_wt);
    cudaGetSymbolAddress((void**)&gwh,   g_gwh);
    cudaGetSymbolAddress((void**)&gwl,   g_gwl);
    cudaGetSymbolAddress((void**)&glp,   g_glp);
    cudaGetSymbolAddress((void**)&attnh, g_attnh);
    cudaGetSymbolAddress((void**)&mask,  g_mask);
    cudaGetSymbolAddress((void**)&yb,    g_yb);
    cudaGetSymbolAddress((void**)&wot,   g_wot);
    cudaGetSymbolAddress((void**)&blob,  g_blob);

    // one fused pack/split pass over all inputs
    pack_all<<<(int)((PACK_TOTAL + 255) / 256), 256>>>(
        x, Wq, Wk, Wv, Ws, Wd, Wo, xbh, xbl, wt, gwh, gwl, wot);

    size_t h1sm = (size_t)3 * H1_STG * sizeof(uint32_t);   // 46080
    cudaFuncSetAttribute(tgemmh1,  cudaFuncAttributeMaxDynamicSharedMemorySize, (int)h1sm);
    cudaFuncSetAttribute(tgemmh1p, cudaFuncAttributeMaxDynamicSharedMemorySize, (int)h1sm);

    // proj GEMM (single fp16, fp16 output): (8192x1024)@(1024x1344)
    dim3 gp(PW2 / 64, NTOK / 128);
    tgemmh1p<<<gp, 256, h1sm>>>(xbh, wt, projh, NTOK, PW2, DD);

    // gate GEMM (fp16 3-term, split-K=2): (8192x1024)@(1024x128) -> partials
    size_t h3sm = (size_t)3 * H3_STG * sizeof(uint32_t);   // 92160
    cudaFuncSetAttribute(tgemmh3, cudaFuncAttributeMaxDynamicSharedMemorySize, (int)h3sm);
    dim3 gg(NG / 64, NTOK / 128, KSPL);
    tgemmh3<<<gg, 256, h3sm>>>(xbh, xbl, gwh, gwl, glp, NTOK, NG, DD);

    // fused gating + V combine + K/V blob + out-mask
    dim3 bg(NTILE, BB * HH);
    gate_kv_kernel<<<bg, 256>>>(glp, projh, blob, mask);

    // attention (pure fp16, fp16 in/out)
    size_t asmem = (size_t)3 * TILE4_U32 * sizeof(uint32_t);  // 61440
    cudaFuncSetAttribute(attn5_kernel, cudaFuncAttributeMaxDynamicSharedMemorySize, (int)asmem);
    dim3 ag(TT / 128, BB * HH);
    attn5_kernel<<<ag, 256, asmem>>>(projh, blob, attnh);

    // masked combine (fp16 in/out), then output GEMM (fp32 out)
    combine_out_kernel<<<NTOK, XVW / 2>>>(attnh, mask, yb);
    dim3 go(DD / 64, NTOK / 128);
    tgemmh1<<<go, 256, h1sm>>>(yb, wot, out, NTOK, DD, XVW);
}